// round 1
// baseline (speedup 1.0000x reference)
#include <cuda_runtime.h>
#include <math.h>

// Problem constants
#define BB 4
#define LL 2048
#define DD 1024
#define HH 4
#define DK 256
#define NT (BB*LL)       // 8192 tokens
#define NCHUNK 64        // chunks per sequence
#define CHK 32           // chunk length
#define NBH 16           // B*H

// ---------------- scratch (device globals; no allocation allowed) -------------
__device__ float g_QL[NT*DD];
__device__ float g_KL[NT*DD];
__device__ float g_VL[NT*DD];
__device__ float g_Q[NT*DD];
__device__ float g_K[NT*DD];
__device__ float g_V[NT*DD];
__device__ float g_beta[NT*HH];
__device__ float g_gamma[NT*HH];
__device__ float g_mixlin[NT*HH];
__device__ float g_mixg[NT*HH];
__device__ float g_W[NBH*NCHUNK*CHK*DK];     // w = T @ k_beta  (bh, chunk, 32, 256)
__device__ float g_T[NBH*NCHUNK*CHK*CHK];    // triangular inverse T
__device__ float g_At[NBH*NCHUNK*CHK*CHK];   // attn_i = tril(q@k^T)
__device__ float g_Od[NT*DD];                // delta-rule output
__device__ float g_Oe[NT*DD];                // ema output
__device__ float g_Op[NT*DD];                // pre-Wo (after mix+rms)

__device__ __forceinline__ float silu_f(float x){ return x / (1.f + expf(-x)); }
__device__ __forceinline__ float sigm_f(float x){ return 1.f / (1.f + expf(-x)); }

// ---------------- SGEMM: C = A(MxK) * B(KxN), row-major, M,N,K mult of 128 ----
#define GBM 128
#define GBN 128
#define GBK 8
#define GTM 8
#define GTN 8
__global__ void __launch_bounds__(256) sgemm128(const float* __restrict__ A,
                                                const float* __restrict__ B,
                                                float* __restrict__ C,
                                                int M, int N, int K)
{
    __shared__ float As[GBK][GBM];
    __shared__ float Bs[GBK][GBN];
    const int tid = threadIdx.x;
    const int brow = blockIdx.y, bcol = blockIdx.x;
    const int tr = tid / (GBN/GTN);     // 0..15
    const int tc = tid % (GBN/GTN);     // 0..15
    const int aRow  = tid >> 1;         // 0..127
    const int aCol4 = (tid & 1) << 2;   // 0 or 4
    const int bRow  = tid >> 5;         // 0..7
    const int bCol4 = (tid & 31) << 2;  // 0..124
    const float* Ag = A + (size_t)brow*GBM*K;
    const float* Bg = B + (size_t)bcol*GBN;
    float acc[GTM][GTN];
    #pragma unroll
    for (int i=0;i<GTM;i++)
        #pragma unroll
        for (int j=0;j<GTN;j++) acc[i][j]=0.f;

    for (int k0 = 0; k0 < K; k0 += GBK){
        float4 av = *(const float4*)(Ag + (size_t)aRow*K + k0 + aCol4);
        As[aCol4+0][aRow]=av.x; As[aCol4+1][aRow]=av.y;
        As[aCol4+2][aRow]=av.z; As[aCol4+3][aRow]=av.w;
        float4 bv = *(const float4*)(Bg + (size_t)(k0+bRow)*N + bCol4);
        *(float4*)&Bs[bRow][bCol4] = bv;
        __syncthreads();
        #pragma unroll
        for (int kk=0;kk<GBK;kk++){
            float ra[GTM], rb[GTN];
            #pragma unroll
            for(int i=0;i<GTM;i++) ra[i]=As[kk][tr*GTM+i];
            #pragma unroll
            for(int j=0;j<GTN;j++) rb[j]=Bs[kk][tc*GTN+j];
            #pragma unroll
            for(int i=0;i<GTM;i++)
                #pragma unroll
                for(int j=0;j<GTN;j++) acc[i][j] += ra[i]*rb[j];
        }
        __syncthreads();
    }
    float* Cg = C + (size_t)brow*GBM*N + bcol*GBN;
    #pragma unroll
    for (int i=0;i<GTM;i++)
        #pragma unroll
        for (int j=0;j<GTN;j+=4){
            float4 v; v.x=acc[i][j]; v.y=acc[i][j+1]; v.z=acc[i][j+2]; v.w=acc[i][j+3];
            *(float4*)(Cg + (size_t)(tr*GTM+i)*N + tc*GTN+j) = v;
        }
}

// ---------------- small projections: beta, gamma (sigmoid), mixlin (raw) -----
__global__ void smallproj_kernel(const float* __restrict__ Xh,
                                 const float* __restrict__ Wb,
                                 const float* __restrict__ Wdec,
                                 const float* __restrict__ Wmix)
{
    __shared__ float part[12][128];
    int row = blockIdx.x, tid = threadIdx.x;
    float acc[12];
    #pragma unroll
    for (int j=0;j<12;j++) acc[j]=0.f;
    for (int c=tid; c<DD; c+=128){
        float hv = Xh[(size_t)row*DD + c];
        #pragma unroll
        for (int j=0;j<4;j++){
            acc[j]   += hv * Wb  [c*4+j];
            acc[4+j] += hv * Wdec[c*4+j];
            acc[8+j] += hv * Wmix[c*4+j];
        }
    }
    #pragma unroll
    for (int j=0;j<12;j++) part[j][tid]=acc[j];
    __syncthreads();
    for (int s=64;s;s>>=1){
        if (tid<s){
            #pragma unroll
            for (int j=0;j<12;j++) part[j][tid]+=part[j][tid+s];
        }
        __syncthreads();
    }
    if (tid<4)        g_beta  [row*4+tid]   = sigm_f(part[tid][0]);
    else if (tid<8)   g_gamma [row*4+tid-4] = sigm_f(part[tid][0]);
    else if (tid<12)  g_mixlin[row*4+tid-8] = part[tid][0];
}

// ---------------- causal short conv (K=4) + silu (optionally twice) ----------
__global__ void conv_silu_kernel(const float* __restrict__ X,
                                 const float* __restrict__ Wc,
                                 float* __restrict__ Y, int dbl)
{
    int idx = blockIdx.x*blockDim.x + threadIdx.x;
    if (idx >= NT*DD) return;
    int ch = idx & (DD-1);
    int bt = idx >> 10;
    int t  = bt & (LL-1);
    float acc = 0.f;
    #pragma unroll
    for (int k=0;k<4;k++){
        int ts = t-3+k;
        if (ts>=0) acc += X[(size_t)idx + (size_t)(ts-t)*DD] * Wc[ch*4+k];
    }
    float y = silu_f(acc);
    if (dbl) y = silu_f(y);
    Y[idx] = y;
}

// ---------------- mix path: conv over H channels + silu + sigmoid(+bias) -----
__global__ void mixconv_kernel(const float* __restrict__ convmix,
                               const float* __restrict__ mixbias)
{
    int idx = blockIdx.x*blockDim.x + threadIdx.x;
    if (idx >= NT*HH) return;
    int h = idx & 3;
    int bt = idx >> 2;
    int t = bt & (LL-1);
    float acc = 0.f;
    #pragma unroll
    for (int k=0;k<4;k++){
        int ts = t-3+k;
        if (ts>=0) acc += g_mixlin[idx + (ts-t)*HH] * convmix[h*4+k];
    }
    float mi = silu_f(acc);
    g_mixg[idx] = sigm_f(mi + mixbias[h]);
}

// ---------------- per-(token,head) l2 norm on Q and K (in place) -------------
__global__ void l2norm_kernel()
{
    __shared__ float red[256];
    int row = blockIdx.x, tid = threadIdx.x;
    for (int h=0;h<HH;h++){
        size_t base = (size_t)row*DD + h*DK;
        float v = g_Q[base + tid];
        red[tid]=v*v; __syncthreads();
        for (int s=128;s;s>>=1){ if(tid<s) red[tid]+=red[tid+s]; __syncthreads(); }
        float sc = rsqrtf(red[0] + 1e-6f);
        g_Q[base+tid] = v*sc;
        __syncthreads();
        float w = g_K[base + tid];
        red[tid]=w*w; __syncthreads();
        for (int s=128;s;s>>=1){ if(tid<s) red[tid]+=red[tid+s]; __syncthreads(); }
        sc = rsqrtf(red[0] + 1e-6f);
        g_K[base+tid] = w*sc;
        __syncthreads();
    }
}

// ---------------- per-chunk: T (tri inverse), W = T@k_beta, Attn = tril(q k^T)
#define KPAD 257
__global__ void __launch_bounds__(256) chunk_kernel()
{
    extern __shared__ float sm[];
    float* kc     = sm;                 // 32*257
    float* qc     = kc + 32*KPAD;       // 32*257
    float* Amat   = qc + 32*KPAD;       // 32*33
    float* bet    = Amat + 32*33;       // 32
    float* rowtmp = bet + 32;           // 32

    int blk = blockIdx.x;               // bh*64 + c
    int bh = blk >> 6, c = blk & 63;
    int b = bh >> 2, h = bh & 3;
    int tid = threadIdx.x;
    int rowbase = b*LL + c*CHK;

    for (int e = tid; e < 32*64; e += 256){
        int r = e >> 6; int c4 = (e & 63) << 2;
        float4 kv = *(const float4*)&g_K[(size_t)(rowbase+r)*DD + h*DK + c4];
        kc[r*KPAD+c4+0]=kv.x; kc[r*KPAD+c4+1]=kv.y; kc[r*KPAD+c4+2]=kv.z; kc[r*KPAD+c4+3]=kv.w;
        float4 qv = *(const float4*)&g_Q[(size_t)(rowbase+r)*DD + h*DK + c4];
        qc[r*KPAD+c4+0]=qv.x; qc[r*KPAD+c4+1]=qv.y; qc[r*KPAD+c4+2]=qv.z; qc[r*KPAD+c4+3]=qv.w;
    }
    if (tid < 32) bet[tid] = g_beta[(rowbase+tid)*HH + h];
    __syncthreads();

    // A = -tril(k_beta @ k^T, -1),  Attn = tril(q @ k^T, 0)
    {
        int i = tid >> 3, j0 = (tid & 7) << 2;
        float da[4], dq[4];
        #pragma unroll
        for (int u=0;u<4;u++){
            int j = j0+u;
            float a=0.f, q=0.f;
            #pragma unroll 8
            for (int m=0;m<256;m++){
                float kj = kc[j*KPAD+m];
                a += kc[i*KPAD+m]*kj;
                q += qc[i*KPAD+m]*kj;
            }
            da[u]=a; dq[u]=q;
        }
        #pragma unroll
        for (int u=0;u<4;u++){
            int j = j0+u;
            Amat[i*33+j] = (j < i) ? -bet[i]*da[u] : 0.f;
            g_At[(size_t)blk*1024 + i*32 + j] = (j <= i) ? dq[u] : 0.f;
        }
    }
    __syncthreads();

    // sequential forward-substitution (warp 0)
    if (tid < 32){
        int cx = tid;
        for (int ii=1; ii<32; ii++){
            rowtmp[cx] = Amat[ii*33+cx];
            __syncwarp();
            float acc = 0.f;
            if (cx < ii){
                acc = rowtmp[cx];
                for (int j=cx+1; j<ii; j++) acc += rowtmp[j]*Amat[j*33+cx];
            }
            __syncwarp();
            if (cx < ii) Amat[ii*33+cx] = acc;
            __syncwarp();
        }
        Amat[cx*33+cx] = 1.0f;   // T = A + I
    }
    __syncthreads();

    for (int e=tid; e<1024; e+=256)
        g_T[(size_t)blk*1024 + e] = Amat[(e>>5)*33 + (e&31)];

    // W = T @ (beta * k)
    {
        int i = tid >> 3, m0 = (tid & 7) << 5;
        float acc[32];
        #pragma unroll
        for (int m=0;m<32;m++) acc[m]=0.f;
        for (int j=0;j<32;j++){
            float tv = Amat[i*33+j]*bet[j];
            #pragma unroll
            for (int m=0;m<32;m++) acc[m] += tv * kc[j*KPAD + m0 + m];
        }
        #pragma unroll
        for (int m=0;m<32;m++) g_W[((size_t)blk*32 + i)*DK + m0 + m] = acc[m];
    }
}

// ---------------- sequential inter-chunk scan, state S in SMEM ---------------
// grid: 128 blocks = 16 (b,h) x 8 dv-slabs of 32 columns
__global__ void __launch_bounds__(256,1) scan_kernel()
{
    extern __shared__ float sm[];
    float* S    = sm;                 // 256*33
    float* w    = S   + 256*33;       // 32*257
    float* q    = w   + 32*KPAD;      // 32*257
    float* kc   = q   + 32*KPAD;      // 32*257
    float* att  = kc  + 32*KPAD;      // 32*33
    float* Tt   = att + 32*33;        // 32*33
    float* vb   = Tt  + 32*33;        // 32*33
    float* ua   = vb  + 32*33;        // 32*33

    int tid = threadIdx.x;
    int bh   = blockIdx.x >> 3;
    int slab = blockIdx.x & 7;
    int b = bh >> 2, h = bh & 3;

    for (int e=tid; e<256*33; e+=256) S[e]=0.f;
    __syncthreads();

    const int i0 = (tid >> 4) << 1;   // 0..30 step 2
    const int j0 = (tid & 15) << 1;   // 0..30 step 2

    for (int c=0; c<NCHUNK; c++){
        int blk = bh*NCHUNK + c;
        int rowbase = b*LL + c*CHK;
        // ---- load tiles
        for (int e=tid; e<32*64; e+=256){
            int r = e >> 6; int c4 = (e & 63) << 2;
            float4 wv = *(const float4*)&g_W[((size_t)blk*32 + r)*DK + c4];
            w[r*KPAD+c4+0]=wv.x; w[r*KPAD+c4+1]=wv.y; w[r*KPAD+c4+2]=wv.z; w[r*KPAD+c4+3]=wv.w;
            float4 qv = *(const float4*)&g_Q[(size_t)(rowbase+r)*DD + h*DK + c4];
            q[r*KPAD+c4+0]=qv.x; q[r*KPAD+c4+1]=qv.y; q[r*KPAD+c4+2]=qv.z; q[r*KPAD+c4+3]=qv.w;
            float4 kv = *(const float4*)&g_K[(size_t)(rowbase+r)*DD + h*DK + c4];
            kc[r*KPAD+c4+0]=kv.x; kc[r*KPAD+c4+1]=kv.y; kc[r*KPAD+c4+2]=kv.z; kc[r*KPAD+c4+3]=kv.w;
        }
        for (int e=tid; e<1024; e+=256){
            int r = e >> 5, jj = e & 31;
            att[r*33+jj] = g_At[(size_t)blk*1024 + e];
            Tt [r*33+jj] = g_T [(size_t)blk*1024 + e];
            float be = g_beta[(rowbase+r)*HH + h];
            vb [r*33+jj] = g_V[(size_t)(rowbase+r)*DD + h*DK + slab*32 + jj] * be;
        }
        __syncthreads();

        // ---- u_i = T @ vb   (2x2 microtile)
        float ui00=0,ui01=0,ui10=0,ui11=0;
        #pragma unroll
        for (int m=0;m<32;m++){
            float v0=vb[m*33+j0], v1=vb[m*33+j0+1];
            float t0=Tt[i0*33+m], t1=Tt[(i0+1)*33+m];
            ui00+=t0*v0; ui01+=t0*v1; ui10+=t1*v0; ui11+=t1*v1;
        }
        // ---- w@S and q@S in one pass over k (share S loads)
        float aU00=0,aU01=0,aU10=0,aU11=0;
        float aO00=0,aO01=0,aO10=0,aO11=0;
        #pragma unroll 8
        for (int k=0;k<256;k++){
            float s0=S[k*33+j0], s1=S[k*33+j0+1];
            float w0=w[i0*KPAD+k], w1=w[(i0+1)*KPAD+k];
            float q0=q[i0*KPAD+k], q1=q[(i0+1)*KPAD+k];
            aU00+=w0*s0; aU01+=w0*s1; aU10+=w1*s0; aU11+=w1*s1;
            aO00+=q0*s0; aO01+=q0*s1; aO10+=q1*s0; aO11+=q1*s1;
        }
        ua[i0*33+j0]      = ui00-aU00;
        ua[i0*33+j0+1]    = ui01-aU01;
        ua[(i0+1)*33+j0]  = ui10-aU10;
        ua[(i0+1)*33+j0+1]= ui11-aU11;
        __syncthreads();

        // ---- o = q@S + attn @ u_adj  -> global
        #pragma unroll
        for (int m=0;m<32;m++){
            float u0=ua[m*33+j0], u1=ua[m*33+j0+1];
            float a0=att[i0*33+m], a1=att[(i0+1)*33+m];
            aO00+=a0*u0; aO01+=a0*u1; aO10+=a1*u0; aO11+=a1*u1;
        }
        size_t ocol = (size_t)h*DK + slab*32;
        g_Od[(size_t)(rowbase+i0  )*DD + ocol + j0  ] = aO00;
        g_Od[(size_t)(rowbase+i0  )*DD + ocol + j0+1] = aO01;
        g_Od[(size_t)(rowbase+i0+1)*DD + ocol + j0  ] = aO10;
        g_Od[(size_t)(rowbase+i0+1)*DD + ocol + j0+1] = aO11;

        // ---- S += k^T @ u_adj  (thread owns dk-row tid)
        float kv[32];
        #pragma unroll
        for (int i=0;i<32;i++) kv[i]=kc[i*KPAD+tid];
        #pragma unroll 4
        for (int j=0;j<32;j++){
            float acc=0.f;
            #pragma unroll
            for (int i=0;i<32;i++) acc += kv[i]*ua[i*33+j];
            S[tid*33+j] += acc;
        }
        __syncthreads();
    }
}

// ---------------- EMA over time per (b,h), thread = dv channel ---------------
__global__ void ema_kernel()
{
    int bh = blockIdx.x;
    int b = bh >> 2, h = bh & 3;
    int j = threadIdx.x;
    float s = 0.f;
    int base = b*LL;
    for (int t=0;t<LL;t++){
        float g = g_gamma[(base+t)*HH + h];
        float v = g_V[(size_t)(base+t)*DD + h*DK + j];
        s = g*s + (1.f-g)*v;
        g_Oe[(size_t)(base+t)*DD + h*DK + j] = s;
    }
}

// ---------------- mix combine + per-head RMS norm ----------------------------
__global__ void combine_rms_kernel(const float* __restrict__ rmsw)
{
    __shared__ float red[256];
    int row = blockIdx.x, tid = threadIdx.x;
    for (int h=0;h<HH;h++){
        __syncthreads();
        float m  = g_mixg[row*HH+h];
        size_t base = (size_t)row*DD + h*DK;
        float od = g_Od[base + tid];
        float oe = g_Oe[base + tid];
        float o  = (1.f-m)*od + m*oe;
        red[tid] = o*o; __syncthreads();
        for (int s=128;s;s>>=1){ if(tid<s) red[tid]+=red[tid+s]; __syncthreads(); }
        float sc = rsqrtf(red[0]*(1.f/256.f) + 1e-5f);
        g_Op[base+tid] = o*sc*rmsw[tid];
    }
}

// ---------------- host driver -----------------------------------------------
extern "C" void kernel_launch(void* const* d_in, const int* in_sizes, int n_in,
                              void* d_out, int out_size)
{
    const float* hs      = (const float*)d_in[0];
    const float* Wq      = (const float*)d_in[1];
    const float* Wk      = (const float*)d_in[2];
    const float* Wv      = (const float*)d_in[3];
    const float* convq   = (const float*)d_in[4];
    const float* convk   = (const float*)d_in[5];
    const float* convv   = (const float*)d_in[6];
    const float* Wb      = (const float*)d_in[7];
    const float* Wdec    = (const float*)d_in[8];
    const float* Wmix    = (const float*)d_in[9];
    const float* convmix = (const float*)d_in[10];
    const float* mixbias = (const float*)d_in[11];
    const float* rmsw    = (const float*)d_in[12];
    const float* Wo      = (const float*)d_in[13];

    void *pQL,*pKL,*pVL,*pQ,*pK,*pV,*pOp;
    cudaGetSymbolAddress(&pQL, g_QL);
    cudaGetSymbolAddress(&pKL, g_KL);
    cudaGetSymbolAddress(&pVL, g_VL);
    cudaGetSymbolAddress(&pQ,  g_Q);
    cudaGetSymbolAddress(&pK,  g_K);
    cudaGetSymbolAddress(&pV,  g_V);
    cudaGetSymbolAddress(&pOp, g_Op);

    int smem_chunk = (2*32*KPAD + 32*33 + 64) * 4;
    int smem_scan  = (256*33 + 3*32*KPAD + 4*32*33) * 4;
    cudaFuncSetAttribute(chunk_kernel, cudaFuncAttributeMaxDynamicSharedMemorySize, smem_chunk);
    cudaFuncSetAttribute(scan_kernel,  cudaFuncAttributeMaxDynamicSharedMemorySize, smem_scan);

    dim3 gg(DD/GBN, NT/GBM);   // (8, 64)

    sgemm128<<<gg,256>>>(hs, Wq, (float*)pQL, NT, DD, DD);
    sgemm128<<<gg,256>>>(hs, Wk, (float*)pKL, NT, DD, DD);
    sgemm128<<<gg,256>>>(hs, Wv, (float*)pVL, NT, DD, DD);
    smallproj_kernel<<<NT,128>>>(hs, Wb, Wdec, Wmix);

    int nconv = NT*DD/256;
    conv_silu_kernel<<<nconv,256>>>((const float*)pQL, convq, (float*)pQ, 1);
    conv_silu_kernel<<<nconv,256>>>((const float*)pKL, convk, (float*)pK, 1);
    conv_silu_kernel<<<nconv,256>>>((const float*)pVL, convv, (float*)pV, 0);
    mixconv_kernel<<<(NT*HH+127)/128,128>>>(convmix, mixbias);

    l2norm_kernel<<<NT,256>>>();
    chunk_kernel<<<NBH*NCHUNK,256,smem_chunk>>>();
    scan_kernel<<<NBH*8,256,smem_scan>>>();
    ema_kernel<<<NBH,256>>>();
    combine_rms_kernel<<<NT,256>>>(rmsw);

    sgemm128<<<gg,256>>>((const float*)pOp, Wo, (float*)d_out, NT, DD, DD);
}

// round 4
// speedup vs baseline: 1.4055x; 1.4055x over previous
#include <cuda_runtime.h>
#include <cuda_bf16.h>
#include <math.h>
#include <stdint.h>

// Problem constants
#define BB 4
#define LL 2048
#define DD 1024
#define HH 4
#define DK 256
#define NT (BB*LL)       // 8192 tokens
#define NCHUNK 64        // chunks per sequence
#define CHK 32           // chunk length
#define NBH 16           // B*H

// ---------------- scratch (device globals; no allocation allowed) -------------
__device__ float g_QL[NT*DD];
__device__ float g_KL[NT*DD];
__device__ float g_VL[NT*DD];
__device__ float g_Q[NT*DD];
__device__ float g_K[NT*DD];
__device__ float g_V[NT*DD];
__device__ float g_beta[NT*HH];
__device__ float g_gamma[NT*HH];
__device__ float g_mixlin[NT*HH];
__device__ float g_mixg[NT*HH];
__device__ float g_W[NBH*NCHUNK*CHK*DK];     // w = T @ k_beta
__device__ float g_T[NBH*NCHUNK*CHK*CHK];    // triangular inverse T
__device__ float g_At[NBH*NCHUNK*CHK*CHK];   // attn_i = tril(q@k^T)
__device__ float g_Od[NT*DD];                // delta-rule output
__device__ float g_Oe[NT*DD];                // ema output
__device__ float g_Op[NT*DD];                // pre-Wo (after mix+rms)

// bf16 split buffers for tensor-core GEMMs
__device__ __nv_bfloat16 g_hs_hi[NT*DD], g_hs_lo[NT*DD];
__device__ __nv_bfloat16 g_Op_hi[NT*DD], g_Op_lo[NT*DD];
__device__ __nv_bfloat16 g_WqT_hi[DD*DD], g_WqT_lo[DD*DD];
__device__ __nv_bfloat16 g_WkT_hi[DD*DD], g_WkT_lo[DD*DD];
__device__ __nv_bfloat16 g_WvT_hi[DD*DD], g_WvT_lo[DD*DD];
__device__ __nv_bfloat16 g_WoT_hi[DD*DD], g_WoT_lo[DD*DD];

__device__ __forceinline__ float silu_f(float x){ return x / (1.f + expf(-x)); }
__device__ __forceinline__ float sigm_f(float x){ return 1.f / (1.f + expf(-x)); }

// ===================== PTX helpers (mma.sync / ldmatrix / cp.async) ==========
__device__ __forceinline__ uint32_t smem_u32(const void* p){
    uint32_t a;
    asm("{ .reg .u64 t; cvta.to.shared.u64 t, %1; cvt.u32.u64 %0, t; }" : "=r"(a) : "l"(p));
    return a;
}
__device__ __forceinline__ void cp_async16(uint32_t dst, const void* src){
    asm volatile("cp.async.cg.shared.global [%0], [%1], 16;" :: "r"(dst), "l"(src) : "memory");
}
__device__ __forceinline__ void cp_commit(){ asm volatile("cp.async.commit_group;" ::: "memory"); }

#define LDSM_X4(r0,r1,r2,r3, addr) \
    asm volatile("ldmatrix.sync.aligned.m8n8.x4.shared.b16 {%0,%1,%2,%3}, [%4];" \
        : "=r"(r0),"=r"(r1),"=r"(r2),"=r"(r3) : "r"(addr))

#define MMA16816(d, a, b0, b1) \
    asm volatile("mma.sync.aligned.m16n8k16.row.col.f32.bf16.bf16.f32 " \
        "{%0,%1,%2,%3}, {%4,%5,%6,%7}, {%8,%9}, {%0,%1,%2,%3};" \
        : "+f"((d)[0]),"+f"((d)[1]),"+f"((d)[2]),"+f"((d)[3]) \
        : "r"((a)[0]),"r"((a)[1]),"r"((a)[2]),"r"((a)[3]), "r"(b0),"r"(b1))

// ===================== split/transpose conversion kernels ====================
__global__ void split_kernel(const float* __restrict__ X,
                             __nv_bfloat16* __restrict__ hi,
                             __nv_bfloat16* __restrict__ lo, int n)
{
    int i = blockIdx.x*256 + threadIdx.x;
    if (i < n){
        float x = X[i];
        __nv_bfloat16 h = __float2bfloat16(x);
        hi[i] = h;
        lo[i] = __float2bfloat16(x - __bfloat162float(h));
    }
}
// W is [K=1024, N=1024] row-major; write W^T split into [N, K] bf16 hi/lo
__global__ void wsplitT_kernel(const float* __restrict__ W,
                               __nv_bfloat16* __restrict__ hiT,
                               __nv_bfloat16* __restrict__ loT)
{
    __shared__ float t[32][33];
    int n0 = blockIdx.x*32, k0 = blockIdx.y*32;
    int tx = threadIdx.x, ty = threadIdx.y;   // 32 x 8
    for (int i = ty; i < 32; i += 8)
        t[i][tx] = W[(size_t)(k0+i)*DD + n0+tx];
    __syncthreads();
    for (int i = ty; i < 32; i += 8){
        float x = t[tx][i];                   // W[k0+tx][n0+i]
        __nv_bfloat16 h = __float2bfloat16(x);
        hiT[(size_t)(n0+i)*DD + k0+tx] = h;
        loT[(size_t)(n0+i)*DD + k0+tx] = __float2bfloat16(x - __bfloat162float(h));
    }
}

// ===================== mma.sync split-bf16 GEMM ==============================
// C[M,N] = A[M,K] @ B[K,N]; A as hi/lo bf16 [M,K], B as hi/lo bf16 [N,K] (B^T).
// CTA tile 128x128, warp tile 32x64 (4x2 warps), K staged 32, double buffered.
#define GRS 40            // smem row stride in bf16 elements (80 bytes)
#define MATB (128*GRS*2)  // 10240 bytes per matrix tile
#define STGB (4*MATB)     // 40960 per stage

__global__ void __launch_bounds__(256,2) gemm_bf16s(
    const __nv_bfloat16* __restrict__ Ahi, const __nv_bfloat16* __restrict__ Alo,
    const __nv_bfloat16* __restrict__ BhiT, const __nv_bfloat16* __restrict__ BloT,
    float* __restrict__ C, int M, int N, int K)
{
    extern __shared__ char smem[];
    const uint32_t sbase = smem_u32(smem);
    const int tid  = threadIdx.x;
    const int lane = tid & 31, wid = tid >> 5;
    const int wm = wid & 3, wn = wid >> 2;          // 4x2 warp grid
    const int row0 = blockIdx.y*128, col0 = blockIdx.x*128;

    const __nv_bfloat16* g0 = Ahi  + (size_t)row0*K;
    const __nv_bfloat16* g1 = Alo  + (size_t)row0*K;
    const __nv_bfloat16* g2 = BhiT + (size_t)col0*K;
    const __nv_bfloat16* g3 = BloT + (size_t)col0*K;

    float acc[2][8][4];
    #pragma unroll
    for (int i=0;i<2;i++)
        #pragma unroll
        for (int j=0;j<8;j++)
            #pragma unroll
            for (int u=0;u<4;u++) acc[i][j][u]=0.f;

    // fill one stage (k-block kb)
    auto fill = [&](int stage, int kb){
        uint32_t sb = sbase + stage*STGB;
        #pragma unroll
        for (int t=0;t<2;t++){
            int ci = tid + t*256;
            int r = ci >> 2, c = ci & 3;
            uint32_t dst = sb + r*(GRS*2) + c*16;
            size_t go = (size_t)r*K + (size_t)kb*32 + c*8;
            cp_async16(dst + 0*MATB, g0 + go);
            cp_async16(dst + 1*MATB, g1 + go);
            cp_async16(dst + 2*MATB, g2 + go);
            cp_async16(dst + 3*MATB, g3 + go);
        }
        cp_commit();
    };

    const int nkb = K/32;
    fill(0, 0);

    // lane-derived ldmatrix offsets
    const int a_r  = lane & 15;
    const int a_ko = ((lane >> 4) & 1) << 3;
    const int b_n  = (lane & 7) + (((lane >> 4) & 1) << 3);
    const int b_ko = ((lane >> 3) & 1) << 3;

    for (int kb = 0; kb < nkb; kb++){
        if (kb+1 < nkb){
            fill((kb+1)&1, kb+1);
            asm volatile("cp.async.wait_group 1;" ::: "memory");
        } else {
            asm volatile("cp.async.wait_group 0;" ::: "memory");
        }
        __syncthreads();

        uint32_t sb = sbase + (kb&1)*STGB;
        #pragma unroll
        for (int ks=0; ks<2; ks++){
            const int k16 = ks*16;
            uint32_t ah[2][4], al[2][4];
            #pragma unroll
            for (int mt=0; mt<2; mt++){
                uint32_t ad = sb + (wm*32 + mt*16 + a_r)*(GRS*2) + (k16 + a_ko)*2;
                LDSM_X4(ah[mt][0],ah[mt][1],ah[mt][2],ah[mt][3], ad + 0*MATB);
                LDSM_X4(al[mt][0],al[mt][1],al[mt][2],al[mt][3], ad + 1*MATB);
            }
            #pragma unroll
            for (int n4=0; n4<4; n4++){
                uint32_t bd = sb + 2*MATB + (wn*64 + n4*16 + b_n)*(GRS*2) + (k16 + b_ko)*2;
                uint32_t bh[4], bl[4];
                LDSM_X4(bh[0],bh[1],bh[2],bh[3], bd);
                LDSM_X4(bl[0],bl[1],bl[2],bl[3], bd + MATB);
                #pragma unroll
                for (int mt=0; mt<2; mt++){
                    MMA16816(acc[mt][n4*2  ], ah[mt], bh[0], bh[1]);
                    MMA16816(acc[mt][n4*2+1], ah[mt], bh[2], bh[3]);
                    MMA16816(acc[mt][n4*2  ], ah[mt], bl[0], bl[1]);
                    MMA16816(acc[mt][n4*2+1], ah[mt], bl[2], bl[3]);
                    MMA16816(acc[mt][n4*2  ], al[mt], bh[0], bh[1]);
                    MMA16816(acc[mt][n4*2+1], al[mt], bh[2], bh[3]);
                }
            }
        }
        __syncthreads();
    }

    // epilogue
    float* Cg = C + (size_t)(row0 + wm*32)*N + col0 + wn*64;
    const int cr = lane >> 2, cc = (lane & 3) << 1;
    #pragma unroll
    for (int mt=0; mt<2; mt++)
        #pragma unroll
        for (int nt=0; nt<8; nt++){
            float2 v0; v0.x = acc[mt][nt][0]; v0.y = acc[mt][nt][1];
            *(float2*)&Cg[(size_t)(mt*16+cr)*N + nt*8+cc] = v0;
            float2 v1; v1.x = acc[mt][nt][2]; v1.y = acc[mt][nt][3];
            *(float2*)&Cg[(size_t)(mt*16+cr+8)*N + nt*8+cc] = v1;
        }
}

// ---------------- small projections: beta, gamma (sigmoid), mixlin (raw) -----
__global__ void smallproj_kernel(const float* __restrict__ Xh,
                                 const float* __restrict__ Wb,
                                 const float* __restrict__ Wdec,
                                 const float* __restrict__ Wmix)
{
    __shared__ float part[12][128];
    int row = blockIdx.x, tid = threadIdx.x;
    float acc[12];
    #pragma unroll
    for (int j=0;j<12;j++) acc[j]=0.f;
    for (int c=tid; c<DD; c+=128){
        float hv = Xh[(size_t)row*DD + c];
        #pragma unroll
        for (int j=0;j<4;j++){
            acc[j]   += hv * Wb  [c*4+j];
            acc[4+j] += hv * Wdec[c*4+j];
            acc[8+j] += hv * Wmix[c*4+j];
        }
    }
    #pragma unroll
    for (int j=0;j<12;j++) part[j][tid]=acc[j];
    __syncthreads();
    for (int s=64;s;s>>=1){
        if (tid<s){
            #pragma unroll
            for (int j=0;j<12;j++) part[j][tid]+=part[j][tid+s];
        }
        __syncthreads();
    }
    if (tid<4)        g_beta  [row*4+tid]   = sigm_f(part[tid][0]);
    else if (tid<8)   g_gamma [row*4+tid-4] = sigm_f(part[tid][0]);
    else if (tid<12)  g_mixlin[row*4+tid-8] = part[tid][0];
}

// ---------------- causal short conv (K=4) + silu (optionally twice) ----------
__global__ void conv_silu_kernel(const float* __restrict__ X,
                                 const float* __restrict__ Wc,
                                 float* __restrict__ Y, int dbl)
{
    int idx = blockIdx.x*blockDim.x + threadIdx.x;
    if (idx >= NT*DD) return;
    int ch = idx & (DD-1);
    int bt = idx >> 10;
    int t  = bt & (LL-1);
    float acc = 0.f;
    #pragma unroll
    for (int k=0;k<4;k++){
        int ts = t-3+k;
        if (ts>=0) acc += X[(size_t)idx + (size_t)(ts-t)*DD] * Wc[ch*4+k];
    }
    float y = silu_f(acc);
    if (dbl) y = silu_f(y);
    Y[idx] = y;
}

// ---------------- mix path: conv over H channels + silu + sigmoid(+bias) -----
__global__ void mixconv_kernel(const float* __restrict__ convmix,
                               const float* __restrict__ mixbias)
{
    int idx = blockIdx.x*blockDim.x + threadIdx.x;
    if (idx >= NT*HH) return;
    int h = idx & 3;
    int bt = idx >> 2;
    int t = bt & (LL-1);
    float acc = 0.f;
    #pragma unroll
    for (int k=0;k<4;k++){
        int ts = t-3+k;
        if (ts>=0) acc += g_mixlin[idx + (ts-t)*HH] * convmix[h*4+k];
    }
    float mi = silu_f(acc);
    g_mixg[idx] = sigm_f(mi + mixbias[h]);
}

// ---------------- per-(token,head) l2 norm on Q and K (in place) -------------
__global__ void l2norm_kernel()
{
    __shared__ float red[256];
    int row = blockIdx.x, tid = threadIdx.x;
    for (int h=0;h<HH;h++){
        size_t base = (size_t)row*DD + h*DK;
        float v = g_Q[base + tid];
        red[tid]=v*v; __syncthreads();
        for (int s=128;s;s>>=1){ if(tid<s) red[tid]+=red[tid+s]; __syncthreads(); }
        float sc = rsqrtf(red[0] + 1e-6f);
        g_Q[base+tid] = v*sc;
        __syncthreads();
        float w = g_K[base + tid];
        red[tid]=w*w; __syncthreads();
        for (int s=128;s;s>>=1){ if(tid<s) red[tid]+=red[tid+s]; __syncthreads(); }
        sc = rsqrtf(red[0] + 1e-6f);
        g_K[base+tid] = w*sc;
        __syncthreads();
    }
}

// ---------------- per-chunk: T (tri inverse), W = T@k_beta, Attn = tril(q k^T)
#define KPAD 257
__global__ void __launch_bounds__(256) chunk_kernel()
{
    extern __shared__ float sm[];
    float* kc     = sm;                 // 32*257
    float* qc     = kc + 32*KPAD;       // 32*257
    float* Amat   = qc + 32*KPAD;       // 32*33
    float* bet    = Amat + 32*33;       // 32
    float* rowtmp = bet + 32;           // 32

    int blk = blockIdx.x;               // bh*64 + c
    int bh = blk >> 6, c = blk & 63;
    int b = bh >> 2, h = bh & 3;
    int tid = threadIdx.x;
    int rowbase = b*LL + c*CHK;

    for (int e = tid; e < 32*64; e += 256){
        int r = e >> 6; int c4 = (e & 63) << 2;
        float4 kv = *(const float4*)&g_K[(size_t)(rowbase+r)*DD + h*DK + c4];
        kc[r*KPAD+c4+0]=kv.x; kc[r*KPAD+c4+1]=kv.y; kc[r*KPAD+c4+2]=kv.z; kc[r*KPAD+c4+3]=kv.w;
        float4 qv = *(const float4*)&g_Q[(size_t)(rowbase+r)*DD + h*DK + c4];
        qc[r*KPAD+c4+0]=qv.x; qc[r*KPAD+c4+1]=qv.y; qc[r*KPAD+c4+2]=qv.z; qc[r*KPAD+c4+3]=qv.w;
    }
    if (tid < 32) bet[tid] = g_beta[(rowbase+tid)*HH + h];
    __syncthreads();

    // A = -tril(k_beta @ k^T, -1),  Attn = tril(q @ k^T, 0)
    {
        int i = tid >> 3, j0 = (tid & 7) << 2;
        float da[4], dq[4];
        #pragma unroll
        for (int u=0;u<4;u++){
            int j = j0+u;
            float a=0.f, q=0.f;
            #pragma unroll 8
            for (int m=0;m<256;m++){
                float kj = kc[j*KPAD+m];
                a += kc[i*KPAD+m]*kj;
                q += qc[i*KPAD+m]*kj;
            }
            da[u]=a; dq[u]=q;
        }
        #pragma unroll
        for (int u=0;u<4;u++){
            int j = j0+u;
            Amat[i*33+j] = (j < i) ? -bet[i]*da[u] : 0.f;
            g_At[(size_t)blk*1024 + i*32 + j] = (j <= i) ? dq[u] : 0.f;
        }
    }
    __syncthreads();

    // sequential forward-substitution (warp 0)
    if (tid < 32){
        int cx = tid;
        for (int ii=1; ii<32; ii++){
            rowtmp[cx] = Amat[ii*33+cx];
            __syncwarp();
            float acc = 0.f;
            if (cx < ii){
                acc = rowtmp[cx];
                for (int j=cx+1; j<ii; j++) acc += rowtmp[j]*Amat[j*33+cx];
            }
            __syncwarp();
            if (cx < ii) Amat[ii*33+cx] = acc;
            __syncwarp();
        }
        Amat[cx*33+cx] = 1.0f;   // T = A + I
    }
    __syncthreads();

    for (int e=tid; e<1024; e+=256)
        g_T[(size_t)blk*1024 + e] = Amat[(e>>5)*33 + (e&31)];

    // W = T @ (beta * k)
    {
        int i = tid >> 3, m0 = (tid & 7) << 5;
        float acc[32];
        #pragma unroll
        for (int m=0;m<32;m++) acc[m]=0.f;
        for (int j=0;j<32;j++){
            float tv = Amat[i*33+j]*bet[j];
            #pragma unroll
            for (int m=0;m<32;m++) acc[m] += tv * kc[j*KPAD + m0 + m];
        }
        #pragma unroll
        for (int m=0;m<32;m++) g_W[((size_t)blk*32 + i)*DK + m0 + m] = acc[m];
    }
}

// ---------------- sequential inter-chunk scan, state S in SMEM ---------------
__global__ void __launch_bounds__(256,1) scan_kernel()
{
    extern __shared__ float sm[];
    float* S    = sm;                 // 256*33
    float* w    = S   + 256*33;       // 32*257
    float* q    = w   + 32*KPAD;      // 32*257
    float* kc   = q   + 32*KPAD;      // 32*257
    float* att  = kc  + 32*KPAD;      // 32*33
    float* Tt   = att + 32*33;        // 32*33
    float* vb   = Tt  + 32*33;        // 32*33
    float* ua   = vb  + 32*33;        // 32*33

    int tid = threadIdx.x;
    int bh   = blockIdx.x >> 3;
    int slab = blockIdx.x & 7;
    int b = bh >> 2, h = bh & 3;

    for (int e=tid; e<256*33; e+=256) S[e]=0.f;
    __syncthreads();

    const int i0 = (tid >> 4) << 1;
    const int j0 = (tid & 15) << 1;

    for (int c=0; c<NCHUNK; c++){
        int blk = bh*NCHUNK + c;
        int rowbase = b*LL + c*CHK;
        for (int e=tid; e<32*64; e+=256){
            int r = e >> 6; int c4 = (e & 63) << 2;
            float4 wv = *(const float4*)&g_W[((size_t)blk*32 + r)*DK + c4];
            w[r*KPAD+c4+0]=wv.x; w[r*KPAD+c4+1]=wv.y; w[r*KPAD+c4+2]=wv.z; w[r*KPAD+c4+3]=wv.w;
            float4 qv = *(const float4*)&g_Q[(size_t)(rowbase+r)*DD + h*DK + c4];
            q[r*KPAD+c4+0]=qv.x; q[r*KPAD+c4+1]=qv.y; q[r*KPAD+c4+2]=qv.z; q[r*KPAD+c4+3]=qv.w;
            float4 kv = *(const float4*)&g_K[(size_t)(rowbase+r)*DD + h*DK + c4];
            kc[r*KPAD+c4+0]=kv.x; kc[r*KPAD+c4+1]=kv.y; kc[r*KPAD+c4+2]=kv.z; kc[r*KPAD+c4+3]=kv.w;
        }
        for (int e=tid; e<1024; e+=256){
            int r = e >> 5, jj = e & 31;
            att[r*33+jj] = g_At[(size_t)blk*1024 + e];
            Tt [r*33+jj] = g_T [(size_t)blk*1024 + e];
            float be = g_beta[(rowbase+r)*HH + h];
            vb [r*33+jj] = g_V[(size_t)(rowbase+r)*DD + h*DK + slab*32 + jj] * be;
        }
        __syncthreads();

        float ui00=0,ui01=0,ui10=0,ui11=0;
        #pragma unroll
        for (int m=0;m<32;m++){
            float v0=vb[m*33+j0], v1=vb[m*33+j0+1];
            float t0=Tt[i0*33+m], t1=Tt[(i0+1)*33+m];
            ui00+=t0*v0; ui01+=t0*v1; ui10+=t1*v0; ui11+=t1*v1;
        }
        float aU00=0,aU01=0,aU10=0,aU11=0;
        float aO00=0,aO01=0,aO10=0,aO11=0;
        #pragma unroll 8
        for (int k=0;k<256;k++){
            float s0=S[k*33+j0], s1=S[k*33+j0+1];
            float w0=w[i0*KPAD+k], w1=w[(i0+1)*KPAD+k];
            float q0=q[i0*KPAD+k], q1=q[(i0+1)*KPAD+k];
            aU00+=w0*s0; aU01+=w0*s1; aU10+=w1*s0; aU11+=w1*s1;
            aO00+=q0*s0; aO01+=q0*s1; aO10+=q1*s0; aO11+=q1*s1;
        }
        ua[i0*33+j0]      = ui00-aU00;
        ua[i0*33+j0+1]    = ui01-aU01;
        ua[(i0+1)*33+j0]  = ui10-aU10;
        ua[(i0+1)*33+j0+1]= ui11-aU11;
        __syncthreads();

        #pragma unroll
        for (int m=0;m<32;m++){
            float u0=ua[m*33+j0], u1=ua[m*33+j0+1];
            float a0=att[i0*33+m], a1=att[(i0+1)*33+m];
            aO00+=a0*u0; aO01+=a0*u1; aO10+=a1*u0; aO11+=a1*u1;
        }
        size_t ocol = (size_t)h*DK + slab*32;
        g_Od[(size_t)(rowbase+i0  )*DD + ocol + j0  ] = aO00;
        g_Od[(size_t)(rowbase+i0  )*DD + ocol + j0+1] = aO01;
        g_Od[(size_t)(rowbase+i0+1)*DD + ocol + j0  ] = aO10;
        g_Od[(size_t)(rowbase+i0+1)*DD + ocol + j0+1] = aO11;

        float kv[32];
        #pragma unroll
        for (int i=0;i<32;i++) kv[i]=kc[i*KPAD+tid];
        #pragma unroll 4
        for (int j=0;j<32;j++){
            float acc=0.f;
            #pragma unroll
            for (int i=0;i<32;i++) acc += kv[i]*ua[i*33+j];
            S[tid*33+j] += acc;
        }
        __syncthreads();
    }
}

// ---------------- EMA over time per (b,h), thread = dv channel ---------------
__global__ void ema_kernel()
{
    int bh = blockIdx.x;
    int b = bh >> 2, h = bh & 3;
    int j = threadIdx.x;
    float s = 0.f;
    int base = b*LL;
    for (int t=0;t<LL;t++){
        float g = g_gamma[(base+t)*HH + h];
        float v = g_V[(size_t)(base+t)*DD + h*DK + j];
        s = g*s + (1.f-g)*v;
        g_Oe[(size_t)(base+t)*DD + h*DK + j] = s;
    }
}

// ---------------- mix combine + per-head RMS norm ----------------------------
__global__ void combine_rms_kernel(const float* __restrict__ rmsw)
{
    __shared__ float red[256];
    int row = blockIdx.x, tid = threadIdx.x;
    for (int h=0;h<HH;h++){
        __syncthreads();
        float m  = g_mixg[row*HH+h];
        size_t base = (size_t)row*DD + h*DK;
        float od = g_Od[base + tid];
        float oe = g_Oe[base + tid];
        float o  = (1.f-m)*od + m*oe;
        red[tid] = o*o; __syncthreads();
        for (int s=128;s;s>>=1){ if(tid<s) red[tid]+=red[tid+s]; __syncthreads(); }
        float sc = rsqrtf(red[0]*(1.f/256.f) + 1e-5f);
        g_Op[base+tid] = o*sc*rmsw[tid];
    }
}

// ---------------- host driver -----------------------------------------------
extern "C" void kernel_launch(void* const* d_in, const int* in_sizes, int n_in,
                              void* d_out, int out_size)
{
    const float* hs      = (const float*)d_in[0];
    const float* Wq      = (const float*)d_in[1];
    const float* Wk      = (const float*)d_in[2];
    const float* Wv      = (const float*)d_in[3];
    const float* convq   = (const float*)d_in[4];
    const float* convk   = (const float*)d_in[5];
    const float* convv   = (const float*)d_in[6];
    const float* Wb      = (const float*)d_in[7];
    const float* Wdec    = (const float*)d_in[8];
    const float* Wmix    = (const float*)d_in[9];
    const float* convmix = (const float*)d_in[10];
    const float* mixbias = (const float*)d_in[11];
    const float* rmsw    = (const float*)d_in[12];
    const float* Wo      = (const float*)d_in[13];

    void *pQL,*pKL,*pVL,*pQ,*pK,*pV,*pOp;
    cudaGetSymbolAddress(&pQL, g_QL);
    cudaGetSymbolAddress(&pKL, g_KL);
    cudaGetSymbolAddress(&pVL, g_VL);
    cudaGetSymbolAddress(&pQ,  g_Q);
    cudaGetSymbolAddress(&pK,  g_K);
    cudaGetSymbolAddress(&pV,  g_V);
    cudaGetSymbolAddress(&pOp, g_Op);

    void *p_hs_hi,*p_hs_lo,*p_Op_hi,*p_Op_lo;
    void *p_WqT_hi,*p_WqT_lo,*p_WkT_hi,*p_WkT_lo,*p_WvT_hi,*p_WvT_lo,*p_WoT_hi,*p_WoT_lo;
    cudaGetSymbolAddress(&p_hs_hi, g_hs_hi);  cudaGetSymbolAddress(&p_hs_lo, g_hs_lo);
    cudaGetSymbolAddress(&p_Op_hi, g_Op_hi);  cudaGetSymbolAddress(&p_Op_lo, g_Op_lo);
    cudaGetSymbolAddress(&p_WqT_hi, g_WqT_hi); cudaGetSymbolAddress(&p_WqT_lo, g_WqT_lo);
    cudaGetSymbolAddress(&p_WkT_hi, g_WkT_hi); cudaGetSymbolAddress(&p_WkT_lo, g_WkT_lo);
    cudaGetSymbolAddress(&p_WvT_hi, g_WvT_hi); cudaGetSymbolAddress(&p_WvT_lo, g_WvT_lo);
    cudaGetSymbolAddress(&p_WoT_hi, g_WoT_hi); cudaGetSymbolAddress(&p_WoT_lo, g_WoT_lo);

    int smem_chunk = (2*32*KPAD + 32*33 + 64) * 4;
    int smem_scan  = (256*33 + 3*32*KPAD + 4*32*33) * 4;
    int smem_gemm  = 2*STGB;   // 81920 B double buffer
    cudaFuncSetAttribute(chunk_kernel, cudaFuncAttributeMaxDynamicSharedMemorySize, smem_chunk);
    cudaFuncSetAttribute(scan_kernel,  cudaFuncAttributeMaxDynamicSharedMemorySize, smem_scan);
    cudaFuncSetAttribute(gemm_bf16s,   cudaFuncAttributeMaxDynamicSharedMemorySize, smem_gemm);

    // ---- conversions for tensor-core GEMMs
    split_kernel<<<NT*DD/256,256>>>(hs, (__nv_bfloat16*)p_hs_hi, (__nv_bfloat16*)p_hs_lo, NT*DD);
    dim3 wg(32,32), wb(32,8);
    wsplitT_kernel<<<wg,wb>>>(Wq, (__nv_bfloat16*)p_WqT_hi, (__nv_bfloat16*)p_WqT_lo);
    wsplitT_kernel<<<wg,wb>>>(Wk, (__nv_bfloat16*)p_WkT_hi, (__nv_bfloat16*)p_WkT_lo);
    wsplitT_kernel<<<wg,wb>>>(Wv, (__nv_bfloat16*)p_WvT_hi, (__nv_bfloat16*)p_WvT_lo);
    wsplitT_kernel<<<wg,wb>>>(Wo, (__nv_bfloat16*)p_WoT_hi, (__nv_bfloat16*)p_WoT_lo);

    dim3 gg(DD/128, NT/128);   // (8, 64)
    gemm_bf16s<<<gg,256,smem_gemm>>>((__nv_bfloat16*)p_hs_hi,(__nv_bfloat16*)p_hs_lo,
                                     (__nv_bfloat16*)p_WqT_hi,(__nv_bfloat16*)p_WqT_lo,
                                     (float*)pQL, NT, DD, DD);
    gemm_bf16s<<<gg,256,smem_gemm>>>((__nv_bfloat16*)p_hs_hi,(__nv_bfloat16*)p_hs_lo,
                                     (__nv_bfloat16*)p_WkT_hi,(__nv_bfloat16*)p_WkT_lo,
                                     (float*)pKL, NT, DD, DD);
    gemm_bf16s<<<gg,256,smem_gemm>>>((__nv_bfloat16*)p_hs_hi,(__nv_bfloat16*)p_hs_lo,
                                     (__nv_bfloat16*)p_WvT_hi,(__nv_bfloat16*)p_WvT_lo,
                                     (float*)pVL, NT, DD, DD);
    smallproj_kernel<<<NT,128>>>(hs, Wb, Wdec, Wmix);

    int nconv = NT*DD/256;
    conv_silu_kernel<<<nconv,256>>>((const float*)pQL, convq, (float*)pQ, 1);
    conv_silu_kernel<<<nconv,256>>>((const float*)pKL, convk, (float*)pK, 1);
    conv_silu_kernel<<<nconv,256>>>((const float*)pVL, convv, (float*)pV, 0);
    mixconv_kernel<<<(NT*HH+127)/128,128>>>(convmix, mixbias);

    l2norm_kernel<<<NT,256>>>();
    chunk_kernel<<<NBH*NCHUNK,256,smem_chunk>>>();
    scan_kernel<<<NBH*8,256,smem_scan>>>();
    ema_kernel<<<NBH,256>>>();
    combine_rms_kernel<<<NT,256>>>(rmsw);

    split_kernel<<<NT*DD/256,256>>>((const float*)pOp, (__nv_bfloat16*)p_Op_hi, (__nv_bfloat16*)p_Op_lo, NT*DD);
    gemm_bf16s<<<gg,256,smem_gemm>>>((__nv_bfloat16*)p_Op_hi,(__nv_bfloat16*)p_Op_lo,
                                     (__nv_bfloat16*)p_WoT_hi,(__nv_bfloat16*)p_WoT_lo,
                                     (float*)d_out, NT, DD, DD);
}

// round 5
// speedup vs baseline: 1.7456x; 1.2420x over previous
#include <cuda_runtime.h>
#include <cuda_bf16.h>
#include <math.h>
#include <stdint.h>

// Problem constants
#define BB 4
#define LL 2048
#define DD 1024
#define HH 4
#define DK 256
#define NT (BB*LL)       // 8192 tokens
#define NCHUNK 64        // chunks per sequence
#define CHK 32           // chunk length
#define NBH 16           // B*H

// ---------------- scratch (device globals; no allocation allowed) -------------
__device__ float g_QL[NT*DD];
__device__ float g_KL[NT*DD];
__device__ float g_VL[NT*DD];
__device__ float g_Q[NT*DD];
__device__ float g_K[NT*DD];
__device__ float g_V[NT*DD];
__device__ float g_beta[NT*HH];
__device__ float g_gamma[NT*HH];
__device__ float g_mixlin[NT*HH];
__device__ float g_mixg[NT*HH];
__device__ float g_W[NBH*NCHUNK*CHK*DK];     // w = T @ k_beta
__device__ float g_T[NBH*NCHUNK*CHK*CHK];    // triangular inverse T
__device__ float g_At[NBH*NCHUNK*CHK*CHK];   // attn_i = tril(q@k^T)
__device__ float g_Od[NT*DD];                // delta-rule output
__device__ float g_Oe[NT*DD];                // ema output
__device__ float g_Op[NT*DD];                // pre-Wo (after mix+rms)

// bf16 split buffers for tensor-core GEMMs
__device__ __nv_bfloat16 g_hs_hi[NT*DD], g_hs_lo[NT*DD];
__device__ __nv_bfloat16 g_Op_hi[NT*DD], g_Op_lo[NT*DD];
__device__ __nv_bfloat16 g_WqT_hi[DD*DD], g_WqT_lo[DD*DD];
__device__ __nv_bfloat16 g_WkT_hi[DD*DD], g_WkT_lo[DD*DD];
__device__ __nv_bfloat16 g_WvT_hi[DD*DD], g_WvT_lo[DD*DD];
__device__ __nv_bfloat16 g_WoT_hi[DD*DD], g_WoT_lo[DD*DD];

__device__ __forceinline__ float silu_f(float x){ return x / (1.f + expf(-x)); }
__device__ __forceinline__ float sigm_f(float x){ return 1.f / (1.f + expf(-x)); }

// ===================== PTX helpers (mma.sync / ldmatrix / cp.async) ==========
__device__ __forceinline__ uint32_t smem_u32(const void* p){
    uint32_t a;
    asm("{ .reg .u64 t; cvta.to.shared.u64 t, %1; cvt.u32.u64 %0, t; }" : "=r"(a) : "l"(p));
    return a;
}
__device__ __forceinline__ void cp_async16(uint32_t dst, const void* src){
    asm volatile("cp.async.cg.shared.global [%0], [%1], 16;" :: "r"(dst), "l"(src) : "memory");
}
__device__ __forceinline__ void cp_commit(){ asm volatile("cp.async.commit_group;" ::: "memory"); }

#define LDSM_X4(r0,r1,r2,r3, addr) \
    asm volatile("ldmatrix.sync.aligned.m8n8.x4.shared.b16 {%0,%1,%2,%3}, [%4];" \
        : "=r"(r0),"=r"(r1),"=r"(r2),"=r"(r3) : "r"(addr))

#define MMA16816(d, a, b0, b1) \
    asm volatile("mma.sync.aligned.m16n8k16.row.col.f32.bf16.bf16.f32 " \
        "{%0,%1,%2,%3}, {%4,%5,%6,%7}, {%8,%9}, {%0,%1,%2,%3};" \
        : "+f"((d)[0]),"+f"((d)[1]),"+f"((d)[2]),"+f"((d)[3]) \
        : "r"((a)[0]),"r"((a)[1]),"r"((a)[2]),"r"((a)[3]), "r"(b0),"r"(b1))

// ===================== split/transpose conversion kernels ====================
__global__ void split_kernel(const float* __restrict__ X,
                             __nv_bfloat16* __restrict__ hi,
                             __nv_bfloat16* __restrict__ lo, int n)
{
    int i = blockIdx.x*256 + threadIdx.x;
    if (i < n){
        float x = X[i];
        __nv_bfloat16 h = __float2bfloat16(x);
        hi[i] = h;
        lo[i] = __float2bfloat16(x - __bfloat162float(h));
    }
}
// All 4 weights transposed+split in one launch. W row-major [K,N] -> [N,K] hi/lo
__global__ void wsplit_all_kernel(const float* __restrict__ W0, const float* __restrict__ W1,
                                  const float* __restrict__ W2, const float* __restrict__ W3,
                                  __nv_bfloat16* __restrict__ h0, __nv_bfloat16* __restrict__ l0,
                                  __nv_bfloat16* __restrict__ h1, __nv_bfloat16* __restrict__ l1,
                                  __nv_bfloat16* __restrict__ h2, __nv_bfloat16* __restrict__ l2,
                                  __nv_bfloat16* __restrict__ h3, __nv_bfloat16* __restrict__ l3)
{
    __shared__ float t[32][33];
    const float* W; __nv_bfloat16 *hiT, *loT;
    int z = blockIdx.z;
    if      (z==0){ W=W0; hiT=h0; loT=l0; }
    else if (z==1){ W=W1; hiT=h1; loT=l1; }
    else if (z==2){ W=W2; hiT=h2; loT=l2; }
    else          { W=W3; hiT=h3; loT=l3; }
    int n0 = blockIdx.x*32, k0 = blockIdx.y*32;
    int tx = threadIdx.x, ty = threadIdx.y;   // 32 x 8
    for (int i = ty; i < 32; i += 8)
        t[i][tx] = W[(size_t)(k0+i)*DD + n0+tx];
    __syncthreads();
    for (int i = ty; i < 32; i += 8){
        float x = t[tx][i];                   // W[k0+tx][n0+i]
        __nv_bfloat16 h = __float2bfloat16(x);
        hiT[(size_t)(n0+i)*DD + k0+tx] = h;
        loT[(size_t)(n0+i)*DD + k0+tx] = __float2bfloat16(x - __bfloat162float(h));
    }
}

// ===================== mma.sync split-bf16 GEMM ==============================
#define GRS 40            // smem row stride in bf16 elements (80 bytes)
#define MATB (128*GRS*2)  // 10240 bytes per matrix tile
#define STGB (4*MATB)     // 40960 per stage

__global__ void __launch_bounds__(256,2) gemm_bf16s(
    const __nv_bfloat16* __restrict__ Ahi, const __nv_bfloat16* __restrict__ Alo,
    const __nv_bfloat16* __restrict__ BhiT, const __nv_bfloat16* __restrict__ BloT,
    float* __restrict__ C, int M, int N, int K)
{
    extern __shared__ char smem[];
    const uint32_t sbase = smem_u32(smem);
    const int tid  = threadIdx.x;
    const int lane = tid & 31, wid = tid >> 5;
    const int wm = wid & 3, wn = wid >> 2;          // 4x2 warp grid
    const int row0 = blockIdx.y*128, col0 = blockIdx.x*128;

    const __nv_bfloat16* g0 = Ahi  + (size_t)row0*K;
    const __nv_bfloat16* g1 = Alo  + (size_t)row0*K;
    const __nv_bfloat16* g2 = BhiT + (size_t)col0*K;
    const __nv_bfloat16* g3 = BloT + (size_t)col0*K;

    float acc[2][8][4];
    #pragma unroll
    for (int i=0;i<2;i++)
        #pragma unroll
        for (int j=0;j<8;j++)
            #pragma unroll
            for (int u=0;u<4;u++) acc[i][j][u]=0.f;

    auto fill = [&](int stage, int kb){
        uint32_t sb = sbase + stage*STGB;
        #pragma unroll
        for (int t=0;t<2;t++){
            int ci = tid + t*256;
            int r = ci >> 2, c = ci & 3;
            uint32_t dst = sb + r*(GRS*2) + c*16;
            size_t go = (size_t)r*K + (size_t)kb*32 + c*8;
            cp_async16(dst + 0*MATB, g0 + go);
            cp_async16(dst + 1*MATB, g1 + go);
            cp_async16(dst + 2*MATB, g2 + go);
            cp_async16(dst + 3*MATB, g3 + go);
        }
        cp_commit();
    };

    const int nkb = K/32;
    fill(0, 0);

    const int a_r  = lane & 15;
    const int a_ko = ((lane >> 4) & 1) << 3;
    const int b_n  = (lane & 7) + (((lane >> 4) & 1) << 3);
    const int b_ko = ((lane >> 3) & 1) << 3;

    for (int kb = 0; kb < nkb; kb++){
        if (kb+1 < nkb){
            fill((kb+1)&1, kb+1);
            asm volatile("cp.async.wait_group 1;" ::: "memory");
        } else {
            asm volatile("cp.async.wait_group 0;" ::: "memory");
        }
        __syncthreads();

        uint32_t sb = sbase + (kb&1)*STGB;
        #pragma unroll
        for (int ks=0; ks<2; ks++){
            const int k16 = ks*16;
            uint32_t ah[2][4], al[2][4];
            #pragma unroll
            for (int mt=0; mt<2; mt++){
                uint32_t ad = sb + (wm*32 + mt*16 + a_r)*(GRS*2) + (k16 + a_ko)*2;
                LDSM_X4(ah[mt][0],ah[mt][1],ah[mt][2],ah[mt][3], ad + 0*MATB);
                LDSM_X4(al[mt][0],al[mt][1],al[mt][2],al[mt][3], ad + 1*MATB);
            }
            #pragma unroll
            for (int n4=0; n4<4; n4++){
                uint32_t bd = sb + 2*MATB + (wn*64 + n4*16 + b_n)*(GRS*2) + (k16 + b_ko)*2;
                uint32_t bh[4], bl[4];
                LDSM_X4(bh[0],bh[1],bh[2],bh[3], bd);
                LDSM_X4(bl[0],bl[1],bl[2],bl[3], bd + MATB);
                #pragma unroll
                for (int mt=0; mt<2; mt++){
                    MMA16816(acc[mt][n4*2  ], ah[mt], bh[0], bh[1]);
                    MMA16816(acc[mt][n4*2+1], ah[mt], bh[2], bh[3]);
                    MMA16816(acc[mt][n4*2  ], ah[mt], bl[0], bl[1]);
                    MMA16816(acc[mt][n4*2+1], ah[mt], bl[2], bl[3]);
                    MMA16816(acc[mt][n4*2  ], al[mt], bh[0], bh[1]);
                    MMA16816(acc[mt][n4*2+1], al[mt], bh[2], bh[3]);
                }
            }
        }
        __syncthreads();
    }

    float* Cg = C + (size_t)(row0 + wm*32)*N + col0 + wn*64;
    const int cr = lane >> 2, cc = (lane & 3) << 1;
    #pragma unroll
    for (int mt=0; mt<2; mt++)
        #pragma unroll
        for (int nt=0; nt<8; nt++){
            float2 v0; v0.x = acc[mt][nt][0]; v0.y = acc[mt][nt][1];
            *(float2*)&Cg[(size_t)(mt*16+cr)*N + nt*8+cc] = v0;
            float2 v1; v1.x = acc[mt][nt][2]; v1.y = acc[mt][nt][3];
            *(float2*)&Cg[(size_t)(mt*16+cr+8)*N + nt*8+cc] = v1;
        }
}

// ---------------- small projections: warp per row ----------------------------
__global__ void __launch_bounds__(256) smallproj_kernel(const float* __restrict__ Xh,
                                 const float* __restrict__ Wb,
                                 const float* __restrict__ Wdec,
                                 const float* __restrict__ Wmix)
{
    int wid = threadIdx.x >> 5, lane = threadIdx.x & 31;
    int row = blockIdx.x*8 + wid;
    const float* xr = Xh + (size_t)row*DD;
    float a[12];
    #pragma unroll
    for (int j=0;j<12;j++) a[j]=0.f;
    for (int c=lane; c<DD; c+=32){
        float hv = xr[c];
        float4 wb = *(const float4*)&Wb[c*4];
        float4 wd = *(const float4*)&Wdec[c*4];
        float4 wm = *(const float4*)&Wmix[c*4];
        a[0]+=hv*wb.x; a[1]+=hv*wb.y; a[2]+=hv*wb.z; a[3]+=hv*wb.w;
        a[4]+=hv*wd.x; a[5]+=hv*wd.y; a[6]+=hv*wd.z; a[7]+=hv*wd.w;
        a[8]+=hv*wm.x; a[9]+=hv*wm.y; a[10]+=hv*wm.z; a[11]+=hv*wm.w;
    }
    #pragma unroll
    for (int off=16; off; off>>=1){
        #pragma unroll
        for (int j=0;j<12;j++) a[j] += __shfl_down_sync(0xffffffffu, a[j], off);
    }
    if (lane == 0){
        #pragma unroll
        for (int j=0;j<4;j++){
            g_beta  [row*4+j] = sigm_f(a[j]);
            g_gamma [row*4+j] = sigm_f(a[4+j]);
            g_mixlin[row*4+j] = a[8+j];
        }
    }
}

// ---------------- causal short conv (K=4) + silu (optionally twice) ----------
__global__ void conv_silu_kernel(const float* __restrict__ X,
                                 const float* __restrict__ Wc,
                                 float* __restrict__ Y, int dbl)
{
    int idx = blockIdx.x*blockDim.x + threadIdx.x;
    if (idx >= NT*DD) return;
    int ch = idx & (DD-1);
    int bt = idx >> 10;
    int t  = bt & (LL-1);
    float acc = 0.f;
    #pragma unroll
    for (int k=0;k<4;k++){
        int ts = t-3+k;
        if (ts>=0) acc += X[(size_t)idx + (size_t)(ts-t)*DD] * Wc[ch*4+k];
    }
    float y = silu_f(acc);
    if (dbl) y = silu_f(y);
    Y[idx] = y;
}

// ---------------- mix path: conv over H channels + silu + sigmoid(+bias) -----
__global__ void mixconv_kernel(const float* __restrict__ convmix,
                               const float* __restrict__ mixbias)
{
    int idx = blockIdx.x*blockDim.x + threadIdx.x;
    if (idx >= NT*HH) return;
    int h = idx & 3;
    int bt = idx >> 2;
    int t = bt & (LL-1);
    float acc = 0.f;
    #pragma unroll
    for (int k=0;k<4;k++){
        int ts = t-3+k;
        if (ts>=0) acc += g_mixlin[idx + (ts-t)*HH] * convmix[h*4+k];
    }
    float mi = silu_f(acc);
    g_mixg[idx] = sigm_f(mi + mixbias[h]);
}

// ---------------- l2 norm: warp per (row,head) -------------------------------
__global__ void __launch_bounds__(256) l2norm_kernel()
{
    int wid = threadIdx.x >> 5, lane = threadIdx.x & 31;
    int g = blockIdx.x*8 + wid;
    int row = g >> 2, h = g & 3;
    size_t base = (size_t)row*DD + h*DK;

    // Q
    {
        float4 v0 = *(float4*)&g_Q[base + lane*4];
        float4 v1 = *(float4*)&g_Q[base + 128 + lane*4];
        float s = v0.x*v0.x+v0.y*v0.y+v0.z*v0.z+v0.w*v0.w
                + v1.x*v1.x+v1.y*v1.y+v1.z*v1.z+v1.w*v1.w;
        #pragma unroll
        for (int off=16; off; off>>=1) s += __shfl_xor_sync(0xffffffffu, s, off);
        float sc = rsqrtf(s + 1e-6f);
        v0.x*=sc; v0.y*=sc; v0.z*=sc; v0.w*=sc;
        v1.x*=sc; v1.y*=sc; v1.z*=sc; v1.w*=sc;
        *(float4*)&g_Q[base + lane*4] = v0;
        *(float4*)&g_Q[base + 128 + lane*4] = v1;
    }
    // K
    {
        float4 v0 = *(float4*)&g_K[base + lane*4];
        float4 v1 = *(float4*)&g_K[base + 128 + lane*4];
        float s = v0.x*v0.x+v0.y*v0.y+v0.z*v0.z+v0.w*v0.w
                + v1.x*v1.x+v1.y*v1.y+v1.z*v1.z+v1.w*v1.w;
        #pragma unroll
        for (int off=16; off; off>>=1) s += __shfl_xor_sync(0xffffffffu, s, off);
        float sc = rsqrtf(s + 1e-6f);
        v0.x*=sc; v0.y*=sc; v0.z*=sc; v0.w*=sc;
        v1.x*=sc; v1.y*=sc; v1.z*=sc; v1.w*=sc;
        *(float4*)&g_K[base + lane*4] = v0;
        *(float4*)&g_K[base + 128 + lane*4] = v1;
    }
}

// ---------------- per-chunk: T (tri inverse), W = T@k_beta, Attn = tril(q k^T)
#define WP 260   // float stride for 32x256 tiles (float4-aligned, conflict-aware)
#define SP 36    // float stride for 32x32 / 256x32 tiles

__global__ void __launch_bounds__(256) chunk_kernel()
{
    extern __shared__ float sm[];
    float* kc     = sm;                 // 32*WP
    float* qc     = kc + 32*WP;         // 32*WP
    float* Amat   = qc + 32*WP;         // 32*33
    float* bet    = Amat + 32*33;       // 32
    float* rowtmp = bet + 32;           // 32

    int blk = blockIdx.x;               // bh*64 + c
    int bh = blk >> 6, c = blk & 63;
    int b = bh >> 2, h = bh & 3;
    int tid = threadIdx.x;
    int rowbase = b*LL + c*CHK;

    for (int e = tid; e < 2048; e += 256){
        int r = e >> 6; int c4 = (e & 63) << 2;
        *(float4*)&kc[r*WP+c4] = *(const float4*)&g_K[(size_t)(rowbase+r)*DD + h*DK + c4];
        *(float4*)&qc[r*WP+c4] = *(const float4*)&g_Q[(size_t)(rowbase+r)*DD + h*DK + c4];
    }
    if (tid < 32) bet[tid] = g_beta[(rowbase+tid)*HH + h];
    __syncthreads();

    // A = -tril(k_beta @ k^T, -1),  Attn = tril(q @ k^T, 0)
    {
        int i = tid >> 3, j0 = tid & 7;
        float da[4]={0,0,0,0}, dq[4]={0,0,0,0};
        #pragma unroll 4
        for (int m=0;m<256;m+=4){
            float4 ki = *(float4*)&kc[i*WP+m];
            float4 qi = *(float4*)&qc[i*WP+m];
            #pragma unroll
            for (int u=0;u<4;u++){
                float4 kj = *(float4*)&kc[(j0+8*u)*WP+m];
                da[u] += ki.x*kj.x + ki.y*kj.y + ki.z*kj.z + ki.w*kj.w;
                dq[u] += qi.x*kj.x + qi.y*kj.y + qi.z*kj.z + qi.w*kj.w;
            }
        }
        #pragma unroll
        for (int u=0;u<4;u++){
            int j = j0 + 8*u;
            Amat[i*33+j] = (j < i) ? -bet[i]*da[u] : 0.f;
            g_At[(size_t)blk*1024 + i*32 + j] = (j <= i) ? dq[u] : 0.f;
        }
    }
    __syncthreads();

    // sequential forward-substitution (warp 0)
    if (tid < 32){
        int cx = tid;
        for (int ii=1; ii<32; ii++){
            rowtmp[cx] = Amat[ii*33+cx];
            __syncwarp();
            float acc = 0.f;
            if (cx < ii){
                acc = rowtmp[cx];
                for (int j=cx+1; j<ii; j++) acc += rowtmp[j]*Amat[j*33+cx];
            }
            __syncwarp();
            if (cx < ii) Amat[ii*33+cx] = acc;
            __syncwarp();
        }
        Amat[cx*33+cx] = 1.0f;   // T = A + I
    }
    __syncthreads();

    for (int e=tid; e<1024; e+=256)
        g_T[(size_t)blk*1024 + e] = Amat[(e>>5)*33 + (e&31)];

    // W = T @ (beta * k)
    {
        int i = tid >> 3, mb = (tid & 7) << 2;
        float4 acc[8];
        #pragma unroll
        for (int s=0;s<8;s++) acc[s] = make_float4(0.f,0.f,0.f,0.f);
        for (int j=0;j<32;j++){
            float tv = Amat[i*33+j]*bet[j];
            #pragma unroll
            for (int s=0;s<8;s++){
                float4 kv = *(float4*)&kc[j*WP + s*32 + mb];
                acc[s].x += tv*kv.x; acc[s].y += tv*kv.y;
                acc[s].z += tv*kv.z; acc[s].w += tv*kv.w;
            }
        }
        #pragma unroll
        for (int s=0;s<8;s++)
            *(float4*)&g_W[((size_t)blk*32 + i)*DK + s*32 + mb] = acc[s];
    }
}

// ---------------- sequential inter-chunk scan, state S in SMEM ---------------
// grid: 128 blocks = 16 (b,h) x 8 dv-slabs of 32 columns
__global__ void __launch_bounds__(256,1) scan_kernel()
{
    extern __shared__ float sm[];
    float* S    = sm;                 // 256*SP
    float* w    = S   + 256*SP;       // 32*WP
    float* q    = w   + 32*WP;        // 32*WP
    float* kc   = q   + 32*WP;        // 32*WP
    float* att  = kc  + 32*WP;        // 32*SP
    float* Tt   = att + 32*SP;        // 32*SP
    float* vb   = Tt  + 32*SP;        // 32*SP
    float* ua   = vb  + 32*SP;        // 32*SP

    int tid = threadIdx.x;
    int bh   = blockIdx.x >> 3;
    int slab = blockIdx.x & 7;
    int b = bh >> 2, h = bh & 3;

    for (int e=tid; e<256*SP; e+=256) S[e]=0.f;
    __syncthreads();

    const int i  = tid >> 3;          // 0..31
    const int jb = (tid & 7) << 2;    // 0,4,...,28
    const size_t ocol = (size_t)h*DK + slab*32;

    for (int c=0; c<NCHUNK; c++){
        int blk = bh*NCHUNK + c;
        int rowbase = b*LL + c*CHK;
        // ---- load tiles (float4)
        for (int e=tid; e<2048; e+=256){
            int r = e >> 6; int c4 = (e & 63) << 2;
            *(float4*)&w [r*WP+c4] = *(const float4*)&g_W[((size_t)blk*32 + r)*DK + c4];
            *(float4*)&q [r*WP+c4] = *(const float4*)&g_Q[(size_t)(rowbase+r)*DD + h*DK + c4];
            *(float4*)&kc[r*WP+c4] = *(const float4*)&g_K[(size_t)(rowbase+r)*DD + h*DK + c4];
        }
        {
            int r = tid >> 3, c4 = (tid & 7) << 2;
            *(float4*)&att[r*SP+c4] = *(const float4*)&g_At[(size_t)blk*1024 + r*32 + c4];
            *(float4*)&Tt [r*SP+c4] = *(const float4*)&g_T [(size_t)blk*1024 + r*32 + c4];
            float be = g_beta[(rowbase+r)*HH + h];
            float4 vv = *(const float4*)&g_V[(size_t)(rowbase+r)*DD + ocol + c4];
            vv.x*=be; vv.y*=be; vv.z*=be; vv.w*=be;
            *(float4*)&vb[r*SP+c4] = vv;
        }
        __syncthreads();

        // ---- u_i = T @ vb
        float4 ui = make_float4(0.f,0.f,0.f,0.f);
        #pragma unroll
        for (int m=0;m<32;m++){
            float t0 = Tt[i*SP+m];
            float4 vv = *(float4*)&vb[m*SP+jb];
            ui.x += t0*vv.x; ui.y += t0*vv.y; ui.z += t0*vv.z; ui.w += t0*vv.w;
        }
        // ---- w@S and q@S in one pass over k
        float4 aU = make_float4(0.f,0.f,0.f,0.f);
        float4 aO = make_float4(0.f,0.f,0.f,0.f);
        #pragma unroll 4
        for (int k=0;k<256;k+=4){
            float4 wv = *(float4*)&w[i*WP+k];
            float4 qv = *(float4*)&q[i*WP+k];
            float4 s0 = *(float4*)&S[(k  )*SP+jb];
            float4 s1 = *(float4*)&S[(k+1)*SP+jb];
            float4 s2 = *(float4*)&S[(k+2)*SP+jb];
            float4 s3 = *(float4*)&S[(k+3)*SP+jb];
            aU.x += wv.x*s0.x + wv.y*s1.x + wv.z*s2.x + wv.w*s3.x;
            aU.y += wv.x*s0.y + wv.y*s1.y + wv.z*s2.y + wv.w*s3.y;
            aU.z += wv.x*s0.z + wv.y*s1.z + wv.z*s2.z + wv.w*s3.z;
            aU.w += wv.x*s0.w + wv.y*s1.w + wv.z*s2.w + wv.w*s3.w;
            aO.x += qv.x*s0.x + qv.y*s1.x + qv.z*s2.x + qv.w*s3.x;
            aO.y += qv.x*s0.y + qv.y*s1.y + qv.z*s2.y + qv.w*s3.y;
            aO.z += qv.x*s0.z + qv.y*s1.z + qv.z*s2.z + qv.w*s3.z;
            aO.w += qv.x*s0.w + qv.y*s1.w + qv.z*s2.w + qv.w*s3.w;
        }
        float4 uav;
        uav.x = ui.x - aU.x; uav.y = ui.y - aU.y;
        uav.z = ui.z - aU.z; uav.w = ui.w - aU.w;
        *(float4*)&ua[i*SP+jb] = uav;
        __syncthreads();

        // ---- o = q@S + attn @ u_adj  -> global
        #pragma unroll
        for (int m=0;m<32;m++){
            float av = att[i*SP+m];
            float4 uv = *(float4*)&ua[m*SP+jb];
            aO.x += av*uv.x; aO.y += av*uv.y; aO.z += av*uv.z; aO.w += av*uv.w;
        }
        *(float4*)&g_Od[(size_t)(rowbase+i)*DD + ocol + jb] = aO;

        // ---- S += k^T @ u_adj  (thread owns dk-row tid, 8 float4 accumulators)
        float4 acc[8];
        #pragma unroll
        for (int x=0;x<8;x++) acc[x] = make_float4(0.f,0.f,0.f,0.f);
        #pragma unroll 4
        for (int m=0;m<32;m++){
            float kv = kc[m*WP + tid];
            #pragma unroll
            for (int x=0;x<8;x++){
                float4 uv = *(float4*)&ua[m*SP + x*4];
                acc[x].x += kv*uv.x; acc[x].y += kv*uv.y;
                acc[x].z += kv*uv.z; acc[x].w += kv*uv.w;
            }
        }
        #pragma unroll
        for (int x=0;x<8;x++){
            float4 sv = *(float4*)&S[tid*SP + x*4];
            sv.x += acc[x].x; sv.y += acc[x].y; sv.z += acc[x].z; sv.w += acc[x].w;
            *(float4*)&S[tid*SP + x*4] = sv;
        }
        __syncthreads();
    }
}

// ---------------- EMA over time: (b,h) x 4 col-slabs of 64 -------------------
__global__ void ema_kernel()
{
    int bh = blockIdx.x;
    int b = bh >> 2, h = bh & 3;
    int j = blockIdx.y*64 + threadIdx.x;
    float s = 0.f;
    int base = b*LL;
    for (int t=0;t<LL;t++){
        float g = g_gamma[(base+t)*HH + h];
        float v = g_V[(size_t)(base+t)*DD + h*DK + j];
        s = g*s + (1.f-g)*v;
        g_Oe[(size_t)(base+t)*DD + h*DK + j] = s;
    }
}

// ---------------- mix combine + per-head RMS norm: warp per (row,head) -------
__global__ void __launch_bounds__(256) combine_rms_kernel(const float* __restrict__ rmsw)
{
    int wid = threadIdx.x >> 5, lane = threadIdx.x & 31;
    int g = blockIdx.x*8 + wid;
    int row = g >> 2, h = g & 3;
    float m = g_mixg[row*4+h];
    size_t base = (size_t)row*DD + h*DK;

    float4 d0 = *(float4*)&g_Od[base + lane*4];
    float4 d1 = *(float4*)&g_Od[base + 128 + lane*4];
    float4 e0 = *(float4*)&g_Oe[base + lane*4];
    float4 e1 = *(float4*)&g_Oe[base + 128 + lane*4];
    float4 o0, o1;
    float om = 1.f - m;
    o0.x = om*d0.x + m*e0.x; o0.y = om*d0.y + m*e0.y;
    o0.z = om*d0.z + m*e0.z; o0.w = om*d0.w + m*e0.w;
    o1.x = om*d1.x + m*e1.x; o1.y = om*d1.y + m*e1.y;
    o1.z = om*d1.z + m*e1.z; o1.w = om*d1.w + m*e1.w;
    float s = o0.x*o0.x+o0.y*o0.y+o0.z*o0.z+o0.w*o0.w
            + o1.x*o1.x+o1.y*o1.y+o1.z*o1.z+o1.w*o1.w;
    #pragma unroll
    for (int off=16; off; off>>=1) s += __shfl_xor_sync(0xffffffffu, s, off);
    float sc = rsqrtf(s*(1.f/256.f) + 1e-5f);
    float4 r0 = *(const float4*)&rmsw[lane*4];
    float4 r1 = *(const float4*)&rmsw[128 + lane*4];
    o0.x *= sc*r0.x; o0.y *= sc*r0.y; o0.z *= sc*r0.z; o0.w *= sc*r0.w;
    o1.x *= sc*r1.x; o1.y *= sc*r1.y; o1.z *= sc*r1.z; o1.w *= sc*r1.w;
    *(float4*)&g_Op[base + lane*4] = o0;
    *(float4*)&g_Op[base + 128 + lane*4] = o1;
}

// ---------------- host driver -----------------------------------------------
extern "C" void kernel_launch(void* const* d_in, const int* in_sizes, int n_in,
                              void* d_out, int out_size)
{
    const float* hs      = (const float*)d_in[0];
    const float* Wq      = (const float*)d_in[1];
    const float* Wk      = (const float*)d_in[2];
    const float* Wv      = (const float*)d_in[3];
    const float* convq   = (const float*)d_in[4];
    const float* convk   = (const float*)d_in[5];
    const float* convv   = (const float*)d_in[6];
    const float* Wb      = (const float*)d_in[7];
    const float* Wdec    = (const float*)d_in[8];
    const float* Wmix    = (const float*)d_in[9];
    const float* convmix = (const float*)d_in[10];
    const float* mixbias = (const float*)d_in[11];
    const float* rmsw    = (const float*)d_in[12];
    const float* Wo      = (const float*)d_in[13];

    void *pQL,*pKL,*pVL,*pQ,*pK,*pV,*pOp;
    cudaGetSymbolAddress(&pQL, g_QL);
    cudaGetSymbolAddress(&pKL, g_KL);
    cudaGetSymbolAddress(&pVL, g_VL);
    cudaGetSymbolAddress(&pQ,  g_Q);
    cudaGetSymbolAddress(&pK,  g_K);
    cudaGetSymbolAddress(&pV,  g_V);
    cudaGetSymbolAddress(&pOp, g_Op);

    void *p_hs_hi,*p_hs_lo,*p_Op_hi,*p_Op_lo;
    void *p_WqT_hi,*p_WqT_lo,*p_WkT_hi,*p_WkT_lo,*p_WvT_hi,*p_WvT_lo,*p_WoT_hi,*p_WoT_lo;
    cudaGetSymbolAddress(&p_hs_hi, g_hs_hi);  cudaGetSymbolAddress(&p_hs_lo, g_hs_lo);
    cudaGetSymbolAddress(&p_Op_hi, g_Op_hi);  cudaGetSymbolAddress(&p_Op_lo, g_Op_lo);
    cudaGetSymbolAddress(&p_WqT_hi, g_WqT_hi); cudaGetSymbolAddress(&p_WqT_lo, g_WqT_lo);
    cudaGetSymbolAddress(&p_WkT_hi, g_WkT_hi); cudaGetSymbolAddress(&p_WkT_lo, g_WkT_lo);
    cudaGetSymbolAddress(&p_WvT_hi, g_WvT_hi); cudaGetSymbolAddress(&p_WvT_lo, g_WvT_lo);
    cudaGetSymbolAddress(&p_WoT_hi, g_WoT_hi); cudaGetSymbolAddress(&p_WoT_lo, g_WoT_lo);

    int smem_chunk = (2*32*WP + 32*33 + 64) * 4;
    int smem_scan  = (256*SP + 3*32*WP + 4*32*SP) * 4;
    int smem_gemm  = 2*STGB;
    cudaFuncSetAttribute(chunk_kernel, cudaFuncAttributeMaxDynamicSharedMemorySize, smem_chunk);
    cudaFuncSetAttribute(scan_kernel,  cudaFuncAttributeMaxDynamicSharedMemorySize, smem_scan);
    cudaFuncSetAttribute(gemm_bf16s,   cudaFuncAttributeMaxDynamicSharedMemorySize, smem_gemm);

    // 1: split activations
    split_kernel<<<NT*DD/256,256>>>(hs, (__nv_bfloat16*)p_hs_hi, (__nv_bfloat16*)p_hs_lo, NT*DD);
    // 2: all weight transposes+splits in one launch
    dim3 wg(32,32,4), wb(32,8);
    wsplit_all_kernel<<<wg,wb>>>(Wq, Wk, Wv, Wo,
        (__nv_bfloat16*)p_WqT_hi,(__nv_bfloat16*)p_WqT_lo,
        (__nv_bfloat16*)p_WkT_hi,(__nv_bfloat16*)p_WkT_lo,
        (__nv_bfloat16*)p_WvT_hi,(__nv_bfloat16*)p_WvT_lo,
        (__nv_bfloat16*)p_WoT_hi,(__nv_bfloat16*)p_WoT_lo);
    // 3: small projections
    smallproj_kernel<<<NT/8,256>>>(hs, Wb, Wdec, Wmix);

    // 4-6: the three input GEMMs (launch #4 is the ncu-profiled one)
    dim3 gg(DD/128, NT/128);   // (8, 64)
    gemm_bf16s<<<gg,256,smem_gemm>>>((__nv_bfloat16*)p_hs_hi,(__nv_bfloat16*)p_hs_lo,
                                     (__nv_bfloat16*)p_WqT_hi,(__nv_bfloat16*)p_WqT_lo,
                                     (float*)pQL, NT, DD, DD);
    gemm_bf16s<<<gg,256,smem_gemm>>>((__nv_bfloat16*)p_hs_hi,(__nv_bfloat16*)p_hs_lo,
                                     (__nv_bfloat16*)p_WkT_hi,(__nv_bfloat16*)p_WkT_lo,
                                     (float*)pKL, NT, DD, DD);
    gemm_bf16s<<<gg,256,smem_gemm>>>((__nv_bfloat16*)p_hs_hi,(__nv_bfloat16*)p_hs_lo,
                                     (__nv_bfloat16*)p_WvT_hi,(__nv_bfloat16*)p_WvT_lo,
                                     (float*)pVL, NT, DD, DD);

    int nconv = NT*DD/256;
    conv_silu_kernel<<<nconv,256>>>((const float*)pQL, convq, (float*)pQ, 1);
    conv_silu_kernel<<<nconv,256>>>((const float*)pKL, convk, (float*)pK, 1);
    conv_silu_kernel<<<nconv,256>>>((const float*)pVL, convv, (float*)pV, 0);
    mixconv_kernel<<<(NT*HH+127)/128,128>>>(convmix, mixbias);

    l2norm_kernel<<<NT*HH/8,256>>>();
    chunk_kernel<<<NBH*NCHUNK,256,smem_chunk>>>();
    scan_kernel<<<NBH*8,256,smem_scan>>>();
    ema_kernel<<<dim3(NBH,4),64>>>();
    combine_rms_kernel<<<NT*HH/8,256>>>(rmsw);

    split_kernel<<<NT*DD/256,256>>>((const float*)pOp, (__nv_bfloat16*)p_Op_hi, (__nv_bfloat16*)p_Op_lo, NT*DD);
    gemm_bf16s<<<gg,256,smem_gemm>>>((__nv_bfloat16*)p_Op_hi,(__nv_bfloat16*)p_Op_lo,
                                     (__nv_bfloat16*)p_WoT_hi,(__nv_bfloat16*)p_WoT_lo,
                                     (float*)d_out, NT, DD, DD);
}

// round 6
// speedup vs baseline: 1.7588x; 1.0075x over previous
#include <cuda_runtime.h>
#include <cuda_bf16.h>
#include <math.h>
#include <stdint.h>

// Problem constants
#define BB 4
#define LL 2048
#define DD 1024
#define HH 4
#define DK 256
#define NT (BB*LL)       // 8192 tokens
#define NCHUNK 64        // chunks per sequence
#define CHK 32           // chunk length
#define NBH 16           // B*H

typedef unsigned long long u64t;

// ---------------- scratch (device globals; no allocation allowed) -------------
__device__ float g_QL[NT*DD];
__device__ float g_KL[NT*DD];
__device__ float g_VL[NT*DD];
__device__ float g_Q[NT*DD];
__device__ float g_K[NT*DD];
__device__ float g_V[NT*DD];
__device__ float g_beta[NT*HH];
__device__ float g_gamma[NT*HH];
__device__ float g_mixlin[NT*HH];
__device__ float g_mixg[NT*HH];
__device__ float g_W[NBH*NCHUNK*CHK*DK];     // w = T @ k_beta
__device__ float g_T[NBH*NCHUNK*CHK*CHK];    // triangular inverse T
__device__ float g_At[NBH*NCHUNK*CHK*CHK];   // attn_i = tril(q@k^T)
__device__ float g_Od[NT*DD];                // delta-rule output
__device__ float g_Oe[NT*DD];                // ema output

// bf16 split buffers for tensor-core GEMMs
__device__ __nv_bfloat16 g_hs_hi[NT*DD], g_hs_lo[NT*DD];
__device__ __nv_bfloat16 g_Op_hi[NT*DD], g_Op_lo[NT*DD];
__device__ __nv_bfloat16 g_WT_hi[3*DD*DD], g_WT_lo[3*DD*DD];  // Wq|Wk|Wv transposed
__device__ __nv_bfloat16 g_WoT_hi[DD*DD], g_WoT_lo[DD*DD];

__device__ __forceinline__ float silu_f(float x){ return x / (1.f + expf(-x)); }
__device__ __forceinline__ float sigm_f(float x){ return 1.f / (1.f + expf(-x)); }

// ===================== f32x2 packed-math helpers =============================
__device__ __forceinline__ u64t f2dup(float x){
    u64t r; unsigned int xi = __float_as_uint(x);
    asm("mov.b64 %0, {%1,%1};" : "=l"(r) : "r"(xi));
    return r;
}
__device__ __forceinline__ u64t ffma2(u64t a, u64t b, u64t c){
    u64t d; asm("fma.rn.f32x2 %0, %1, %2, %3;" : "=l"(d) : "l"(a), "l"(b), "l"(c));
    return d;
}
__device__ __forceinline__ u64t fadd2(u64t a, u64t b){
    u64t d; asm("add.rn.f32x2 %0, %1, %2;" : "=l"(d) : "l"(a), "l"(b));
    return d;
}
__device__ __forceinline__ float2 f2unpack(u64t p){
    unsigned int lo, hi;
    asm("mov.b64 {%0,%1}, %2;" : "=r"(lo), "=r"(hi) : "l"(p));
    return make_float2(__uint_as_float(lo), __uint_as_float(hi));
}

// ===================== PTX helpers (mma.sync / ldmatrix / cp.async) ==========
__device__ __forceinline__ uint32_t smem_u32(const void* p){
    uint32_t a;
    asm("{ .reg .u64 t; cvta.to.shared.u64 t, %1; cvt.u32.u64 %0, t; }" : "=r"(a) : "l"(p));
    return a;
}
__device__ __forceinline__ void cp_async16(uint32_t dst, const void* src){
    asm volatile("cp.async.cg.shared.global [%0], [%1], 16;" :: "r"(dst), "l"(src) : "memory");
}
__device__ __forceinline__ void cp_commit(){ asm volatile("cp.async.commit_group;" ::: "memory"); }

#define LDSM_X4(r0,r1,r2,r3, addr) \
    asm volatile("ldmatrix.sync.aligned.m8n8.x4.shared.b16 {%0,%1,%2,%3}, [%4];" \
        : "=r"(r0),"=r"(r1),"=r"(r2),"=r"(r3) : "r"(addr))

#define MMA16816(d, a, b0, b1) \
    asm volatile("mma.sync.aligned.m16n8k16.row.col.f32.bf16.bf16.f32 " \
        "{%0,%1,%2,%3}, {%4,%5,%6,%7}, {%8,%9}, {%0,%1,%2,%3};" \
        : "+f"((d)[0]),"+f"((d)[1]),"+f"((d)[2]),"+f"((d)[3]) \
        : "r"((a)[0]),"r"((a)[1]),"r"((a)[2]),"r"((a)[3]), "r"(b0),"r"(b1))

// ===================== split/transpose conversion kernels ====================
__global__ void split_kernel(const float* __restrict__ X,
                             __nv_bfloat16* __restrict__ hi,
                             __nv_bfloat16* __restrict__ lo, int n)
{
    int i = blockIdx.x*256 + threadIdx.x;
    if (i < n){
        float x = X[i];
        __nv_bfloat16 h = __float2bfloat16(x);
        hi[i] = h;
        lo[i] = __float2bfloat16(x - __bfloat162float(h));
    }
}
// 4 weights transposed+split; Wq/Wk/Wv into combined [3072,1024], Wo separate.
__global__ void wsplit_all_kernel(const float* __restrict__ W0, const float* __restrict__ W1,
                                  const float* __restrict__ W2, const float* __restrict__ W3,
                                  __nv_bfloat16* __restrict__ bigh, __nv_bfloat16* __restrict__ bigl,
                                  __nv_bfloat16* __restrict__ woh, __nv_bfloat16* __restrict__ wol)
{
    __shared__ float t[32][33];
    const float* W; __nv_bfloat16 *hiT, *loT;
    int z = blockIdx.z;
    if      (z==0){ W=W0; hiT=bigh;            loT=bigl; }
    else if (z==1){ W=W1; hiT=bigh+DD*DD;      loT=bigl+DD*DD; }
    else if (z==2){ W=W2; hiT=bigh+2*DD*DD;    loT=bigl+2*DD*DD; }
    else          { W=W3; hiT=woh;             loT=wol; }
    int n0 = blockIdx.x*32, k0 = blockIdx.y*32;
    int tx = threadIdx.x, ty = threadIdx.y;   // 32 x 8
    for (int i = ty; i < 32; i += 8)
        t[i][tx] = W[(size_t)(k0+i)*DD + n0+tx];
    __syncthreads();
    for (int i = ty; i < 32; i += 8){
        float x = t[tx][i];                   // W[k0+tx][n0+i]
        __nv_bfloat16 h = __float2bfloat16(x);
        hiT[(size_t)(n0+i)*DD + k0+tx] = h;
        loT[(size_t)(n0+i)*DD + k0+tx] = __float2bfloat16(x - __bfloat162float(h));
    }
}

// ===================== mma.sync split-bf16 GEMM ==============================
// C[:,seg][M,DD] = A[M,K] @ Bseg; B given transposed, possibly 3 segments wide.
#define GRS 40            // smem row stride in bf16 elements (80 bytes)
#define MATB (128*GRS*2)  // 10240 bytes per matrix tile
#define STGB (4*MATB)     // 40960 per stage

__global__ void __launch_bounds__(256,2) gemm_bf16s(
    const __nv_bfloat16* __restrict__ Ahi, const __nv_bfloat16* __restrict__ Alo,
    const __nv_bfloat16* __restrict__ BhiT, const __nv_bfloat16* __restrict__ BloT,
    float* C0, float* C1, float* C2, int K)
{
    extern __shared__ char smem[];
    const uint32_t sbase = smem_u32(smem);
    const int tid  = threadIdx.x;
    const int lane = tid & 31, wid = tid >> 5;
    const int wm = wid & 3, wn = wid >> 2;          // 4x2 warp grid
    const int row0 = blockIdx.y*128;
    const int bcol = blockIdx.x*128;                // into B (up to 3072 wide)
    const int seg  = blockIdx.x >> 3;
    const int col0 = (blockIdx.x & 7)*128;          // into C
    float* C = (seg==0) ? C0 : (seg==1 ? C1 : C2);

    const __nv_bfloat16* g0 = Ahi  + (size_t)row0*K;
    const __nv_bfloat16* g1 = Alo  + (size_t)row0*K;
    const __nv_bfloat16* g2 = BhiT + (size_t)bcol*K;
    const __nv_bfloat16* g3 = BloT + (size_t)bcol*K;

    float acc[2][8][4];
    #pragma unroll
    for (int i=0;i<2;i++)
        #pragma unroll
        for (int j=0;j<8;j++)
            #pragma unroll
            for (int u=0;u<4;u++) acc[i][j][u]=0.f;

    auto fill = [&](int stage, int kb){
        uint32_t sb = sbase + stage*STGB;
        #pragma unroll
        for (int t=0;t<2;t++){
            int ci = tid + t*256;
            int r = ci >> 2, c = ci & 3;
            uint32_t dst = sb + r*(GRS*2) + c*16;
            size_t go = (size_t)r*K + (size_t)kb*32 + c*8;
            cp_async16(dst + 0*MATB, g0 + go);
            cp_async16(dst + 1*MATB, g1 + go);
            cp_async16(dst + 2*MATB, g2 + go);
            cp_async16(dst + 3*MATB, g3 + go);
        }
        cp_commit();
    };

    const int nkb = K/32;
    fill(0, 0);

    const int a_r  = lane & 15;
    const int a_ko = ((lane >> 4) & 1) << 3;
    const int b_n  = (lane & 7) + (((lane >> 4) & 1) << 3);
    const int b_ko = ((lane >> 3) & 1) << 3;

    for (int kb = 0; kb < nkb; kb++){
        if (kb+1 < nkb){
            fill((kb+1)&1, kb+1);
            asm volatile("cp.async.wait_group 1;" ::: "memory");
        } else {
            asm volatile("cp.async.wait_group 0;" ::: "memory");
        }
        __syncthreads();

        uint32_t sb = sbase + (kb&1)*STGB;
        #pragma unroll
        for (int ks=0; ks<2; ks++){
            const int k16 = ks*16;
            uint32_t ah[2][4], al[2][4];
            #pragma unroll
            for (int mt=0; mt<2; mt++){
                uint32_t ad = sb + (wm*32 + mt*16 + a_r)*(GRS*2) + (k16 + a_ko)*2;
                LDSM_X4(ah[mt][0],ah[mt][1],ah[mt][2],ah[mt][3], ad + 0*MATB);
                LDSM_X4(al[mt][0],al[mt][1],al[mt][2],al[mt][3], ad + 1*MATB);
            }
            #pragma unroll
            for (int n4=0; n4<4; n4++){
                uint32_t bd = sb + 2*MATB + (wn*64 + n4*16 + b_n)*(GRS*2) + (k16 + b_ko)*2;
                uint32_t bh[4], bl[4];
                LDSM_X4(bh[0],bh[1],bh[2],bh[3], bd);
                LDSM_X4(bl[0],bl[1],bl[2],bl[3], bd + MATB);
                #pragma unroll
                for (int mt=0; mt<2; mt++){
                    MMA16816(acc[mt][n4*2  ], ah[mt], bh[0], bh[1]);
                    MMA16816(acc[mt][n4*2+1], ah[mt], bh[2], bh[3]);
                    MMA16816(acc[mt][n4*2  ], ah[mt], bl[0], bl[1]);
                    MMA16816(acc[mt][n4*2+1], ah[mt], bl[2], bl[3]);
                    MMA16816(acc[mt][n4*2  ], al[mt], bh[0], bh[1]);
                    MMA16816(acc[mt][n4*2+1], al[mt], bh[2], bh[3]);
                }
            }
        }
        __syncthreads();
    }

    float* Cg = C + (size_t)(row0 + wm*32)*DD + col0 + wn*64;
    const int cr = lane >> 2, cc = (lane & 3) << 1;
    #pragma unroll
    for (int mt=0; mt<2; mt++)
        #pragma unroll
        for (int nt=0; nt<8; nt++){
            float2 v0; v0.x = acc[mt][nt][0]; v0.y = acc[mt][nt][1];
            *(float2*)&Cg[(size_t)(mt*16+cr)*DD + nt*8+cc] = v0;
            float2 v1; v1.x = acc[mt][nt][2]; v1.y = acc[mt][nt][3];
            *(float2*)&Cg[(size_t)(mt*16+cr+8)*DD + nt*8+cc] = v1;
        }
}

// ---------------- small projections: warp per row ----------------------------
__global__ void __launch_bounds__(256) smallproj_kernel(const float* __restrict__ Xh,
                                 const float* __restrict__ Wb,
                                 const float* __restrict__ Wdec,
                                 const float* __restrict__ Wmix)
{
    int wid = threadIdx.x >> 5, lane = threadIdx.x & 31;
    int row = blockIdx.x*8 + wid;
    const float* xr = Xh + (size_t)row*DD;
    float a[12];
    #pragma unroll
    for (int j=0;j<12;j++) a[j]=0.f;
    for (int c=lane; c<DD; c+=32){
        float hv = xr[c];
        float4 wb = *(const float4*)&Wb[c*4];
        float4 wd = *(const float4*)&Wdec[c*4];
        float4 wm = *(const float4*)&Wmix[c*4];
        a[0]+=hv*wb.x; a[1]+=hv*wb.y; a[2]+=hv*wb.z; a[3]+=hv*wb.w;
        a[4]+=hv*wd.x; a[5]+=hv*wd.y; a[6]+=hv*wd.z; a[7]+=hv*wd.w;
        a[8]+=hv*wm.x; a[9]+=hv*wm.y; a[10]+=hv*wm.z; a[11]+=hv*wm.w;
    }
    #pragma unroll
    for (int off=16; off; off>>=1){
        #pragma unroll
        for (int j=0;j<12;j++) a[j] += __shfl_down_sync(0xffffffffu, a[j], off);
    }
    if (lane == 0){
        #pragma unroll
        for (int j=0;j<4;j++){
            g_beta  [row*4+j] = sigm_f(a[j]);
            g_gamma [row*4+j] = sigm_f(a[4+j]);
            g_mixlin[row*4+j] = a[8+j];
        }
    }
}

// ---------------- causal short conv (K=4) + silu (optionally twice) ----------
__global__ void conv_silu_kernel(const float* __restrict__ X,
                                 const float* __restrict__ Wc,
                                 float* __restrict__ Y, int dbl)
{
    int idx = blockIdx.x*blockDim.x + threadIdx.x;
    if (idx >= NT*DD) return;
    int ch = idx & (DD-1);
    int bt = idx >> 10;
    int t  = bt & (LL-1);
    float acc = 0.f;
    #pragma unroll
    for (int k=0;k<4;k++){
        int ts = t-3+k;
        if (ts>=0) acc += X[(size_t)idx + (size_t)(ts-t)*DD] * Wc[ch*4+k];
    }
    float y = silu_f(acc);
    if (dbl) y = silu_f(y);
    Y[idx] = y;
}

// ---------------- mix path: conv over H channels + silu + sigmoid(+bias) -----
__global__ void mixconv_kernel(const float* __restrict__ convmix,
                               const float* __restrict__ mixbias)
{
    int idx = blockIdx.x*blockDim.x + threadIdx.x;
    if (idx >= NT*HH) return;
    int h = idx & 3;
    int bt = idx >> 2;
    int t = bt & (LL-1);
    float acc = 0.f;
    #pragma unroll
    for (int k=0;k<4;k++){
        int ts = t-3+k;
        if (ts>=0) acc += g_mixlin[idx + (ts-t)*HH] * convmix[h*4+k];
    }
    float mi = silu_f(acc);
    g_mixg[idx] = sigm_f(mi + mixbias[h]);
}

// ---------------- l2 norm: warp per (row,head) -------------------------------
__global__ void __launch_bounds__(256) l2norm_kernel()
{
    int wid = threadIdx.x >> 5, lane = threadIdx.x & 31;
    int g = blockIdx.x*8 + wid;
    int row = g >> 2, h = g & 3;
    size_t base = (size_t)row*DD + h*DK;

    {
        float4 v0 = *(float4*)&g_Q[base + lane*4];
        float4 v1 = *(float4*)&g_Q[base + 128 + lane*4];
        float s = v0.x*v0.x+v0.y*v0.y+v0.z*v0.z+v0.w*v0.w
                + v1.x*v1.x+v1.y*v1.y+v1.z*v1.z+v1.w*v1.w;
        #pragma unroll
        for (int off=16; off; off>>=1) s += __shfl_xor_sync(0xffffffffu, s, off);
        float sc = rsqrtf(s + 1e-6f);
        v0.x*=sc; v0.y*=sc; v0.z*=sc; v0.w*=sc;
        v1.x*=sc; v1.y*=sc; v1.z*=sc; v1.w*=sc;
        *(float4*)&g_Q[base + lane*4] = v0;
        *(float4*)&g_Q[base + 128 + lane*4] = v1;
    }
    {
        float4 v0 = *(float4*)&g_K[base + lane*4];
        float4 v1 = *(float4*)&g_K[base + 128 + lane*4];
        float s = v0.x*v0.x+v0.y*v0.y+v0.z*v0.z+v0.w*v0.w
                + v1.x*v1.x+v1.y*v1.y+v1.z*v1.z+v1.w*v1.w;
        #pragma unroll
        for (int off=16; off; off>>=1) s += __shfl_xor_sync(0xffffffffu, s, off);
        float sc = rsqrtf(s + 1e-6f);
        v0.x*=sc; v0.y*=sc; v0.z*=sc; v0.w*=sc;
        v1.x*=sc; v1.y*=sc; v1.z*=sc; v1.w*=sc;
        *(float4*)&g_K[base + lane*4] = v0;
        *(float4*)&g_K[base + 128 + lane*4] = v1;
    }
}

// ---------------- per-chunk: T (tri inverse), W = T@k_beta, Attn = tril(q k^T)
#define WP 260   // float stride for 32x256 tiles
#define SP 36    // float stride for 32x32 / 256x32 tiles

__global__ void __launch_bounds__(256) chunk_kernel()
{
    extern __shared__ float sm[];
    float* kc     = sm;                 // 32*WP
    float* qc     = kc + 32*WP;         // 32*WP
    float* Amat   = qc + 32*WP;         // 32*33
    float* bet    = Amat + 32*33;       // 32
    float* rowtmp = bet + 32;           // 32

    int blk = blockIdx.x;               // bh*64 + c
    int bh = blk >> 6, c = blk & 63;
    int b = bh >> 2, h = bh & 3;
    int tid = threadIdx.x;
    int rowbase = b*LL + c*CHK;

    for (int e = tid; e < 2048; e += 256){
        int r = e >> 6; int c4 = (e & 63) << 2;
        *(float4*)&kc[r*WP+c4] = *(const float4*)&g_K[(size_t)(rowbase+r)*DD + h*DK + c4];
        *(float4*)&qc[r*WP+c4] = *(const float4*)&g_Q[(size_t)(rowbase+r)*DD + h*DK + c4];
    }
    if (tid < 32) bet[tid] = g_beta[(rowbase+tid)*HH + h];
    __syncthreads();

    // A = -tril(k_beta @ k^T, -1),  Attn = tril(q @ k^T, 0)   [f32x2, pair over m]
    {
        int i = tid >> 3, j0 = tid & 7;
        u64t da[4], dq[4];
        #pragma unroll
        for (int u=0;u<4;u++){ da[u]=0ull; dq[u]=0ull; }
        #pragma unroll 4
        for (int m=0;m<256;m+=4){
            ulonglong2 ki = *(ulonglong2*)&kc[i*WP+m];
            ulonglong2 qi = *(ulonglong2*)&qc[i*WP+m];
            #pragma unroll
            for (int u=0;u<4;u++){
                ulonglong2 kj = *(ulonglong2*)&kc[(j0+8*u)*WP+m];
                da[u] = ffma2(ki.x, kj.x, da[u]);
                da[u] = ffma2(ki.y, kj.y, da[u]);
                dq[u] = ffma2(qi.x, kj.x, dq[u]);
                dq[u] = ffma2(qi.y, kj.y, dq[u]);
            }
        }
        #pragma unroll
        for (int u=0;u<4;u++){
            int j = j0 + 8*u;
            float2 ta = f2unpack(da[u]);
            float2 tq = f2unpack(dq[u]);
            float av = ta.x + ta.y, qv = tq.x + tq.y;
            Amat[i*33+j] = (j < i) ? -bet[i]*av : 0.f;
            g_At[(size_t)blk*1024 + i*32 + j] = (j <= i) ? qv : 0.f;
        }
    }
    __syncthreads();

    // sequential forward-substitution (warp 0)
    if (tid < 32){
        int cx = tid;
        for (int ii=1; ii<32; ii++){
            rowtmp[cx] = Amat[ii*33+cx];
            __syncwarp();
            float acc = 0.f;
            if (cx < ii){
                acc = rowtmp[cx];
                for (int j=cx+1; j<ii; j++) acc += rowtmp[j]*Amat[j*33+cx];
            }
            __syncwarp();
            if (cx < ii) Amat[ii*33+cx] = acc;
            __syncwarp();
        }
        Amat[cx*33+cx] = 1.0f;   // T = A + I
    }
    __syncthreads();

    for (int e=tid; e<1024; e+=256)
        g_T[(size_t)blk*1024 + e] = Amat[(e>>5)*33 + (e&31)];

    // W = T @ (beta * k)   [f32x2, pair over dk]
    {
        int i = tid >> 3, mb = (tid & 7) << 2;
        u64t acc[16];
        #pragma unroll
        for (int s=0;s<16;s++) acc[s]=0ull;
        for (int j=0;j<32;j++){
            u64t td = f2dup(Amat[i*33+j]*bet[j]);
            #pragma unroll
            for (int s=0;s<8;s++){
                ulonglong2 kv = *(ulonglong2*)&kc[j*WP + s*32 + mb];
                acc[2*s]   = ffma2(td, kv.x, acc[2*s]);
                acc[2*s+1] = ffma2(td, kv.y, acc[2*s+1]);
            }
        }
        #pragma unroll
        for (int s=0;s<8;s++){
            ulonglong2 ov; ov.x = acc[2*s]; ov.y = acc[2*s+1];
            *(ulonglong2*)&g_W[((size_t)blk*32 + i)*DK + s*32 + mb] = ov;
        }
    }
}

// ---------------- sequential inter-chunk scan, state S in SMEM, f32x2 --------
__global__ void __launch_bounds__(256,1) scan_kernel()
{
    extern __shared__ float sm[];
    float* S    = sm;                 // 256*SP
    float* w    = S   + 256*SP;       // 32*WP  (stored NEGATED)
    float* q    = w   + 32*WP;        // 32*WP
    float* kc   = q   + 32*WP;        // 32*WP
    float* att  = kc  + 32*WP;        // 32*SP
    float* Tt   = att + 32*SP;        // 32*SP
    float* vb   = Tt  + 32*SP;        // 32*SP
    float* ua   = vb  + 32*SP;        // 32*SP

    int tid = threadIdx.x;
    int bh   = blockIdx.x >> 3;
    int slab = blockIdx.x & 7;
    int b = bh >> 2, h = bh & 3;

    for (int e=tid; e<256*SP; e+=256) S[e]=0.f;
    __syncthreads();

    const int i  = tid >> 3;          // 0..31
    const int jb = (tid & 7) << 2;    // 0,4,...,28
    const size_t ocol = (size_t)h*DK + slab*32;

    for (int c=0; c<NCHUNK; c++){
        int blk = bh*NCHUNK + c;
        int rowbase = b*LL + c*CHK;
        // ---- load tiles (w negated at load)
        for (int e=tid; e<2048; e+=256){
            int r = e >> 6; int c4 = (e & 63) << 2;
            float4 wv = *(const float4*)&g_W[((size_t)blk*32 + r)*DK + c4];
            wv.x=-wv.x; wv.y=-wv.y; wv.z=-wv.z; wv.w=-wv.w;
            *(float4*)&w [r*WP+c4] = wv;
            *(float4*)&q [r*WP+c4] = *(const float4*)&g_Q[(size_t)(rowbase+r)*DD + h*DK + c4];
            *(float4*)&kc[r*WP+c4] = *(const float4*)&g_K[(size_t)(rowbase+r)*DD + h*DK + c4];
        }
        {
            int r = tid >> 3, c4 = (tid & 7) << 2;
            *(float4*)&att[r*SP+c4] = *(const float4*)&g_At[(size_t)blk*1024 + r*32 + c4];
            *(float4*)&Tt [r*SP+c4] = *(const float4*)&g_T [(size_t)blk*1024 + r*32 + c4];
            float be = g_beta[(rowbase+r)*HH + h];
            float4 vv = *(const float4*)&g_V[(size_t)(rowbase+r)*DD + ocol + c4];
            vv.x*=be; vv.y*=be; vv.z*=be; vv.w*=be;
            *(float4*)&vb[r*SP+c4] = vv;
        }
        __syncthreads();

        // ---- u_i = T @ vb  (pairs over j)
        u64t ui0=0ull, ui1=0ull;
        #pragma unroll
        for (int m=0;m<32;m++){
            u64t td = f2dup(Tt[i*SP+m]);
            ulonglong2 vv = *(ulonglong2*)&vb[m*SP+jb];
            ui0 = ffma2(td, vv.x, ui0);
            ui1 = ffma2(td, vv.y, ui1);
        }
        // ---- (-w)@S and q@S in one pass over k
        u64t nU0=0ull,nU1=0ull, aO0=0ull,aO1=0ull;
        #pragma unroll 4
        for (int k=0;k<256;k+=4){
            float4 wv = *(float4*)&w[i*WP+k];
            float4 qv = *(float4*)&q[i*WP+k];
            ulonglong2 s0 = *(ulonglong2*)&S[(k  )*SP+jb];
            ulonglong2 s1 = *(ulonglong2*)&S[(k+1)*SP+jb];
            ulonglong2 s2 = *(ulonglong2*)&S[(k+2)*SP+jb];
            ulonglong2 s3 = *(ulonglong2*)&S[(k+3)*SP+jb];
            u64t d;
            d=f2dup(wv.x); nU0=ffma2(d,s0.x,nU0); nU1=ffma2(d,s0.y,nU1);
            d=f2dup(qv.x); aO0=ffma2(d,s0.x,aO0); aO1=ffma2(d,s0.y,aO1);
            d=f2dup(wv.y); nU0=ffma2(d,s1.x,nU0); nU1=ffma2(d,s1.y,nU1);
            d=f2dup(qv.y); aO0=ffma2(d,s1.x,aO0); aO1=ffma2(d,s1.y,aO1);
            d=f2dup(wv.z); nU0=ffma2(d,s2.x,nU0); nU1=ffma2(d,s2.y,nU1);
            d=f2dup(qv.z); aO0=ffma2(d,s2.x,aO0); aO1=ffma2(d,s2.y,aO1);
            d=f2dup(wv.w); nU0=ffma2(d,s3.x,nU0); nU1=ffma2(d,s3.y,nU1);
            d=f2dup(qv.w); aO0=ffma2(d,s3.x,aO0); aO1=ffma2(d,s3.y,aO1);
        }
        // u_adj = u_i + (-w@S)
        ulonglong2 uav; uav.x = fadd2(ui0, nU0); uav.y = fadd2(ui1, nU1);
        *(ulonglong2*)&ua[i*SP+jb] = uav;
        __syncthreads();

        // ---- o = q@S + attn @ u_adj  -> global
        #pragma unroll
        for (int m=0;m<32;m++){
            u64t ad = f2dup(att[i*SP+m]);
            ulonglong2 uv = *(ulonglong2*)&ua[m*SP+jb];
            aO0 = ffma2(ad, uv.x, aO0);
            aO1 = ffma2(ad, uv.y, aO1);
        }
        ulonglong2 ov; ov.x = aO0; ov.y = aO1;
        *(ulonglong2*)&g_Od[(size_t)(rowbase+i)*DD + ocol + jb] = ov;

        // ---- S += k^T @ u_adj  (thread owns dk-row tid; 16 packed accumulators)
        u64t acc[16];
        #pragma unroll
        for (int x=0;x<16;x++) acc[x]=0ull;
        #pragma unroll 4
        for (int m=0;m<32;m++){
            u64t kd = f2dup(kc[m*WP + tid]);
            #pragma unroll
            for (int x=0;x<8;x++){
                ulonglong2 uv = *(ulonglong2*)&ua[m*SP + x*4];
                acc[2*x]   = ffma2(kd, uv.x, acc[2*x]);
                acc[2*x+1] = ffma2(kd, uv.y, acc[2*x+1]);
            }
        }
        #pragma unroll
        for (int x=0;x<8;x++){
            ulonglong2 sv = *(ulonglong2*)&S[tid*SP + x*4];
            sv.x = fadd2(sv.x, acc[2*x]);
            sv.y = fadd2(sv.y, acc[2*x+1]);
            *(ulonglong2*)&S[tid*SP + x*4] = sv;
        }
        __syncthreads();
    }
}

// ---------------- EMA over time: (b,h) x 4 col-slabs of 64 -------------------
__global__ void ema_kernel()
{
    int bh = blockIdx.x;
    int b = bh >> 2, h = bh & 3;
    int j = blockIdx.y*64 + threadIdx.x;
    float s = 0.f;
    int base = b*LL;
    for (int t=0;t<LL;t++){
        float g = g_gamma[(base+t)*HH + h];
        float v = g_V[(size_t)(base+t)*DD + h*DK + j];
        s = g*s + (1.f-g)*v;
        g_Oe[(size_t)(base+t)*DD + h*DK + j] = s;
    }
}

// ---------------- mix combine + RMS norm + bf16 split (fused) ----------------
__global__ void __launch_bounds__(256) combine_rms_kernel(const float* __restrict__ rmsw)
{
    int wid = threadIdx.x >> 5, lane = threadIdx.x & 31;
    int g = blockIdx.x*8 + wid;
    int row = g >> 2, h = g & 3;
    float m = g_mixg[row*4+h];
    size_t base = (size_t)row*DD + h*DK;

    float4 d0 = *(float4*)&g_Od[base + lane*4];
    float4 d1 = *(float4*)&g_Od[base + 128 + lane*4];
    float4 e0 = *(float4*)&g_Oe[base + lane*4];
    float4 e1 = *(float4*)&g_Oe[base + 128 + lane*4];
    float4 o0, o1;
    float om = 1.f - m;
    o0.x = om*d0.x + m*e0.x; o0.y = om*d0.y + m*e0.y;
    o0.z = om*d0.z + m*e0.z; o0.w = om*d0.w + m*e0.w;
    o1.x = om*d1.x + m*e1.x; o1.y = om*d1.y + m*e1.y;
    o1.z = om*d1.z + m*e1.z; o1.w = om*d1.w + m*e1.w;
    float s = o0.x*o0.x+o0.y*o0.y+o0.z*o0.z+o0.w*o0.w
            + o1.x*o1.x+o1.y*o1.y+o1.z*o1.z+o1.w*o1.w;
    #pragma unroll
    for (int off=16; off; off>>=1) s += __shfl_xor_sync(0xffffffffu, s, off);
    float sc = rsqrtf(s*(1.f/256.f) + 1e-5f);
    float4 r0 = *(const float4*)&rmsw[lane*4];
    float4 r1 = *(const float4*)&rmsw[128 + lane*4];
    o0.x *= sc*r0.x; o0.y *= sc*r0.y; o0.z *= sc*r0.z; o0.w *= sc*r0.w;
    o1.x *= sc*r1.x; o1.y *= sc*r1.y; o1.z *= sc*r1.z; o1.w *= sc*r1.w;

    // split to bf16 hi/lo directly
    __nv_bfloat16 h4[4], l4[4];
    float v[4];
    v[0]=o0.x; v[1]=o0.y; v[2]=o0.z; v[3]=o0.w;
    #pragma unroll
    for (int u=0;u<4;u++){
        h4[u]=__float2bfloat16(v[u]);
        l4[u]=__float2bfloat16(v[u]-__bfloat162float(h4[u]));
    }
    *(u64t*)&g_Op_hi[base + lane*4] = *(u64t*)h4;
    *(u64t*)&g_Op_lo[base + lane*4] = *(u64t*)l4;
    v[0]=o1.x; v[1]=o1.y; v[2]=o1.z; v[3]=o1.w;
    #pragma unroll
    for (int u=0;u<4;u++){
        h4[u]=__float2bfloat16(v[u]);
        l4[u]=__float2bfloat16(v[u]-__bfloat162float(h4[u]));
    }
    *(u64t*)&g_Op_hi[base + 128 + lane*4] = *(u64t*)h4;
    *(u64t*)&g_Op_lo[base + 128 + lane*4] = *(u64t*)l4;
}

// ---------------- host driver -----------------------------------------------
extern "C" void kernel_launch(void* const* d_in, const int* in_sizes, int n_in,
                              void* d_out, int out_size)
{
    const float* hs      = (const float*)d_in[0];
    const float* Wq      = (const float*)d_in[1];
    const float* Wk      = (const float*)d_in[2];
    const float* Wv      = (const float*)d_in[3];
    const float* convq   = (const float*)d_in[4];
    const float* convk   = (const float*)d_in[5];
    const float* convv   = (const float*)d_in[6];
    const float* Wb      = (const float*)d_in[7];
    const float* Wdec    = (const float*)d_in[8];
    const float* Wmix    = (const float*)d_in[9];
    const float* convmix = (const float*)d_in[10];
    const float* mixbias = (const float*)d_in[11];
    const float* rmsw    = (const float*)d_in[12];
    const float* Wo      = (const float*)d_in[13];

    void *pQL,*pKL,*pVL,*pQ,*pK,*pV;
    cudaGetSymbolAddress(&pQL, g_QL);
    cudaGetSymbolAddress(&pKL, g_KL);
    cudaGetSymbolAddress(&pVL, g_VL);
    cudaGetSymbolAddress(&pQ,  g_Q);
    cudaGetSymbolAddress(&pK,  g_K);
    cudaGetSymbolAddress(&pV,  g_V);

    void *p_hs_hi,*p_hs_lo,*p_Op_hi,*p_Op_lo;
    void *p_WT_hi,*p_WT_lo,*p_WoT_hi,*p_WoT_lo;
    cudaGetSymbolAddress(&p_hs_hi, g_hs_hi);  cudaGetSymbolAddress(&p_hs_lo, g_hs_lo);
    cudaGetSymbolAddress(&p_Op_hi, g_Op_hi);  cudaGetSymbolAddress(&p_Op_lo, g_Op_lo);
    cudaGetSymbolAddress(&p_WT_hi, g_WT_hi);  cudaGetSymbolAddress(&p_WT_lo, g_WT_lo);
    cudaGetSymbolAddress(&p_WoT_hi, g_WoT_hi); cudaGetSymbolAddress(&p_WoT_lo, g_WoT_lo);

    int smem_chunk = (2*32*WP + 32*33 + 64) * 4;
    int smem_scan  = (256*SP + 3*32*WP + 4*32*SP) * 4;
    int smem_gemm  = 2*STGB;
    cudaFuncSetAttribute(chunk_kernel, cudaFuncAttributeMaxDynamicSharedMemorySize, smem_chunk);
    cudaFuncSetAttribute(scan_kernel,  cudaFuncAttributeMaxDynamicSharedMemorySize, smem_scan);
    cudaFuncSetAttribute(gemm_bf16s,   cudaFuncAttributeMaxDynamicSharedMemorySize, smem_gemm);

    // 1: split activations
    split_kernel<<<NT*DD/256,256>>>(hs, (__nv_bfloat16*)p_hs_hi, (__nv_bfloat16*)p_hs_lo, NT*DD);
    // 2: weight transposes+splits
    dim3 wg(32,32,4), wb(32,8);
    wsplit_all_kernel<<<wg,wb>>>(Wq, Wk, Wv, Wo,
        (__nv_bfloat16*)p_WT_hi,(__nv_bfloat16*)p_WT_lo,
        (__nv_bfloat16*)p_WoT_hi,(__nv_bfloat16*)p_WoT_lo);
    // 3: small projections
    smallproj_kernel<<<NT/8,256>>>(hs, Wb, Wdec, Wmix);

    // 4: merged QKV GEMM (1536 CTAs, ~1 large wave)
    gemm_bf16s<<<dim3(24,64),256,smem_gemm>>>(
        (__nv_bfloat16*)p_hs_hi,(__nv_bfloat16*)p_hs_lo,
        (__nv_bfloat16*)p_WT_hi,(__nv_bfloat16*)p_WT_lo,
        (float*)pQL, (float*)pKL, (float*)pVL, DD);

    int nconv = NT*DD/256;
    conv_silu_kernel<<<nconv,256>>>((const float*)pQL, convq, (float*)pQ, 1);
    conv_silu_kernel<<<nconv,256>>>((const float*)pKL, convk, (float*)pK, 1);
    conv_silu_kernel<<<nconv,256>>>((const float*)pVL, convv, (float*)pV, 0);
    mixconv_kernel<<<(NT*HH+127)/128,128>>>(convmix, mixbias);

    l2norm_kernel<<<NT*HH/8,256>>>();
    chunk_kernel<<<NBH*NCHUNK,256,smem_chunk>>>();
    scan_kernel<<<NBH*8,256,smem_scan>>>();
    ema_kernel<<<dim3(NBH,4),64>>>();
    combine_rms_kernel<<<NT*HH/8,256>>>(rmsw);

    gemm_bf16s<<<dim3(8,64),256,smem_gemm>>>(
        (__nv_bfloat16*)p_Op_hi,(__nv_bfloat16*)p_Op_lo,
        (__nv_bfloat16*)p_WoT_hi,(__nv_bfloat16*)p_WoT_lo,
        (float*)d_out, (float*)d_out, (float*)d_out, DD);
}

// round 7
// speedup vs baseline: 2.5883x; 1.4717x over previous
#include <cuda_runtime.h>
#include <cuda_bf16.h>
#include <math.h>
#include <stdint.h>

// Problem constants
#define BB 4
#define LL 2048
#define DD 1024
#define HH 4
#define DK 256
#define NT (BB*LL)       // 8192 tokens
#define NCHUNK 64        // chunks per sequence
#define CHK 32           // chunk length
#define NBH 16           // B*H
#define ESEG 128         // ema segment length
#define NSEG (LL/ESEG)   // 16

typedef unsigned long long u64t;

// ---------------- scratch (device globals; no allocation allowed) -------------
__device__ float g_QL[NT*DD];
__device__ float g_KL[NT*DD];
__device__ float g_VL[NT*DD];
__device__ float g_Q[NT*DD];
__device__ float g_K[NT*DD];
__device__ float g_V[NT*DD];
__device__ float g_beta[NT*HH];
__device__ float g_gamma[NT*HH];
__device__ float g_mixlin[NT*HH];
__device__ float g_mixg[NT*HH];
__device__ float g_W[NBH*NCHUNK*CHK*DK];     // w = T @ k_beta
__device__ float g_T[NBH*NCHUNK*CHK*CHK];    // triangular inverse T
__device__ float g_At[NBH*NCHUNK*CHK*CHK];   // attn_i = tril(q@k^T)
__device__ float g_Od[NT*DD];                // delta-rule output
__device__ float g_Oe[NT*DD];                // ema LOCAL output (y_t)
__device__ float g_P[NBH*LL];                // in-segment prefix products of gamma
__device__ float g_C[NBH*NSEG*DK];           // carry state at segment start

// bf16 split buffers for tensor-core GEMMs
__device__ __nv_bfloat16 g_hs_hi[NT*DD], g_hs_lo[NT*DD];
__device__ __nv_bfloat16 g_Op_hi[NT*DD], g_Op_lo[NT*DD];
__device__ __nv_bfloat16 g_WT_hi[3*DD*DD], g_WT_lo[3*DD*DD];  // Wq|Wk|Wv transposed
__device__ __nv_bfloat16 g_WoT_hi[DD*DD], g_WoT_lo[DD*DD];

__device__ __forceinline__ float silu_f(float x){ return x / (1.f + expf(-x)); }
__device__ __forceinline__ float sigm_f(float x){ return 1.f / (1.f + expf(-x)); }

// ===================== f32x2 packed-math helpers =============================
__device__ __forceinline__ u64t f2dup(float x){
    u64t r; unsigned int xi = __float_as_uint(x);
    asm("mov.b64 %0, {%1,%1};" : "=l"(r) : "r"(xi));
    return r;
}
__device__ __forceinline__ u64t ffma2(u64t a, u64t b, u64t c){
    u64t d; asm("fma.rn.f32x2 %0, %1, %2, %3;" : "=l"(d) : "l"(a), "l"(b), "l"(c));
    return d;
}
__device__ __forceinline__ u64t fadd2(u64t a, u64t b){
    u64t d; asm("add.rn.f32x2 %0, %1, %2;" : "=l"(d) : "l"(a), "l"(b));
    return d;
}
__device__ __forceinline__ float2 f2unpack(u64t p){
    unsigned int lo, hi;
    asm("mov.b64 {%0,%1}, %2;" : "=r"(lo), "=r"(hi) : "l"(p));
    return make_float2(__uint_as_float(lo), __uint_as_float(hi));
}

// ===================== PTX helpers (mma.sync / ldmatrix / cp.async) ==========
__device__ __forceinline__ uint32_t smem_u32(const void* p){
    uint32_t a;
    asm("{ .reg .u64 t; cvta.to.shared.u64 t, %1; cvt.u32.u64 %0, t; }" : "=r"(a) : "l"(p));
    return a;
}
__device__ __forceinline__ void cp_async16(uint32_t dst, const void* src){
    asm volatile("cp.async.cg.shared.global [%0], [%1], 16;" :: "r"(dst), "l"(src) : "memory");
}
__device__ __forceinline__ void cp_commit(){ asm volatile("cp.async.commit_group;" ::: "memory"); }

#define LDSM_X4(r0,r1,r2,r3, addr) \
    asm volatile("ldmatrix.sync.aligned.m8n8.x4.shared.b16 {%0,%1,%2,%3}, [%4];" \
        : "=r"(r0),"=r"(r1),"=r"(r2),"=r"(r3) : "r"(addr))

#define MMA16816(d, a, b0, b1) \
    asm volatile("mma.sync.aligned.m16n8k16.row.col.f32.bf16.bf16.f32 " \
        "{%0,%1,%2,%3}, {%4,%5,%6,%7}, {%8,%9}, {%0,%1,%2,%3};" \
        : "+f"((d)[0]),"+f"((d)[1]),"+f"((d)[2]),"+f"((d)[3]) \
        : "r"((a)[0]),"r"((a)[1]),"r"((a)[2]),"r"((a)[3]), "r"(b0),"r"(b1))

// ===================== split/transpose conversion kernels ====================
__global__ void split_kernel(const float* __restrict__ X,
                             __nv_bfloat16* __restrict__ hi,
                             __nv_bfloat16* __restrict__ lo, int n)
{
    int i = blockIdx.x*256 + threadIdx.x;
    if (i < n){
        float x = X[i];
        __nv_bfloat16 h = __float2bfloat16(x);
        hi[i] = h;
        lo[i] = __float2bfloat16(x - __bfloat162float(h));
    }
}
// 4 weights transposed+split; Wq/Wk/Wv into combined [3072,1024], Wo separate.
__global__ void wsplit_all_kernel(const float* __restrict__ W0, const float* __restrict__ W1,
                                  const float* __restrict__ W2, const float* __restrict__ W3,
                                  __nv_bfloat16* __restrict__ bigh, __nv_bfloat16* __restrict__ bigl,
                                  __nv_bfloat16* __restrict__ woh, __nv_bfloat16* __restrict__ wol)
{
    __shared__ float t[32][33];
    const float* W; __nv_bfloat16 *hiT, *loT;
    int z = blockIdx.z;
    if      (z==0){ W=W0; hiT=bigh;            loT=bigl; }
    else if (z==1){ W=W1; hiT=bigh+DD*DD;      loT=bigl+DD*DD; }
    else if (z==2){ W=W2; hiT=bigh+2*DD*DD;    loT=bigl+2*DD*DD; }
    else          { W=W3; hiT=woh;             loT=wol; }
    int n0 = blockIdx.x*32, k0 = blockIdx.y*32;
    int tx = threadIdx.x, ty = threadIdx.y;   // 32 x 8
    for (int i = ty; i < 32; i += 8)
        t[i][tx] = W[(size_t)(k0+i)*DD + n0+tx];
    __syncthreads();
    for (int i = ty; i < 32; i += 8){
        float x = t[tx][i];                   // W[k0+tx][n0+i]
        __nv_bfloat16 h = __float2bfloat16(x);
        hiT[(size_t)(n0+i)*DD + k0+tx] = h;
        loT[(size_t)(n0+i)*DD + k0+tx] = __float2bfloat16(x - __bfloat162float(h));
    }
}

// ===================== mma.sync split-bf16 GEMM ==============================
#define GRS 40            // smem row stride in bf16 elements (80 bytes)
#define MATB (128*GRS*2)  // 10240 bytes per matrix tile
#define STGB (4*MATB)     // 40960 per stage

__global__ void __launch_bounds__(256,2) gemm_bf16s(
    const __nv_bfloat16* __restrict__ Ahi, const __nv_bfloat16* __restrict__ Alo,
    const __nv_bfloat16* __restrict__ BhiT, const __nv_bfloat16* __restrict__ BloT,
    float* C0, float* C1, float* C2, int K)
{
    extern __shared__ char smem[];
    const uint32_t sbase = smem_u32(smem);
    const int tid  = threadIdx.x;
    const int lane = tid & 31, wid = tid >> 5;
    const int wm = wid & 3, wn = wid >> 2;          // 4x2 warp grid
    const int row0 = blockIdx.y*128;
    const int bcol = blockIdx.x*128;                // into B (up to 3072 wide)
    const int seg  = blockIdx.x >> 3;
    const int col0 = (blockIdx.x & 7)*128;          // into C
    float* C = (seg==0) ? C0 : (seg==1 ? C1 : C2);

    const __nv_bfloat16* g0 = Ahi  + (size_t)row0*K;
    const __nv_bfloat16* g1 = Alo  + (size_t)row0*K;
    const __nv_bfloat16* g2 = BhiT + (size_t)bcol*K;
    const __nv_bfloat16* g3 = BloT + (size_t)bcol*K;

    float acc[2][8][4];
    #pragma unroll
    for (int i=0;i<2;i++)
        #pragma unroll
        for (int j=0;j<8;j++)
            #pragma unroll
            for (int u=0;u<4;u++) acc[i][j][u]=0.f;

    auto fill = [&](int stage, int kb){
        uint32_t sb = sbase + stage*STGB;
        #pragma unroll
        for (int t=0;t<2;t++){
            int ci = tid + t*256;
            int r = ci >> 2, c = ci & 3;
            uint32_t dst = sb + r*(GRS*2) + c*16;
            size_t go = (size_t)r*K + (size_t)kb*32 + c*8;
            cp_async16(dst + 0*MATB, g0 + go);
            cp_async16(dst + 1*MATB, g1 + go);
            cp_async16(dst + 2*MATB, g2 + go);
            cp_async16(dst + 3*MATB, g3 + go);
        }
        cp_commit();
    };

    const int nkb = K/32;
    fill(0, 0);

    const int a_r  = lane & 15;
    const int a_ko = ((lane >> 4) & 1) << 3;
    const int b_n  = (lane & 7) + (((lane >> 4) & 1) << 3);
    const int b_ko = ((lane >> 3) & 1) << 3;

    for (int kb = 0; kb < nkb; kb++){
        if (kb+1 < nkb){
            fill((kb+1)&1, kb+1);
            asm volatile("cp.async.wait_group 1;" ::: "memory");
        } else {
            asm volatile("cp.async.wait_group 0;" ::: "memory");
        }
        __syncthreads();

        uint32_t sb = sbase + (kb&1)*STGB;
        #pragma unroll
        for (int ks=0; ks<2; ks++){
            const int k16 = ks*16;
            uint32_t ah[2][4], al[2][4];
            #pragma unroll
            for (int mt=0; mt<2; mt++){
                uint32_t ad = sb + (wm*32 + mt*16 + a_r)*(GRS*2) + (k16 + a_ko)*2;
                LDSM_X4(ah[mt][0],ah[mt][1],ah[mt][2],ah[mt][3], ad + 0*MATB);
                LDSM_X4(al[mt][0],al[mt][1],al[mt][2],al[mt][3], ad + 1*MATB);
            }
            #pragma unroll
            for (int n4=0; n4<4; n4++){
                uint32_t bd = sb + 2*MATB + (wn*64 + n4*16 + b_n)*(GRS*2) + (k16 + b_ko)*2;
                uint32_t bh[4], bl[4];
                LDSM_X4(bh[0],bh[1],bh[2],bh[3], bd);
                LDSM_X4(bl[0],bl[1],bl[2],bl[3], bd + MATB);
                #pragma unroll
                for (int mt=0; mt<2; mt++){
                    MMA16816(acc[mt][n4*2  ], ah[mt], bh[0], bh[1]);
                    MMA16816(acc[mt][n4*2+1], ah[mt], bh[2], bh[3]);
                    MMA16816(acc[mt][n4*2  ], ah[mt], bl[0], bl[1]);
                    MMA16816(acc[mt][n4*2+1], ah[mt], bl[2], bl[3]);
                    MMA16816(acc[mt][n4*2  ], al[mt], bh[0], bh[1]);
                    MMA16816(acc[mt][n4*2+1], al[mt], bh[2], bh[3]);
                }
            }
        }
        __syncthreads();
    }

    float* Cg = C + (size_t)(row0 + wm*32)*DD + col0 + wn*64;
    const int cr = lane >> 2, cc = (lane & 3) << 1;
    #pragma unroll
    for (int mt=0; mt<2; mt++)
        #pragma unroll
        for (int nt=0; nt<8; nt++){
            float2 v0; v0.x = acc[mt][nt][0]; v0.y = acc[mt][nt][1];
            *(float2*)&Cg[(size_t)(mt*16+cr)*DD + nt*8+cc] = v0;
            float2 v1; v1.x = acc[mt][nt][2]; v1.y = acc[mt][nt][3];
            *(float2*)&Cg[(size_t)(mt*16+cr+8)*DD + nt*8+cc] = v1;
        }
}

// ---------------- small projections: warp per row ----------------------------
__global__ void __launch_bounds__(256) smallproj_kernel(const float* __restrict__ Xh,
                                 const float* __restrict__ Wb,
                                 const float* __restrict__ Wdec,
                                 const float* __restrict__ Wmix)
{
    int wid = threadIdx.x >> 5, lane = threadIdx.x & 31;
    int row = blockIdx.x*8 + wid;
    const float* xr = Xh + (size_t)row*DD;
    float a[12];
    #pragma unroll
    for (int j=0;j<12;j++) a[j]=0.f;
    for (int c=lane; c<DD; c+=32){
        float hv = xr[c];
        float4 wb = *(const float4*)&Wb[c*4];
        float4 wd = *(const float4*)&Wdec[c*4];
        float4 wm = *(const float4*)&Wmix[c*4];
        a[0]+=hv*wb.x; a[1]+=hv*wb.y; a[2]+=hv*wb.z; a[3]+=hv*wb.w;
        a[4]+=hv*wd.x; a[5]+=hv*wd.y; a[6]+=hv*wd.z; a[7]+=hv*wd.w;
        a[8]+=hv*wm.x; a[9]+=hv*wm.y; a[10]+=hv*wm.z; a[11]+=hv*wm.w;
    }
    #pragma unroll
    for (int off=16; off; off>>=1){
        #pragma unroll
        for (int j=0;j<12;j++) a[j] += __shfl_down_sync(0xffffffffu, a[j], off);
    }
    if (lane == 0){
        #pragma unroll
        for (int j=0;j<4;j++){
            g_beta  [row*4+j] = sigm_f(a[j]);
            g_gamma [row*4+j] = sigm_f(a[4+j]);
            g_mixlin[row*4+j] = a[8+j];
        }
    }
}

// ---------------- causal short conv (K=4) + silu (optionally twice) ----------
__global__ void conv_silu_kernel(const float* __restrict__ X,
                                 const float* __restrict__ Wc,
                                 float* __restrict__ Y, int dbl)
{
    int idx = blockIdx.x*blockDim.x + threadIdx.x;
    if (idx >= NT*DD) return;
    int ch = idx & (DD-1);
    int bt = idx >> 10;
    int t  = bt & (LL-1);
    float acc = 0.f;
    #pragma unroll
    for (int k=0;k<4;k++){
        int ts = t-3+k;
        if (ts>=0) acc += X[(size_t)idx + (size_t)(ts-t)*DD] * Wc[ch*4+k];
    }
    float y = silu_f(acc);
    if (dbl) y = silu_f(y);
    Y[idx] = y;
}

// ---------------- mix path: conv over H channels + silu + sigmoid(+bias) -----
__global__ void mixconv_kernel(const float* __restrict__ convmix,
                               const float* __restrict__ mixbias)
{
    int idx = blockIdx.x*blockDim.x + threadIdx.x;
    if (idx >= NT*HH) return;
    int h = idx & 3;
    int bt = idx >> 2;
    int t = bt & (LL-1);
    float acc = 0.f;
    #pragma unroll
    for (int k=0;k<4;k++){
        int ts = t-3+k;
        if (ts>=0) acc += g_mixlin[idx + (ts-t)*HH] * convmix[h*4+k];
    }
    float mi = silu_f(acc);
    g_mixg[idx] = sigm_f(mi + mixbias[h]);
}

// ---------------- l2 norm: warp per (row,head) -------------------------------
__global__ void __launch_bounds__(256) l2norm_kernel()
{
    int wid = threadIdx.x >> 5, lane = threadIdx.x & 31;
    int g = blockIdx.x*8 + wid;
    int row = g >> 2, h = g & 3;
    size_t base = (size_t)row*DD + h*DK;

    {
        float4 v0 = *(float4*)&g_Q[base + lane*4];
        float4 v1 = *(float4*)&g_Q[base + 128 + lane*4];
        float s = v0.x*v0.x+v0.y*v0.y+v0.z*v0.z+v0.w*v0.w
                + v1.x*v1.x+v1.y*v1.y+v1.z*v1.z+v1.w*v1.w;
        #pragma unroll
        for (int off=16; off; off>>=1) s += __shfl_xor_sync(0xffffffffu, s, off);
        float sc = rsqrtf(s + 1e-6f);
        v0.x*=sc; v0.y*=sc; v0.z*=sc; v0.w*=sc;
        v1.x*=sc; v1.y*=sc; v1.z*=sc; v1.w*=sc;
        *(float4*)&g_Q[base + lane*4] = v0;
        *(float4*)&g_Q[base + 128 + lane*4] = v1;
    }
    {
        float4 v0 = *(float4*)&g_K[base + lane*4];
        float4 v1 = *(float4*)&g_K[base + 128 + lane*4];
        float s = v0.x*v0.x+v0.y*v0.y+v0.z*v0.z+v0.w*v0.w
                + v1.x*v1.x+v1.y*v1.y+v1.z*v1.z+v1.w*v1.w;
        #pragma unroll
        for (int off=16; off; off>>=1) s += __shfl_xor_sync(0xffffffffu, s, off);
        float sc = rsqrtf(s + 1e-6f);
        v0.x*=sc; v0.y*=sc; v0.z*=sc; v0.w*=sc;
        v1.x*=sc; v1.y*=sc; v1.z*=sc; v1.w*=sc;
        *(float4*)&g_K[base + lane*4] = v0;
        *(float4*)&g_K[base + 128 + lane*4] = v1;
    }
}

// ---------------- per-chunk: T (tri inverse), W = T@k_beta, Attn = tril(q k^T)
#define WP 260   // float stride for 32x256 tiles
#define SP 36    // float stride for 32x32 / 256x32 tiles

__global__ void __launch_bounds__(256) chunk_kernel()
{
    extern __shared__ float sm[];
    float* kc     = sm;                 // 32*WP
    float* qc     = kc + 32*WP;         // 32*WP
    float* Amat   = qc + 32*WP;         // 32*33
    float* bet    = Amat + 32*33;       // 32
    float* rowtmp = bet + 32;           // 32

    int blk = blockIdx.x;               // bh*64 + c
    int bh = blk >> 6, c = blk & 63;
    int b = bh >> 2, h = bh & 3;
    int tid = threadIdx.x;
    int rowbase = b*LL + c*CHK;

    for (int e = tid; e < 2048; e += 256){
        int r = e >> 6; int c4 = (e & 63) << 2;
        *(float4*)&kc[r*WP+c4] = *(const float4*)&g_K[(size_t)(rowbase+r)*DD + h*DK + c4];
        *(float4*)&qc[r*WP+c4] = *(const float4*)&g_Q[(size_t)(rowbase+r)*DD + h*DK + c4];
    }
    if (tid < 32) bet[tid] = g_beta[(rowbase+tid)*HH + h];
    __syncthreads();

    // A = -tril(k_beta @ k^T, -1),  Attn = tril(q @ k^T, 0)   [f32x2, pair over m]
    {
        int i = tid >> 3, j0 = tid & 7;
        u64t da[4], dq[4];
        #pragma unroll
        for (int u=0;u<4;u++){ da[u]=0ull; dq[u]=0ull; }
        #pragma unroll 4
        for (int m=0;m<256;m+=4){
            ulonglong2 ki = *(ulonglong2*)&kc[i*WP+m];
            ulonglong2 qi = *(ulonglong2*)&qc[i*WP+m];
            #pragma unroll
            for (int u=0;u<4;u++){
                ulonglong2 kj = *(ulonglong2*)&kc[(j0+8*u)*WP+m];
                da[u] = ffma2(ki.x, kj.x, da[u]);
                da[u] = ffma2(ki.y, kj.y, da[u]);
                dq[u] = ffma2(qi.x, kj.x, dq[u]);
                dq[u] = ffma2(qi.y, kj.y, dq[u]);
            }
        }
        #pragma unroll
        for (int u=0;u<4;u++){
            int j = j0 + 8*u;
            float2 ta = f2unpack(da[u]);
            float2 tq = f2unpack(dq[u]);
            float av = ta.x + ta.y, qv = tq.x + tq.y;
            Amat[i*33+j] = (j < i) ? -bet[i]*av : 0.f;
            g_At[(size_t)blk*1024 + i*32 + j] = (j <= i) ? qv : 0.f;
        }
    }
    __syncthreads();

    // sequential forward-substitution (warp 0)
    if (tid < 32){
        int cx = tid;
        for (int ii=1; ii<32; ii++){
            rowtmp[cx] = Amat[ii*33+cx];
            __syncwarp();
            float acc = 0.f;
            if (cx < ii){
                acc = rowtmp[cx];
                for (int j=cx+1; j<ii; j++) acc += rowtmp[j]*Amat[j*33+cx];
            }
            __syncwarp();
            if (cx < ii) Amat[ii*33+cx] = acc;
            __syncwarp();
        }
        Amat[cx*33+cx] = 1.0f;   // T = A + I
    }
    __syncthreads();

    for (int e=tid; e<1024; e+=256)
        g_T[(size_t)blk*1024 + e] = Amat[(e>>5)*33 + (e&31)];

    // W = T @ (beta * k)   [f32x2, pair over dk]
    {
        int i = tid >> 3, mb = (tid & 7) << 2;
        u64t acc[16];
        #pragma unroll
        for (int s=0;s<16;s++) acc[s]=0ull;
        for (int j=0;j<32;j++){
            u64t td = f2dup(Amat[i*33+j]*bet[j]);
            #pragma unroll
            for (int s=0;s<8;s++){
                ulonglong2 kv = *(ulonglong2*)&kc[j*WP + s*32 + mb];
                acc[2*s]   = ffma2(td, kv.x, acc[2*s]);
                acc[2*s+1] = ffma2(td, kv.y, acc[2*s+1]);
            }
        }
        #pragma unroll
        for (int s=0;s<8;s++){
            ulonglong2 ov; ov.x = acc[2*s]; ov.y = acc[2*s+1];
            *(ulonglong2*)&g_W[((size_t)blk*32 + i)*DK + s*32 + mb] = ov;
        }
    }
}

// ---------------- sequential inter-chunk scan, state S in SMEM, f32x2 --------
__global__ void __launch_bounds__(256,1) scan_kernel()
{
    extern __shared__ float sm[];
    float* S    = sm;                 // 256*SP
    float* w    = S   + 256*SP;       // 32*WP  (stored NEGATED)
    float* q    = w   + 32*WP;        // 32*WP
    float* kc   = q   + 32*WP;        // 32*WP
    float* att  = kc  + 32*WP;        // 32*SP
    float* Tt   = att + 32*SP;        // 32*SP
    float* vb   = Tt  + 32*SP;        // 32*SP
    float* ua   = vb  + 32*SP;        // 32*SP

    int tid = threadIdx.x;
    int bh   = blockIdx.x >> 3;
    int slab = blockIdx.x & 7;
    int b = bh >> 2, h = bh & 3;

    for (int e=tid; e<256*SP; e+=256) S[e]=0.f;
    __syncthreads();

    const int i  = tid >> 3;          // 0..31
    const int jb = (tid & 7) << 2;    // 0,4,...,28
    const size_t ocol = (size_t)h*DK + slab*32;

    for (int c=0; c<NCHUNK; c++){
        int blk = bh*NCHUNK + c;
        int rowbase = b*LL + c*CHK;
        // ---- load tiles (w negated at load)
        for (int e=tid; e<2048; e+=256){
            int r = e >> 6; int c4 = (e & 63) << 2;
            float4 wv = *(const float4*)&g_W[((size_t)blk*32 + r)*DK + c4];
            wv.x=-wv.x; wv.y=-wv.y; wv.z=-wv.z; wv.w=-wv.w;
            *(float4*)&w [r*WP+c4] = wv;
            *(float4*)&q [r*WP+c4] = *(const float4*)&g_Q[(size_t)(rowbase+r)*DD + h*DK + c4];
            *(float4*)&kc[r*WP+c4] = *(const float4*)&g_K[(size_t)(rowbase+r)*DD + h*DK + c4];
        }
        {
            int r = tid >> 3, c4 = (tid & 7) << 2;
            *(float4*)&att[r*SP+c4] = *(const float4*)&g_At[(size_t)blk*1024 + r*32 + c4];
            *(float4*)&Tt [r*SP+c4] = *(const float4*)&g_T [(size_t)blk*1024 + r*32 + c4];
            float be = g_beta[(rowbase+r)*HH + h];
            float4 vv = *(const float4*)&g_V[(size_t)(rowbase+r)*DD + ocol + c4];
            vv.x*=be; vv.y*=be; vv.z*=be; vv.w*=be;
            *(float4*)&vb[r*SP+c4] = vv;
        }
        __syncthreads();

        // ---- u_i = T @ vb  (pairs over j)
        u64t ui0=0ull, ui1=0ull;
        #pragma unroll
        for (int m=0;m<32;m++){
            u64t td = f2dup(Tt[i*SP+m]);
            ulonglong2 vv = *(ulonglong2*)&vb[m*SP+jb];
            ui0 = ffma2(td, vv.x, ui0);
            ui1 = ffma2(td, vv.y, ui1);
        }
        // ---- (-w)@S and q@S in one pass over k
        u64t nU0=0ull,nU1=0ull, aO0=0ull,aO1=0ull;
        #pragma unroll 4
        for (int k=0;k<256;k+=4){
            float4 wv = *(float4*)&w[i*WP+k];
            float4 qv = *(float4*)&q[i*WP+k];
            ulonglong2 s0 = *(ulonglong2*)&S[(k  )*SP+jb];
            ulonglong2 s1 = *(ulonglong2*)&S[(k+1)*SP+jb];
            ulonglong2 s2 = *(ulonglong2*)&S[(k+2)*SP+jb];
            ulonglong2 s3 = *(ulonglong2*)&S[(k+3)*SP+jb];
            u64t d;
            d=f2dup(wv.x); nU0=ffma2(d,s0.x,nU0); nU1=ffma2(d,s0.y,nU1);
            d=f2dup(qv.x); aO0=ffma2(d,s0.x,aO0); aO1=ffma2(d,s0.y,aO1);
            d=f2dup(wv.y); nU0=ffma2(d,s1.x,nU0); nU1=ffma2(d,s1.y,nU1);
            d=f2dup(qv.y); aO0=ffma2(d,s1.x,aO0); aO1=ffma2(d,s1.y,aO1);
            d=f2dup(wv.z); nU0=ffma2(d,s2.x,nU0); nU1=ffma2(d,s2.y,nU1);
            d=f2dup(qv.z); aO0=ffma2(d,s2.x,aO0); aO1=ffma2(d,s2.y,aO1);
            d=f2dup(wv.w); nU0=ffma2(d,s3.x,nU0); nU1=ffma2(d,s3.y,nU1);
            d=f2dup(qv.w); aO0=ffma2(d,s3.x,aO0); aO1=ffma2(d,s3.y,aO1);
        }
        // u_adj = u_i + (-w@S)
        ulonglong2 uav; uav.x = fadd2(ui0, nU0); uav.y = fadd2(ui1, nU1);
        *(ulonglong2*)&ua[i*SP+jb] = uav;
        __syncthreads();

        // ---- o = q@S + attn @ u_adj  -> global
        #pragma unroll
        for (int m=0;m<32;m++){
            u64t ad = f2dup(att[i*SP+m]);
            ulonglong2 uv = *(ulonglong2*)&ua[m*SP+jb];
            aO0 = ffma2(ad, uv.x, aO0);
            aO1 = ffma2(ad, uv.y, aO1);
        }
        ulonglong2 ov; ov.x = aO0; ov.y = aO1;
        *(ulonglong2*)&g_Od[(size_t)(rowbase+i)*DD + ocol + jb] = ov;

        // ---- S += k^T @ u_adj  (thread owns dk-row tid; 16 packed accumulators)
        u64t acc[16];
        #pragma unroll
        for (int x=0;x<16;x++) acc[x]=0ull;
        #pragma unroll 4
        for (int m=0;m<32;m++){
            u64t kd = f2dup(kc[m*WP + tid]);
            #pragma unroll
            for (int x=0;x<8;x++){
                ulonglong2 uv = *(ulonglong2*)&ua[m*SP + x*4];
                acc[2*x]   = ffma2(kd, uv.x, acc[2*x]);
                acc[2*x+1] = ffma2(kd, uv.y, acc[2*x+1]);
            }
        }
        #pragma unroll
        for (int x=0;x<8;x++){
            ulonglong2 sv = *(ulonglong2*)&S[tid*SP + x*4];
            sv.x = fadd2(sv.x, acc[2*x]);
            sv.y = fadd2(sv.y, acc[2*x+1]);
            *(ulonglong2*)&S[tid*SP + x*4] = sv;
        }
        __syncthreads();
    }
}

// ---------------- EMA phase 1: segmented local scan --------------------------
// grid (NBH, NSEG), 256 threads (one per dv channel). SMEM-staged.
__global__ void __launch_bounds__(256) ema_local_kernel()
{
    extern __shared__ float esm[];
    float* cbuf = esm;            // ESEG*256 = 32768 floats (c, then y)
    float* gbuf = cbuf + ESEG*256; // ESEG
    float* Ps   = gbuf + ESEG;     // ESEG

    int bh = blockIdx.x, seg = blockIdx.y;
    int b = bh >> 2, h = bh & 3;
    int tid = threadIdx.x;
    int rowbase = b*LL + seg*ESEG;
    size_t hcol = (size_t)h*DK;

    // stage gamma
    if (tid < ESEG) gbuf[tid] = g_gamma[(rowbase+tid)*HH + h];
    __syncthreads();

    // stage c = (1-g)*v  (bulk float4 loads, high MLP)
    for (int e = tid; e < ESEG*64; e += 256){
        int r = e >> 6, c4 = (e & 63) << 2;
        float om = 1.f - gbuf[r];
        float4 vv = *(const float4*)&g_V[(size_t)(rowbase+r)*DD + hcol + c4];
        vv.x*=om; vv.y*=om; vv.z*=om; vv.w*=om;
        *(float4*)&cbuf[r*256 + c4] = vv;
    }
    // in-segment prefix products of gamma (warps 0..3)
    if (tid < ESEG){
        int lane = tid & 31;
        float p = gbuf[tid];
        #pragma unroll
        for (int off=1; off<32; off<<=1){
            float o = __shfl_up_sync(0xffffffffu, p, off);
            if (lane >= off) p *= o;
        }
        Ps[tid] = p;
    }
    __syncthreads();
    if (tid < ESEG){
        int wmy = tid >> 5;
        float pre = 1.f;
        for (int wq = 0; wq < wmy; wq++) pre *= Ps[wq*32+31];
        g_P[bh*LL + seg*ESEG + tid] = pre * Ps[tid];
    }

    // serial local recurrence from SMEM: y_t = g_t*y_{t-1} + c_t
    float s = 0.f;
    #pragma unroll 8
    for (int t = 0; t < ESEG; t++){
        s = fmaf(gbuf[t], s, cbuf[t*256 + tid]);
        cbuf[t*256 + tid] = s;
    }
    __syncthreads();

    // bulk store y to g_Oe
    for (int e = tid; e < ESEG*64; e += 256){
        int r = e >> 6, c4 = (e & 63) << 2;
        *(float4*)&g_Oe[(size_t)(rowbase+r)*DD + hcol + c4] = *(float4*)&cbuf[r*256 + c4];
    }
}

// ---------------- EMA phase 2: carry across segments -------------------------
__global__ void __launch_bounds__(256) ema_carry_kernel()
{
    int bh = blockIdx.x;
    int b = bh >> 2, h = bh & 3;
    int dv = threadIdx.x;
    float s = 0.f;
    #pragma unroll
    for (int seg = 0; seg < NSEG; seg++){
        g_C[(bh*NSEG + seg)*DK + dv] = s;
        int rend = b*LL + seg*ESEG + (ESEG-1);
        float P  = g_P[bh*LL + seg*ESEG + (ESEG-1)];
        float ye = g_Oe[(size_t)rend*DD + h*DK + dv];
        s = fmaf(P, s, ye);
    }
}

// ---------------- mix combine + RMS norm + bf16 split (fused, + ema carry) ---
__global__ void __launch_bounds__(256) combine_rms_kernel(const float* __restrict__ rmsw)
{
    int wid = threadIdx.x >> 5, lane = threadIdx.x & 31;
    int g = blockIdx.x*8 + wid;
    int row = g >> 2, h = g & 3;
    int b = row >> 11, t = row & (LL-1);
    int bh = b*4 + h, seg = t >> 7;
    float m = g_mixg[row*4+h];
    size_t base = (size_t)row*DD + h*DK;

    float P = g_P[bh*LL + t];
    const float* cav = &g_C[(bh*NSEG + seg)*DK];
    float4 c0 = *(const float4*)&cav[lane*4];
    float4 c1 = *(const float4*)&cav[128 + lane*4];

    float4 d0 = *(float4*)&g_Od[base + lane*4];
    float4 d1 = *(float4*)&g_Od[base + 128 + lane*4];
    float4 e0 = *(float4*)&g_Oe[base + lane*4];
    float4 e1 = *(float4*)&g_Oe[base + 128 + lane*4];
    // apply ema segment carry: oe = y + P*carry
    e0.x += P*c0.x; e0.y += P*c0.y; e0.z += P*c0.z; e0.w += P*c0.w;
    e1.x += P*c1.x; e1.y += P*c1.y; e1.z += P*c1.z; e1.w += P*c1.w;

    float4 o0, o1;
    float om = 1.f - m;
    o0.x = om*d0.x + m*e0.x; o0.y = om*d0.y + m*e0.y;
    o0.z = om*d0.z + m*e0.z; o0.w = om*d0.w + m*e0.w;
    o1.x = om*d1.x + m*e1.x; o1.y = om*d1.y + m*e1.y;
    o1.z = om*d1.z + m*e1.z; o1.w = om*d1.w + m*e1.w;
    float s = o0.x*o0.x+o0.y*o0.y+o0.z*o0.z+o0.w*o0.w
            + o1.x*o1.x+o1.y*o1.y+o1.z*o1.z+o1.w*o1.w;
    #pragma unroll
    for (int off=16; off; off>>=1) s += __shfl_xor_sync(0xffffffffu, s, off);
    float sc = rsqrtf(s*(1.f/256.f) + 1e-5f);
    float4 r0 = *(const float4*)&rmsw[lane*4];
    float4 r1 = *(const float4*)&rmsw[128 + lane*4];
    o0.x *= sc*r0.x; o0.y *= sc*r0.y; o0.z *= sc*r0.z; o0.w *= sc*r0.w;
    o1.x *= sc*r1.x; o1.y *= sc*r1.y; o1.z *= sc*r1.z; o1.w *= sc*r1.w;

    // split to bf16 hi/lo directly
    __nv_bfloat16 h4[4], l4[4];
    float v[4];
    v[0]=o0.x; v[1]=o0.y; v[2]=o0.z; v[3]=o0.w;
    #pragma unroll
    for (int u=0;u<4;u++){
        h4[u]=__float2bfloat16(v[u]);
        l4[u]=__float2bfloat16(v[u]-__bfloat162float(h4[u]));
    }
    *(u64t*)&g_Op_hi[base + lane*4] = *(u64t*)h4;
    *(u64t*)&g_Op_lo[base + lane*4] = *(u64t*)l4;
    v[0]=o1.x; v[1]=o1.y; v[2]=o1.z; v[3]=o1.w;
    #pragma unroll
    for (int u=0;u<4;u++){
        h4[u]=__float2bfloat16(v[u]);
        l4[u]=__float2bfloat16(v[u]-__bfloat162float(h4[u]));
    }
    *(u64t*)&g_Op_hi[base + 128 + lane*4] = *(u64t*)h4;
    *(u64t*)&g_Op_lo[base + 128 + lane*4] = *(u64t*)l4;
}

// ---------------- host driver -----------------------------------------------
extern "C" void kernel_launch(void* const* d_in, const int* in_sizes, int n_in,
                              void* d_out, int out_size)
{
    const float* hs      = (const float*)d_in[0];
    const float* Wq      = (const float*)d_in[1];
    const float* Wk      = (const float*)d_in[2];
    const float* Wv      = (const float*)d_in[3];
    const float* convq   = (const float*)d_in[4];
    const float* convk   = (const float*)d_in[5];
    const float* convv   = (const float*)d_in[6];
    const float* Wb      = (const float*)d_in[7];
    const float* Wdec    = (const float*)d_in[8];
    const float* Wmix    = (const float*)d_in[9];
    const float* convmix = (const float*)d_in[10];
    const float* mixbias = (const float*)d_in[11];
    const float* rmsw    = (const float*)d_in[12];
    const float* Wo      = (const float*)d_in[13];

    void *pQL,*pKL,*pVL,*pQ,*pK,*pV;
    cudaGetSymbolAddress(&pQL, g_QL);
    cudaGetSymbolAddress(&pKL, g_KL);
    cudaGetSymbolAddress(&pVL, g_VL);
    cudaGetSymbolAddress(&pQ,  g_Q);
    cudaGetSymbolAddress(&pK,  g_K);
    cudaGetSymbolAddress(&pV,  g_V);

    void *p_hs_hi,*p_hs_lo,*p_Op_hi,*p_Op_lo;
    void *p_WT_hi,*p_WT_lo,*p_WoT_hi,*p_WoT_lo;
    cudaGetSymbolAddress(&p_hs_hi, g_hs_hi);  cudaGetSymbolAddress(&p_hs_lo, g_hs_lo);
    cudaGetSymbolAddress(&p_Op_hi, g_Op_hi);  cudaGetSymbolAddress(&p_Op_lo, g_Op_lo);
    cudaGetSymbolAddress(&p_WT_hi, g_WT_hi);  cudaGetSymbolAddress(&p_WT_lo, g_WT_lo);
    cudaGetSymbolAddress(&p_WoT_hi, g_WoT_hi); cudaGetSymbolAddress(&p_WoT_lo, g_WoT_lo);

    int smem_chunk = (2*32*WP + 32*33 + 64) * 4;
    int smem_scan  = (256*SP + 3*32*WP + 4*32*SP) * 4;
    int smem_gemm  = 2*STGB;
    int smem_ema   = (ESEG*256 + 2*ESEG) * 4;   // 132,096 B
    cudaFuncSetAttribute(chunk_kernel, cudaFuncAttributeMaxDynamicSharedMemorySize, smem_chunk);
    cudaFuncSetAttribute(scan_kernel,  cudaFuncAttributeMaxDynamicSharedMemorySize, smem_scan);
    cudaFuncSetAttribute(gemm_bf16s,   cudaFuncAttributeMaxDynamicSharedMemorySize, smem_gemm);
    cudaFuncSetAttribute(ema_local_kernel, cudaFuncAttributeMaxDynamicSharedMemorySize, smem_ema);

    // 1: split activations
    split_kernel<<<NT*DD/256,256>>>(hs, (__nv_bfloat16*)p_hs_hi, (__nv_bfloat16*)p_hs_lo, NT*DD);
    // 2: weight transposes+splits
    dim3 wg(32,32,4), wb(32,8);
    wsplit_all_kernel<<<wg,wb>>>(Wq, Wk, Wv, Wo,
        (__nv_bfloat16*)p_WT_hi,(__nv_bfloat16*)p_WT_lo,
        (__nv_bfloat16*)p_WoT_hi,(__nv_bfloat16*)p_WoT_lo);
    // 3: small projections
    smallproj_kernel<<<NT/8,256>>>(hs, Wb, Wdec, Wmix);

    // 4: merged QKV GEMM (1536 CTAs)
    gemm_bf16s<<<dim3(24,64),256,smem_gemm>>>(
        (__nv_bfloat16*)p_hs_hi,(__nv_bfloat16*)p_hs_lo,
        (__nv_bfloat16*)p_WT_hi,(__nv_bfloat16*)p_WT_lo,
        (float*)pQL, (float*)pKL, (float*)pVL, DD);

    int nconv = NT*DD/256;
    conv_silu_kernel<<<nconv,256>>>((const float*)pQL, convq, (float*)pQ, 1);
    conv_silu_kernel<<<nconv,256>>>((const float*)pKL, convk, (float*)pK, 1);
    conv_silu_kernel<<<nconv,256>>>((const float*)pVL, convv, (float*)pV, 0);
    mixconv_kernel<<<(NT*HH+127)/128,128>>>(convmix, mixbias);

    l2norm_kernel<<<NT*HH/8,256>>>();
    chunk_kernel<<<NBH*NCHUNK,256,smem_chunk>>>();
    scan_kernel<<<NBH*8,256,smem_scan>>>();

    // EMA: segmented parallel linear-recurrence scan
    ema_local_kernel<<<dim3(NBH,NSEG),256,smem_ema>>>();
    ema_carry_kernel<<<NBH,DK>>>();

    combine_rms_kernel<<<NT*HH/8,256>>>(rmsw);

    gemm_bf16s<<<dim3(8,64),256,smem_gemm>>>(
        (__nv_bfloat16*)p_Op_hi,(__nv_bfloat16*)p_Op_lo,
        (__nv_bfloat16*)p_WoT_hi,(__nv_bfloat16*)p_WoT_lo,
        (float*)d_out, (float*)d_out, (float*)d_out, DD);
}

// round 8
// speedup vs baseline: 2.9758x; 1.1497x over previous
#include <cuda_runtime.h>
#include <cuda_bf16.h>
#include <cuda_fp16.h>
#include <math.h>
#include <stdint.h>

// Problem constants
#define BB 4
#define LL 2048
#define DD 1024
#define HH 4
#define DK 256
#define NT (BB*LL)       // 8192 tokens
#define NCHUNK 64        // chunks per sequence
#define CHK 32           // chunk length
#define NBH 16           // B*H
#define ESEG 128         // ema segment length
#define NSEG (LL/ESEG)   // 16

typedef unsigned long long u64t;

// ---------------- scratch (device globals; no allocation allowed) -------------
__device__ float g_QL[NT*DD];
__device__ float g_KL[NT*DD];
__device__ float g_VL[NT*DD];
__device__ float g_Q[NT*DD];
__device__ float g_K[NT*DD];
__device__ float g_V[NT*DD];
__device__ float g_beta[NT*HH];
__device__ float g_gamma[NT*HH];
__device__ float g_mixlin[NT*HH];
__device__ float g_mixg[NT*HH];
__device__ float g_W[NBH*NCHUNK*CHK*DK];     // w = T @ k_beta
__device__ float g_T[NBH*NCHUNK*CHK*CHK];    // triangular inverse T
__device__ float g_At[NBH*NCHUNK*CHK*CHK];   // attn_i = tril(q@k^T)
__device__ float g_Od[NT*DD];                // delta-rule output
__device__ float g_Oe[NT*DD];                // ema LOCAL output (y_t)
__device__ float g_P[NBH*LL];                // in-segment prefix products of gamma
__device__ float g_C[NBH*NSEG*DK];           // carry state at segment start

// fp16 limb buffers for tensor-core GEMMs (A: 2 limbs; B: single fp16)
__device__ __half g_hs_hi[NT*DD], g_hs_lo[NT*DD];
__device__ __half g_Op_hi[NT*DD], g_Op_lo[NT*DD];
__device__ __half g_WT_h[3*DD*DD];           // Wq|Wk|Wv transposed, fp16
__device__ __half g_WoT_h[DD*DD];            // Wo transposed, fp16

__device__ __forceinline__ float silu_f(float x){ return x / (1.f + expf(-x)); }
__device__ __forceinline__ float sigm_f(float x){ return 1.f / (1.f + expf(-x)); }

// ===================== f32x2 packed-math helpers =============================
__device__ __forceinline__ u64t f2dup(float x){
    u64t r; unsigned int xi = __float_as_uint(x);
    asm("mov.b64 %0, {%1,%1};" : "=l"(r) : "r"(xi));
    return r;
}
__device__ __forceinline__ u64t ffma2(u64t a, u64t b, u64t c){
    u64t d; asm("fma.rn.f32x2 %0, %1, %2, %3;" : "=l"(d) : "l"(a), "l"(b), "l"(c));
    return d;
}
__device__ __forceinline__ u64t fadd2(u64t a, u64t b){
    u64t d; asm("add.rn.f32x2 %0, %1, %2;" : "=l"(d) : "l"(a), "l"(b));
    return d;
}
__device__ __forceinline__ float2 f2unpack(u64t p){
    unsigned int lo, hi;
    asm("mov.b64 {%0,%1}, %2;" : "=r"(lo), "=r"(hi) : "l"(p));
    return make_float2(__uint_as_float(lo), __uint_as_float(hi));
}

// ===================== PTX helpers (mma.sync / ldmatrix / cp.async) ==========
__device__ __forceinline__ uint32_t smem_u32(const void* p){
    uint32_t a;
    asm("{ .reg .u64 t; cvta.to.shared.u64 t, %1; cvt.u32.u64 %0, t; }" : "=r"(a) : "l"(p));
    return a;
}
__device__ __forceinline__ void cp_async16(uint32_t dst, const void* src){
    asm volatile("cp.async.cg.shared.global [%0], [%1], 16;" :: "r"(dst), "l"(src) : "memory");
}
__device__ __forceinline__ void cp_commit(){ asm volatile("cp.async.commit_group;" ::: "memory"); }

#define LDSM_X4(r0,r1,r2,r3, addr) \
    asm volatile("ldmatrix.sync.aligned.m8n8.x4.shared.b16 {%0,%1,%2,%3}, [%4];" \
        : "=r"(r0),"=r"(r1),"=r"(r2),"=r"(r3) : "r"(addr))

#define MMAF16(d, a, b0, b1) \
    asm volatile("mma.sync.aligned.m16n8k16.row.col.f32.f16.f16.f32 " \
        "{%0,%1,%2,%3}, {%4,%5,%6,%7}, {%8,%9}, {%0,%1,%2,%3};" \
        : "+f"((d)[0]),"+f"((d)[1]),"+f"((d)[2]),"+f"((d)[3]) \
        : "r"((a)[0]),"r"((a)[1]),"r"((a)[2]),"r"((a)[3]), "r"(b0),"r"(b1))

// ===================== split/transpose conversion kernels ====================
__global__ void split_kernel(const float* __restrict__ X,
                             __half* __restrict__ hi,
                             __half* __restrict__ lo, int n)
{
    int i = blockIdx.x*256 + threadIdx.x;
    if (i < n){
        float x = X[i];
        __half h = __float2half_rn(x);
        hi[i] = h;
        lo[i] = __float2half_rn(x - __half2float(h));
    }
}
// 4 weights transposed to fp16; Wq/Wk/Wv into combined [3072,1024], Wo separate.
__global__ void wsplit_all_kernel(const float* __restrict__ W0, const float* __restrict__ W1,
                                  const float* __restrict__ W2, const float* __restrict__ W3,
                                  __half* __restrict__ bigh, __half* __restrict__ woh)
{
    __shared__ float t[32][33];
    const float* W; __half* hiT;
    int z = blockIdx.z;
    if      (z==0){ W=W0; hiT=bigh; }
    else if (z==1){ W=W1; hiT=bigh+DD*DD; }
    else if (z==2){ W=W2; hiT=bigh+2*DD*DD; }
    else          { W=W3; hiT=woh; }
    int n0 = blockIdx.x*32, k0 = blockIdx.y*32;
    int tx = threadIdx.x, ty = threadIdx.y;   // 32 x 8
    for (int i = ty; i < 32; i += 8)
        t[i][tx] = W[(size_t)(k0+i)*DD + n0+tx];
    __syncthreads();
    for (int i = ty; i < 32; i += 8)
        hiT[(size_t)(n0+i)*DD + k0+tx] = __float2half_rn(t[tx][i]);
}

// ===================== mma.sync fp16 2-limb GEMM =============================
// C = A@B ; A as 2 fp16 limbs [M,K], B as single fp16 [N,K] (transposed).
#define GRS 40            // smem row stride in fp16 elements (80 bytes)
#define MATB (128*GRS*2)  // 10240 bytes per matrix tile
#define STGB (3*MATB)     // 30720 per stage (Ahi, Alo, B)
#define NSTG 3

__global__ void __launch_bounds__(256,2) gemm_f16s(
    const __half* __restrict__ Ahi, const __half* __restrict__ Alo,
    const __half* __restrict__ BT,
    float* C0, float* C1, float* C2, int K)
{
    extern __shared__ char smem[];
    const uint32_t sbase = smem_u32(smem);
    const int tid  = threadIdx.x;
    const int lane = tid & 31, wid = tid >> 5;
    const int wm = wid & 3, wn = wid >> 2;          // 4x2 warp grid
    const int row0 = blockIdx.y*128;
    const int bcol = blockIdx.x*128;                // into B (up to 3072 wide)
    const int seg  = blockIdx.x >> 3;
    const int col0 = (blockIdx.x & 7)*128;          // into C
    float* C = (seg==0) ? C0 : (seg==1 ? C1 : C2);

    const __half* g0 = Ahi + (size_t)row0*K;
    const __half* g1 = Alo + (size_t)row0*K;
    const __half* g2 = BT  + (size_t)bcol*K;

    float acc[2][8][4];
    #pragma unroll
    for (int i=0;i<2;i++)
        #pragma unroll
        for (int j=0;j<8;j++)
            #pragma unroll
            for (int u=0;u<4;u++) acc[i][j][u]=0.f;

    auto fill = [&](int kb){
        uint32_t sb = sbase + (kb%NSTG)*STGB;
        #pragma unroll
        for (int t=0;t<2;t++){
            int ci = tid + t*256;
            int r = ci >> 2, c = ci & 3;
            uint32_t dst = sb + r*(GRS*2) + c*16;
            size_t go = (size_t)r*K + (size_t)kb*32 + c*8;
            cp_async16(dst + 0*MATB, g0 + go);
            cp_async16(dst + 1*MATB, g1 + go);
            cp_async16(dst + 2*MATB, g2 + go);
        }
        cp_commit();
    };

    const int nkb = K/32;
    fill(0);
    fill(1);

    const int a_r  = lane & 15;
    const int a_ko = ((lane >> 4) & 1) << 3;
    const int b_n  = (lane & 7) + (((lane >> 4) & 1) << 3);
    const int b_ko = ((lane >> 3) & 1) << 3;

    for (int kb = 0; kb < nkb; kb++){
        if (kb+1 < nkb) asm volatile("cp.async.wait_group 1;" ::: "memory");
        else            asm volatile("cp.async.wait_group 0;" ::: "memory");
        __syncthreads();

        uint32_t sb = sbase + (kb%NSTG)*STGB;
        #pragma unroll
        for (int ks=0; ks<2; ks++){
            const int k16 = ks*16;
            uint32_t ah[2][4], al[2][4];
            #pragma unroll
            for (int mt=0; mt<2; mt++){
                uint32_t ad = sb + (wm*32 + mt*16 + a_r)*(GRS*2) + (k16 + a_ko)*2;
                LDSM_X4(ah[mt][0],ah[mt][1],ah[mt][2],ah[mt][3], ad + 0*MATB);
                LDSM_X4(al[mt][0],al[mt][1],al[mt][2],al[mt][3], ad + 1*MATB);
            }
            #pragma unroll
            for (int n4=0; n4<4; n4++){
                uint32_t bd = sb + 2*MATB + (wn*64 + n4*16 + b_n)*(GRS*2) + (k16 + b_ko)*2;
                uint32_t bh[4];
                LDSM_X4(bh[0],bh[1],bh[2],bh[3], bd);
                #pragma unroll
                for (int mt=0; mt<2; mt++){
                    MMAF16(acc[mt][n4*2  ], ah[mt], bh[0], bh[1]);
                    MMAF16(acc[mt][n4*2+1], ah[mt], bh[2], bh[3]);
                    MMAF16(acc[mt][n4*2  ], al[mt], bh[0], bh[1]);
                    MMAF16(acc[mt][n4*2+1], al[mt], bh[2], bh[3]);
                }
            }
        }
        if (kb+2 < nkb) fill(kb+2);
    }

    float* Cg = C + (size_t)(row0 + wm*32)*DD + col0 + wn*64;
    const int cr = lane >> 2, cc = (lane & 3) << 1;
    #pragma unroll
    for (int mt=0; mt<2; mt++)
        #pragma unroll
        for (int nt=0; nt<8; nt++){
            float2 v0; v0.x = acc[mt][nt][0]; v0.y = acc[mt][nt][1];
            *(float2*)&Cg[(size_t)(mt*16+cr)*DD + nt*8+cc] = v0;
            float2 v1; v1.x = acc[mt][nt][2]; v1.y = acc[mt][nt][3];
            *(float2*)&Cg[(size_t)(mt*16+cr+8)*DD + nt*8+cc] = v1;
        }
}

// ---------------- small projections: warp per row ----------------------------
__global__ void __launch_bounds__(256) smallproj_kernel(const float* __restrict__ Xh,
                                 const float* __restrict__ Wb,
                                 const float* __restrict__ Wdec,
                                 const float* __restrict__ Wmix)
{
    int wid = threadIdx.x >> 5, lane = threadIdx.x & 31;
    int row = blockIdx.x*8 + wid;
    const float* xr = Xh + (size_t)row*DD;
    float a[12];
    #pragma unroll
    for (int j=0;j<12;j++) a[j]=0.f;
    for (int c=lane; c<DD; c+=32){
        float hv = xr[c];
        float4 wb = *(const float4*)&Wb[c*4];
        float4 wd = *(const float4*)&Wdec[c*4];
        float4 wm = *(const float4*)&Wmix[c*4];
        a[0]+=hv*wb.x; a[1]+=hv*wb.y; a[2]+=hv*wb.z; a[3]+=hv*wb.w;
        a[4]+=hv*wd.x; a[5]+=hv*wd.y; a[6]+=hv*wd.z; a[7]+=hv*wd.w;
        a[8]+=hv*wm.x; a[9]+=hv*wm.y; a[10]+=hv*wm.z; a[11]+=hv*wm.w;
    }
    #pragma unroll
    for (int off=16; off; off>>=1){
        #pragma unroll
        for (int j=0;j<12;j++) a[j] += __shfl_down_sync(0xffffffffu, a[j], off);
    }
    if (lane == 0){
        #pragma unroll
        for (int j=0;j<4;j++){
            g_beta  [row*4+j] = sigm_f(a[j]);
            g_gamma [row*4+j] = sigm_f(a[4+j]);
            g_mixlin[row*4+j] = a[8+j];
        }
    }
}

// ---------------- causal short conv (K=4) + silu (optionally twice) ----------
__global__ void conv_silu_kernel(const float* __restrict__ X,
                                 const float* __restrict__ Wc,
                                 float* __restrict__ Y, int dbl)
{
    int idx = blockIdx.x*blockDim.x + threadIdx.x;
    if (idx >= NT*DD) return;
    int ch = idx & (DD-1);
    int bt = idx >> 10;
    int t  = bt & (LL-1);
    float acc = 0.f;
    #pragma unroll
    for (int k=0;k<4;k++){
        int ts = t-3+k;
        if (ts>=0) acc += X[(size_t)idx + (size_t)(ts-t)*DD] * Wc[ch*4+k];
    }
    float y = silu_f(acc);
    if (dbl) y = silu_f(y);
    Y[idx] = y;
}

// ---------------- mix path: conv over H channels + silu + sigmoid(+bias) -----
__global__ void mixconv_kernel(const float* __restrict__ convmix,
                               const float* __restrict__ mixbias)
{
    int idx = blockIdx.x*blockDim.x + threadIdx.x;
    if (idx >= NT*HH) return;
    int h = idx & 3;
    int bt = idx >> 2;
    int t = bt & (LL-1);
    float acc = 0.f;
    #pragma unroll
    for (int k=0;k<4;k++){
        int ts = t-3+k;
        if (ts>=0) acc += g_mixlin[idx + (ts-t)*HH] * convmix[h*4+k];
    }
    float mi = silu_f(acc);
    g_mixg[idx] = sigm_f(mi + mixbias[h]);
}

// ---------------- l2 norm: warp per (row,head) -------------------------------
__global__ void __launch_bounds__(256) l2norm_kernel()
{
    int wid = threadIdx.x >> 5, lane = threadIdx.x & 31;
    int g = blockIdx.x*8 + wid;
    int row = g >> 2, h = g & 3;
    size_t base = (size_t)row*DD + h*DK;

    {
        float4 v0 = *(float4*)&g_Q[base + lane*4];
        float4 v1 = *(float4*)&g_Q[base + 128 + lane*4];
        float s = v0.x*v0.x+v0.y*v0.y+v0.z*v0.z+v0.w*v0.w
                + v1.x*v1.x+v1.y*v1.y+v1.z*v1.z+v1.w*v1.w;
        #pragma unroll
        for (int off=16; off; off>>=1) s += __shfl_xor_sync(0xffffffffu, s, off);
        float sc = rsqrtf(s + 1e-6f);
        v0.x*=sc; v0.y*=sc; v0.z*=sc; v0.w*=sc;
        v1.x*=sc; v1.y*=sc; v1.z*=sc; v1.w*=sc;
        *(float4*)&g_Q[base + lane*4] = v0;
        *(float4*)&g_Q[base + 128 + lane*4] = v1;
    }
    {
        float4 v0 = *(float4*)&g_K[base + lane*4];
        float4 v1 = *(float4*)&g_K[base + 128 + lane*4];
        float s = v0.x*v0.x+v0.y*v0.y+v0.z*v0.z+v0.w*v0.w
                + v1.x*v1.x+v1.y*v1.y+v1.z*v1.z+v1.w*v1.w;
        #pragma unroll
        for (int off=16; off; off>>=1) s += __shfl_xor_sync(0xffffffffu, s, off);
        float sc = rsqrtf(s + 1e-6f);
        v0.x*=sc; v0.y*=sc; v0.z*=sc; v0.w*=sc;
        v1.x*=sc; v1.y*=sc; v1.z*=sc; v1.w*=sc;
        *(float4*)&g_K[base + lane*4] = v0;
        *(float4*)&g_K[base + 128 + lane*4] = v1;
    }
}

// ---------------- per-chunk: T (tri inverse), W = T@k_beta, Attn = tril(q k^T)
#define WP 260   // float stride for 32x256 tiles
#define SP 36    // float stride for 32x32 / 256x32 tiles

__global__ void __launch_bounds__(256) chunk_kernel()
{
    extern __shared__ float sm[];
    float* kc     = sm;                 // 32*WP
    float* qc     = kc + 32*WP;         // 32*WP
    float* Amat   = qc + 32*WP;         // 32*33
    float* bet    = Amat + 32*33;       // 32
    float* rowtmp = bet + 32;           // 32

    int blk = blockIdx.x;               // bh*64 + c
    int bh = blk >> 6, c = blk & 63;
    int b = bh >> 2, h = bh & 3;
    int tid = threadIdx.x;
    int rowbase = b*LL + c*CHK;

    for (int e = tid; e < 2048; e += 256){
        int r = e >> 6; int c4 = (e & 63) << 2;
        *(float4*)&kc[r*WP+c4] = *(const float4*)&g_K[(size_t)(rowbase+r)*DD + h*DK + c4];
        *(float4*)&qc[r*WP+c4] = *(const float4*)&g_Q[(size_t)(rowbase+r)*DD + h*DK + c4];
    }
    if (tid < 32) bet[tid] = g_beta[(rowbase+tid)*HH + h];
    __syncthreads();

    // A = -tril(k_beta @ k^T, -1),  Attn = tril(q @ k^T, 0)   [f32x2, pair over m]
    {
        int i = tid >> 3, j0 = tid & 7;
        u64t da[4], dq[4];
        #pragma unroll
        for (int u=0;u<4;u++){ da[u]=0ull; dq[u]=0ull; }
        #pragma unroll 4
        for (int m=0;m<256;m+=4){
            ulonglong2 ki = *(ulonglong2*)&kc[i*WP+m];
            ulonglong2 qi = *(ulonglong2*)&qc[i*WP+m];
            #pragma unroll
            for (int u=0;u<4;u++){
                ulonglong2 kj = *(ulonglong2*)&kc[(j0+8*u)*WP+m];
                da[u] = ffma2(ki.x, kj.x, da[u]);
                da[u] = ffma2(ki.y, kj.y, da[u]);
                dq[u] = ffma2(qi.x, kj.x, dq[u]);
                dq[u] = ffma2(qi.y, kj.y, dq[u]);
            }
        }
        #pragma unroll
        for (int u=0;u<4;u++){
            int j = j0 + 8*u;
            float2 ta = f2unpack(da[u]);
            float2 tq = f2unpack(dq[u]);
            float av = ta.x + ta.y, qv = tq.x + tq.y;
            Amat[i*33+j] = (j < i) ? -bet[i]*av : 0.f;
            g_At[(size_t)blk*1024 + i*32 + j] = (j <= i) ? qv : 0.f;
        }
    }
    __syncthreads();

    // sequential forward-substitution (warp 0)
    if (tid < 32){
        int cx = tid;
        for (int ii=1; ii<32; ii++){
            rowtmp[cx] = Amat[ii*33+cx];
            __syncwarp();
            float acc = 0.f;
            if (cx < ii){
                acc = rowtmp[cx];
                for (int j=cx+1; j<ii; j++) acc += rowtmp[j]*Amat[j*33+cx];
            }
            __syncwarp();
            if (cx < ii) Amat[ii*33+cx] = acc;
            __syncwarp();
        }
        Amat[cx*33+cx] = 1.0f;   // T = A + I
    }
    __syncthreads();

    for (int e=tid; e<1024; e+=256)
        g_T[(size_t)blk*1024 + e] = Amat[(e>>5)*33 + (e&31)];

    // W = T @ (beta * k)   [f32x2, pair over dk]
    {
        int i = tid >> 3, mb = (tid & 7) << 2;
        u64t acc[16];
        #pragma unroll
        for (int s=0;s<16;s++) acc[s]=0ull;
        for (int j=0;j<32;j++){
            u64t td = f2dup(Amat[i*33+j]*bet[j]);
            #pragma unroll
            for (int s=0;s<8;s++){
                ulonglong2 kv = *(ulonglong2*)&kc[j*WP + s*32 + mb];
                acc[2*s]   = ffma2(td, kv.x, acc[2*s]);
                acc[2*s+1] = ffma2(td, kv.y, acc[2*s+1]);
            }
        }
        #pragma unroll
        for (int s=0;s<8;s++){
            ulonglong2 ov; ov.x = acc[2*s]; ov.y = acc[2*s+1];
            *(ulonglong2*)&g_W[((size_t)blk*32 + i)*DK + s*32 + mb] = ov;
        }
    }
}

// ---------------- sequential inter-chunk scan, state S in SMEM, f32x2 --------
__global__ void __launch_bounds__(256,1) scan_kernel()
{
    extern __shared__ float sm[];
    float* S    = sm;                 // 256*SP
    float* w    = S   + 256*SP;       // 32*WP  (stored NEGATED)
    float* q    = w   + 32*WP;        // 32*WP
    float* kc   = q   + 32*WP;        // 32*WP
    float* att  = kc  + 32*WP;        // 32*SP
    float* Tt   = att + 32*SP;        // 32*SP
    float* vb   = Tt  + 32*SP;        // 32*SP
    float* ua   = vb  + 32*SP;        // 32*SP

    int tid = threadIdx.x;
    int bh   = blockIdx.x >> 3;
    int slab = blockIdx.x & 7;
    int b = bh >> 2, h = bh & 3;

    for (int e=tid; e<256*SP; e+=256) S[e]=0.f;
    __syncthreads();

    const int i  = tid >> 3;          // 0..31
    const int jb = (tid & 7) << 2;    // 0,4,...,28
    const size_t ocol = (size_t)h*DK + slab*32;

    for (int c=0; c<NCHUNK; c++){
        int blk = bh*NCHUNK + c;
        int rowbase = b*LL + c*CHK;
        // ---- load tiles (w negated at load)
        for (int e=tid; e<2048; e+=256){
            int r = e >> 6; int c4 = (e & 63) << 2;
            float4 wv = *(const float4*)&g_W[((size_t)blk*32 + r)*DK + c4];
            wv.x=-wv.x; wv.y=-wv.y; wv.z=-wv.z; wv.w=-wv.w;
            *(float4*)&w [r*WP+c4] = wv;
            *(float4*)&q [r*WP+c4] = *(const float4*)&g_Q[(size_t)(rowbase+r)*DD + h*DK + c4];
            *(float4*)&kc[r*WP+c4] = *(const float4*)&g_K[(size_t)(rowbase+r)*DD + h*DK + c4];
        }
        {
            int r = tid >> 3, c4 = (tid & 7) << 2;
            *(float4*)&att[r*SP+c4] = *(const float4*)&g_At[(size_t)blk*1024 + r*32 + c4];
            *(float4*)&Tt [r*SP+c4] = *(const float4*)&g_T [(size_t)blk*1024 + r*32 + c4];
            float be = g_beta[(rowbase+r)*HH + h];
            float4 vv = *(const float4*)&g_V[(size_t)(rowbase+r)*DD + ocol + c4];
            vv.x*=be; vv.y*=be; vv.z*=be; vv.w*=be;
            *(float4*)&vb[r*SP+c4] = vv;
        }
        __syncthreads();

        // ---- u_i = T @ vb  (pairs over j)
        u64t ui0=0ull, ui1=0ull;
        #pragma unroll
        for (int m=0;m<32;m++){
            u64t td = f2dup(Tt[i*SP+m]);
            ulonglong2 vv = *(ulonglong2*)&vb[m*SP+jb];
            ui0 = ffma2(td, vv.x, ui0);
            ui1 = ffma2(td, vv.y, ui1);
        }
        // ---- (-w)@S and q@S in one pass over k
        u64t nU0=0ull,nU1=0ull, aO0=0ull,aO1=0ull;
        #pragma unroll 4
        for (int k=0;k<256;k+=4){
            float4 wv = *(float4*)&w[i*WP+k];
            float4 qv = *(float4*)&q[i*WP+k];
            ulonglong2 s0 = *(ulonglong2*)&S[(k  )*SP+jb];
            ulonglong2 s1 = *(ulonglong2*)&S[(k+1)*SP+jb];
            ulonglong2 s2 = *(ulonglong2*)&S[(k+2)*SP+jb];
            ulonglong2 s3 = *(ulonglong2*)&S[(k+3)*SP+jb];
            u64t d;
            d=f2dup(wv.x); nU0=ffma2(d,s0.x,nU0); nU1=ffma2(d,s0.y,nU1);
            d=f2dup(qv.x); aO0=ffma2(d,s0.x,aO0); aO1=ffma2(d,s0.y,aO1);
            d=f2dup(wv.y); nU0=ffma2(d,s1.x,nU0); nU1=ffma2(d,s1.y,nU1);
            d=f2dup(qv.y); aO0=ffma2(d,s1.x,aO0); aO1=ffma2(d,s1.y,aO1);
            d=f2dup(wv.z); nU0=ffma2(d,s2.x,nU0); nU1=ffma2(d,s2.y,nU1);
            d=f2dup(qv.z); aO0=ffma2(d,s2.x,aO0); aO1=ffma2(d,s2.y,aO1);
            d=f2dup(wv.w); nU0=ffma2(d,s3.x,nU0); nU1=ffma2(d,s3.y,nU1);
            d=f2dup(qv.w); aO0=ffma2(d,s3.x,aO0); aO1=ffma2(d,s3.y,aO1);
        }
        // u_adj = u_i + (-w@S)
        ulonglong2 uav; uav.x = fadd2(ui0, nU0); uav.y = fadd2(ui1, nU1);
        *(ulonglong2*)&ua[i*SP+jb] = uav;
        __syncthreads();

        // ---- o = q@S + attn @ u_adj  -> global
        #pragma unroll
        for (int m=0;m<32;m++){
            u64t ad = f2dup(att[i*SP+m]);
            ulonglong2 uv = *(ulonglong2*)&ua[m*SP+jb];
            aO0 = ffma2(ad, uv.x, aO0);
            aO1 = ffma2(ad, uv.y, aO1);
        }
        ulonglong2 ov; ov.x = aO0; ov.y = aO1;
        *(ulonglong2*)&g_Od[(size_t)(rowbase+i)*DD + ocol + jb] = ov;

        // ---- S += k^T @ u_adj  (thread owns dk-row tid; 16 packed accumulators)
        u64t acc[16];
        #pragma unroll
        for (int x=0;x<16;x++) acc[x]=0ull;
        #pragma unroll 4
        for (int m=0;m<32;m++){
            u64t kd = f2dup(kc[m*WP + tid]);
            #pragma unroll
            for (int x=0;x<8;x++){
                ulonglong2 uv = *(ulonglong2*)&ua[m*SP + x*4];
                acc[2*x]   = ffma2(kd, uv.x, acc[2*x]);
                acc[2*x+1] = ffma2(kd, uv.y, acc[2*x+1]);
            }
        }
        #pragma unroll
        for (int x=0;x<8;x++){
            ulonglong2 sv = *(ulonglong2*)&S[tid*SP + x*4];
            sv.x = fadd2(sv.x, acc[2*x]);
            sv.y = fadd2(sv.y, acc[2*x+1]);
            *(ulonglong2*)&S[tid*SP + x*4] = sv;
        }
        __syncthreads();
    }
}

// ---------------- EMA phase 1: segmented local scan --------------------------
__global__ void __launch_bounds__(256) ema_local_kernel()
{
    extern __shared__ float esm[];
    float* cbuf = esm;             // ESEG*256
    float* gbuf = cbuf + ESEG*256; // ESEG
    float* Ps   = gbuf + ESEG;     // ESEG

    int bh = blockIdx.x, seg = blockIdx.y;
    int b = bh >> 2, h = bh & 3;
    int tid = threadIdx.x;
    int rowbase = b*LL + seg*ESEG;
    size_t hcol = (size_t)h*DK;

    if (tid < ESEG) gbuf[tid] = g_gamma[(rowbase+tid)*HH + h];
    __syncthreads();

    for (int e = tid; e < ESEG*64; e += 256){
        int r = e >> 6, c4 = (e & 63) << 2;
        float om = 1.f - gbuf[r];
        float4 vv = *(const float4*)&g_V[(size_t)(rowbase+r)*DD + hcol + c4];
        vv.x*=om; vv.y*=om; vv.z*=om; vv.w*=om;
        *(float4*)&cbuf[r*256 + c4] = vv;
    }
    if (tid < ESEG){
        int lane = tid & 31;
        float p = gbuf[tid];
        #pragma unroll
        for (int off=1; off<32; off<<=1){
            float o = __shfl_up_sync(0xffffffffu, p, off);
            if (lane >= off) p *= o;
        }
        Ps[tid] = p;
    }
    __syncthreads();
    if (tid < ESEG){
        int wmy = tid >> 5;
        float pre = 1.f;
        for (int wq = 0; wq < wmy; wq++) pre *= Ps[wq*32+31];
        g_P[bh*LL + seg*ESEG + tid] = pre * Ps[tid];
    }

    float s = 0.f;
    #pragma unroll 8
    for (int t = 0; t < ESEG; t++){
        s = fmaf(gbuf[t], s, cbuf[t*256 + tid]);
        cbuf[t*256 + tid] = s;
    }
    __syncthreads();

    for (int e = tid; e < ESEG*64; e += 256){
        int r = e >> 6, c4 = (e & 63) << 2;
        *(float4*)&g_Oe[(size_t)(rowbase+r)*DD + hcol + c4] = *(float4*)&cbuf[r*256 + c4];
    }
}

// ---------------- EMA phase 2: carry across segments -------------------------
__global__ void __launch_bounds__(256) ema_carry_kernel()
{
    int bh = blockIdx.x;
    int b = bh >> 2, h = bh & 3;
    int dv = threadIdx.x;
    float s = 0.f;
    #pragma unroll
    for (int seg = 0; seg < NSEG; seg++){
        g_C[(bh*NSEG + seg)*DK + dv] = s;
        int rend = b*LL + seg*ESEG + (ESEG-1);
        float P  = g_P[bh*LL + seg*ESEG + (ESEG-1)];
        float ye = g_Oe[(size_t)rend*DD + h*DK + dv];
        s = fmaf(P, s, ye);
    }
}

// ---------------- mix combine + RMS norm + fp16 split (fused, + ema carry) ---
__global__ void __launch_bounds__(256) combine_rms_kernel(const float* __restrict__ rmsw)
{
    int wid = threadIdx.x >> 5, lane = threadIdx.x & 31;
    int g = blockIdx.x*8 + wid;
    int row = g >> 2, h = g & 3;
    int b = row >> 11, t = row & (LL-1);
    int bh = b*4 + h, seg = t >> 7;
    float m = g_mixg[row*4+h];
    size_t base = (size_t)row*DD + h*DK;

    float P = g_P[bh*LL + t];
    const float* cav = &g_C[(bh*NSEG + seg)*DK];
    float4 c0 = *(const float4*)&cav[lane*4];
    float4 c1 = *(const float4*)&cav[128 + lane*4];

    float4 d0 = *(float4*)&g_Od[base + lane*4];
    float4 d1 = *(float4*)&g_Od[base + 128 + lane*4];
    float4 e0 = *(float4*)&g_Oe[base + lane*4];
    float4 e1 = *(float4*)&g_Oe[base + 128 + lane*4];
    e0.x += P*c0.x; e0.y += P*c0.y; e0.z += P*c0.z; e0.w += P*c0.w;
    e1.x += P*c1.x; e1.y += P*c1.y; e1.z += P*c1.z; e1.w += P*c1.w;

    float4 o0, o1;
    float om = 1.f - m;
    o0.x = om*d0.x + m*e0.x; o0.y = om*d0.y + m*e0.y;
    o0.z = om*d0.z + m*e0.z; o0.w = om*d0.w + m*e0.w;
    o1.x = om*d1.x + m*e1.x; o1.y = om*d1.y + m*e1.y;
    o1.z = om*d1.z + m*e1.z; o1.w = om*d1.w + m*e1.w;
    float s = o0.x*o0.x+o0.y*o0.y+o0.z*o0.z+o0.w*o0.w
            + o1.x*o1.x+o1.y*o1.y+o1.z*o1.z+o1.w*o1.w;
    #pragma unroll
    for (int off=16; off; off>>=1) s += __shfl_xor_sync(0xffffffffu, s, off);
    float sc = rsqrtf(s*(1.f/256.f) + 1e-5f);
    float4 r0 = *(const float4*)&rmsw[lane*4];
    float4 r1 = *(const float4*)&rmsw[128 + lane*4];
    o0.x *= sc*r0.x; o0.y *= sc*r0.y; o0.z *= sc*r0.z; o0.w *= sc*r0.w;
    o1.x *= sc*r1.x; o1.y *= sc*r1.y; o1.z *= sc*r1.z; o1.w *= sc*r1.w;

    __half h4[4], l4[4];
    float v[4];
    v[0]=o0.x; v[1]=o0.y; v[2]=o0.z; v[3]=o0.w;
    #pragma unroll
    for (int u=0;u<4;u++){
        h4[u]=__float2half_rn(v[u]);
        l4[u]=__float2half_rn(v[u]-__half2float(h4[u]));
    }
    *(u64t*)&g_Op_hi[base + lane*4] = *(u64t*)h4;
    *(u64t*)&g_Op_lo[base + lane*4] = *(u64t*)l4;
    v[0]=o1.x; v[1]=o1.y; v[2]=o1.z; v[3]=o1.w;
    #pragma unroll
    for (int u=0;u<4;u++){
        h4[u]=__float2half_rn(v[u]);
        l4[u]=__float2half_rn(v[u]-__half2float(h4[u]));
    }
    *(u64t*)&g_Op_hi[base + 128 + lane*4] = *(u64t*)h4;
    *(u64t*)&g_Op_lo[base + 128 + lane*4] = *(u64t*)l4;
}

// ---------------- host driver -----------------------------------------------
extern "C" void kernel_launch(void* const* d_in, const int* in_sizes, int n_in,
                              void* d_out, int out_size)
{
    const float* hs      = (const float*)d_in[0];
    const float* Wq      = (const float*)d_in[1];
    const float* Wk      = (const float*)d_in[2];
    const float* Wv      = (const float*)d_in[3];
    const float* convq   = (const float*)d_in[4];
    const float* convk   = (const float*)d_in[5];
    const float* convv   = (const float*)d_in[6];
    const float* Wb      = (const float*)d_in[7];
    const float* Wdec    = (const float*)d_in[8];
    const float* Wmix    = (const float*)d_in[9];
    const float* convmix = (const float*)d_in[10];
    const float* mixbias = (const float*)d_in[11];
    const float* rmsw    = (const float*)d_in[12];
    const float* Wo      = (const float*)d_in[13];

    void *pQL,*pKL,*pVL,*pQ,*pK,*pV;
    cudaGetSymbolAddress(&pQL, g_QL);
    cudaGetSymbolAddress(&pKL, g_KL);
    cudaGetSymbolAddress(&pVL, g_VL);
    cudaGetSymbolAddress(&pQ,  g_Q);
    cudaGetSymbolAddress(&pK,  g_K);
    cudaGetSymbolAddress(&pV,  g_V);

    void *p_hs_hi,*p_hs_lo,*p_Op_hi,*p_Op_lo,*p_WT_h,*p_WoT_h;
    cudaGetSymbolAddress(&p_hs_hi, g_hs_hi);  cudaGetSymbolAddress(&p_hs_lo, g_hs_lo);
    cudaGetSymbolAddress(&p_Op_hi, g_Op_hi);  cudaGetSymbolAddress(&p_Op_lo, g_Op_lo);
    cudaGetSymbolAddress(&p_WT_h, g_WT_h);    cudaGetSymbolAddress(&p_WoT_h, g_WoT_h);

    int smem_chunk = (2*32*WP + 32*33 + 64) * 4;
    int smem_scan  = (256*SP + 3*32*WP + 4*32*SP) * 4;
    int smem_gemm  = NSTG*STGB;                 // 92160
    int smem_ema   = (ESEG*256 + 2*ESEG) * 4;
    cudaFuncSetAttribute(chunk_kernel, cudaFuncAttributeMaxDynamicSharedMemorySize, smem_chunk);
    cudaFuncSetAttribute(scan_kernel,  cudaFuncAttributeMaxDynamicSharedMemorySize, smem_scan);
    cudaFuncSetAttribute(gemm_f16s,    cudaFuncAttributeMaxDynamicSharedMemorySize, smem_gemm);
    cudaFuncSetAttribute(ema_local_kernel, cudaFuncAttributeMaxDynamicSharedMemorySize, smem_ema);

    // 1: split activations to fp16 limbs
    split_kernel<<<NT*DD/256,256>>>(hs, (__half*)p_hs_hi, (__half*)p_hs_lo, NT*DD);
    // 2: weight transposes to fp16
    dim3 wg(32,32,4), wb(32,8);
    wsplit_all_kernel<<<wg,wb>>>(Wq, Wk, Wv, Wo, (__half*)p_WT_h, (__half*)p_WoT_h);
    // 3: small projections
    smallproj_kernel<<<NT/8,256>>>(hs, Wb, Wdec, Wmix);

    // 4: merged QKV GEMM (1536 CTAs)
    gemm_f16s<<<dim3(24,64),256,smem_gemm>>>(
        (__half*)p_hs_hi,(__half*)p_hs_lo,(__half*)p_WT_h,
        (float*)pQL, (float*)pKL, (float*)pVL, DD);

    int nconv = NT*DD/256;
    conv_silu_kernel<<<nconv,256>>>((const float*)pQL, convq, (float*)pQ, 1);
    conv_silu_kernel<<<nconv,256>>>((const float*)pKL, convk, (float*)pK, 1);
    conv_silu_kernel<<<nconv,256>>>((const float*)pVL, convv, (float*)pV, 0);
    mixconv_kernel<<<(NT*HH+127)/128,128>>>(convmix, mixbias);

    l2norm_kernel<<<NT*HH/8,256>>>();
    chunk_kernel<<<NBH*NCHUNK,256,smem_chunk>>>();
    scan_kernel<<<NBH*8,256,smem_scan>>>();

    ema_local_kernel<<<dim3(NBH,NSEG),256,smem_ema>>>();
    ema_carry_kernel<<<NBH,DK>>>();

    combine_rms_kernel<<<NT*HH/8,256>>>(rmsw);

    gemm_f16s<<<dim3(8,64),256,smem_gemm>>>(
        (__half*)p_Op_hi,(__half*)p_Op_lo,(__half*)p_WoT_h,
        (float*)d_out, (float*)d_out, (float*)d_out, DD);
}

// round 10
// speedup vs baseline: 3.0981x; 1.0411x over previous
#include <cuda_runtime.h>
#include <cuda_bf16.h>
#include <cuda_fp16.h>
#include <math.h>
#include <stdint.h>

// Problem constants
#define BB 4
#define LL 2048
#define DD 1024
#define HH 4
#define DK 256
#define NT (BB*LL)       // 8192 tokens
#define NCHUNK 64        // chunks per sequence
#define CHK 32           // chunk length
#define NBH 16           // B*H
#define ESEG 128         // ema segment length
#define NSEG (LL/ESEG)   // 16

typedef unsigned long long u64t;

// ---------------- scratch (device globals; no allocation allowed) -------------
__device__ float g_QL[NT*DD];
__device__ float g_KL[NT*DD];
__device__ float g_VL[NT*DD];
__device__ float g_Q[NT*DD];
__device__ float g_K[NT*DD];
__device__ float g_V[NT*DD];
__device__ float g_beta[NT*HH];
__device__ float g_gamma[NT*HH];
__device__ float g_mixlin[NT*HH];
__device__ float g_mixg[NT*HH];
__device__ float g_W[NBH*NCHUNK*CHK*DK];     // w = T @ k_beta
__device__ float g_T[NBH*NCHUNK*CHK*CHK];    // triangular inverse T
__device__ float g_At[NBH*NCHUNK*CHK*CHK];   // attn_i = tril(q@k^T)
__device__ float g_Od[NT*DD];                // delta-rule output
__device__ float g_Oe[NT*DD];                // ema LOCAL output (y_t)
__device__ float g_P[NBH*LL];                // in-segment prefix products of gamma
__device__ float g_C[NBH*NSEG*DK];           // carry state at segment start

// fp16 limb buffers for tensor-core GEMMs (A: 2 limbs; B: single fp16)
__device__ __half g_hs_hi[NT*DD], g_hs_lo[NT*DD];
__device__ __half g_Op_hi[NT*DD], g_Op_lo[NT*DD];
__device__ __half g_WT_h[3*DD*DD];           // Wq|Wk|Wv transposed, fp16
__device__ __half g_WoT_h[DD*DD];            // Wo transposed, fp16

__device__ __forceinline__ float silu_f(float x){ return x / (1.f + expf(-x)); }
__device__ __forceinline__ float sigm_f(float x){ return 1.f / (1.f + expf(-x)); }

// ===================== f32x2 packed-math helpers =============================
__device__ __forceinline__ u64t f2dup(float x){
    u64t r; unsigned int xi = __float_as_uint(x);
    asm("mov.b64 %0, {%1,%1};" : "=l"(r) : "r"(xi));
    return r;
}
__device__ __forceinline__ u64t f2pack(float x, float y){
    u64t r;
    asm("mov.b64 %0, {%1,%2};" : "=l"(r) : "r"(__float_as_uint(x)), "r"(__float_as_uint(y)));
    return r;
}
__device__ __forceinline__ u64t ffma2(u64t a, u64t b, u64t c){
    u64t d; asm("fma.rn.f32x2 %0, %1, %2, %3;" : "=l"(d) : "l"(a), "l"(b), "l"(c));
    return d;
}
__device__ __forceinline__ float2 f2unpack(u64t p){
    unsigned int lo, hi;
    asm("mov.b64 {%0,%1}, %2;" : "=r"(lo), "=r"(hi) : "l"(p));
    return make_float2(__uint_as_float(lo), __uint_as_float(hi));
}

// ===================== PTX helpers (mma.sync / ldmatrix / cp.async) ==========
__device__ __forceinline__ uint32_t smem_u32(const void* p){
    uint32_t a;
    asm("{ .reg .u64 t; cvta.to.shared.u64 t, %1; cvt.u32.u64 %0, t; }" : "=r"(a) : "l"(p));
    return a;
}
__device__ __forceinline__ void cp_async16(uint32_t dst, const void* src){
    asm volatile("cp.async.cg.shared.global [%0], [%1], 16;" :: "r"(dst), "l"(src) : "memory");
}
__device__ __forceinline__ void cp_commit(){ asm volatile("cp.async.commit_group;" ::: "memory"); }

#define LDSM_X4(r0,r1,r2,r3, addr) \
    asm volatile("ldmatrix.sync.aligned.m8n8.x4.shared.b16 {%0,%1,%2,%3}, [%4];" \
        : "=r"(r0),"=r"(r1),"=r"(r2),"=r"(r3) : "r"(addr))

#define LDSM_X4_T(r0,r1,r2,r3, addr) \
    asm volatile("ldmatrix.sync.aligned.m8n8.x4.trans.shared.b16 {%0,%1,%2,%3}, [%4];" \
        : "=r"(r0),"=r"(r1),"=r"(r2),"=r"(r3) : "r"(addr))

#define MMAF16(d, a, b0, b1) \
    asm volatile("mma.sync.aligned.m16n8k16.row.col.f32.f16.f16.f32 " \
        "{%0,%1,%2,%3}, {%4,%5,%6,%7}, {%8,%9}, {%0,%1,%2,%3};" \
        : "+f"((d)[0]),"+f"((d)[1]),"+f"((d)[2]),"+f"((d)[3]) \
        : "r"((a)[0]),"r"((a)[1]),"r"((a)[2]),"r"((a)[3]), "r"(b0),"r"(b1))

#define MMABF16(d, a, b0, b1) \
    asm volatile("mma.sync.aligned.m16n8k16.row.col.f32.bf16.bf16.f32 " \
        "{%0,%1,%2,%3}, {%4,%5,%6,%7}, {%8,%9}, {%0,%1,%2,%3};" \
        : "+f"((d)[0]),"+f"((d)[1]),"+f"((d)[2]),"+f"((d)[3]) \
        : "r"((a)[0]),"r"((a)[1]),"r"((a)[2]),"r"((a)[3]), "r"(b0),"r"(b1))

// bf16 hi/lo split-store of a float4 (4B-aligned destinations)
__device__ __forceinline__ void split_store4(float4 v, __nv_bfloat16* ph, __nv_bfloat16* pl){
    __nv_bfloat162 h01, h23, l01, l23;
    h01.x = __float2bfloat16(v.x); h01.y = __float2bfloat16(v.y);
    h23.x = __float2bfloat16(v.z); h23.y = __float2bfloat16(v.w);
    l01.x = __float2bfloat16(v.x - __bfloat162float(h01.x));
    l01.y = __float2bfloat16(v.y - __bfloat162float(h01.y));
    l23.x = __float2bfloat16(v.z - __bfloat162float(h23.x));
    l23.y = __float2bfloat16(v.w - __bfloat162float(h23.y));
    *(__nv_bfloat162*)(ph)   = h01; *(__nv_bfloat162*)(ph+2) = h23;
    *(__nv_bfloat162*)(pl)   = l01; *(__nv_bfloat162*)(pl+2) = l23;
}

// ===================== split/transpose conversion kernels ====================
__global__ void split_kernel(const float* __restrict__ X,
                             __half* __restrict__ hi,
                             __half* __restrict__ lo, int n)
{
    int i = blockIdx.x*256 + threadIdx.x;
    if (i < n){
        float x = X[i];
        __half h = __float2half_rn(x);
        hi[i] = h;
        lo[i] = __float2half_rn(x - __half2float(h));
    }
}
// 4 weights transposed to fp16; Wq/Wk/Wv into combined [3072,1024], Wo separate.
__global__ void wsplit_all_kernel(const float* __restrict__ W0, const float* __restrict__ W1,
                                  const float* __restrict__ W2, const float* __restrict__ W3,
                                  __half* __restrict__ bigh, __half* __restrict__ woh)
{
    __shared__ float t[32][33];
    const float* W; __half* hiT;
    int z = blockIdx.z;
    if      (z==0){ W=W0; hiT=bigh; }
    else if (z==1){ W=W1; hiT=bigh+DD*DD; }
    else if (z==2){ W=W2; hiT=bigh+2*DD*DD; }
    else          { W=W3; hiT=woh; }
    int n0 = blockIdx.x*32, k0 = blockIdx.y*32;
    int tx = threadIdx.x, ty = threadIdx.y;   // 32 x 8
    for (int i = ty; i < 32; i += 8)
        t[i][tx] = W[(size_t)(k0+i)*DD + n0+tx];
    __syncthreads();
    for (int i = ty; i < 32; i += 8)
        hiT[(size_t)(n0+i)*DD + k0+tx] = __float2half_rn(t[tx][i]);
}

// ===================== mma.sync fp16 2-limb GEMM =============================
#define GRS 40            // smem row stride in fp16 elements (80 bytes)
#define MATB (128*GRS*2)  // 10240 bytes per matrix tile
#define STGB (3*MATB)     // 30720 per stage (Ahi, Alo, B)
#define NSTG 3

__global__ void __launch_bounds__(256,2) gemm_f16s(
    const __half* __restrict__ Ahi, const __half* __restrict__ Alo,
    const __half* __restrict__ BT,
    float* C0, float* C1, float* C2, int K)
{
    extern __shared__ char smem[];
    const uint32_t sbase = smem_u32(smem);
    const int tid  = threadIdx.x;
    const int lane = tid & 31, wid = tid >> 5;
    const int wm = wid & 3, wn = wid >> 2;          // 4x2 warp grid
    const int row0 = blockIdx.y*128;
    const int bcol = blockIdx.x*128;                // into B (up to 3072 wide)
    const int seg  = blockIdx.x >> 3;
    const int col0 = (blockIdx.x & 7)*128;          // into C
    float* C = (seg==0) ? C0 : (seg==1 ? C1 : C2);

    const __half* g0 = Ahi + (size_t)row0*K;
    const __half* g1 = Alo + (size_t)row0*K;
    const __half* g2 = BT  + (size_t)bcol*K;

    float acc[2][8][4];
    #pragma unroll
    for (int i=0;i<2;i++)
        #pragma unroll
        for (int j=0;j<8;j++)
            #pragma unroll
            for (int u=0;u<4;u++) acc[i][j][u]=0.f;

    auto fill = [&](int kb){
        uint32_t sb = sbase + (kb%NSTG)*STGB;
        #pragma unroll
        for (int t=0;t<2;t++){
            int ci = tid + t*256;
            int r = ci >> 2, c = ci & 3;
            uint32_t dst = sb + r*(GRS*2) + c*16;
            size_t go = (size_t)r*K + (size_t)kb*32 + c*8;
            cp_async16(dst + 0*MATB, g0 + go);
            cp_async16(dst + 1*MATB, g1 + go);
            cp_async16(dst + 2*MATB, g2 + go);
        }
        cp_commit();
    };

    const int nkb = K/32;
    fill(0);
    fill(1);

    const int a_r  = lane & 15;
    const int a_ko = ((lane >> 4) & 1) << 3;
    const int b_n  = (lane & 7) + (((lane >> 4) & 1) << 3);
    const int b_ko = ((lane >> 3) & 1) << 3;

    for (int kb = 0; kb < nkb; kb++){
        if (kb+1 < nkb) asm volatile("cp.async.wait_group 1;" ::: "memory");
        else            asm volatile("cp.async.wait_group 0;" ::: "memory");
        __syncthreads();

        uint32_t sb = sbase + (kb%NSTG)*STGB;
        #pragma unroll
        for (int ks=0; ks<2; ks++){
            const int k16 = ks*16;
            uint32_t ah[2][4], al[2][4];
            #pragma unroll
            for (int mt=0; mt<2; mt++){
                uint32_t ad = sb + (wm*32 + mt*16 + a_r)*(GRS*2) + (k16 + a_ko)*2;
                LDSM_X4(ah[mt][0],ah[mt][1],ah[mt][2],ah[mt][3], ad + 0*MATB);
                LDSM_X4(al[mt][0],al[mt][1],al[mt][2],al[mt][3], ad + 1*MATB);
            }
            #pragma unroll
            for (int n4=0; n4<4; n4++){
                uint32_t bd = sb + 2*MATB + (wn*64 + n4*16 + b_n)*(GRS*2) + (k16 + b_ko)*2;
                uint32_t bh[4];
                LDSM_X4(bh[0],bh[1],bh[2],bh[3], bd);
                #pragma unroll
                for (int mt=0; mt<2; mt++){
                    MMAF16(acc[mt][n4*2  ], ah[mt], bh[0], bh[1]);
                    MMAF16(acc[mt][n4*2+1], ah[mt], bh[2], bh[3]);
                    MMAF16(acc[mt][n4*2  ], al[mt], bh[0], bh[1]);
                    MMAF16(acc[mt][n4*2+1], al[mt], bh[2], bh[3]);
                }
            }
        }
        if (kb+2 < nkb) fill(kb+2);
    }

    float* Cg = C + (size_t)(row0 + wm*32)*DD + col0 + wn*64;
    const int cr = lane >> 2, cc = (lane & 3) << 1;
    #pragma unroll
    for (int mt=0; mt<2; mt++)
        #pragma unroll
        for (int nt=0; nt<8; nt++){
            float2 v0; v0.x = acc[mt][nt][0]; v0.y = acc[mt][nt][1];
            *(float2*)&Cg[(size_t)(mt*16+cr)*DD + nt*8+cc] = v0;
            float2 v1; v1.x = acc[mt][nt][2]; v1.y = acc[mt][nt][3];
            *(float2*)&Cg[(size_t)(mt*16+cr+8)*DD + nt*8+cc] = v1;
        }
}

// ---------------- small projections: warp per row ----------------------------
__global__ void __launch_bounds__(256) smallproj_kernel(const float* __restrict__ Xh,
                                 const float* __restrict__ Wb,
                                 const float* __restrict__ Wdec,
                                 const float* __restrict__ Wmix)
{
    int wid = threadIdx.x >> 5, lane = threadIdx.x & 31;
    int row = blockIdx.x*8 + wid;
    const float* xr = Xh + (size_t)row*DD;
    float a[12];
    #pragma unroll
    for (int j=0;j<12;j++) a[j]=0.f;
    for (int c=lane; c<DD; c+=32){
        float hv = xr[c];
        float4 wb = *(const float4*)&Wb[c*4];
        float4 wd = *(const float4*)&Wdec[c*4];
        float4 wm = *(const float4*)&Wmix[c*4];
        a[0]+=hv*wb.x; a[1]+=hv*wb.y; a[2]+=hv*wb.z; a[3]+=hv*wb.w;
        a[4]+=hv*wd.x; a[5]+=hv*wd.y; a[6]+=hv*wd.z; a[7]+=hv*wd.w;
        a[8]+=hv*wm.x; a[9]+=hv*wm.y; a[10]+=hv*wm.z; a[11]+=hv*wm.w;
    }
    #pragma unroll
    for (int off=16; off; off>>=1){
        #pragma unroll
        for (int j=0;j<12;j++) a[j] += __shfl_down_sync(0xffffffffu, a[j], off);
    }
    if (lane == 0){
        #pragma unroll
        for (int j=0;j<4;j++){
            g_beta  [row*4+j] = sigm_f(a[j]);
            g_gamma [row*4+j] = sigm_f(a[4+j]);
            g_mixlin[row*4+j] = a[8+j];
        }
    }
}

// ---------------- causal short conv (K=4) + silu, all 3 tensors, float4 ------
__global__ void __launch_bounds__(256) conv_silu3_kernel(
    const float* __restrict__ convq, const float* __restrict__ convk,
    const float* __restrict__ convv)
{
    int z = blockIdx.y;
    const float* X  = (z==0) ? g_QL : (z==1 ? g_KL : g_VL);
    const float* Wc = (z==0) ? convq : (z==1 ? convk : convv);
    float* Y        = (z==0) ? g_Q : (z==1 ? g_K : g_V);
    int idx4 = blockIdx.x*256 + threadIdx.x;     // over NT*DD/4
    int ch  = (idx4 & 255) << 2;                 // channel base (0..1020)
    int bt  = idx4 >> 8;                         // token index
    int t   = bt & (LL-1);
    float4 acc = make_float4(0.f,0.f,0.f,0.f);
    #pragma unroll
    for (int k=0;k<4;k++){
        int ts = t-3+k;
        if (ts>=0){
            float4 xv = *(const float4*)&X[(size_t)(bt + (ts-t))*DD + ch];
            acc.x += xv.x * Wc[(ch+0)*4+k];
            acc.y += xv.y * Wc[(ch+1)*4+k];
            acc.z += xv.z * Wc[(ch+2)*4+k];
            acc.w += xv.w * Wc[(ch+3)*4+k];
        }
    }
    float4 y;
    y.x = silu_f(acc.x); y.y = silu_f(acc.y); y.z = silu_f(acc.z); y.w = silu_f(acc.w);
    if (z < 2){ y.x = silu_f(y.x); y.y = silu_f(y.y); y.z = silu_f(y.z); y.w = silu_f(y.w); }
    *(float4*)&Y[(size_t)bt*DD + ch] = y;
}

// ---------------- mix path: conv over H channels + silu + sigmoid(+bias) -----
__global__ void mixconv_kernel(const float* __restrict__ convmix,
                               const float* __restrict__ mixbias)
{
    int idx = blockIdx.x*blockDim.x + threadIdx.x;
    if (idx >= NT*HH) return;
    int h = idx & 3;
    int bt = idx >> 2;
    int t = bt & (LL-1);
    float acc = 0.f;
    #pragma unroll
    for (int k=0;k<4;k++){
        int ts = t-3+k;
        if (ts>=0) acc += g_mixlin[idx + (ts-t)*HH] * convmix[h*4+k];
    }
    float mi = silu_f(acc);
    g_mixg[idx] = sigm_f(mi + mixbias[h]);
}

// ---------------- l2 norm: warp per (row,head) -------------------------------
__global__ void __launch_bounds__(256) l2norm_kernel()
{
    int wid = threadIdx.x >> 5, lane = threadIdx.x & 31;
    int g = blockIdx.x*8 + wid;
    int row = g >> 2, h = g & 3;
    size_t base = (size_t)row*DD + h*DK;

    {
        float4 v0 = *(float4*)&g_Q[base + lane*4];
        float4 v1 = *(float4*)&g_Q[base + 128 + lane*4];
        float s = v0.x*v0.x+v0.y*v0.y+v0.z*v0.z+v0.w*v0.w
                + v1.x*v1.x+v1.y*v1.y+v1.z*v1.z+v1.w*v1.w;
        #pragma unroll
        for (int off=16; off; off>>=1) s += __shfl_xor_sync(0xffffffffu, s, off);
        float sc = rsqrtf(s + 1e-6f);
        v0.x*=sc; v0.y*=sc; v0.z*=sc; v0.w*=sc;
        v1.x*=sc; v1.y*=sc; v1.z*=sc; v1.w*=sc;
        *(float4*)&g_Q[base + lane*4] = v0;
        *(float4*)&g_Q[base + 128 + lane*4] = v1;
    }
    {
        float4 v0 = *(float4*)&g_K[base + lane*4];
        float4 v1 = *(float4*)&g_K[base + 128 + lane*4];
        float s = v0.x*v0.x+v0.y*v0.y+v0.z*v0.z+v0.w*v0.w
                + v1.x*v1.x+v1.y*v1.y+v1.z*v1.z+v1.w*v1.w;
        #pragma unroll
        for (int off=16; off; off>>=1) s += __shfl_xor_sync(0xffffffffu, s, off);
        float sc = rsqrtf(s + 1e-6f);
        v0.x*=sc; v0.y*=sc; v0.z*=sc; v0.w*=sc;
        v1.x*=sc; v1.y*=sc; v1.z*=sc; v1.w*=sc;
        *(float4*)&g_K[base + lane*4] = v0;
        *(float4*)&g_K[base + 128 + lane*4] = v1;
    }
}

// ---------------- per-chunk: T (tri inverse), W = T@k_beta, Attn = tril(q k^T)
#define WP 260   // float stride for 32x256 tiles
#define SP 36    // float stride for 32x32 / 256x32 tiles

__global__ void __launch_bounds__(256) chunk_kernel()
{
    extern __shared__ float sm[];
    float* kc     = sm;                 // 32*WP
    float* qc     = kc + 32*WP;         // 32*WP
    float* Amat   = qc + 32*WP;         // 32*33
    float* bet    = Amat + 32*33;       // 32
    float* rowtmp = bet + 32;           // 32

    int blk = blockIdx.x;               // bh*64 + c
    int bh = blk >> 6, c = blk & 63;
    int b = bh >> 2, h = bh & 3;
    int tid = threadIdx.x;
    int rowbase = b*LL + c*CHK;

    for (int e = tid; e < 2048; e += 256){
        int r = e >> 6; int c4 = (e & 63) << 2;
        *(float4*)&kc[r*WP+c4] = *(const float4*)&g_K[(size_t)(rowbase+r)*DD + h*DK + c4];
        *(float4*)&qc[r*WP+c4] = *(const float4*)&g_Q[(size_t)(rowbase+r)*DD + h*DK + c4];
    }
    if (tid < 32) bet[tid] = g_beta[(rowbase+tid)*HH + h];
    __syncthreads();

    // A = -tril(k_beta @ k^T, -1),  Attn = tril(q @ k^T, 0)   [f32x2, pair over m]
    {
        int i = tid >> 3, j0 = tid & 7;
        u64t da[4], dq[4];
        #pragma unroll
        for (int u=0;u<4;u++){ da[u]=0ull; dq[u]=0ull; }
        #pragma unroll 4
        for (int m=0;m<256;m+=4){
            ulonglong2 ki = *(ulonglong2*)&kc[i*WP+m];
            ulonglong2 qi = *(ulonglong2*)&qc[i*WP+m];
            #pragma unroll
            for (int u=0;u<4;u++){
                ulonglong2 kj = *(ulonglong2*)&kc[(j0+8*u)*WP+m];
                da[u] = ffma2(ki.x, kj.x, da[u]);
                da[u] = ffma2(ki.y, kj.y, da[u]);
                dq[u] = ffma2(qi.x, kj.x, dq[u]);
                dq[u] = ffma2(qi.y, kj.y, dq[u]);
            }
        }
        #pragma unroll
        for (int u=0;u<4;u++){
            int j = j0 + 8*u;
            float2 ta = f2unpack(da[u]);
            float2 tq = f2unpack(dq[u]);
            float av = ta.x + ta.y, qv = tq.x + tq.y;
            Amat[i*33+j] = (j < i) ? -bet[i]*av : 0.f;
            g_At[(size_t)blk*1024 + i*32 + j] = (j <= i) ? qv : 0.f;
        }
    }
    __syncthreads();

    // sequential forward-substitution (warp 0)
    if (tid < 32){
        int cx = tid;
        for (int ii=1; ii<32; ii++){
            rowtmp[cx] = Amat[ii*33+cx];
            __syncwarp();
            float acc = 0.f;
            if (cx < ii){
                acc = rowtmp[cx];
                for (int j=cx+1; j<ii; j++) acc += rowtmp[j]*Amat[j*33+cx];
            }
            __syncwarp();
            if (cx < ii) Amat[ii*33+cx] = acc;
            __syncwarp();
        }
        Amat[cx*33+cx] = 1.0f;   // T = A + I
    }
    __syncthreads();

    for (int e=tid; e<1024; e+=256)
        g_T[(size_t)blk*1024 + e] = Amat[(e>>5)*33 + (e&31)];

    // W = T @ (beta * k)   [f32x2, pair over dk]
    {
        int i = tid >> 3, mb = (tid & 7) << 2;
        u64t acc[16];
        #pragma unroll
        for (int s=0;s<16;s++) acc[s]=0ull;
        for (int j=0;j<32;j++){
            u64t td = f2dup(Amat[i*33+j]*bet[j]);
            #pragma unroll
            for (int s=0;s<8;s++){
                ulonglong2 kv = *(ulonglong2*)&kc[j*WP + s*32 + mb];
                acc[2*s]   = ffma2(td, kv.x, acc[2*s]);
                acc[2*s+1] = ffma2(td, kv.y, acc[2*s+1]);
            }
        }
        #pragma unroll
        for (int s=0;s<8;s++){
            ulonglong2 ov; ov.x = acc[2*s]; ov.y = acc[2*s+1];
            *(ulonglong2*)&g_W[((size_t)blk*32 + i)*DK + s*32 + mb] = ov;
        }
    }
}

// ---------------- inter-chunk scan: tensor-core (bf16 3-limb) version --------
// grid: 128 blocks = 16 (b,h) x 8 dv-slabs of 32 columns; 256 threads.
#define SBP 40    // bf16 stride for S / ua limb tiles (80 B rows)
#define WQP 264   // bf16 stride for wq / kt limb tiles (528 B rows)

__global__ void __launch_bounds__(256,1) scan_kernel()
{
    extern __shared__ char sraw[];
    float* S32   = (float*)sraw;              // 256*36
    float* P32   = S32  + 256*36;             // 64*36
    float* att32 = P32  + 64*36;              // 32*36
    float* T32   = att32+ 32*36;              // 32*36
    float* vb32  = T32  + 32*36;              // 32*36
    float* ua32  = vb32 + 32*36;              // 32*36
    __nv_bfloat16* S_hi  = (__nv_bfloat16*)(ua32 + 32*36);
    __nv_bfloat16* S_lo  = S_hi  + 256*SBP;
    __nv_bfloat16* wq_hi = S_lo  + 256*SBP;   // 64 rows (w:0-31, q:32-63)
    __nv_bfloat16* wq_lo = wq_hi + 64*WQP;
    __nv_bfloat16* kt_hi = wq_lo + 64*WQP;    // 32 rows
    __nv_bfloat16* kt_lo = kt_hi + 32*WQP;
    __nv_bfloat16* ua_hi = kt_lo + 32*WQP;    // 32 rows
    __nv_bfloat16* ua_lo = ua_hi + 32*SBP;

    const int tid  = threadIdx.x;
    const int lane = tid & 31, wid = tid >> 5;
    const int bh   = blockIdx.x >> 3;
    const int slab = blockIdx.x & 7;
    const int b = bh >> 2, h = bh & 3;
    const size_t ocol = (size_t)h*DK + slab*32;

    const uint32_t u_S_hi  = smem_u32(S_hi),  u_S_lo  = smem_u32(S_lo);
    const uint32_t u_wq_hi = smem_u32(wq_hi), u_wq_lo = smem_u32(wq_lo);
    const uint32_t u_kt_hi = smem_u32(kt_hi), u_kt_lo = smem_u32(kt_lo);
    const uint32_t u_ua_hi = smem_u32(ua_hi), u_ua_lo = smem_u32(ua_lo);

    // init S and its limbs
    for (int e=tid; e<256*36; e+=256) S32[e]=0.f;
    for (int e=tid; e<256*SBP; e+=256){
        ((uint16_t*)S_hi)[e] = 0; ((uint16_t*)S_lo)[e] = 0;
    }
    __syncthreads();

    const int i  = tid >> 3;          // scalar stage: row 0..31
    const int jb = (tid & 7) << 2;    // scalar stage: col base

    // stage-A lane geometry
    const int wmA = wid & 3, wnA = wid >> 2;
    const int aArow = wmA*16 + (lane & 15);
    const int aAcb  = ((lane >> 4) & 1) << 3;
    const int bArow = (lane & 15);
    const int bAcb  = wnA*16 + (((lane >> 4) & 1) << 3);
    // stage-B lane geometry
    const int aBrow = (lane & 7) + (((lane >> 4) & 1) << 3);   // kt row within k16
    const int aBcb  = ((lane >> 3) & 1) << 3;                  // d offset within tile
    const int bBrow = (lane & 15);
    const int cr = lane >> 2, cc = (lane & 3) << 1;

    for (int c=0; c<NCHUNK; c++){
        int blk = bh*NCHUNK + c;
        int rowbase = b*LL + c*CHK;

        // ---- load + limb-convert tiles
        for (int e=tid; e<2048; e+=256){
            int r = e >> 6; int c4 = (e & 63) << 2;
            float4 wv = *(const float4*)&g_W[((size_t)blk*32 + r)*DK + c4];
            split_store4(wv, &wq_hi[r*WQP+c4], &wq_lo[r*WQP+c4]);
            float4 qv = *(const float4*)&g_Q[(size_t)(rowbase+r)*DD + h*DK + c4];
            split_store4(qv, &wq_hi[(32+r)*WQP+c4], &wq_lo[(32+r)*WQP+c4]);
            float4 kv = *(const float4*)&g_K[(size_t)(rowbase+r)*DD + h*DK + c4];
            split_store4(kv, &kt_hi[r*WQP+c4], &kt_lo[r*WQP+c4]);
        }
        {
            int r = tid >> 3, c4 = (tid & 7) << 2;
            *(float4*)&att32[r*SP+c4] = *(const float4*)&g_At[(size_t)blk*1024 + r*32 + c4];
            *(float4*)&T32 [r*SP+c4]  = *(const float4*)&g_T [(size_t)blk*1024 + r*32 + c4];
            float be = g_beta[(rowbase+r)*HH + h];
            float4 vv = *(const float4*)&g_V[(size_t)(rowbase+r)*DD + ocol + c4];
            vv.x*=be; vv.y*=be; vv.z*=be; vv.w*=be;
            *(float4*)&vb32[r*SP+c4] = vv;
        }
        __syncthreads();

        // ---- stage A: P = [w|q] @ S  (M=64, N=32, K=256), bf16 3-limb
        {
            float acc[2][4];
            #pragma unroll
            for (int n8=0;n8<2;n8++)
                #pragma unroll
                for (int u=0;u<4;u++) acc[n8][u]=0.f;
            #pragma unroll 4
            for (int k16=0;k16<16;k16++){
                uint32_t ah[4], al[4], bh_[4], bl_[4];
                uint32_t aofs = (uint32_t)(aArow*WQP + k16*16 + aAcb)*2;
                LDSM_X4(ah[0],ah[1],ah[2],ah[3], u_wq_hi + aofs);
                LDSM_X4(al[0],al[1],al[2],al[3], u_wq_lo + aofs);
                uint32_t bofs = (uint32_t)((k16*16 + bArow)*SBP + bAcb)*2;
                LDSM_X4_T(bh_[0],bh_[1],bh_[2],bh_[3], u_S_hi + bofs);
                LDSM_X4_T(bl_[0],bl_[1],bl_[2],bl_[3], u_S_lo + bofs);
                MMABF16(acc[0], ah, bh_[0], bh_[1]);
                MMABF16(acc[1], ah, bh_[2], bh_[3]);
                MMABF16(acc[0], ah, bl_[0], bl_[1]);
                MMABF16(acc[1], ah, bl_[2], bl_[3]);
                MMABF16(acc[0], al, bh_[0], bh_[1]);
                MMABF16(acc[1], al, bh_[2], bh_[3]);
            }
            #pragma unroll
            for (int n8=0;n8<2;n8++){
                int col = wnA*16 + n8*8 + cc;
                P32[(wmA*16+cr  )*SP + col  ] = acc[n8][0];
                P32[(wmA*16+cr  )*SP + col+1] = acc[n8][1];
                P32[(wmA*16+cr+8)*SP + col  ] = acc[n8][2];
                P32[(wmA*16+cr+8)*SP + col+1] = acc[n8][3];
            }
        }
        __syncthreads();

        // ---- scalar: u = T@vb ; ua = u - P_w ; ua limbs
        {
            u64t ui0=0ull, ui1=0ull;
            #pragma unroll
            for (int m=0;m<32;m++){
                u64t td = f2dup(T32[i*SP+m]);
                ulonglong2 vv = *(ulonglong2*)&vb32[m*SP+jb];
                ui0 = ffma2(td, vv.x, ui0);
                ui1 = ffma2(td, vv.y, ui1);
            }
            float2 u01 = f2unpack(ui0), u23 = f2unpack(ui1);
            float4 pw = *(float4*)&P32[i*SP+jb];
            float4 uav;
            uav.x = u01.x - pw.x; uav.y = u01.y - pw.y;
            uav.z = u23.x - pw.z; uav.w = u23.y - pw.w;
            *(float4*)&ua32[i*SP+jb] = uav;
            split_store4(uav, &ua_hi[i*SBP+jb], &ua_lo[i*SBP+jb]);
        }
        __syncthreads();

        // ---- scalar: o = P_q + att @ ua  -> global
        {
            float4 pq = *(float4*)&P32[(32+i)*SP+jb];
            u64t aO0 = f2pack(pq.x, pq.y), aO1 = f2pack(pq.z, pq.w);
            #pragma unroll
            for (int m=0;m<32;m++){
                u64t ad = f2dup(att32[i*SP+m]);
                ulonglong2 uv = *(ulonglong2*)&ua32[m*SP+jb];
                aO0 = ffma2(ad, uv.x, aO0);
                aO1 = ffma2(ad, uv.y, aO1);
            }
            ulonglong2 ov; ov.x = aO0; ov.y = aO1;
            *(ulonglong2*)&g_Od[(size_t)(rowbase+i)*DD + ocol + jb] = ov;
        }

        // ---- stage B: dS = k^T @ ua  (M=256 over 8 warps, N=32, K=32)
        {
            float acc[2][4][4];
            #pragma unroll
            for (int mt=0;mt<2;mt++)
                #pragma unroll
                for (int n8=0;n8<4;n8++)
                    #pragma unroll
                    for (int u=0;u<4;u++) acc[mt][n8][u]=0.f;
            #pragma unroll
            for (int kk=0;kk<2;kk++){
                uint32_t bh0[4], bl0[4], bh1[4], bl1[4];
                uint32_t bofs0 = (uint32_t)((kk*16 + bBrow)*SBP + (((lane>>4)&1)<<3))*2;
                uint32_t bofs1 = bofs0 + 16*2;
                LDSM_X4_T(bh0[0],bh0[1],bh0[2],bh0[3], u_ua_hi + bofs0);
                LDSM_X4_T(bl0[0],bl0[1],bl0[2],bl0[3], u_ua_lo + bofs0);
                LDSM_X4_T(bh1[0],bh1[1],bh1[2],bh1[3], u_ua_hi + bofs1);
                LDSM_X4_T(bl1[0],bl1[1],bl1[2],bl1[3], u_ua_lo + bofs1);
                #pragma unroll
                for (int mt=0;mt<2;mt++){
                    int D0 = wid*32 + mt*16;
                    uint32_t ah[4], al[4];
                    uint32_t aofs = (uint32_t)((kk*16 + aBrow)*WQP + D0 + aBcb)*2;
                    LDSM_X4_T(ah[0],ah[1],ah[2],ah[3], u_kt_hi + aofs);
                    LDSM_X4_T(al[0],al[1],al[2],al[3], u_kt_lo + aofs);
                    MMABF16(acc[mt][0], ah, bh0[0], bh0[1]);
                    MMABF16(acc[mt][1], ah, bh0[2], bh0[3]);
                    MMABF16(acc[mt][2], ah, bh1[0], bh1[1]);
                    MMABF16(acc[mt][3], ah, bh1[2], bh1[3]);
                    MMABF16(acc[mt][0], ah, bl0[0], bl0[1]);
                    MMABF16(acc[mt][1], ah, bl0[2], bl0[3]);
                    MMABF16(acc[mt][2], ah, bl1[0], bl1[1]);
                    MMABF16(acc[mt][3], ah, bl1[2], bl1[3]);
                    MMABF16(acc[mt][0], al, bh0[0], bh0[1]);
                    MMABF16(acc[mt][1], al, bh0[2], bh0[3]);
                    MMABF16(acc[mt][2], al, bh1[0], bh1[1]);
                    MMABF16(acc[mt][3], al, bh1[2], bh1[3]);
                }
            }
            #pragma unroll
            for (int mt=0;mt<2;mt++){
                int r0 = wid*32 + mt*16 + cr;
                #pragma unroll
                for (int n8=0;n8<4;n8++){
                    int col = n8*8 + cc;
                    S32[(r0  )*SP + col  ] += acc[mt][n8][0];
                    S32[(r0  )*SP + col+1] += acc[mt][n8][1];
                    S32[(r0+8)*SP + col  ] += acc[mt][n8][2];
                    S32[(r0+8)*SP + col+1] += acc[mt][n8][3];
                }
            }
        }
        __syncwarp();
        // ---- refresh S limbs for own row (row tid belongs to warp tid>>5's range)
        #pragma unroll
        for (int c4=0;c4<32;c4+=4){
            float4 sv = *(float4*)&S32[tid*SP + c4];
            split_store4(sv, &S_hi[tid*SBP+c4], &S_lo[tid*SBP+c4]);
        }
        __syncthreads();
    }
}

// ---------------- EMA phase 1: segmented local scan --------------------------
__global__ void __launch_bounds__(256) ema_local_kernel()
{
    extern __shared__ float esm[];
    float* cbuf = esm;             // ESEG*256
    float* gbuf = cbuf + ESEG*256; // ESEG
    float* Ps   = gbuf + ESEG;     // ESEG

    int bh = blockIdx.x, seg = blockIdx.y;
    int b = bh >> 2, h = bh & 3;
    int tid = threadIdx.x;
    int rowbase = b*LL + seg*ESEG;
    size_t hcol = (size_t)h*DK;

    if (tid < ESEG) gbuf[tid] = g_gamma[(rowbase+tid)*HH + h];
    __syncthreads();

    for (int e = tid; e < ESEG*64; e += 256){
        int r = e >> 6, c4 = (e & 63) << 2;
        float om = 1.f - gbuf[r];
        float4 vv = *(const float4*)&g_V[(size_t)(rowbase+r)*DD + hcol + c4];
        vv.x*=om; vv.y*=om; vv.z*=om; vv.w*=om;
        *(float4*)&cbuf[r*256 + c4] = vv;
    }
    if (tid < ESEG){
        int lane = tid & 31;
        float p = gbuf[tid];
        #pragma unroll
        for (int off=1; off<32; off<<=1){
            float o = __shfl_up_sync(0xffffffffu, p, off);
            if (lane >= off) p *= o;
        }
        Ps[tid] = p;
    }
    __syncthreads();
    if (tid < ESEG){
        int wmy = tid >> 5;
        float pre = 1.f;
        for (int wq = 0; wq < wmy; wq++) pre *= Ps[wq*32+31];
        g_P[bh*LL + seg*ESEG + tid] = pre * Ps[tid];
    }

    float s = 0.f;
    #pragma unroll 8
    for (int t = 0; t < ESEG; t++){
        s = fmaf(gbuf[t], s, cbuf[t*256 + tid]);
        cbuf[t*256 + tid] = s;
    }
    __syncthreads();

    for (int e = tid; e < ESEG*64; e += 256){
        int r = e >> 6, c4 = (e & 63) << 2;
        *(float4*)&g_Oe[(size_t)(rowbase+r)*DD + hcol + c4] = *(float4*)&cbuf[r*256 + c4];
    }
}

// ---------------- EMA phase 2: carry across segments -------------------------
__global__ void __launch_bounds__(256) ema_carry_kernel()
{
    int bh = blockIdx.x;
    int b = bh >> 2, h = bh & 3;
    int dv = threadIdx.x;
    float s = 0.f;
    #pragma unroll
    for (int seg = 0; seg < NSEG; seg++){
        g_C[(bh*NSEG + seg)*DK + dv] = s;
        int rend = b*LL + seg*ESEG + (ESEG-1);
        float P  = g_P[bh*LL + seg*ESEG + (ESEG-1)];
        float ye = g_Oe[(size_t)rend*DD + h*DK + dv];
        s = fmaf(P, s, ye);
    }
}

// ---------------- mix combine + RMS norm + fp16 split (fused, + ema carry) ---
__global__ void __launch_bounds__(256) combine_rms_kernel(const float* __restrict__ rmsw)
{
    int wid = threadIdx.x >> 5, lane = threadIdx.x & 31;
    int g = blockIdx.x*8 + wid;
    int row = g >> 2, h = g & 3;
    int b = row >> 11, t = row & (LL-1);
    int bh = b*4 + h, seg = t >> 7;
    float m = g_mixg[row*4+h];
    size_t base = (size_t)row*DD + h*DK;

    float P = g_P[bh*LL + t];
    const float* cav = &g_C[(bh*NSEG + seg)*DK];
    float4 c0 = *(const float4*)&cav[lane*4];
    float4 c1 = *(const float4*)&cav[128 + lane*4];

    float4 d0 = *(float4*)&g_Od[base + lane*4];
    float4 d1 = *(float4*)&g_Od[base + 128 + lane*4];
    float4 e0 = *(float4*)&g_Oe[base + lane*4];
    float4 e1 = *(float4*)&g_Oe[base + 128 + lane*4];
    e0.x += P*c0.x; e0.y += P*c0.y; e0.z += P*c0.z; e0.w += P*c0.w;
    e1.x += P*c1.x; e1.y += P*c1.y; e1.z += P*c1.z; e1.w += P*c1.w;

    float4 o0, o1;
    float om = 1.f - m;
    o0.x = om*d0.x + m*e0.x; o0.y = om*d0.y + m*e0.y;
    o0.z = om*d0.z + m*e0.z; o0.w = om*d0.w + m*e0.w;
    o1.x = om*d1.x + m*e1.x; o1.y = om*d1.y + m*e1.y;
    o1.z = om*d1.z + m*e1.z; o1.w = om*d1.w + m*e1.w;
    float s = o0.x*o0.x+o0.y*o0.y+o0.z*o0.z+o0.w*o0.w
            + o1.x*o1.x+o1.y*o1.y+o1.z*o1.z+o1.w*o1.w;
    #pragma unroll
    for (int off=16; off; off>>=1) s += __shfl_xor_sync(0xffffffffu, s, off);
    float sc = rsqrtf(s*(1.f/256.f) + 1e-5f);
    float4 r0 = *(const float4*)&rmsw[lane*4];
    float4 r1 = *(const float4*)&rmsw[128 + lane*4];
    o0.x *= sc*r0.x; o0.y *= sc*r0.y; o0.z *= sc*r0.z; o0.w *= sc*r0.w;
    o1.x *= sc*r1.x; o1.y *= sc*r1.y; o1.z *= sc*r1.z; o1.w *= sc*r1.w;

    __half h4[4], l4[4];
    float v[4];
    v[0]=o0.x; v[1]=o0.y; v[2]=o0.z; v[3]=o0.w;
    #pragma unroll
    for (int u=0;u<4;u++){
        h4[u]=__float2half_rn(v[u]);
        l4[u]=__float2half_rn(v[u]-__half2float(h4[u]));
    }
    *(u64t*)&g_Op_hi[base + lane*4] = *(u64t*)h4;
    *(u64t*)&g_Op_lo[base + lane*4] = *(u64t*)l4;
    v[0]=o1.x; v[1]=o1.y; v[2]=o1.z; v[3]=o1.w;
    #pragma unroll
    for (int u=0;u<4;u++){
        h4[u]=__float2half_rn(v[u]);
        l4[u]=__float2half_rn(v[u]-__half2float(h4[u]));
    }
    *(u64t*)&g_Op_hi[base + 128 + lane*4] = *(u64t*)h4;
    *(u64t*)&g_Op_lo[base + 128 + lane*4] = *(u64t*)l4;
}

// ---------------- host driver -----------------------------------------------
extern "C" void kernel_launch(void* const* d_in, const int* in_sizes, int n_in,
                              void* d_out, int out_size)
{
    const float* hs      = (const float*)d_in[0];
    const float* Wq      = (const float*)d_in[1];
    const float* Wk      = (const float*)d_in[2];
    const float* Wv      = (const float*)d_in[3];
    const float* convq   = (const float*)d_in[4];
    const float* convk   = (const float*)d_in[5];
    const float* convv   = (const float*)d_in[6];
    const float* Wb      = (const float*)d_in[7];
    const float* Wdec    = (const float*)d_in[8];
    const float* Wmix    = (const float*)d_in[9];
    const float* convmix = (const float*)d_in[10];
    const float* mixbias = (const float*)d_in[11];
    const float* rmsw    = (const float*)d_in[12];
    const float* Wo      = (const float*)d_in[13];

    void *pQL,*pKL,*pVL;
    cudaGetSymbolAddress(&pQL, g_QL);
    cudaGetSymbolAddress(&pKL, g_KL);
    cudaGetSymbolAddress(&pVL, g_VL);

    void *p_hs_hi,*p_hs_lo,*p_Op_hi,*p_Op_lo,*p_WT_h,*p_WoT_h;
    cudaGetSymbolAddress(&p_hs_hi, g_hs_hi);  cudaGetSymbolAddress(&p_hs_lo, g_hs_lo);
    cudaGetSymbolAddress(&p_Op_hi, g_Op_hi);  cudaGetSymbolAddress(&p_Op_lo, g_Op_lo);
    cudaGetSymbolAddress(&p_WT_h, g_WT_h);    cudaGetSymbolAddress(&p_WoT_h, g_WoT_h);

    int smem_chunk = (2*32*WP + 32*33 + 64) * 4;
    int smem_scan  = (256*36 + 64*36 + 4*32*36)*4
                   + (2*256*SBP + 2*64*WQP + 2*32*WQP + 2*32*SBP)*2;  // 211968
    int smem_gemm  = NSTG*STGB;
    int smem_ema   = (ESEG*256 + 2*ESEG) * 4;
    cudaFuncSetAttribute(chunk_kernel, cudaFuncAttributeMaxDynamicSharedMemorySize, smem_chunk);
    cudaFuncSetAttribute(scan_kernel,  cudaFuncAttributeMaxDynamicSharedMemorySize, smem_scan);
    cudaFuncSetAttribute(gemm_f16s,    cudaFuncAttributeMaxDynamicSharedMemorySize, smem_gemm);
    cudaFuncSetAttribute(ema_local_kernel, cudaFuncAttributeMaxDynamicSharedMemorySize, smem_ema);

    // 1: split activations to fp16 limbs
    split_kernel<<<NT*DD/256,256>>>(hs, (__half*)p_hs_hi, (__half*)p_hs_lo, NT*DD);
    // 2: weight transposes to fp16
    dim3 wg(32,32,4), wb(32,8);
    wsplit_all_kernel<<<wg,wb>>>(Wq, Wk, Wv, Wo, (__half*)p_WT_h, (__half*)p_WoT_h);
    // 3: small projections
    smallproj_kernel<<<NT/8,256>>>(hs, Wb, Wdec, Wmix);

    // 4: merged QKV GEMM (1536 CTAs)
    gemm_f16s<<<dim3(24,64),256,smem_gemm>>>(
        (__half*)p_hs_hi,(__half*)p_hs_lo,(__half*)p_WT_h,
        (float*)pQL, (float*)pKL, (float*)pVL, DD);

    conv_silu3_kernel<<<dim3(NT*DD/4/256,3),256>>>(convq, convk, convv);
    mixconv_kernel<<<(NT*HH+127)/128,128>>>(convmix, mixbias);

    l2norm_kernel<<<NT*HH/8,256>>>();
    chunk_kernel<<<NBH*NCHUNK,256,smem_chunk>>>();
    scan_kernel<<<NBH*8,256,smem_scan>>>();

    ema_local_kernel<<<dim3(NBH,NSEG),256,smem_ema>>>();
    ema_carry_kernel<<<NBH,DK>>>();

    combine_rms_kernel<<<NT*HH/8,256>>>(rmsw);

    gemm_f16s<<<dim3(8,64),256,smem_gemm>>>(
        (__half*)p_Op_hi,(__half*)p_Op_lo,(__half*)p_WoT_h,
        (float*)d_out, (float*)d_out, (float*)d_out, DD);
}

// round 11
// speedup vs baseline: 3.4841x; 1.1246x over previous
#include <cuda_runtime.h>
#include <cuda_bf16.h>
#include <cuda_fp16.h>
#include <math.h>
#include <stdint.h>

// Problem constants
#define BB 4
#define LL 2048
#define DD 1024
#define HH 4
#define DK 256
#define NT (BB*LL)       // 8192 tokens
#define NCHUNK 64        // chunks per sequence
#define CHK 32           // chunk length
#define NBH 16           // B*H
#define ESEG 128         // ema segment length
#define NSEG (LL/ESEG)   // 16

typedef unsigned long long u64t;

// ---------------- scratch (device globals; no allocation allowed) -------------
__device__ float g_QL[NT*DD];
__device__ float g_KL[NT*DD];
__device__ float g_VL[NT*DD];
__device__ float g_Q[NT*DD];
__device__ float g_K[NT*DD];
__device__ float g_V[NT*DD];
__device__ float g_beta[NT*HH];
__device__ float g_gamma[NT*HH];
__device__ float g_mixlin[NT*HH];
__device__ float g_mixg[NT*HH];
__device__ float g_T[NBH*NCHUNK*CHK*CHK];    // triangular inverse T
__device__ float g_At[NBH*NCHUNK*CHK*CHK];   // attn_i = tril(q@k^T)
__device__ float g_Od[NT*DD];                // delta-rule output
__device__ float g_Oe[NT*DD];                // ema LOCAL output (y_t)
__device__ float g_P[NBH*LL];                // in-segment prefix products of gamma
__device__ float g_C[NBH*NSEG*DK];           // carry state at segment start

// bf16 limb arrays for the scan's tensor-core stages
__device__ __nv_bfloat16 g_Qh[NT*DD], g_Ql[NT*DD];
__device__ __nv_bfloat16 g_Kh[NT*DD], g_Kl[NT*DD];
__device__ __nv_bfloat16 g_Wh[NBH*NCHUNK*CHK*DK], g_Wl[NBH*NCHUNK*CHK*DK];

// fp16 limb buffers for tensor-core GEMMs (A: 2 limbs; B: single fp16)
__device__ __half g_hs_hi[NT*DD], g_hs_lo[NT*DD];
__device__ __half g_Op_hi[NT*DD], g_Op_lo[NT*DD];
__device__ __half g_WT_h[3*DD*DD];           // Wq|Wk|Wv transposed, fp16
__device__ __half g_WoT_h[DD*DD];            // Wo transposed, fp16

__device__ __forceinline__ float silu_f(float x){ return x / (1.f + expf(-x)); }
__device__ __forceinline__ float sigm_f(float x){ return 1.f / (1.f + expf(-x)); }

// ===================== f32x2 packed-math helpers =============================
__device__ __forceinline__ u64t f2dup(float x){
    u64t r; unsigned int xi = __float_as_uint(x);
    asm("mov.b64 %0, {%1,%1};" : "=l"(r) : "r"(xi));
    return r;
}
__device__ __forceinline__ u64t f2pack(float x, float y){
    u64t r;
    asm("mov.b64 %0, {%1,%2};" : "=l"(r) : "r"(__float_as_uint(x)), "r"(__float_as_uint(y)));
    return r;
}
__device__ __forceinline__ u64t ffma2(u64t a, u64t b, u64t c){
    u64t d; asm("fma.rn.f32x2 %0, %1, %2, %3;" : "=l"(d) : "l"(a), "l"(b), "l"(c));
    return d;
}
__device__ __forceinline__ float2 f2unpack(u64t p){
    unsigned int lo, hi;
    asm("mov.b64 {%0,%1}, %2;" : "=r"(lo), "=r"(hi) : "l"(p));
    return make_float2(__uint_as_float(lo), __uint_as_float(hi));
}

// ===================== PTX helpers (mma.sync / ldmatrix / cp.async) ==========
__device__ __forceinline__ uint32_t smem_u32(const void* p){
    uint32_t a;
    asm("{ .reg .u64 t; cvta.to.shared.u64 t, %1; cvt.u32.u64 %0, t; }" : "=r"(a) : "l"(p));
    return a;
}
__device__ __forceinline__ void cp_async16(uint32_t dst, const void* src){
    asm volatile("cp.async.cg.shared.global [%0], [%1], 16;" :: "r"(dst), "l"(src) : "memory");
}
__device__ __forceinline__ void cp_commit(){ asm volatile("cp.async.commit_group;" ::: "memory"); }

#define LDSM_X4(r0,r1,r2,r3, addr) \
    asm volatile("ldmatrix.sync.aligned.m8n8.x4.shared.b16 {%0,%1,%2,%3}, [%4];" \
        : "=r"(r0),"=r"(r1),"=r"(r2),"=r"(r3) : "r"(addr))

#define LDSM_X4_T(r0,r1,r2,r3, addr) \
    asm volatile("ldmatrix.sync.aligned.m8n8.x4.trans.shared.b16 {%0,%1,%2,%3}, [%4];" \
        : "=r"(r0),"=r"(r1),"=r"(r2),"=r"(r3) : "r"(addr))

#define MMAF16(d, a, b0, b1) \
    asm volatile("mma.sync.aligned.m16n8k16.row.col.f32.f16.f16.f32 " \
        "{%0,%1,%2,%3}, {%4,%5,%6,%7}, {%8,%9}, {%0,%1,%2,%3};" \
        : "+f"((d)[0]),"+f"((d)[1]),"+f"((d)[2]),"+f"((d)[3]) \
        : "r"((a)[0]),"r"((a)[1]),"r"((a)[2]),"r"((a)[3]), "r"(b0),"r"(b1))

#define MMABF16(d, a, b0, b1) \
    asm volatile("mma.sync.aligned.m16n8k16.row.col.f32.bf16.bf16.f32 " \
        "{%0,%1,%2,%3}, {%4,%5,%6,%7}, {%8,%9}, {%0,%1,%2,%3};" \
        : "+f"((d)[0]),"+f"((d)[1]),"+f"((d)[2]),"+f"((d)[3]) \
        : "r"((a)[0]),"r"((a)[1]),"r"((a)[2]),"r"((a)[3]), "r"(b0),"r"(b1))

// bf16 hi/lo split-store of a float4 (4B-aligned destinations)
__device__ __forceinline__ void split_store4(float4 v, __nv_bfloat16* ph, __nv_bfloat16* pl){
    __nv_bfloat162 h01, h23, l01, l23;
    h01.x = __float2bfloat16(v.x); h01.y = __float2bfloat16(v.y);
    h23.x = __float2bfloat16(v.z); h23.y = __float2bfloat16(v.w);
    l01.x = __float2bfloat16(v.x - __bfloat162float(h01.x));
    l01.y = __float2bfloat16(v.y - __bfloat162float(h01.y));
    l23.x = __float2bfloat16(v.z - __bfloat162float(h23.x));
    l23.y = __float2bfloat16(v.w - __bfloat162float(h23.y));
    *(__nv_bfloat162*)(ph)   = h01; *(__nv_bfloat162*)(ph+2) = h23;
    *(__nv_bfloat162*)(pl)   = l01; *(__nv_bfloat162*)(pl+2) = l23;
}

// ===================== split/transpose conversion kernels ====================
__global__ void __launch_bounds__(256) split_kernel(const float* __restrict__ X,
                             __half* __restrict__ hi,
                             __half* __restrict__ lo)
{
    int i4 = blockIdx.x*256 + threadIdx.x;   // over NT*DD/4
    float4 v = *(const float4*)&X[(size_t)i4*4];
    __half h[4], l[4];
    float a[4] = {v.x, v.y, v.z, v.w};
    #pragma unroll
    for (int u=0;u<4;u++){
        h[u] = __float2half_rn(a[u]);
        l[u] = __float2half_rn(a[u] - __half2float(h[u]));
    }
    *(u64t*)&hi[(size_t)i4*4] = *(u64t*)h;
    *(u64t*)&lo[(size_t)i4*4] = *(u64t*)l;
}
// 4 weights transposed to fp16; Wq/Wk/Wv into combined [3072,1024], Wo separate.
__global__ void wsplit_all_kernel(const float* __restrict__ W0, const float* __restrict__ W1,
                                  const float* __restrict__ W2, const float* __restrict__ W3,
                                  __half* __restrict__ bigh, __half* __restrict__ woh)
{
    __shared__ float t[32][33];
    const float* W; __half* hiT;
    int z = blockIdx.z;
    if      (z==0){ W=W0; hiT=bigh; }
    else if (z==1){ W=W1; hiT=bigh+DD*DD; }
    else if (z==2){ W=W2; hiT=bigh+2*DD*DD; }
    else          { W=W3; hiT=woh; }
    int n0 = blockIdx.x*32, k0 = blockIdx.y*32;
    int tx = threadIdx.x, ty = threadIdx.y;   // 32 x 8
    for (int i = ty; i < 32; i += 8)
        t[i][tx] = W[(size_t)(k0+i)*DD + n0+tx];
    __syncthreads();
    for (int i = ty; i < 32; i += 8)
        hiT[(size_t)(n0+i)*DD + k0+tx] = __float2half_rn(t[tx][i]);
}

// ===================== mma.sync fp16 2-limb GEMM =============================
#define GRS 40            // smem row stride in fp16 elements (80 bytes)
#define MATB (128*GRS*2)  // 10240 bytes per matrix tile
#define STGB (3*MATB)     // 30720 per stage (Ahi, Alo, B)
#define NSTG 3

__global__ void __launch_bounds__(256,2) gemm_f16s(
    const __half* __restrict__ Ahi, const __half* __restrict__ Alo,
    const __half* __restrict__ BT,
    float* C0, float* C1, float* C2, int K)
{
    extern __shared__ char smem[];
    const uint32_t sbase = smem_u32(smem);
    const int tid  = threadIdx.x;
    const int lane = tid & 31, wid = tid >> 5;
    const int wm = wid & 3, wn = wid >> 2;          // 4x2 warp grid
    const int row0 = blockIdx.y*128;
    const int bcol = blockIdx.x*128;                // into B (up to 3072 wide)
    const int seg  = blockIdx.x >> 3;
    const int col0 = (blockIdx.x & 7)*128;          // into C
    float* C = (seg==0) ? C0 : (seg==1 ? C1 : C2);

    const __half* g0 = Ahi + (size_t)row0*K;
    const __half* g1 = Alo + (size_t)row0*K;
    const __half* g2 = BT  + (size_t)bcol*K;

    float acc[2][8][4];
    #pragma unroll
    for (int i=0;i<2;i++)
        #pragma unroll
        for (int j=0;j<8;j++)
            #pragma unroll
            for (int u=0;u<4;u++) acc[i][j][u]=0.f;

    auto fill = [&](int kb){
        uint32_t sb = sbase + (kb%NSTG)*STGB;
        #pragma unroll
        for (int t=0;t<2;t++){
            int ci = tid + t*256;
            int r = ci >> 2, c = ci & 3;
            uint32_t dst = sb + r*(GRS*2) + c*16;
            size_t go = (size_t)r*K + (size_t)kb*32 + c*8;
            cp_async16(dst + 0*MATB, g0 + go);
            cp_async16(dst + 1*MATB, g1 + go);
            cp_async16(dst + 2*MATB, g2 + go);
        }
        cp_commit();
    };

    const int nkb = K/32;
    fill(0);
    fill(1);

    const int a_r  = lane & 15;
    const int a_ko = ((lane >> 4) & 1) << 3;
    const int b_n  = (lane & 7) + (((lane >> 4) & 1) << 3);
    const int b_ko = ((lane >> 3) & 1) << 3;

    for (int kb = 0; kb < nkb; kb++){
        if (kb+1 < nkb) asm volatile("cp.async.wait_group 1;" ::: "memory");
        else            asm volatile("cp.async.wait_group 0;" ::: "memory");
        __syncthreads();

        uint32_t sb = sbase + (kb%NSTG)*STGB;
        #pragma unroll
        for (int ks=0; ks<2; ks++){
            const int k16 = ks*16;
            uint32_t ah[2][4], al[2][4];
            #pragma unroll
            for (int mt=0; mt<2; mt++){
                uint32_t ad = sb + (wm*32 + mt*16 + a_r)*(GRS*2) + (k16 + a_ko)*2;
                LDSM_X4(ah[mt][0],ah[mt][1],ah[mt][2],ah[mt][3], ad + 0*MATB);
                LDSM_X4(al[mt][0],al[mt][1],al[mt][2],al[mt][3], ad + 1*MATB);
            }
            #pragma unroll
            for (int n4=0; n4<4; n4++){
                uint32_t bd = sb + 2*MATB + (wn*64 + n4*16 + b_n)*(GRS*2) + (k16 + b_ko)*2;
                uint32_t bh[4];
                LDSM_X4(bh[0],bh[1],bh[2],bh[3], bd);
                #pragma unroll
                for (int mt=0; mt<2; mt++){
                    MMAF16(acc[mt][n4*2  ], ah[mt], bh[0], bh[1]);
                    MMAF16(acc[mt][n4*2+1], ah[mt], bh[2], bh[3]);
                    MMAF16(acc[mt][n4*2  ], al[mt], bh[0], bh[1]);
                    MMAF16(acc[mt][n4*2+1], al[mt], bh[2], bh[3]);
                }
            }
        }
        if (kb+2 < nkb) fill(kb+2);
    }

    float* Cg = C + (size_t)(row0 + wm*32)*DD + col0 + wn*64;
    const int cr = lane >> 2, cc = (lane & 3) << 1;
    #pragma unroll
    for (int mt=0; mt<2; mt++)
        #pragma unroll
        for (int nt=0; nt<8; nt++){
            float2 v0; v0.x = acc[mt][nt][0]; v0.y = acc[mt][nt][1];
            *(float2*)&Cg[(size_t)(mt*16+cr)*DD + nt*8+cc] = v0;
            float2 v1; v1.x = acc[mt][nt][2]; v1.y = acc[mt][nt][3];
            *(float2*)&Cg[(size_t)(mt*16+cr+8)*DD + nt*8+cc] = v1;
        }
}

// ---------------- small projections: warp per row ----------------------------
__global__ void __launch_bounds__(256) smallproj_kernel(const float* __restrict__ Xh,
                                 const float* __restrict__ Wb,
                                 const float* __restrict__ Wdec,
                                 const float* __restrict__ Wmix)
{
    int wid = threadIdx.x >> 5, lane = threadIdx.x & 31;
    int row = blockIdx.x*8 + wid;
    const float* xr = Xh + (size_t)row*DD;
    float a[12];
    #pragma unroll
    for (int j=0;j<12;j++) a[j]=0.f;
    for (int c=lane; c<DD; c+=32){
        float hv = xr[c];
        float4 wb = *(const float4*)&Wb[c*4];
        float4 wd = *(const float4*)&Wdec[c*4];
        float4 wm = *(const float4*)&Wmix[c*4];
        a[0]+=hv*wb.x; a[1]+=hv*wb.y; a[2]+=hv*wb.z; a[3]+=hv*wb.w;
        a[4]+=hv*wd.x; a[5]+=hv*wd.y; a[6]+=hv*wd.z; a[7]+=hv*wd.w;
        a[8]+=hv*wm.x; a[9]+=hv*wm.y; a[10]+=hv*wm.z; a[11]+=hv*wm.w;
    }
    #pragma unroll
    for (int off=16; off; off>>=1){
        #pragma unroll
        for (int j=0;j<12;j++) a[j] += __shfl_down_sync(0xffffffffu, a[j], off);
    }
    if (lane == 0){
        #pragma unroll
        for (int j=0;j<4;j++){
            g_beta  [row*4+j] = sigm_f(a[j]);
            g_gamma [row*4+j] = sigm_f(a[4+j]);
            g_mixlin[row*4+j] = a[8+j];
        }
    }
}

// ---------------- causal short conv (K=4) + silu, all 3 tensors, float4 ------
__global__ void __launch_bounds__(256) conv_silu3_kernel(
    const float* __restrict__ convq, const float* __restrict__ convk,
    const float* __restrict__ convv)
{
    int z = blockIdx.y;
    const float* X  = (z==0) ? g_QL : (z==1 ? g_KL : g_VL);
    const float* Wc = (z==0) ? convq : (z==1 ? convk : convv);
    float* Y        = (z==0) ? g_Q : (z==1 ? g_K : g_V);
    int idx4 = blockIdx.x*256 + threadIdx.x;     // over NT*DD/4
    int ch  = (idx4 & 255) << 2;                 // channel base (0..1020)
    int bt  = idx4 >> 8;                         // token index
    int t   = bt & (LL-1);
    float4 acc = make_float4(0.f,0.f,0.f,0.f);
    #pragma unroll
    for (int k=0;k<4;k++){
        int ts = t-3+k;
        if (ts>=0){
            float4 xv = *(const float4*)&X[(size_t)(bt + (ts-t))*DD + ch];
            acc.x += xv.x * Wc[(ch+0)*4+k];
            acc.y += xv.y * Wc[(ch+1)*4+k];
            acc.z += xv.z * Wc[(ch+2)*4+k];
            acc.w += xv.w * Wc[(ch+3)*4+k];
        }
    }
    float4 y;
    y.x = silu_f(acc.x); y.y = silu_f(acc.y); y.z = silu_f(acc.z); y.w = silu_f(acc.w);
    if (z < 2){ y.x = silu_f(y.x); y.y = silu_f(y.y); y.z = silu_f(y.z); y.w = silu_f(y.w); }
    *(float4*)&Y[(size_t)bt*DD + ch] = y;
}

// ---------------- mix path: conv over H channels + silu + sigmoid(+bias) -----
__global__ void mixconv_kernel(const float* __restrict__ convmix,
                               const float* __restrict__ mixbias)
{
    int idx = blockIdx.x*blockDim.x + threadIdx.x;
    if (idx >= NT*HH) return;
    int h = idx & 3;
    int bt = idx >> 2;
    int t = bt & (LL-1);
    float acc = 0.f;
    #pragma unroll
    for (int k=0;k<4;k++){
        int ts = t-3+k;
        if (ts>=0) acc += g_mixlin[idx + (ts-t)*HH] * convmix[h*4+k];
    }
    float mi = silu_f(acc);
    g_mixg[idx] = sigm_f(mi + mixbias[h]);
}

// ---------------- l2 norm + bf16 limb emission: warp per (row,head) ----------
__global__ void __launch_bounds__(256) l2norm_kernel()
{
    int wid = threadIdx.x >> 5, lane = threadIdx.x & 31;
    int g = blockIdx.x*8 + wid;
    int row = g >> 2, h = g & 3;
    size_t base = (size_t)row*DD + h*DK;

    {
        float4 v0 = *(float4*)&g_Q[base + lane*4];
        float4 v1 = *(float4*)&g_Q[base + 128 + lane*4];
        float s = v0.x*v0.x+v0.y*v0.y+v0.z*v0.z+v0.w*v0.w
                + v1.x*v1.x+v1.y*v1.y+v1.z*v1.z+v1.w*v1.w;
        #pragma unroll
        for (int off=16; off; off>>=1) s += __shfl_xor_sync(0xffffffffu, s, off);
        float sc = rsqrtf(s + 1e-6f);
        v0.x*=sc; v0.y*=sc; v0.z*=sc; v0.w*=sc;
        v1.x*=sc; v1.y*=sc; v1.z*=sc; v1.w*=sc;
        *(float4*)&g_Q[base + lane*4] = v0;
        *(float4*)&g_Q[base + 128 + lane*4] = v1;
        split_store4(v0, &g_Qh[base + lane*4], &g_Ql[base + lane*4]);
        split_store4(v1, &g_Qh[base + 128 + lane*4], &g_Ql[base + 128 + lane*4]);
    }
    {
        float4 v0 = *(float4*)&g_K[base + lane*4];
        float4 v1 = *(float4*)&g_K[base + 128 + lane*4];
        float s = v0.x*v0.x+v0.y*v0.y+v0.z*v0.z+v0.w*v0.w
                + v1.x*v1.x+v1.y*v1.y+v1.z*v1.z+v1.w*v1.w;
        #pragma unroll
        for (int off=16; off; off>>=1) s += __shfl_xor_sync(0xffffffffu, s, off);
        float sc = rsqrtf(s + 1e-6f);
        v0.x*=sc; v0.y*=sc; v0.z*=sc; v0.w*=sc;
        v1.x*=sc; v1.y*=sc; v1.z*=sc; v1.w*=sc;
        *(float4*)&g_K[base + lane*4] = v0;
        *(float4*)&g_K[base + 128 + lane*4] = v1;
        split_store4(v0, &g_Kh[base + lane*4], &g_Kl[base + lane*4]);
        split_store4(v1, &g_Kh[base + 128 + lane*4], &g_Kl[base + 128 + lane*4]);
    }
}

// ---------------- per-chunk: T (tri inverse), W limbs, Attn ------------------
#define WP 260   // float stride for 32x256 tiles
#define SP 36    // float stride for 32x32 / 256x32 tiles

__global__ void __launch_bounds__(256) chunk_kernel()
{
    extern __shared__ float sm[];
    float* kc     = sm;                 // 32*WP
    float* qc     = kc + 32*WP;         // 32*WP
    float* Amat   = qc + 32*WP;         // 32*33
    float* bet    = Amat + 32*33;       // 32
    float* rowtmp = bet + 32;           // 32

    int blk = blockIdx.x;               // bh*64 + c
    int bh = blk >> 6, c = blk & 63;
    int b = bh >> 2, h = bh & 3;
    int tid = threadIdx.x;
    int rowbase = b*LL + c*CHK;

    for (int e = tid; e < 2048; e += 256){
        int r = e >> 6; int c4 = (e & 63) << 2;
        *(float4*)&kc[r*WP+c4] = *(const float4*)&g_K[(size_t)(rowbase+r)*DD + h*DK + c4];
        *(float4*)&qc[r*WP+c4] = *(const float4*)&g_Q[(size_t)(rowbase+r)*DD + h*DK + c4];
    }
    if (tid < 32) bet[tid] = g_beta[(rowbase+tid)*HH + h];
    __syncthreads();

    // A = -tril(k_beta @ k^T, -1),  Attn = tril(q @ k^T, 0)   [f32x2, pair over m]
    {
        int i = tid >> 3, j0 = tid & 7;
        u64t da[4], dq[4];
        #pragma unroll
        for (int u=0;u<4;u++){ da[u]=0ull; dq[u]=0ull; }
        #pragma unroll 4
        for (int m=0;m<256;m+=4){
            ulonglong2 ki = *(ulonglong2*)&kc[i*WP+m];
            ulonglong2 qi = *(ulonglong2*)&qc[i*WP+m];
            #pragma unroll
            for (int u=0;u<4;u++){
                ulonglong2 kj = *(ulonglong2*)&kc[(j0+8*u)*WP+m];
                da[u] = ffma2(ki.x, kj.x, da[u]);
                da[u] = ffma2(ki.y, kj.y, da[u]);
                dq[u] = ffma2(qi.x, kj.x, dq[u]);
                dq[u] = ffma2(qi.y, kj.y, dq[u]);
            }
        }
        #pragma unroll
        for (int u=0;u<4;u++){
            int j = j0 + 8*u;
            float2 ta = f2unpack(da[u]);
            float2 tq = f2unpack(dq[u]);
            float av = ta.x + ta.y, qv = tq.x + tq.y;
            Amat[i*33+j] = (j < i) ? -bet[i]*av : 0.f;
            g_At[(size_t)blk*1024 + i*32 + j] = (j <= i) ? qv : 0.f;
        }
    }
    __syncthreads();

    // sequential forward-substitution (warp 0)
    if (tid < 32){
        int cx = tid;
        for (int ii=1; ii<32; ii++){
            rowtmp[cx] = Amat[ii*33+cx];
            __syncwarp();
            float acc = 0.f;
            if (cx < ii){
                acc = rowtmp[cx];
                for (int j=cx+1; j<ii; j++) acc += rowtmp[j]*Amat[j*33+cx];
            }
            __syncwarp();
            if (cx < ii) Amat[ii*33+cx] = acc;
            __syncwarp();
        }
        Amat[cx*33+cx] = 1.0f;   // T = A + I
    }
    __syncthreads();

    for (int e=tid; e<1024; e+=256)
        g_T[(size_t)blk*1024 + e] = Amat[(e>>5)*33 + (e&31)];

    // W = T @ (beta * k)   [f32x2, pair over dk] -> write bf16 limbs directly
    {
        int i = tid >> 3, mb = (tid & 7) << 2;
        u64t acc[16];
        #pragma unroll
        for (int s=0;s<16;s++) acc[s]=0ull;
        for (int j=0;j<32;j++){
            u64t td = f2dup(Amat[i*33+j]*bet[j]);
            #pragma unroll
            for (int s=0;s<8;s++){
                ulonglong2 kv = *(ulonglong2*)&kc[j*WP + s*32 + mb];
                acc[2*s]   = ffma2(td, kv.x, acc[2*s]);
                acc[2*s+1] = ffma2(td, kv.y, acc[2*s+1]);
            }
        }
        #pragma unroll
        for (int s=0;s<8;s++){
            float2 p0 = f2unpack(acc[2*s]), p1 = f2unpack(acc[2*s+1]);
            float4 wv; wv.x = p0.x; wv.y = p0.y; wv.z = p1.x; wv.w = p1.y;
            size_t go = ((size_t)blk*32 + i)*DK + s*32 + mb;
            split_store4(wv, &g_Wh[go], &g_Wl[go]);
        }
    }
}

// ---------------- inter-chunk scan: tensor-core (bf16 3-limb) version --------
// grid: 128 blocks = 16 (b,h) x 8 dv-slabs of 32 columns; 256 threads.
#define SBP 40    // bf16 stride for S / ua limb tiles (80 B rows)
#define WQP 264   // bf16 stride for wq / kt limb tiles (528 B rows)

__global__ void __launch_bounds__(256,1) scan_kernel()
{
    extern __shared__ char sraw[];
    float* S32   = (float*)sraw;              // 256*36
    float* P32   = S32  + 256*36;             // 64*36
    float* att32 = P32  + 64*36;              // 32*36
    float* T32   = att32+ 32*36;              // 32*36
    float* vb32  = T32  + 32*36;              // 32*36
    float* ua32  = vb32 + 32*36;              // 32*36
    __nv_bfloat16* S_hi  = (__nv_bfloat16*)(ua32 + 32*36);
    __nv_bfloat16* S_lo  = S_hi  + 256*SBP;
    __nv_bfloat16* wq_hi = S_lo  + 256*SBP;   // 64 rows (w:0-31, q:32-63)
    __nv_bfloat16* wq_lo = wq_hi + 64*WQP;
    __nv_bfloat16* kt_hi = wq_lo + 64*WQP;    // 32 rows
    __nv_bfloat16* kt_lo = kt_hi + 32*WQP;
    __nv_bfloat16* ua_hi = kt_lo + 32*WQP;    // 32 rows
    __nv_bfloat16* ua_lo = ua_hi + 32*SBP;

    const int tid  = threadIdx.x;
    const int lane = tid & 31, wid = tid >> 5;
    const int bh   = blockIdx.x >> 3;
    const int slab = blockIdx.x & 7;
    const int b = bh >> 2, h = bh & 3;
    const size_t ocol = (size_t)h*DK + slab*32;

    const uint32_t u_S_hi  = smem_u32(S_hi),  u_S_lo  = smem_u32(S_lo);
    const uint32_t u_wq_hi = smem_u32(wq_hi), u_wq_lo = smem_u32(wq_lo);
    const uint32_t u_kt_hi = smem_u32(kt_hi), u_kt_lo = smem_u32(kt_lo);
    const uint32_t u_ua_hi = smem_u32(ua_hi), u_ua_lo = smem_u32(ua_lo);

    // init S and its limbs
    for (int e=tid; e<256*36; e+=256) S32[e]=0.f;
    for (int e=tid; e<256*SBP; e+=256){
        ((uint16_t*)S_hi)[e] = 0; ((uint16_t*)S_lo)[e] = 0;
    }
    __syncthreads();

    const int i  = tid >> 3;          // scalar stage: row 0..31
    const int jb = (tid & 7) << 2;    // scalar stage: col base

    // stage-A lane geometry
    const int wmA = wid & 3, wnA = wid >> 2;
    const int aArow = wmA*16 + (lane & 15);
    const int aAcb  = ((lane >> 4) & 1) << 3;
    const int bArow = (lane & 15);
    const int bAcb  = wnA*16 + (((lane >> 4) & 1) << 3);
    // stage-B lane geometry
    const int aBrow = (lane & 7) + (((lane >> 4) & 1) << 3);
    const int aBcb  = ((lane >> 3) & 1) << 3;
    const int bBrow = (lane & 15);
    const int cr = lane >> 2, cc = (lane & 3) << 1;

    for (int c=0; c<NCHUNK; c++){
        int blk = bh*NCHUNK + c;
        int rowbase = b*LL + c*CHK;

        // ---- pure limb copies (no conversion): 4 iters x 6 tiles of float4
        for (int e=tid; e<1024; e+=256){
            int r = e >> 5;              // 0..31
            int cx = (e & 31) << 3;      // bf16 col base, 16B chunks
            size_t gw = ((size_t)blk*32 + r)*DK + cx;
            size_t gq = (size_t)(rowbase+r)*DD + h*DK + cx;
            *(float4*)&wq_hi[r*WQP+cx]      = *(const float4*)&g_Wh[gw];
            *(float4*)&wq_lo[r*WQP+cx]      = *(const float4*)&g_Wl[gw];
            *(float4*)&wq_hi[(32+r)*WQP+cx] = *(const float4*)&g_Qh[gq];
            *(float4*)&wq_lo[(32+r)*WQP+cx] = *(const float4*)&g_Ql[gq];
            *(float4*)&kt_hi[r*WQP+cx]      = *(const float4*)&g_Kh[gq];
            *(float4*)&kt_lo[r*WQP+cx]      = *(const float4*)&g_Kl[gq];
        }
        {
            int r = tid >> 3, c4 = (tid & 7) << 2;
            *(float4*)&att32[r*SP+c4] = *(const float4*)&g_At[(size_t)blk*1024 + r*32 + c4];
            *(float4*)&T32 [r*SP+c4]  = *(const float4*)&g_T [(size_t)blk*1024 + r*32 + c4];
            float be = g_beta[(rowbase+r)*HH + h];
            float4 vv = *(const float4*)&g_V[(size_t)(rowbase+r)*DD + ocol + c4];
            vv.x*=be; vv.y*=be; vv.z*=be; vv.w*=be;
            *(float4*)&vb32[r*SP+c4] = vv;
        }
        __syncthreads();

        // ---- stage A: P = [w|q] @ S  (M=64, N=32, K=256), bf16 3-limb
        {
            float acc[2][4];
            #pragma unroll
            for (int n8=0;n8<2;n8++)
                #pragma unroll
                for (int u=0;u<4;u++) acc[n8][u]=0.f;
            #pragma unroll 4
            for (int k16=0;k16<16;k16++){
                uint32_t ah[4], al[4], bh_[4], bl_[4];
                uint32_t aofs = (uint32_t)(aArow*WQP + k16*16 + aAcb)*2;
                LDSM_X4(ah[0],ah[1],ah[2],ah[3], u_wq_hi + aofs);
                LDSM_X4(al[0],al[1],al[2],al[3], u_wq_lo + aofs);
                uint32_t bofs = (uint32_t)((k16*16 + bArow)*SBP + bAcb)*2;
                LDSM_X4_T(bh_[0],bh_[1],bh_[2],bh_[3], u_S_hi + bofs);
                LDSM_X4_T(bl_[0],bl_[1],bl_[2],bl_[3], u_S_lo + bofs);
                MMABF16(acc[0], ah, bh_[0], bh_[1]);
                MMABF16(acc[1], ah, bh_[2], bh_[3]);
                MMABF16(acc[0], ah, bl_[0], bl_[1]);
                MMABF16(acc[1], ah, bl_[2], bl_[3]);
                MMABF16(acc[0], al, bh_[0], bh_[1]);
                MMABF16(acc[1], al, bh_[2], bh_[3]);
            }
            #pragma unroll
            for (int n8=0;n8<2;n8++){
                int col = wnA*16 + n8*8 + cc;
                P32[(wmA*16+cr  )*SP + col  ] = acc[n8][0];
                P32[(wmA*16+cr  )*SP + col+1] = acc[n8][1];
                P32[(wmA*16+cr+8)*SP + col  ] = acc[n8][2];
                P32[(wmA*16+cr+8)*SP + col+1] = acc[n8][3];
            }
        }
        __syncthreads();

        // ---- scalar: u = T@vb ; ua = u - P_w ; ua limbs
        {
            u64t ui0=0ull, ui1=0ull;
            #pragma unroll
            for (int m=0;m<32;m++){
                u64t td = f2dup(T32[i*SP+m]);
                ulonglong2 vv = *(ulonglong2*)&vb32[m*SP+jb];
                ui0 = ffma2(td, vv.x, ui0);
                ui1 = ffma2(td, vv.y, ui1);
            }
            float2 u01 = f2unpack(ui0), u23 = f2unpack(ui1);
            float4 pw = *(float4*)&P32[i*SP+jb];
            float4 uav;
            uav.x = u01.x - pw.x; uav.y = u01.y - pw.y;
            uav.z = u23.x - pw.z; uav.w = u23.y - pw.w;
            *(float4*)&ua32[i*SP+jb] = uav;
            split_store4(uav, &ua_hi[i*SBP+jb], &ua_lo[i*SBP+jb]);
        }
        __syncthreads();

        // ---- scalar: o = P_q + att @ ua  -> global
        {
            float4 pq = *(float4*)&P32[(32+i)*SP+jb];
            u64t aO0 = f2pack(pq.x, pq.y), aO1 = f2pack(pq.z, pq.w);
            #pragma unroll
            for (int m=0;m<32;m++){
                u64t ad = f2dup(att32[i*SP+m]);
                ulonglong2 uv = *(ulonglong2*)&ua32[m*SP+jb];
                aO0 = ffma2(ad, uv.x, aO0);
                aO1 = ffma2(ad, uv.y, aO1);
            }
            ulonglong2 ov; ov.x = aO0; ov.y = aO1;
            *(ulonglong2*)&g_Od[(size_t)(rowbase+i)*DD + ocol + jb] = ov;
        }

        // ---- stage B: dS = k^T @ ua  (M=256 over 8 warps, N=32, K=32)
        {
            float acc[2][4][4];
            #pragma unroll
            for (int mt=0;mt<2;mt++)
                #pragma unroll
                for (int n8=0;n8<4;n8++)
                    #pragma unroll
                    for (int u=0;u<4;u++) acc[mt][n8][u]=0.f;
            #pragma unroll
            for (int kk=0;kk<2;kk++){
                uint32_t bh0[4], bl0[4], bh1[4], bl1[4];
                uint32_t bofs0 = (uint32_t)((kk*16 + bBrow)*SBP + (((lane>>4)&1)<<3))*2;
                uint32_t bofs1 = bofs0 + 16*2;
                LDSM_X4_T(bh0[0],bh0[1],bh0[2],bh0[3], u_ua_hi + bofs0);
                LDSM_X4_T(bl0[0],bl0[1],bl0[2],bl0[3], u_ua_lo + bofs0);
                LDSM_X4_T(bh1[0],bh1[1],bh1[2],bh1[3], u_ua_hi + bofs1);
                LDSM_X4_T(bl1[0],bl1[1],bl1[2],bl1[3], u_ua_lo + bofs1);
                #pragma unroll
                for (int mt=0;mt<2;mt++){
                    int D0 = wid*32 + mt*16;
                    uint32_t ah[4], al[4];
                    uint32_t aofs = (uint32_t)((kk*16 + aBrow)*WQP + D0 + aBcb)*2;
                    LDSM_X4_T(ah[0],ah[1],ah[2],ah[3], u_kt_hi + aofs);
                    LDSM_X4_T(al[0],al[1],al[2],al[3], u_kt_lo + aofs);
                    MMABF16(acc[mt][0], ah, bh0[0], bh0[1]);
                    MMABF16(acc[mt][1], ah, bh0[2], bh0[3]);
                    MMABF16(acc[mt][2], ah, bh1[0], bh1[1]);
                    MMABF16(acc[mt][3], ah, bh1[2], bh1[3]);
                    MMABF16(acc[mt][0], ah, bl0[0], bl0[1]);
                    MMABF16(acc[mt][1], ah, bl0[2], bl0[3]);
                    MMABF16(acc[mt][2], ah, bl1[0], bl1[1]);
                    MMABF16(acc[mt][3], ah, bl1[2], bl1[3]);
                    MMABF16(acc[mt][0], al, bh0[0], bh0[1]);
                    MMABF16(acc[mt][1], al, bh0[2], bh0[3]);
                    MMABF16(acc[mt][2], al, bh1[0], bh1[1]);
                    MMABF16(acc[mt][3], al, bh1[2], bh1[3]);
                }
            }
            #pragma unroll
            for (int mt=0;mt<2;mt++){
                int r0 = wid*32 + mt*16 + cr;
                #pragma unroll
                for (int n8=0;n8<4;n8++){
                    int col = n8*8 + cc;
                    S32[(r0  )*SP + col  ] += acc[mt][n8][0];
                    S32[(r0  )*SP + col+1] += acc[mt][n8][1];
                    S32[(r0+8)*SP + col  ] += acc[mt][n8][2];
                    S32[(r0+8)*SP + col+1] += acc[mt][n8][3];
                }
            }
        }
        __syncwarp();
        // ---- refresh S limbs for own row
        #pragma unroll
        for (int c4=0;c4<32;c4+=4){
            float4 sv = *(float4*)&S32[tid*SP + c4];
            split_store4(sv, &S_hi[tid*SBP+c4], &S_lo[tid*SBP+c4]);
        }
        __syncthreads();
    }
}

// ---------------- EMA phase 1: segmented local scan --------------------------
__global__ void __launch_bounds__(256) ema_local_kernel()
{
    extern __shared__ float esm[];
    float* cbuf = esm;             // ESEG*256
    float* gbuf = cbuf + ESEG*256; // ESEG
    float* Ps   = gbuf + ESEG;     // ESEG

    int bh = blockIdx.x, seg = blockIdx.y;
    int b = bh >> 2, h = bh & 3;
    int tid = threadIdx.x;
    int rowbase = b*LL + seg*ESEG;
    size_t hcol = (size_t)h*DK;

    if (tid < ESEG) gbuf[tid] = g_gamma[(rowbase+tid)*HH + h];
    __syncthreads();

    for (int e = tid; e < ESEG*64; e += 256){
        int r = e >> 6, c4 = (e & 63) << 2;
        float om = 1.f - gbuf[r];
        float4 vv = *(const float4*)&g_V[(size_t)(rowbase+r)*DD + hcol + c4];
        vv.x*=om; vv.y*=om; vv.z*=om; vv.w*=om;
        *(float4*)&cbuf[r*256 + c4] = vv;
    }
    if (tid < ESEG){
        int lane = tid & 31;
        float p = gbuf[tid];
        #pragma unroll
        for (int off=1; off<32; off<<=1){
            float o = __shfl_up_sync(0xffffffffu, p, off);
            if (lane >= off) p *= o;
        }
        Ps[tid] = p;
    }
    __syncthreads();
    if (tid < ESEG){
        int wmy = tid >> 5;
        float pre = 1.f;
        for (int wq = 0; wq < wmy; wq++) pre *= Ps[wq*32+31];
        g_P[bh*LL + seg*ESEG + tid] = pre * Ps[tid];
    }

    float s = 0.f;
    #pragma unroll 8
    for (int t = 0; t < ESEG; t++){
        s = fmaf(gbuf[t], s, cbuf[t*256 + tid]);
        cbuf[t*256 + tid] = s;
    }
    __syncthreads();

    for (int e = tid; e < ESEG*64; e += 256){
        int r = e >> 6, c4 = (e & 63) << 2;
        *(float4*)&g_Oe[(size_t)(rowbase+r)*DD + hcol + c4] = *(float4*)&cbuf[r*256 + c4];
    }
}

// ---------------- EMA phase 2: carry across segments -------------------------
__global__ void __launch_bounds__(256) ema_carry_kernel()
{
    int bh = blockIdx.x;
    int b = bh >> 2, h = bh & 3;
    int dv = threadIdx.x;
    float s = 0.f;
    #pragma unroll
    for (int seg = 0; seg < NSEG; seg++){
        g_C[(bh*NSEG + seg)*DK + dv] = s;
        int rend = b*LL + seg*ESEG + (ESEG-1);
        float P  = g_P[bh*LL + seg*ESEG + (ESEG-1)];
        float ye = g_Oe[(size_t)rend*DD + h*DK + dv];
        s = fmaf(P, s, ye);
    }
}

// ---------------- mix combine + RMS norm + fp16 split (fused, + ema carry) ---
__global__ void __launch_bounds__(256) combine_rms_kernel(const float* __restrict__ rmsw)
{
    int wid = threadIdx.x >> 5, lane = threadIdx.x & 31;
    int g = blockIdx.x*8 + wid;
    int row = g >> 2, h = g & 3;
    int b = row >> 11, t = row & (LL-1);
    int bh = b*4 + h, seg = t >> 7;
    float m = g_mixg[row*4+h];
    size_t base = (size_t)row*DD + h*DK;

    float P = g_P[bh*LL + t];
    const float* cav = &g_C[(bh*NSEG + seg)*DK];
    float4 c0 = *(const float4*)&cav[lane*4];
    float4 c1 = *(const float4*)&cav[128 + lane*4];

    float4 d0 = *(float4*)&g_Od[base + lane*4];
    float4 d1 = *(float4*)&g_Od[base + 128 + lane*4];
    float4 e0 = *(float4*)&g_Oe[base + lane*4];
    float4 e1 = *(float4*)&g_Oe[base + 128 + lane*4];
    e0.x += P*c0.x; e0.y += P*c0.y; e0.z += P*c0.z; e0.w += P*c0.w;
    e1.x += P*c1.x; e1.y += P*c1.y; e1.z += P*c1.z; e1.w += P*c1.w;

    float4 o0, o1;
    float om = 1.f - m;
    o0.x = om*d0.x + m*e0.x; o0.y = om*d0.y + m*e0.y;
    o0.z = om*d0.z + m*e0.z; o0.w = om*d0.w + m*e0.w;
    o1.x = om*d1.x + m*e1.x; o1.y = om*d1.y + m*e1.y;
    o1.z = om*d1.z + m*e1.z; o1.w = om*d1.w + m*e1.w;
    float s = o0.x*o0.x+o0.y*o0.y+o0.z*o0.z+o0.w*o0.w
            + o1.x*o1.x+o1.y*o1.y+o1.z*o1.z+o1.w*o1.w;
    #pragma unroll
    for (int off=16; off; off>>=1) s += __shfl_xor_sync(0xffffffffu, s, off);
    float sc = rsqrtf(s*(1.f/256.f) + 1e-5f);
    float4 r0 = *(const float4*)&rmsw[lane*4];
    float4 r1 = *(const float4*)&rmsw[128 + lane*4];
    o0.x *= sc*r0.x; o0.y *= sc*r0.y; o0.z *= sc*r0.z; o0.w *= sc*r0.w;
    o1.x *= sc*r1.x; o1.y *= sc*r1.y; o1.z *= sc*r1.z; o1.w *= sc*r1.w;

    __half h4[4], l4[4];
    float v[4];
    v[0]=o0.x; v[1]=o0.y; v[2]=o0.z; v[3]=o0.w;
    #pragma unroll
    for (int u=0;u<4;u++){
        h4[u]=__float2half_rn(v[u]);
        l4[u]=__float2half_rn(v[u]-__half2float(h4[u]));
    }
    *(u64t*)&g_Op_hi[base + lane*4] = *(u64t*)h4;
    *(u64t*)&g_Op_lo[base + lane*4] = *(u64t*)l4;
    v[0]=o1.x; v[1]=o1.y; v[2]=o1.z; v[3]=o1.w;
    #pragma unroll
    for (int u=0;u<4;u++){
        h4[u]=__float2half_rn(v[u]);
        l4[u]=__float2half_rn(v[u]-__half2float(h4[u]));
    }
    *(u64t*)&g_Op_hi[base + 128 + lane*4] = *(u64t*)h4;
    *(u64t*)&g_Op_lo[base + 128 + lane*4] = *(u64t*)l4;
}

// ---------------- host driver -----------------------------------------------
extern "C" void kernel_launch(void* const* d_in, const int* in_sizes, int n_in,
                              void* d_out, int out_size)
{
    const float* hs      = (const float*)d_in[0];
    const float* Wq      = (const float*)d_in[1];
    const float* Wk      = (const float*)d_in[2];
    const float* Wv      = (const float*)d_in[3];
    const float* convq   = (const float*)d_in[4];
    const float* convk   = (const float*)d_in[5];
    const float* convv   = (const float*)d_in[6];
    const float* Wb      = (const float*)d_in[7];
    const float* Wdec    = (const float*)d_in[8];
    const float* Wmix    = (const float*)d_in[9];
    const float* convmix = (const float*)d_in[10];
    const float* mixbias = (const float*)d_in[11];
    const float* rmsw    = (const float*)d_in[12];
    const float* Wo      = (const float*)d_in[13];

    void *pQL,*pKL,*pVL;
    cudaGetSymbolAddress(&pQL, g_QL);
    cudaGetSymbolAddress(&pKL, g_KL);
    cudaGetSymbolAddress(&pVL, g_VL);

    void *p_hs_hi,*p_hs_lo,*p_Op_hi,*p_Op_lo,*p_WT_h,*p_WoT_h;
    cudaGetSymbolAddress(&p_hs_hi, g_hs_hi);  cudaGetSymbolAddress(&p_hs_lo, g_hs_lo);
    cudaGetSymbolAddress(&p_Op_hi, g_Op_hi);  cudaGetSymbolAddress(&p_Op_lo, g_Op_lo);
    cudaGetSymbolAddress(&p_WT_h, g_WT_h);    cudaGetSymbolAddress(&p_WoT_h, g_WoT_h);

    int smem_chunk = (2*32*WP + 32*33 + 64) * 4;
    int smem_scan  = (256*36 + 64*36 + 4*32*36)*4
                   + (2*256*SBP + 2*64*WQP + 2*32*WQP + 2*32*SBP)*2;
    int smem_gemm  = NSTG*STGB;
    int smem_ema   = (ESEG*256 + 2*ESEG) * 4;
    cudaFuncSetAttribute(chunk_kernel, cudaFuncAttributeMaxDynamicSharedMemorySize, smem_chunk);
    cudaFuncSetAttribute(scan_kernel,  cudaFuncAttributeMaxDynamicSharedMemorySize, smem_scan);
    cudaFuncSetAttribute(gemm_f16s,    cudaFuncAttributeMaxDynamicSharedMemorySize, smem_gemm);
    cudaFuncSetAttribute(ema_local_kernel, cudaFuncAttributeMaxDynamicSharedMemorySize, smem_ema);

    // 1: split activations to fp16 limbs
    split_kernel<<<NT*DD/4/256,256>>>(hs, (__half*)p_hs_hi, (__half*)p_hs_lo);
    // 2: weight transposes to fp16
    dim3 wg(32,32,4), wb(32,8);
    wsplit_all_kernel<<<wg,wb>>>(Wq, Wk, Wv, Wo, (__half*)p_WT_h, (__half*)p_WoT_h);
    // 3: small projections
    smallproj_kernel<<<NT/8,256>>>(hs, Wb, Wdec, Wmix);

    // 4: merged QKV GEMM (1536 CTAs)
    gemm_f16s<<<dim3(24,64),256,smem_gemm>>>(
        (__half*)p_hs_hi,(__half*)p_hs_lo,(__half*)p_WT_h,
        (float*)pQL, (float*)pKL, (float*)pVL, DD);

    conv_silu3_kernel<<<dim3(NT*DD/4/256,3),256>>>(convq, convk, convv);
    mixconv_kernel<<<(NT*HH+127)/128,128>>>(convmix, mixbias);

    l2norm_kernel<<<NT*HH/8,256>>>();
    chunk_kernel<<<NBH*NCHUNK,256,smem_chunk>>>();
    scan_kernel<<<NBH*8,256,smem_scan>>>();

    ema_local_kernel<<<dim3(NBH,NSEG),256,smem_ema>>>();
    ema_carry_kernel<<<NBH,DK>>>();

    combine_rms_kernel<<<NT*HH/8,256>>>(rmsw);

    gemm_f16s<<<dim3(8,64),256,smem_gemm>>>(
        (__half*)p_Op_hi,(__half*)p_Op_lo,(__half*)p_WoT_h,
        (float*)d_out, (float*)d_out, (float*)d_out, DD);
}

// round 12
// speedup vs baseline: 3.5523x; 1.0196x over previous
#include <cuda_runtime.h>
#include <cuda_bf16.h>
#include <cuda_fp16.h>
#include <math.h>
#include <stdint.h>

// Problem constants
#define BB 4
#define LL 2048
#define DD 1024
#define HH 4
#define DK 256
#define NT (BB*LL)       // 8192 tokens
#define NCHUNK 64        // chunks per sequence
#define CHK 32           // chunk length
#define NBH 16           // B*H
#define ESEG 128         // ema segment length
#define NSEG (LL/ESEG)   // 16

typedef unsigned long long u64t;

// ---------------- scratch (device globals; no allocation allowed) -------------
__device__ float g_QL[NT*DD];
__device__ float g_KL[NT*DD];
__device__ float g_VL[NT*DD];
__device__ float g_Q[NT*DD];
__device__ float g_K[NT*DD];
__device__ float g_V[NT*DD];
__device__ float g_beta[NT*HH];
__device__ float g_gamma[NT*HH];
__device__ float g_mixlin[NT*HH];
__device__ float g_mixg[NT*HH];
__device__ float g_T[NBH*NCHUNK*CHK*CHK];    // triangular inverse T
__device__ float g_At[NBH*NCHUNK*CHK*CHK];   // attn_i = tril(q@k^T)
__device__ float g_Od[NT*DD];                // delta-rule output
__device__ float g_Oe[NT*DD];                // ema LOCAL output (y_t)
__device__ float g_P[NBH*LL];                // in-segment prefix products of gamma
__device__ float g_C[NBH*NSEG*DK];           // carry state at segment start

// bf16 limb arrays for the scan's tensor-core stages
__device__ __nv_bfloat16 g_Qh[NT*DD], g_Ql[NT*DD];
__device__ __nv_bfloat16 g_Kh[NT*DD], g_Kl[NT*DD];
__device__ __nv_bfloat16 g_Wh[NBH*NCHUNK*CHK*DK], g_Wl[NBH*NCHUNK*CHK*DK];

// fp16 limb buffers for tensor-core GEMMs (A: 2 limbs; B: single fp16)
__device__ __half g_hs_hi[NT*DD], g_hs_lo[NT*DD];
__device__ __half g_Op_hi[NT*DD], g_Op_lo[NT*DD];
__device__ __half g_WT_h[3*DD*DD];           // Wq|Wk|Wv transposed, fp16
__device__ __half g_WoT_h[DD*DD];            // Wo transposed, fp16

__device__ __forceinline__ float silu_f(float x){ return x / (1.f + expf(-x)); }
__device__ __forceinline__ float sigm_f(float x){ return 1.f / (1.f + expf(-x)); }

// ===================== f32x2 packed-math helpers =============================
__device__ __forceinline__ u64t f2dup(float x){
    u64t r; unsigned int xi = __float_as_uint(x);
    asm("mov.b64 %0, {%1,%1};" : "=l"(r) : "r"(xi));
    return r;
}
__device__ __forceinline__ u64t f2pack(float x, float y){
    u64t r;
    asm("mov.b64 %0, {%1,%2};" : "=l"(r) : "r"(__float_as_uint(x)), "r"(__float_as_uint(y)));
    return r;
}
__device__ __forceinline__ u64t ffma2(u64t a, u64t b, u64t c){
    u64t d; asm("fma.rn.f32x2 %0, %1, %2, %3;" : "=l"(d) : "l"(a), "l"(b), "l"(c));
    return d;
}
__device__ __forceinline__ float2 f2unpack(u64t p){
    unsigned int lo, hi;
    asm("mov.b64 {%0,%1}, %2;" : "=r"(lo), "=r"(hi) : "l"(p));
    return make_float2(__uint_as_float(lo), __uint_as_float(hi));
}

// ===================== PTX helpers (mma.sync / ldmatrix / cp.async) ==========
__device__ __forceinline__ uint32_t smem_u32(const void* p){
    uint32_t a;
    asm("{ .reg .u64 t; cvta.to.shared.u64 t, %1; cvt.u32.u64 %0, t; }" : "=r"(a) : "l"(p));
    return a;
}
__device__ __forceinline__ void cp_async16(uint32_t dst, const void* src){
    asm volatile("cp.async.cg.shared.global [%0], [%1], 16;" :: "r"(dst), "l"(src) : "memory");
}
__device__ __forceinline__ void cp_commit(){ asm volatile("cp.async.commit_group;" ::: "memory"); }

#define LDSM_X4(r0,r1,r2,r3, addr) \
    asm volatile("ldmatrix.sync.aligned.m8n8.x4.shared.b16 {%0,%1,%2,%3}, [%4];" \
        : "=r"(r0),"=r"(r1),"=r"(r2),"=r"(r3) : "r"(addr))

#define LDSM_X4_T(r0,r1,r2,r3, addr) \
    asm volatile("ldmatrix.sync.aligned.m8n8.x4.trans.shared.b16 {%0,%1,%2,%3}, [%4];" \
        : "=r"(r0),"=r"(r1),"=r"(r2),"=r"(r3) : "r"(addr))

#define MMAF16(d, a, b0, b1) \
    asm volatile("mma.sync.aligned.m16n8k16.row.col.f32.f16.f16.f32 " \
        "{%0,%1,%2,%3}, {%4,%5,%6,%7}, {%8,%9}, {%0,%1,%2,%3};" \
        : "+f"((d)[0]),"+f"((d)[1]),"+f"((d)[2]),"+f"((d)[3]) \
        : "r"((a)[0]),"r"((a)[1]),"r"((a)[2]),"r"((a)[3]), "r"(b0),"r"(b1))

#define MMABF16(d, a, b0, b1) \
    asm volatile("mma.sync.aligned.m16n8k16.row.col.f32.bf16.bf16.f32 " \
        "{%0,%1,%2,%3}, {%4,%5,%6,%7}, {%8,%9}, {%0,%1,%2,%3};" \
        : "+f"((d)[0]),"+f"((d)[1]),"+f"((d)[2]),"+f"((d)[3]) \
        : "r"((a)[0]),"r"((a)[1]),"r"((a)[2]),"r"((a)[3]), "r"(b0),"r"(b1))

// bf16 hi/lo split-store of a float4 (4B-aligned destinations)
__device__ __forceinline__ void split_store4(float4 v, __nv_bfloat16* ph, __nv_bfloat16* pl){
    __nv_bfloat162 h01, h23, l01, l23;
    h01.x = __float2bfloat16(v.x); h01.y = __float2bfloat16(v.y);
    h23.x = __float2bfloat16(v.z); h23.y = __float2bfloat16(v.w);
    l01.x = __float2bfloat16(v.x - __bfloat162float(h01.x));
    l01.y = __float2bfloat16(v.y - __bfloat162float(h01.y));
    l23.x = __float2bfloat16(v.z - __bfloat162float(h23.x));
    l23.y = __float2bfloat16(v.w - __bfloat162float(h23.y));
    *(__nv_bfloat162*)(ph)   = h01; *(__nv_bfloat162*)(ph+2) = h23;
    *(__nv_bfloat162*)(pl)   = l01; *(__nv_bfloat162*)(pl+2) = l23;
}
__device__ __forceinline__ void split_store2(float2 v, __nv_bfloat16* ph, __nv_bfloat16* pl){
    __nv_bfloat162 h01, l01;
    h01.x = __float2bfloat16(v.x); h01.y = __float2bfloat16(v.y);
    l01.x = __float2bfloat16(v.x - __bfloat162float(h01.x));
    l01.y = __float2bfloat16(v.y - __bfloat162float(h01.y));
    *(__nv_bfloat162*)(ph) = h01;
    *(__nv_bfloat162*)(pl) = l01;
}

// ===================== split/transpose conversion kernels ====================
__global__ void __launch_bounds__(256) split_kernel(const float* __restrict__ X,
                             __half* __restrict__ hi,
                             __half* __restrict__ lo)
{
    int i4 = blockIdx.x*256 + threadIdx.x;   // over NT*DD/4
    float4 v = *(const float4*)&X[(size_t)i4*4];
    __half h[4], l[4];
    float a[4] = {v.x, v.y, v.z, v.w};
    #pragma unroll
    for (int u=0;u<4;u++){
        h[u] = __float2half_rn(a[u]);
        l[u] = __float2half_rn(a[u] - __half2float(h[u]));
    }
    *(u64t*)&hi[(size_t)i4*4] = *(u64t*)h;
    *(u64t*)&lo[(size_t)i4*4] = *(u64t*)l;
}
// 4 weights transposed to fp16; Wq/Wk/Wv into combined [3072,1024], Wo separate.
__global__ void wsplit_all_kernel(const float* __restrict__ W0, const float* __restrict__ W1,
                                  const float* __restrict__ W2, const float* __restrict__ W3,
                                  __half* __restrict__ bigh, __half* __restrict__ woh)
{
    __shared__ float t[32][33];
    const float* W; __half* hiT;
    int z = blockIdx.z;
    if      (z==0){ W=W0; hiT=bigh; }
    else if (z==1){ W=W1; hiT=bigh+DD*DD; }
    else if (z==2){ W=W2; hiT=bigh+2*DD*DD; }
    else          { W=W3; hiT=woh; }
    int n0 = blockIdx.x*32, k0 = blockIdx.y*32;
    int tx = threadIdx.x, ty = threadIdx.y;   // 32 x 8
    for (int i = ty; i < 32; i += 8)
        t[i][tx] = W[(size_t)(k0+i)*DD + n0+tx];
    __syncthreads();
    for (int i = ty; i < 32; i += 8)
        hiT[(size_t)(n0+i)*DD + k0+tx] = __float2half_rn(t[tx][i]);
}

// ===================== mma.sync fp16 2-limb GEMM =============================
#define GRS 40            // smem row stride in fp16 elements (80 bytes)
#define MATB (128*GRS*2)  // 10240 bytes per matrix tile
#define STGB (3*MATB)     // 30720 per stage (Ahi, Alo, B)
#define NSTG 3

__global__ void __launch_bounds__(256,2) gemm_f16s(
    const __half* __restrict__ Ahi, const __half* __restrict__ Alo,
    const __half* __restrict__ BT,
    float* C0, float* C1, float* C2, int K)
{
    extern __shared__ char smem[];
    const uint32_t sbase = smem_u32(smem);
    const int tid  = threadIdx.x;
    const int lane = tid & 31, wid = tid >> 5;
    const int wm = wid & 3, wn = wid >> 2;          // 4x2 warp grid
    const int row0 = blockIdx.y*128;
    const int bcol = blockIdx.x*128;                // into B (up to 3072 wide)
    const int seg  = blockIdx.x >> 3;
    const int col0 = (blockIdx.x & 7)*128;          // into C
    float* C = (seg==0) ? C0 : (seg==1 ? C1 : C2);

    const __half* g0 = Ahi + (size_t)row0*K;
    const __half* g1 = Alo + (size_t)row0*K;
    const __half* g2 = BT  + (size_t)bcol*K;

    float acc[2][8][4];
    #pragma unroll
    for (int i=0;i<2;i++)
        #pragma unroll
        for (int j=0;j<8;j++)
            #pragma unroll
            for (int u=0;u<4;u++) acc[i][j][u]=0.f;

    auto fill = [&](int kb){
        uint32_t sb = sbase + (kb%NSTG)*STGB;
        #pragma unroll
        for (int t=0;t<2;t++){
            int ci = tid + t*256;
            int r = ci >> 2, c = ci & 3;
            uint32_t dst = sb + r*(GRS*2) + c*16;
            size_t go = (size_t)r*K + (size_t)kb*32 + c*8;
            cp_async16(dst + 0*MATB, g0 + go);
            cp_async16(dst + 1*MATB, g1 + go);
            cp_async16(dst + 2*MATB, g2 + go);
        }
        cp_commit();
    };

    const int nkb = K/32;
    fill(0);
    fill(1);

    const int a_r  = lane & 15;
    const int a_ko = ((lane >> 4) & 1) << 3;
    const int b_n  = (lane & 7) + (((lane >> 4) & 1) << 3);
    const int b_ko = ((lane >> 3) & 1) << 3;

    for (int kb = 0; kb < nkb; kb++){
        if (kb+1 < nkb) asm volatile("cp.async.wait_group 1;" ::: "memory");
        else            asm volatile("cp.async.wait_group 0;" ::: "memory");
        __syncthreads();

        uint32_t sb = sbase + (kb%NSTG)*STGB;
        #pragma unroll
        for (int ks=0; ks<2; ks++){
            const int k16 = ks*16;
            uint32_t ah[2][4], al[2][4];
            #pragma unroll
            for (int mt=0; mt<2; mt++){
                uint32_t ad = sb + (wm*32 + mt*16 + a_r)*(GRS*2) + (k16 + a_ko)*2;
                LDSM_X4(ah[mt][0],ah[mt][1],ah[mt][2],ah[mt][3], ad + 0*MATB);
                LDSM_X4(al[mt][0],al[mt][1],al[mt][2],al[mt][3], ad + 1*MATB);
            }
            #pragma unroll
            for (int n4=0; n4<4; n4++){
                uint32_t bd = sb + 2*MATB + (wn*64 + n4*16 + b_n)*(GRS*2) + (k16 + b_ko)*2;
                uint32_t bh[4];
                LDSM_X4(bh[0],bh[1],bh[2],bh[3], bd);
                #pragma unroll
                for (int mt=0; mt<2; mt++){
                    MMAF16(acc[mt][n4*2  ], ah[mt], bh[0], bh[1]);
                    MMAF16(acc[mt][n4*2+1], ah[mt], bh[2], bh[3]);
                    MMAF16(acc[mt][n4*2  ], al[mt], bh[0], bh[1]);
                    MMAF16(acc[mt][n4*2+1], al[mt], bh[2], bh[3]);
                }
            }
        }
        if (kb+2 < nkb) fill(kb+2);
    }

    float* Cg = C + (size_t)(row0 + wm*32)*DD + col0 + wn*64;
    const int cr = lane >> 2, cc = (lane & 3) << 1;
    #pragma unroll
    for (int mt=0; mt<2; mt++)
        #pragma unroll
        for (int nt=0; nt<8; nt++){
            float2 v0; v0.x = acc[mt][nt][0]; v0.y = acc[mt][nt][1];
            *(float2*)&Cg[(size_t)(mt*16+cr)*DD + nt*8+cc] = v0;
            float2 v1; v1.x = acc[mt][nt][2]; v1.y = acc[mt][nt][3];
            *(float2*)&Cg[(size_t)(mt*16+cr+8)*DD + nt*8+cc] = v1;
        }
}

// ---------------- small projections: warp per row ----------------------------
__global__ void __launch_bounds__(256) smallproj_kernel(const float* __restrict__ Xh,
                                 const float* __restrict__ Wb,
                                 const float* __restrict__ Wdec,
                                 const float* __restrict__ Wmix)
{
    int wid = threadIdx.x >> 5, lane = threadIdx.x & 31;
    int row = blockIdx.x*8 + wid;
    const float* xr = Xh + (size_t)row*DD;
    float a[12];
    #pragma unroll
    for (int j=0;j<12;j++) a[j]=0.f;
    for (int c=lane; c<DD; c+=32){
        float hv = xr[c];
        float4 wb = *(const float4*)&Wb[c*4];
        float4 wd = *(const float4*)&Wdec[c*4];
        float4 wm = *(const float4*)&Wmix[c*4];
        a[0]+=hv*wb.x; a[1]+=hv*wb.y; a[2]+=hv*wb.z; a[3]+=hv*wb.w;
        a[4]+=hv*wd.x; a[5]+=hv*wd.y; a[6]+=hv*wd.z; a[7]+=hv*wd.w;
        a[8]+=hv*wm.x; a[9]+=hv*wm.y; a[10]+=hv*wm.z; a[11]+=hv*wm.w;
    }
    #pragma unroll
    for (int off=16; off; off>>=1){
        #pragma unroll
        for (int j=0;j<12;j++) a[j] += __shfl_down_sync(0xffffffffu, a[j], off);
    }
    if (lane == 0){
        #pragma unroll
        for (int j=0;j<4;j++){
            g_beta  [row*4+j] = sigm_f(a[j]);
            g_gamma [row*4+j] = sigm_f(a[4+j]);
            g_mixlin[row*4+j] = a[8+j];
        }
    }
}

// ---------------- causal short conv (K=4) + silu, all 3 tensors, float4 ------
__global__ void __launch_bounds__(256) conv_silu3_kernel(
    const float* __restrict__ convq, const float* __restrict__ convk,
    const float* __restrict__ convv)
{
    int z = blockIdx.y;
    const float* X  = (z==0) ? g_QL : (z==1 ? g_KL : g_VL);
    const float* Wc = (z==0) ? convq : (z==1 ? convk : convv);
    float* Y        = (z==0) ? g_Q : (z==1 ? g_K : g_V);
    int idx4 = blockIdx.x*256 + threadIdx.x;     // over NT*DD/4
    int ch  = (idx4 & 255) << 2;                 // channel base (0..1020)
    int bt  = idx4 >> 8;                         // token index
    int t   = bt & (LL-1);
    float4 acc = make_float4(0.f,0.f,0.f,0.f);
    #pragma unroll
    for (int k=0;k<4;k++){
        int ts = t-3+k;
        if (ts>=0){
            float4 xv = *(const float4*)&X[(size_t)(bt + (ts-t))*DD + ch];
            acc.x += xv.x * Wc[(ch+0)*4+k];
            acc.y += xv.y * Wc[(ch+1)*4+k];
            acc.z += xv.z * Wc[(ch+2)*4+k];
            acc.w += xv.w * Wc[(ch+3)*4+k];
        }
    }
    float4 y;
    y.x = silu_f(acc.x); y.y = silu_f(acc.y); y.z = silu_f(acc.z); y.w = silu_f(acc.w);
    if (z < 2){ y.x = silu_f(y.x); y.y = silu_f(y.y); y.z = silu_f(y.z); y.w = silu_f(y.w); }
    *(float4*)&Y[(size_t)bt*DD + ch] = y;
}

// ---------------- mix path: conv over H channels + silu + sigmoid(+bias) -----
__global__ void mixconv_kernel(const float* __restrict__ convmix,
                               const float* __restrict__ mixbias)
{
    int idx = blockIdx.x*blockDim.x + threadIdx.x;
    if (idx >= NT*HH) return;
    int h = idx & 3;
    int bt = idx >> 2;
    int t = bt & (LL-1);
    float acc = 0.f;
    #pragma unroll
    for (int k=0;k<4;k++){
        int ts = t-3+k;
        if (ts>=0) acc += g_mixlin[idx + (ts-t)*HH] * convmix[h*4+k];
    }
    float mi = silu_f(acc);
    g_mixg[idx] = sigm_f(mi + mixbias[h]);
}

// ---------------- l2 norm + bf16 limb emission: warp per (row,head) ----------
__global__ void __launch_bounds__(256) l2norm_kernel()
{
    int wid = threadIdx.x >> 5, lane = threadIdx.x & 31;
    int g = blockIdx.x*8 + wid;
    int row = g >> 2, h = g & 3;
    size_t base = (size_t)row*DD + h*DK;

    {
        float4 v0 = *(float4*)&g_Q[base + lane*4];
        float4 v1 = *(float4*)&g_Q[base + 128 + lane*4];
        float s = v0.x*v0.x+v0.y*v0.y+v0.z*v0.z+v0.w*v0.w
                + v1.x*v1.x+v1.y*v1.y+v1.z*v1.z+v1.w*v1.w;
        #pragma unroll
        for (int off=16; off; off>>=1) s += __shfl_xor_sync(0xffffffffu, s, off);
        float sc = rsqrtf(s + 1e-6f);
        v0.x*=sc; v0.y*=sc; v0.z*=sc; v0.w*=sc;
        v1.x*=sc; v1.y*=sc; v1.z*=sc; v1.w*=sc;
        *(float4*)&g_Q[base + lane*4] = v0;
        *(float4*)&g_Q[base + 128 + lane*4] = v1;
        split_store4(v0, &g_Qh[base + lane*4], &g_Ql[base + lane*4]);
        split_store4(v1, &g_Qh[base + 128 + lane*4], &g_Ql[base + 128 + lane*4]);
    }
    {
        float4 v0 = *(float4*)&g_K[base + lane*4];
        float4 v1 = *(float4*)&g_K[base + 128 + lane*4];
        float s = v0.x*v0.x+v0.y*v0.y+v0.z*v0.z+v0.w*v0.w
                + v1.x*v1.x+v1.y*v1.y+v1.z*v1.z+v1.w*v1.w;
        #pragma unroll
        for (int off=16; off; off>>=1) s += __shfl_xor_sync(0xffffffffu, s, off);
        float sc = rsqrtf(s + 1e-6f);
        v0.x*=sc; v0.y*=sc; v0.z*=sc; v0.w*=sc;
        v1.x*=sc; v1.y*=sc; v1.z*=sc; v1.w*=sc;
        *(float4*)&g_K[base + lane*4] = v0;
        *(float4*)&g_K[base + 128 + lane*4] = v1;
        split_store4(v0, &g_Kh[base + lane*4], &g_Kl[base + lane*4]);
        split_store4(v1, &g_Kh[base + 128 + lane*4], &g_Kl[base + 128 + lane*4]);
    }
}

// ---------------- per-chunk: T (tri inverse), W limbs, Attn ------------------
#define WP 260   // float stride for 32x256 tiles
#define SP 36    // float stride for 32x32 / 256x32 tiles

__global__ void __launch_bounds__(256) chunk_kernel()
{
    extern __shared__ float sm[];
    float* kc     = sm;                 // 32*WP
    float* qc     = kc + 32*WP;         // 32*WP
    float* Amat   = qc + 32*WP;         // 32*33
    float* bet    = Amat + 32*33;       // 32
    float* rowtmp = bet + 32;           // 32

    int blk = blockIdx.x;               // bh*64 + c
    int bh = blk >> 6, c = blk & 63;
    int b = bh >> 2, h = bh & 3;
    int tid = threadIdx.x;
    int rowbase = b*LL + c*CHK;

    for (int e = tid; e < 2048; e += 256){
        int r = e >> 6; int c4 = (e & 63) << 2;
        *(float4*)&kc[r*WP+c4] = *(const float4*)&g_K[(size_t)(rowbase+r)*DD + h*DK + c4];
        *(float4*)&qc[r*WP+c4] = *(const float4*)&g_Q[(size_t)(rowbase+r)*DD + h*DK + c4];
    }
    if (tid < 32) bet[tid] = g_beta[(rowbase+tid)*HH + h];
    __syncthreads();

    // A = -tril(k_beta @ k^T, -1),  Attn = tril(q @ k^T, 0)   [f32x2, pair over m]
    {
        int i = tid >> 3, j0 = tid & 7;
        u64t da[4], dq[4];
        #pragma unroll
        for (int u=0;u<4;u++){ da[u]=0ull; dq[u]=0ull; }
        #pragma unroll 4
        for (int m=0;m<256;m+=4){
            ulonglong2 ki = *(ulonglong2*)&kc[i*WP+m];
            ulonglong2 qi = *(ulonglong2*)&qc[i*WP+m];
            #pragma unroll
            for (int u=0;u<4;u++){
                ulonglong2 kj = *(ulonglong2*)&kc[(j0+8*u)*WP+m];
                da[u] = ffma2(ki.x, kj.x, da[u]);
                da[u] = ffma2(ki.y, kj.y, da[u]);
                dq[u] = ffma2(qi.x, kj.x, dq[u]);
                dq[u] = ffma2(qi.y, kj.y, dq[u]);
            }
        }
        #pragma unroll
        for (int u=0;u<4;u++){
            int j = j0 + 8*u;
            float2 ta = f2unpack(da[u]);
            float2 tq = f2unpack(dq[u]);
            float av = ta.x + ta.y, qv = tq.x + tq.y;
            Amat[i*33+j] = (j < i) ? -bet[i]*av : 0.f;
            g_At[(size_t)blk*1024 + i*32 + j] = (j <= i) ? qv : 0.f;
        }
    }
    __syncthreads();

    // sequential forward-substitution (warp 0)
    if (tid < 32){
        int cx = tid;
        for (int ii=1; ii<32; ii++){
            rowtmp[cx] = Amat[ii*33+cx];
            __syncwarp();
            float acc = 0.f;
            if (cx < ii){
                acc = rowtmp[cx];
                for (int j=cx+1; j<ii; j++) acc += rowtmp[j]*Amat[j*33+cx];
            }
            __syncwarp();
            if (cx < ii) Amat[ii*33+cx] = acc;
            __syncwarp();
        }
        Amat[cx*33+cx] = 1.0f;   // T = A + I
    }
    __syncthreads();

    for (int e=tid; e<1024; e+=256)
        g_T[(size_t)blk*1024 + e] = Amat[(e>>5)*33 + (e&31)];

    // W = T @ (beta * k)   [f32x2, pair over dk] -> write bf16 limbs directly
    {
        int i = tid >> 3, mb = (tid & 7) << 2;
        u64t acc[16];
        #pragma unroll
        for (int s=0;s<16;s++) acc[s]=0ull;
        for (int j=0;j<32;j++){
            u64t td = f2dup(Amat[i*33+j]*bet[j]);
            #pragma unroll
            for (int s=0;s<8;s++){
                ulonglong2 kv = *(ulonglong2*)&kc[j*WP + s*32 + mb];
                acc[2*s]   = ffma2(td, kv.x, acc[2*s]);
                acc[2*s+1] = ffma2(td, kv.y, acc[2*s+1]);
            }
        }
        #pragma unroll
        for (int s=0;s<8;s++){
            float2 p0 = f2unpack(acc[2*s]), p1 = f2unpack(acc[2*s+1]);
            float4 wv; wv.x = p0.x; wv.y = p0.y; wv.z = p1.x; wv.w = p1.y;
            size_t go = ((size_t)blk*32 + i)*DK + s*32 + mb;
            split_store4(wv, &g_Wh[go], &g_Wl[go]);
        }
    }
}

// ---------------- inter-chunk scan: tensor-core, 512 threads -----------------
// grid: 128 blocks = 16 (b,h) x 8 dv-slabs of 32 columns; 512 threads (16 warps)
#define SBP 40    // bf16 stride for S / ua limb tiles (80 B rows)
#define WQP 264   // bf16 stride for wq / kt limb tiles (528 B rows)

__global__ void __launch_bounds__(512,1) scan_kernel()
{
    extern __shared__ char sraw[];
    float* S32   = (float*)sraw;              // 256*36
    float* P32   = S32  + 256*36;             // 2 x 64*36 (partial K-halves)
    float* att32 = P32  + 2*64*36;            // 32*36
    float* T32   = att32+ 32*36;              // 32*36
    float* vb32  = T32  + 32*36;              // 32*36
    float* ua32  = vb32 + 32*36;              // 32*36
    __nv_bfloat16* S_hi  = (__nv_bfloat16*)(ua32 + 32*36);
    __nv_bfloat16* S_lo  = S_hi  + 256*SBP;
    __nv_bfloat16* wq_hi = S_lo  + 256*SBP;   // 64 rows (w:0-31, q:32-63)
    __nv_bfloat16* wq_lo = wq_hi + 64*WQP;
    __nv_bfloat16* kt_hi = wq_lo + 64*WQP;    // 32 rows
    __nv_bfloat16* kt_lo = kt_hi + 32*WQP;
    __nv_bfloat16* ua_hi = kt_lo + 32*WQP;    // 32 rows
    __nv_bfloat16* ua_lo = ua_hi + 32*SBP;

    const int tid  = threadIdx.x;
    const int lane = tid & 31, wid = tid >> 5;
    const int bh   = blockIdx.x >> 3;
    const int slab = blockIdx.x & 7;
    const int b = bh >> 2, h = bh & 3;
    const size_t ocol = (size_t)h*DK + slab*32;

    const uint32_t u_S_hi  = smem_u32(S_hi),  u_S_lo  = smem_u32(S_lo);
    const uint32_t u_wq_hi = smem_u32(wq_hi), u_wq_lo = smem_u32(wq_lo);
    const uint32_t u_kt_hi = smem_u32(kt_hi), u_kt_lo = smem_u32(kt_lo);
    const uint32_t u_ua_hi = smem_u32(ua_hi), u_ua_lo = smem_u32(ua_lo);

    // init S and its limbs
    for (int e=tid; e<256*36; e+=512) S32[e]=0.f;
    for (int e=tid; e<256*SBP; e+=512){
        ((uint16_t*)S_hi)[e] = 0; ((uint16_t*)S_lo)[e] = 0;
    }
    __syncthreads();

    // scalar-stage geometry (512 threads, 2 cols each)
    const int i  = tid >> 4;          // row 0..31
    const int j2 = (tid & 15) << 1;   // col 0..30 step 2

    // stage-A geometry: 4 M-tiles x 2 N-tiles x 2 K-halves
    const int wmA = wid & 3;
    const int wnA = (wid >> 2) & 1;
    const int khA = wid >> 3;                     // 0 or 1
    const int aArow = wmA*16 + (lane & 15);
    const int aAcb  = ((lane >> 4) & 1) << 3;
    const int bArow = (lane & 15);
    const int bAcb  = wnA*16 + (((lane >> 4) & 1) << 3);
    // stage-B geometry: 16 warps x 16 rows
    const int aBrow = (lane & 7) + (((lane >> 4) & 1) << 3);
    const int aBcb  = ((lane >> 3) & 1) << 3;
    const int bBrow = (lane & 15);
    const int cr = lane >> 2, cc = (lane & 3) << 1;

    for (int c=0; c<NCHUNK; c++){
        int blk = bh*NCHUNK + c;
        int rowbase = b*LL + c*CHK;

        // ---- pure limb copies: 2 iters x 6 float4 per thread
        for (int e=tid; e<1024; e+=512){
            int r = e >> 5;              // 0..31
            int cx = (e & 31) << 3;      // bf16 col base
            size_t gw = ((size_t)blk*32 + r)*DK + cx;
            size_t gq = (size_t)(rowbase+r)*DD + h*DK + cx;
            *(float4*)&wq_hi[r*WQP+cx]      = *(const float4*)&g_Wh[gw];
            *(float4*)&wq_lo[r*WQP+cx]      = *(const float4*)&g_Wl[gw];
            *(float4*)&wq_hi[(32+r)*WQP+cx] = *(const float4*)&g_Qh[gq];
            *(float4*)&wq_lo[(32+r)*WQP+cx] = *(const float4*)&g_Ql[gq];
            *(float4*)&kt_hi[r*WQP+cx]      = *(const float4*)&g_Kh[gq];
            *(float4*)&kt_lo[r*WQP+cx]      = *(const float4*)&g_Kl[gq];
        }
        if (tid < 256){
            int r = tid >> 3, c4 = (tid & 7) << 2;
            *(float4*)&att32[r*SP+c4] = *(const float4*)&g_At[(size_t)blk*1024 + r*32 + c4];
            *(float4*)&T32 [r*SP+c4]  = *(const float4*)&g_T [(size_t)blk*1024 + r*32 + c4];
            float be = g_beta[(rowbase+r)*HH + h];
            float4 vv = *(const float4*)&g_V[(size_t)(rowbase+r)*DD + ocol + c4];
            vv.x*=be; vv.y*=be; vv.z*=be; vv.w*=be;
            *(float4*)&vb32[r*SP+c4] = vv;
        }
        __syncthreads();

        // ---- stage A: P_kh = [w|q] @ S_kh  (each warp: 8 k16-steps)
        {
            float acc[2][4];
            #pragma unroll
            for (int n8=0;n8<2;n8++)
                #pragma unroll
                for (int u=0;u<4;u++) acc[n8][u]=0.f;
            #pragma unroll 4
            for (int k16=0;k16<8;k16++){
                int kg = khA*8 + k16;
                uint32_t ah[4], al[4], bh_[4], bl_[4];
                uint32_t aofs = (uint32_t)(aArow*WQP + kg*16 + aAcb)*2;
                LDSM_X4(ah[0],ah[1],ah[2],ah[3], u_wq_hi + aofs);
                LDSM_X4(al[0],al[1],al[2],al[3], u_wq_lo + aofs);
                uint32_t bofs = (uint32_t)((kg*16 + bArow)*SBP + bAcb)*2;
                LDSM_X4_T(bh_[0],bh_[1],bh_[2],bh_[3], u_S_hi + bofs);
                LDSM_X4_T(bl_[0],bl_[1],bl_[2],bl_[3], u_S_lo + bofs);
                MMABF16(acc[0], ah, bh_[0], bh_[1]);
                MMABF16(acc[1], ah, bh_[2], bh_[3]);
                MMABF16(acc[0], ah, bl_[0], bl_[1]);
                MMABF16(acc[1], ah, bl_[2], bl_[3]);
                MMABF16(acc[0], al, bh_[0], bh_[1]);
                MMABF16(acc[1], al, bh_[2], bh_[3]);
            }
            float* Pp = P32 + khA*64*36;
            #pragma unroll
            for (int n8=0;n8<2;n8++){
                int col = wnA*16 + n8*8 + cc;
                Pp[(wmA*16+cr  )*SP + col  ] = acc[n8][0];
                Pp[(wmA*16+cr  )*SP + col+1] = acc[n8][1];
                Pp[(wmA*16+cr+8)*SP + col  ] = acc[n8][2];
                Pp[(wmA*16+cr+8)*SP + col+1] = acc[n8][3];
            }
        }
        __syncthreads();

        // ---- scalar: u = T@vb ; ua = u - (P0+P1)_w ; ua limbs (2 cols/thread)
        {
            u64t ui = 0ull;
            #pragma unroll
            for (int m=0;m<32;m++){
                u64t td = f2dup(T32[i*SP+m]);
                u64t vv = *(u64t*)&vb32[m*SP+j2];
                ui = ffma2(td, vv, ui);
            }
            float2 uu = f2unpack(ui);
            float2 pa = *(float2*)&P32[i*SP+j2];
            float2 pb = *(float2*)&P32[64*36 + i*SP+j2];
            float2 uav;
            uav.x = uu.x - pa.x - pb.x;
            uav.y = uu.y - pa.y - pb.y;
            *(float2*)&ua32[i*SP+j2] = uav;
            split_store2(uav, &ua_hi[i*SBP+j2], &ua_lo[i*SBP+j2]);
        }
        __syncthreads();

        // ---- scalar: o = (P0+P1)_q + att @ ua  -> global (2 cols/thread)
        {
            float2 qa = *(float2*)&P32[(32+i)*SP+j2];
            float2 qb = *(float2*)&P32[64*36 + (32+i)*SP+j2];
            u64t aO = f2pack(qa.x + qb.x, qa.y + qb.y);
            #pragma unroll
            for (int m=0;m<32;m++){
                u64t ad = f2dup(att32[i*SP+m]);
                u64t uv = *(u64t*)&ua32[m*SP+j2];
                aO = ffma2(ad, uv, aO);
            }
            float2 ov = f2unpack(aO);
            *(float2*)&g_Od[(size_t)(rowbase+i)*DD + ocol + j2] = ov;
        }

        // ---- stage B: dS = k^T @ ua  (16 warps x 16 rows, N=32, K=32)
        {
            float acc[4][4];
            #pragma unroll
            for (int n8=0;n8<4;n8++)
                #pragma unroll
                for (int u=0;u<4;u++) acc[n8][u]=0.f;
            const int D0 = wid*16;
            #pragma unroll
            for (int kk=0;kk<2;kk++){
                uint32_t bh0[4], bl0[4], bh1[4], bl1[4];
                uint32_t bofs0 = (uint32_t)((kk*16 + bBrow)*SBP + (((lane>>4)&1)<<3))*2;
                uint32_t bofs1 = bofs0 + 16*2;
                LDSM_X4_T(bh0[0],bh0[1],bh0[2],bh0[3], u_ua_hi + bofs0);
                LDSM_X4_T(bl0[0],bl0[1],bl0[2],bl0[3], u_ua_lo + bofs0);
                LDSM_X4_T(bh1[0],bh1[1],bh1[2],bh1[3], u_ua_hi + bofs1);
                LDSM_X4_T(bl1[0],bl1[1],bl1[2],bl1[3], u_ua_lo + bofs1);
                uint32_t ah[4], al[4];
                uint32_t aofs = (uint32_t)((kk*16 + aBrow)*WQP + D0 + aBcb)*2;
                LDSM_X4_T(ah[0],ah[1],ah[2],ah[3], u_kt_hi + aofs);
                LDSM_X4_T(al[0],al[1],al[2],al[3], u_kt_lo + aofs);
                MMABF16(acc[0], ah, bh0[0], bh0[1]);
                MMABF16(acc[1], ah, bh0[2], bh0[3]);
                MMABF16(acc[2], ah, bh1[0], bh1[1]);
                MMABF16(acc[3], ah, bh1[2], bh1[3]);
                MMABF16(acc[0], ah, bl0[0], bl0[1]);
                MMABF16(acc[1], ah, bl0[2], bl0[3]);
                MMABF16(acc[2], ah, bl1[0], bl1[1]);
                MMABF16(acc[3], ah, bl1[2], bl1[3]);
                MMABF16(acc[0], al, bh0[0], bh0[1]);
                MMABF16(acc[1], al, bh0[2], bh0[3]);
                MMABF16(acc[2], al, bh1[0], bh1[1]);
                MMABF16(acc[3], al, bh1[2], bh1[3]);
            }
            int r0 = D0 + cr;
            #pragma unroll
            for (int n8=0;n8<4;n8++){
                int col = n8*8 + cc;
                S32[(r0  )*SP + col  ] += acc[n8][0];
                S32[(r0  )*SP + col+1] += acc[n8][1];
                S32[(r0+8)*SP + col  ] += acc[n8][2];
                S32[(r0+8)*SP + col+1] += acc[n8][3];
            }
        }
        __syncwarp();
        // ---- refresh S limbs (warp w owns rows w*16..w*16+15; thread: half-row)
        {
            int r  = tid >> 1;
            int cb = (tid & 1) << 4;
            #pragma unroll
            for (int c4=0;c4<16;c4+=4){
                float4 sv = *(float4*)&S32[r*SP + cb + c4];
                split_store4(sv, &S_hi[r*SBP+cb+c4], &S_lo[r*SBP+cb+c4]);
            }
        }
        __syncthreads();
    }
}

// ---------------- EMA phase 1: segmented local scan --------------------------
__global__ void __launch_bounds__(256) ema_local_kernel()
{
    extern __shared__ float esm[];
    float* cbuf = esm;             // ESEG*256
    float* gbuf = cbuf + ESEG*256; // ESEG
    float* Ps   = gbuf + ESEG;     // ESEG

    int bh = blockIdx.x, seg = blockIdx.y;
    int b = bh >> 2, h = bh & 3;
    int tid = threadIdx.x;
    int rowbase = b*LL + seg*ESEG;
    size_t hcol = (size_t)h*DK;

    if (tid < ESEG) gbuf[tid] = g_gamma[(rowbase+tid)*HH + h];
    __syncthreads();

    for (int e = tid; e < ESEG*64; e += 256){
        int r = e >> 6, c4 = (e & 63) << 2;
        float om = 1.f - gbuf[r];
        float4 vv = *(const float4*)&g_V[(size_t)(rowbase+r)*DD + hcol + c4];
        vv.x*=om; vv.y*=om; vv.z*=om; vv.w*=om;
        *(float4*)&cbuf[r*256 + c4] = vv;
    }
    if (tid < ESEG){
        int lane = tid & 31;
        float p = gbuf[tid];
        #pragma unroll
        for (int off=1; off<32; off<<=1){
            float o = __shfl_up_sync(0xffffffffu, p, off);
            if (lane >= off) p *= o;
        }
        Ps[tid] = p;
    }
    __syncthreads();
    if (tid < ESEG){
        int wmy = tid >> 5;
        float pre = 1.f;
        for (int wq = 0; wq < wmy; wq++) pre *= Ps[wq*32+31];
        g_P[bh*LL + seg*ESEG + tid] = pre * Ps[tid];
    }

    float s = 0.f;
    #pragma unroll 8
    for (int t = 0; t < ESEG; t++){
        s = fmaf(gbuf[t], s, cbuf[t*256 + tid]);
        cbuf[t*256 + tid] = s;
    }
    __syncthreads();

    for (int e = tid; e < ESEG*64; e += 256){
        int r = e >> 6, c4 = (e & 63) << 2;
        *(float4*)&g_Oe[(size_t)(rowbase+r)*DD + hcol + c4] = *(float4*)&cbuf[r*256 + c4];
    }
}

// ---------------- EMA phase 2: carry across segments -------------------------
__global__ void __launch_bounds__(256) ema_carry_kernel()
{
    int bh = blockIdx.x;
    int b = bh >> 2, h = bh & 3;
    int dv = threadIdx.x;
    float s = 0.f;
    #pragma unroll
    for (int seg = 0; seg < NSEG; seg++){
        g_C[(bh*NSEG + seg)*DK + dv] = s;
        int rend = b*LL + seg*ESEG + (ESEG-1);
        float P  = g_P[bh*LL + seg*ESEG + (ESEG-1)];
        float ye = g_Oe[(size_t)rend*DD + h*DK + dv];
        s = fmaf(P, s, ye);
    }
}

// ---------------- mix combine + RMS norm + fp16 split (fused, + ema carry) ---
__global__ void __launch_bounds__(256) combine_rms_kernel(const float* __restrict__ rmsw)
{
    int wid = threadIdx.x >> 5, lane = threadIdx.x & 31;
    int g = blockIdx.x*8 + wid;
    int row = g >> 2, h = g & 3;
    int b = row >> 11, t = row & (LL-1);
    int bh = b*4 + h, seg = t >> 7;
    float m = g_mixg[row*4+h];
    size_t base = (size_t)row*DD + h*DK;

    float P = g_P[bh*LL + t];
    const float* cav = &g_C[(bh*NSEG + seg)*DK];
    float4 c0 = *(const float4*)&cav[lane*4];
    float4 c1 = *(const float4*)&cav[128 + lane*4];

    float4 d0 = *(float4*)&g_Od[base + lane*4];
    float4 d1 = *(float4*)&g_Od[base + 128 + lane*4];
    float4 e0 = *(float4*)&g_Oe[base + lane*4];
    float4 e1 = *(float4*)&g_Oe[base + 128 + lane*4];
    e0.x += P*c0.x; e0.y += P*c0.y; e0.z += P*c0.z; e0.w += P*c0.w;
    e1.x += P*c1.x; e1.y += P*c1.y; e1.z += P*c1.z; e1.w += P*c1.w;

    float4 o0, o1;
    float om = 1.f - m;
    o0.x = om*d0.x + m*e0.x; o0.y = om*d0.y + m*e0.y;
    o0.z = om*d0.z + m*e0.z; o0.w = om*d0.w + m*e0.w;
    o1.x = om*d1.x + m*e1.x; o1.y = om*d1.y + m*e1.y;
    o1.z = om*d1.z + m*e1.z; o1.w = om*d1.w + m*e1.w;
    float s = o0.x*o0.x+o0.y*o0.y+o0.z*o0.z+o0.w*o0.w
            + o1.x*o1.x+o1.y*o1.y+o1.z*o1.z+o1.w*o1.w;
    #pragma unroll
    for (int off=16; off; off>>=1) s += __shfl_xor_sync(0xffffffffu, s, off);
    float sc = rsqrtf(s*(1.f/256.f) + 1e-5f);
    float4 r0 = *(const float4*)&rmsw[lane*4];
    float4 r1 = *(const float4*)&rmsw[128 + lane*4];
    o0.x *= sc*r0.x; o0.y *= sc*r0.y; o0.z *= sc*r0.z; o0.w *= sc*r0.w;
    o1.x *= sc*r1.x; o1.y *= sc*r1.y; o1.z *= sc*r1.z; o1.w *= sc*r1.w;

    __half h4[4], l4[4];
    float v[4];
    v[0]=o0.x; v[1]=o0.y; v[2]=o0.z; v[3]=o0.w;
    #pragma unroll
    for (int u=0;u<4;u++){
        h4[u]=__float2half_rn(v[u]);
        l4[u]=__float2half_rn(v[u]-__half2float(h4[u]));
    }
    *(u64t*)&g_Op_hi[base + lane*4] = *(u64t*)h4;
    *(u64t*)&g_Op_lo[base + lane*4] = *(u64t*)l4;
    v[0]=o1.x; v[1]=o1.y; v[2]=o1.z; v[3]=o1.w;
    #pragma unroll
    for (int u=0;u<4;u++){
        h4[u]=__float2half_rn(v[u]);
        l4[u]=__float2half_rn(v[u]-__half2float(h4[u]));
    }
    *(u64t*)&g_Op_hi[base + 128 + lane*4] = *(u64t*)h4;
    *(u64t*)&g_Op_lo[base + 128 + lane*4] = *(u64t*)l4;
}

// ---------------- host driver -----------------------------------------------
extern "C" void kernel_launch(void* const* d_in, const int* in_sizes, int n_in,
                              void* d_out, int out_size)
{
    const float* hs      = (const float*)d_in[0];
    const float* Wq      = (const float*)d_in[1];
    const float* Wk      = (const float*)d_in[2];
    const float* Wv      = (const float*)d_in[3];
    const float* convq   = (const float*)d_in[4];
    const float* convk   = (const float*)d_in[5];
    const float* convv   = (const float*)d_in[6];
    const float* Wb      = (const float*)d_in[7];
    const float* Wdec    = (const float*)d_in[8];
    const float* Wmix    = (const float*)d_in[9];
    const float* convmix = (const float*)d_in[10];
    const float* mixbias = (const float*)d_in[11];
    const float* rmsw    = (const float*)d_in[12];
    const float* Wo      = (const float*)d_in[13];

    void *pQL,*pKL,*pVL;
    cudaGetSymbolAddress(&pQL, g_QL);
    cudaGetSymbolAddress(&pKL, g_KL);
    cudaGetSymbolAddress(&pVL, g_VL);

    void *p_hs_hi,*p_hs_lo,*p_Op_hi,*p_Op_lo,*p_WT_h,*p_WoT_h;
    cudaGetSymbolAddress(&p_hs_hi, g_hs_hi);  cudaGetSymbolAddress(&p_hs_lo, g_hs_lo);
    cudaGetSymbolAddress(&p_Op_hi, g_Op_hi);  cudaGetSymbolAddress(&p_Op_lo, g_Op_lo);
    cudaGetSymbolAddress(&p_WT_h, g_WT_h);    cudaGetSymbolAddress(&p_WoT_h, g_WoT_h);

    int smem_chunk = (2*32*WP + 32*33 + 64) * 4;
    int smem_scan  = (256*36 + 2*64*36 + 4*32*36)*4
                   + (2*256*SBP + 2*64*WQP + 2*32*WQP + 2*32*SBP)*2;  // 221184
    int smem_gemm  = NSTG*STGB;
    int smem_ema   = (ESEG*256 + 2*ESEG) * 4;
    cudaFuncSetAttribute(chunk_kernel, cudaFuncAttributeMaxDynamicSharedMemorySize, smem_chunk);
    cudaFuncSetAttribute(scan_kernel,  cudaFuncAttributeMaxDynamicSharedMemorySize, smem_scan);
    cudaFuncSetAttribute(gemm_f16s,    cudaFuncAttributeMaxDynamicSharedMemorySize, smem_gemm);
    cudaFuncSetAttribute(ema_local_kernel, cudaFuncAttributeMaxDynamicSharedMemorySize, smem_ema);

    // 1: split activations to fp16 limbs
    split_kernel<<<NT*DD/4/256,256>>>(hs, (__half*)p_hs_hi, (__half*)p_hs_lo);
    // 2: weight transposes to fp16
    dim3 wg(32,32,4), wb(32,8);
    wsplit_all_kernel<<<wg,wb>>>(Wq, Wk, Wv, Wo, (__half*)p_WT_h, (__half*)p_WoT_h);
    // 3: small projections
    smallproj_kernel<<<NT/8,256>>>(hs, Wb, Wdec, Wmix);

    // 4: merged QKV GEMM (1536 CTAs)
    gemm_f16s<<<dim3(24,64),256,smem_gemm>>>(
        (__half*)p_hs_hi,(__half*)p_hs_lo,(__half*)p_WT_h,
        (float*)pQL, (float*)pKL, (float*)pVL, DD);

    conv_silu3_kernel<<<dim3(NT*DD/4/256,3),256>>>(convq, convk, convv);
    mixconv_kernel<<<(NT*HH+127)/128,128>>>(convmix, mixbias);

    l2norm_kernel<<<NT*HH/8,256>>>();
    chunk_kernel<<<NBH*NCHUNK,256,smem_chunk>>>();
    scan_kernel<<<NBH*8,512,smem_scan>>>();

    ema_local_kernel<<<dim3(NBH,NSEG),256,smem_ema>>>();
    ema_carry_kernel<<<NBH,DK>>>();

    combine_rms_kernel<<<NT*HH/8,256>>>(rmsw);

    gemm_f16s<<<dim3(8,64),256,smem_gemm>>>(
        (__half*)p_Op_hi,(__half*)p_Op_lo,(__half*)p_WoT_h,
        (float*)d_out, (float*)d_out, (float*)d_out, DD);
}

// round 15
// speedup vs baseline: 3.6432x; 1.0256x over previous
#include <cuda_runtime.h>
#include <cuda_bf16.h>
#include <cuda_fp16.h>
#include <math.h>
#include <stdint.h>

// Problem constants
#define BB 4
#define LL 2048
#define DD 1024
#define HH 4
#define DK 256
#define NT (BB*LL)       // 8192 tokens
#define NCHUNK 64        // chunks per sequence
#define CHK 32           // chunk length
#define NBH 16           // B*H
#define ESEG 128         // ema segment length
#define NSEG (LL/ESEG)   // 16

typedef unsigned long long u64t;

// ---------------- scratch (device globals; no allocation allowed) -------------
__device__ float g_QL[NT*DD];
__device__ float g_KL[NT*DD];
__device__ float g_VL[NT*DD];
__device__ float g_Q[NT*DD];
__device__ float g_K[NT*DD];
__device__ float g_V[NT*DD];
__device__ float g_beta[NT*HH];
__device__ float g_gamma[NT*HH];
__device__ float g_mixlin[NT*HH];
__device__ float g_mixg[NT*HH];
__device__ float g_T[NBH*NCHUNK*CHK*CHK];    // triangular inverse T
__device__ float g_At[NBH*NCHUNK*CHK*CHK];   // attn_i = tril(q@k^T)
__device__ float g_Od[NT*DD];                // delta-rule output
__device__ float g_Oe[NT*DD];                // ema LOCAL output (y_t)
__device__ float g_P[NBH*LL];                // in-segment prefix products of gamma
__device__ float g_C[NBH*NSEG*DK];           // carry state at segment start

// bf16 limb arrays for the scan's tensor-core stages
__device__ __nv_bfloat16 g_Qh[NT*DD], g_Ql[NT*DD];
__device__ __nv_bfloat16 g_Kh[NT*DD], g_Kl[NT*DD];
__device__ __nv_bfloat16 g_Wh[NBH*NCHUNK*CHK*DK], g_Wl[NBH*NCHUNK*CHK*DK];

// fp16 limb buffers for tensor-core GEMMs (A: 2 limbs; B: single fp16)
__device__ __half g_hs_hi[NT*DD], g_hs_lo[NT*DD];
__device__ __half g_Op_hi[NT*DD], g_Op_lo[NT*DD];
__device__ __half g_WT_h[3*DD*DD];           // Wq|Wk|Wv transposed, fp16
__device__ __half g_WoT_h[DD*DD];            // Wo transposed, fp16

__device__ __forceinline__ float silu_f(float x){ return x / (1.f + expf(-x)); }
__device__ __forceinline__ float sigm_f(float x){ return 1.f / (1.f + expf(-x)); }

// ===================== f32x2 packed-math helpers =============================
__device__ __forceinline__ u64t f2dup(float x){
    u64t r; unsigned int xi = __float_as_uint(x);
    asm("mov.b64 %0, {%1,%1};" : "=l"(r) : "r"(xi));
    return r;
}
__device__ __forceinline__ u64t f2pack(float x, float y){
    u64t r;
    asm("mov.b64 %0, {%1,%2};" : "=l"(r) : "r"(__float_as_uint(x)), "r"(__float_as_uint(y)));
    return r;
}
__device__ __forceinline__ u64t ffma2(u64t a, u64t b, u64t c){
    u64t d; asm("fma.rn.f32x2 %0, %1, %2, %3;" : "=l"(d) : "l"(a), "l"(b), "l"(c));
    return d;
}
__device__ __forceinline__ float2 f2unpack(u64t p){
    unsigned int lo, hi;
    asm("mov.b64 {%0,%1}, %2;" : "=r"(lo), "=r"(hi) : "l"(p));
    return make_float2(__uint_as_float(lo), __uint_as_float(hi));
}

// ===================== PTX helpers (mma.sync / ldmatrix / cp.async) ==========
__device__ __forceinline__ uint32_t smem_u32(const void* p){
    uint32_t a;
    asm("{ .reg .u64 t; cvta.to.shared.u64 t, %1; cvt.u32.u64 %0, t; }" : "=r"(a) : "l"(p));
    return a;
}
__device__ __forceinline__ void cp_async16(uint32_t dst, const void* src){
    asm volatile("cp.async.cg.shared.global [%0], [%1], 16;" :: "r"(dst), "l"(src) : "memory");
}
__device__ __forceinline__ void cp_commit(){ asm volatile("cp.async.commit_group;" ::: "memory"); }

#define LDSM_X4(r0,r1,r2,r3, addr) \
    asm volatile("ldmatrix.sync.aligned.m8n8.x4.shared.b16 {%0,%1,%2,%3}, [%4];" \
        : "=r"(r0),"=r"(r1),"=r"(r2),"=r"(r3) : "r"(addr))

#define LDSM_X4_T(r0,r1,r2,r3, addr) \
    asm volatile("ldmatrix.sync.aligned.m8n8.x4.trans.shared.b16 {%0,%1,%2,%3}, [%4];" \
        : "=r"(r0),"=r"(r1),"=r"(r2),"=r"(r3) : "r"(addr))

#define MMAF16(d, a, b0, b1) \
    asm volatile("mma.sync.aligned.m16n8k16.row.col.f32.f16.f16.f32 " \
        "{%0,%1,%2,%3}, {%4,%5,%6,%7}, {%8,%9}, {%0,%1,%2,%3};" \
        : "+f"((d)[0]),"+f"((d)[1]),"+f"((d)[2]),"+f"((d)[3]) \
        : "r"((a)[0]),"r"((a)[1]),"r"((a)[2]),"r"((a)[3]), "r"(b0),"r"(b1))

#define MMABF16(d, a, b0, b1) \
    asm volatile("mma.sync.aligned.m16n8k16.row.col.f32.bf16.bf16.f32 " \
        "{%0,%1,%2,%3}, {%4,%5,%6,%7}, {%8,%9}, {%0,%1,%2,%3};" \
        : "+f"((d)[0]),"+f"((d)[1]),"+f"((d)[2]),"+f"((d)[3]) \
        : "r"((a)[0]),"r"((a)[1]),"r"((a)[2]),"r"((a)[3]), "r"(b0),"r"(b1))

// bf16 hi/lo split-store of a float4 (4B-aligned destinations)
__device__ __forceinline__ void split_store4(float4 v, __nv_bfloat16* ph, __nv_bfloat16* pl){
    __nv_bfloat162 h01, h23, l01, l23;
    h01.x = __float2bfloat16(v.x); h01.y = __float2bfloat16(v.y);
    h23.x = __float2bfloat16(v.z); h23.y = __float2bfloat16(v.w);
    l01.x = __float2bfloat16(v.x - __bfloat162float(h01.x));
    l01.y = __float2bfloat16(v.y - __bfloat162float(h01.y));
    l23.x = __float2bfloat16(v.z - __bfloat162float(h23.x));
    l23.y = __float2bfloat16(v.w - __bfloat162float(h23.y));
    *(__nv_bfloat162*)(ph)   = h01; *(__nv_bfloat162*)(ph+2) = h23;
    *(__nv_bfloat162*)(pl)   = l01; *(__nv_bfloat162*)(pl+2) = l23;
}
__device__ __forceinline__ void split_store2(float2 v, __nv_bfloat16* ph, __nv_bfloat16* pl){
    __nv_bfloat162 h01, l01;
    h01.x = __float2bfloat16(v.x); h01.y = __float2bfloat16(v.y);
    l01.x = __float2bfloat16(v.x - __bfloat162float(h01.x));
    l01.y = __float2bfloat16(v.y - __bfloat162float(h01.y));
    *(__nv_bfloat162*)(ph) = h01;
    *(__nv_bfloat162*)(pl) = l01;
}

// ===================== merged prep: split + wsplitT + smallproj ==============
// grid: [0,8192) split ; [8192,12288) wsplit ; [12288,13312) smallproj
__global__ void __launch_bounds__(256) prep_kernel(
    const float* __restrict__ hs,
    const float* __restrict__ W0, const float* __restrict__ W1,
    const float* __restrict__ W2, const float* __restrict__ W3,
    __half* __restrict__ hs_hi, __half* __restrict__ hs_lo,
    __half* __restrict__ bigh, __half* __restrict__ woh,
    const float* __restrict__ Wb, const float* __restrict__ Wdec,
    const float* __restrict__ Wmix)
{
    __shared__ float t[32][33];
    int bid = blockIdx.x;
    if (bid < 8192){
        // split hs -> fp16 limbs
        int i4 = bid*256 + threadIdx.x;
        float4 v = *(const float4*)&hs[(size_t)i4*4];
        __half hh[4], l[4];
        float a[4] = {v.x, v.y, v.z, v.w};
        #pragma unroll
        for (int u=0;u<4;u++){
            hh[u] = __float2half_rn(a[u]);
            l[u] = __float2half_rn(a[u] - __half2float(hh[u]));
        }
        *(u64t*)&hs_hi[(size_t)i4*4] = *(u64t*)hh;
        *(u64t*)&hs_lo[(size_t)i4*4] = *(u64t*)l;
    } else if (bid < 12288){
        // weight transpose to fp16
        int r = bid - 8192;
        int z  = r >> 10;
        int k0 = ((r >> 5) & 31) * 32;
        int n0 = (r & 31) * 32;
        const float* W; __half* hiT;
        if      (z==0){ W=W0; hiT=bigh; }
        else if (z==1){ W=W1; hiT=bigh+DD*DD; }
        else if (z==2){ W=W2; hiT=bigh+2*DD*DD; }
        else          { W=W3; hiT=woh; }
        int tx = threadIdx.x & 31, ty = threadIdx.x >> 5;
        for (int i = ty; i < 32; i += 8)
            t[i][tx] = W[(size_t)(k0+i)*DD + n0+tx];
        __syncthreads();
        for (int i = ty; i < 32; i += 8)
            hiT[(size_t)(n0+i)*DD + k0+tx] = __float2half_rn(t[tx][i]);
    } else {
        // small projections: warp per row
        int wid = threadIdx.x >> 5, lane = threadIdx.x & 31;
        int row = (bid - 12288)*8 + wid;
        const float* xr = hs + (size_t)row*DD;
        float a[12];
        #pragma unroll
        for (int j=0;j<12;j++) a[j]=0.f;
        for (int c=lane; c<DD; c+=32){
            float hv = xr[c];
            float4 wb = *(const float4*)&Wb[c*4];
            float4 wd = *(const float4*)&Wdec[c*4];
            float4 wm = *(const float4*)&Wmix[c*4];
            a[0]+=hv*wb.x; a[1]+=hv*wb.y; a[2]+=hv*wb.z; a[3]+=hv*wb.w;
            a[4]+=hv*wd.x; a[5]+=hv*wd.y; a[6]+=hv*wd.z; a[7]+=hv*wd.w;
            a[8]+=hv*wm.x; a[9]+=hv*wm.y; a[10]+=hv*wm.z; a[11]+=hv*wm.w;
        }
        #pragma unroll
        for (int off=16; off; off>>=1){
            #pragma unroll
            for (int j=0;j<12;j++) a[j] += __shfl_down_sync(0xffffffffu, a[j], off);
        }
        if (lane == 0){
            #pragma unroll
            for (int j=0;j<4;j++){
                g_beta  [row*4+j] = sigm_f(a[j]);
                g_gamma [row*4+j] = sigm_f(a[4+j]);
                g_mixlin[row*4+j] = a[8+j];
            }
        }
    }
}

// ===================== mma.sync fp16 2-limb GEMM =============================
#define GRS 40            // smem row stride in fp16 elements (80 bytes)
#define MATB (128*GRS*2)  // 10240 bytes per matrix tile
#define STGB (3*MATB)     // 30720 per stage (Ahi, Alo, B)
#define NSTG 3

__global__ void __launch_bounds__(256,2) gemm_f16s(
    const __half* __restrict__ Ahi, const __half* __restrict__ Alo,
    const __half* __restrict__ BT,
    float* C0, float* C1, float* C2, int K)
{
    extern __shared__ char smem[];
    const uint32_t sbase = smem_u32(smem);
    const int tid  = threadIdx.x;
    const int lane = tid & 31, wid = tid >> 5;
    const int wm = wid & 3, wn = wid >> 2;          // 4x2 warp grid
    const int row0 = blockIdx.y*128;
    const int bcol = blockIdx.x*128;                // into B (up to 3072 wide)
    const int seg  = blockIdx.x >> 3;
    const int col0 = (blockIdx.x & 7)*128;          // into C
    float* C = (seg==0) ? C0 : (seg==1 ? C1 : C2);

    const __half* g0 = Ahi + (size_t)row0*K;
    const __half* g1 = Alo + (size_t)row0*K;
    const __half* g2 = BT  + (size_t)bcol*K;

    float acc[2][8][4];
    #pragma unroll
    for (int i=0;i<2;i++)
        #pragma unroll
        for (int j=0;j<8;j++)
            #pragma unroll
            for (int u=0;u<4;u++) acc[i][j][u]=0.f;

    auto fill = [&](int kb){
        uint32_t sb = sbase + (kb%NSTG)*STGB;
        #pragma unroll
        for (int t=0;t<2;t++){
            int ci = tid + t*256;
            int r = ci >> 2, c = ci & 3;
            uint32_t dst = sb + r*(GRS*2) + c*16;
            size_t go = (size_t)r*K + (size_t)kb*32 + c*8;
            cp_async16(dst + 0*MATB, g0 + go);
            cp_async16(dst + 1*MATB, g1 + go);
            cp_async16(dst + 2*MATB, g2 + go);
        }
        cp_commit();
    };

    const int nkb = K/32;
    fill(0);
    fill(1);

    const int a_r  = lane & 15;
    const int a_ko = ((lane >> 4) & 1) << 3;
    const int b_n  = (lane & 7) + (((lane >> 4) & 1) << 3);
    const int b_ko = ((lane >> 3) & 1) << 3;

    for (int kb = 0; kb < nkb; kb++){
        if (kb+1 < nkb) asm volatile("cp.async.wait_group 1;" ::: "memory");
        else            asm volatile("cp.async.wait_group 0;" ::: "memory");
        __syncthreads();

        uint32_t sb = sbase + (kb%NSTG)*STGB;
        #pragma unroll
        for (int ks=0; ks<2; ks++){
            const int k16 = ks*16;
            uint32_t ah[2][4], al[2][4];
            #pragma unroll
            for (int mt=0; mt<2; mt++){
                uint32_t ad = sb + (wm*32 + mt*16 + a_r)*(GRS*2) + (k16 + a_ko)*2;
                LDSM_X4(ah[mt][0],ah[mt][1],ah[mt][2],ah[mt][3], ad + 0*MATB);
                LDSM_X4(al[mt][0],al[mt][1],al[mt][2],al[mt][3], ad + 1*MATB);
            }
            #pragma unroll
            for (int n4=0; n4<4; n4++){
                uint32_t bd = sb + 2*MATB + (wn*64 + n4*16 + b_n)*(GRS*2) + (k16 + b_ko)*2;
                uint32_t bh[4];
                LDSM_X4(bh[0],bh[1],bh[2],bh[3], bd);
                #pragma unroll
                for (int mt=0; mt<2; mt++){
                    MMAF16(acc[mt][n4*2  ], ah[mt], bh[0], bh[1]);
                    MMAF16(acc[mt][n4*2+1], ah[mt], bh[2], bh[3]);
                    MMAF16(acc[mt][n4*2  ], al[mt], bh[0], bh[1]);
                    MMAF16(acc[mt][n4*2+1], al[mt], bh[2], bh[3]);
                }
            }
        }
        if (kb+2 < nkb) fill(kb+2);
    }

    float* Cg = C + (size_t)(row0 + wm*32)*DD + col0 + wn*64;
    const int cr = lane >> 2, cc = (lane & 3) << 1;
    #pragma unroll
    for (int mt=0; mt<2; mt++)
        #pragma unroll
        for (int nt=0; nt<8; nt++){
            float2 v0; v0.x = acc[mt][nt][0]; v0.y = acc[mt][nt][1];
            *(float2*)&Cg[(size_t)(mt*16+cr)*DD + nt*8+cc] = v0;
            float2 v1; v1.x = acc[mt][nt][2]; v1.y = acc[mt][nt][3];
            *(float2*)&Cg[(size_t)(mt*16+cr+8)*DD + nt*8+cc] = v1;
        }
}

// ---------------- causal short conv + silu (3 tensors) + mix path (z=3) ------
__global__ void __launch_bounds__(256) conv4_kernel(
    const float* __restrict__ convq, const float* __restrict__ convk,
    const float* __restrict__ convv, const float* __restrict__ convmix,
    const float* __restrict__ mixbias)
{
    int z = blockIdx.y;
    if (z < 3){
        const float* X  = (z==0) ? g_QL : (z==1 ? g_KL : g_VL);
        const float* Wc = (z==0) ? convq : (z==1 ? convk : convv);
        float* Y        = (z==0) ? g_Q : (z==1 ? g_K : g_V);
        int idx4 = blockIdx.x*256 + threadIdx.x;
        int ch  = (idx4 & 255) << 2;
        int bt  = idx4 >> 8;
        int t   = bt & (LL-1);
        float4 acc = make_float4(0.f,0.f,0.f,0.f);
        #pragma unroll
        for (int k=0;k<4;k++){
            int ts = t-3+k;
            if (ts>=0){
                float4 xv = *(const float4*)&X[(size_t)(bt + (ts-t))*DD + ch];
                acc.x += xv.x * Wc[(ch+0)*4+k];
                acc.y += xv.y * Wc[(ch+1)*4+k];
                acc.z += xv.z * Wc[(ch+2)*4+k];
                acc.w += xv.w * Wc[(ch+3)*4+k];
            }
        }
        float4 y;
        y.x = silu_f(acc.x); y.y = silu_f(acc.y); y.z = silu_f(acc.z); y.w = silu_f(acc.w);
        if (z < 2){ y.x = silu_f(y.x); y.y = silu_f(y.y); y.z = silu_f(y.z); y.w = silu_f(y.w); }
        *(float4*)&Y[(size_t)bt*DD + ch] = y;
    } else {
        int idx = blockIdx.x*256 + threadIdx.x;
        if (idx < NT*HH){
            int hh = idx & 3;
            int bt = idx >> 2;
            int t = bt & (LL-1);
            float acc = 0.f;
            #pragma unroll
            for (int k=0;k<4;k++){
                int ts = t-3+k;
                if (ts>=0) acc += g_mixlin[idx + (ts-t)*HH] * convmix[hh*4+k];
            }
            float mi = silu_f(acc);
            g_mixg[idx] = sigm_f(mi + mixbias[hh]);
        }
    }
}

// ---------------- l2 norm + bf16 limb emission: warp per (row,head) ----------
__global__ void __launch_bounds__(256) l2norm_kernel()
{
    int wid = threadIdx.x >> 5, lane = threadIdx.x & 31;
    int g = blockIdx.x*8 + wid;
    int row = g >> 2, h = g & 3;
    size_t base = (size_t)row*DD + h*DK;

    {
        float4 v0 = *(float4*)&g_Q[base + lane*4];
        float4 v1 = *(float4*)&g_Q[base + 128 + lane*4];
        float s = v0.x*v0.x+v0.y*v0.y+v0.z*v0.z+v0.w*v0.w
                + v1.x*v1.x+v1.y*v1.y+v1.z*v1.z+v1.w*v1.w;
        #pragma unroll
        for (int off=16; off; off>>=1) s += __shfl_xor_sync(0xffffffffu, s, off);
        float sc = rsqrtf(s + 1e-6f);
        v0.x*=sc; v0.y*=sc; v0.z*=sc; v0.w*=sc;
        v1.x*=sc; v1.y*=sc; v1.z*=sc; v1.w*=sc;
        *(float4*)&g_Q[base + lane*4] = v0;
        *(float4*)&g_Q[base + 128 + lane*4] = v1;
        split_store4(v0, &g_Qh[base + lane*4], &g_Ql[base + lane*4]);
        split_store4(v1, &g_Qh[base + 128 + lane*4], &g_Ql[base + 128 + lane*4]);
    }
    {
        float4 v0 = *(float4*)&g_K[base + lane*4];
        float4 v1 = *(float4*)&g_K[base + 128 + lane*4];
        float s = v0.x*v0.x+v0.y*v0.y+v0.z*v0.z+v0.w*v0.w
                + v1.x*v1.x+v1.y*v1.y+v1.z*v1.z+v1.w*v1.w;
        #pragma unroll
        for (int off=16; off; off>>=1) s += __shfl_xor_sync(0xffffffffu, s, off);
        float sc = rsqrtf(s + 1e-6f);
        v0.x*=sc; v0.y*=sc; v0.z*=sc; v0.w*=sc;
        v1.x*=sc; v1.y*=sc; v1.z*=sc; v1.w*=sc;
        *(float4*)&g_K[base + lane*4] = v0;
        *(float4*)&g_K[base + 128 + lane*4] = v1;
        split_store4(v0, &g_Kh[base + lane*4], &g_Kl[base + lane*4]);
        split_store4(v1, &g_Kh[base + 128 + lane*4], &g_Kl[base + 128 + lane*4]);
    }
}

// ---------------- per-chunk: T (tri inverse), W limbs, Attn ------------------
#define WP 260   // float stride for 32x256 tiles
#define SP 36    // float stride for 32x32 / 256x32 tiles

__global__ void __launch_bounds__(256) chunk_kernel()
{
    extern __shared__ float sm[];
    float* kc     = sm;                 // 32*WP
    float* qc     = kc + 32*WP;         // 32*WP
    float* Amat   = qc + 32*WP;         // 32*33
    float* bet    = Amat + 32*33;       // 32
    float* rowtmp = bet + 32;           // 32

    int blk = blockIdx.x;               // bh*64 + c
    int bh = blk >> 6, c = blk & 63;
    int b = bh >> 2, h = bh & 3;
    int tid = threadIdx.x;
    int rowbase = b*LL + c*CHK;

    for (int e = tid; e < 2048; e += 256){
        int r = e >> 6; int c4 = (e & 63) << 2;
        *(float4*)&kc[r*WP+c4] = *(const float4*)&g_K[(size_t)(rowbase+r)*DD + h*DK + c4];
        *(float4*)&qc[r*WP+c4] = *(const float4*)&g_Q[(size_t)(rowbase+r)*DD + h*DK + c4];
    }
    if (tid < 32) bet[tid] = g_beta[(rowbase+tid)*HH + h];
    __syncthreads();

    // A = -tril(k_beta @ k^T, -1),  Attn = tril(q @ k^T, 0)   [f32x2, pair over m]
    {
        int i = tid >> 3, j0 = tid & 7;
        u64t da[4], dq[4];
        #pragma unroll
        for (int u=0;u<4;u++){ da[u]=0ull; dq[u]=0ull; }
        #pragma unroll 4
        for (int m=0;m<256;m+=4){
            ulonglong2 ki = *(ulonglong2*)&kc[i*WP+m];
            ulonglong2 qi = *(ulonglong2*)&qc[i*WP+m];
            #pragma unroll
            for (int u=0;u<4;u++){
                ulonglong2 kj = *(ulonglong2*)&kc[(j0+8*u)*WP+m];
                da[u] = ffma2(ki.x, kj.x, da[u]);
                da[u] = ffma2(ki.y, kj.y, da[u]);
                dq[u] = ffma2(qi.x, kj.x, dq[u]);
                dq[u] = ffma2(qi.y, kj.y, dq[u]);
            }
        }
        #pragma unroll
        for (int u=0;u<4;u++){
            int j = j0 + 8*u;
            float2 ta = f2unpack(da[u]);
            float2 tq = f2unpack(dq[u]);
            float av = ta.x + ta.y, qv = tq.x + tq.y;
            Amat[i*33+j] = (j < i) ? -bet[i]*av : 0.f;
            g_At[(size_t)blk*1024 + i*32 + j] = (j <= i) ? qv : 0.f;
        }
    }
    __syncthreads();

    // sequential forward-substitution (warp 0)
    if (tid < 32){
        int cx = tid;
        for (int ii=1; ii<32; ii++){
            rowtmp[cx] = Amat[ii*33+cx];
            __syncwarp();
            float acc = 0.f;
            if (cx < ii){
                acc = rowtmp[cx];
                for (int j=cx+1; j<ii; j++) acc += rowtmp[j]*Amat[j*33+cx];
            }
            __syncwarp();
            if (cx < ii) Amat[ii*33+cx] = acc;
            __syncwarp();
        }
        Amat[cx*33+cx] = 1.0f;   // T = A + I
    }
    __syncthreads();

    for (int e=tid; e<1024; e+=256)
        g_T[(size_t)blk*1024 + e] = Amat[(e>>5)*33 + (e&31)];

    // W = T @ (beta * k)   [f32x2, pair over dk] -> write bf16 limbs directly
    {
        int i = tid >> 3, mb = (tid & 7) << 2;
        u64t acc[16];
        #pragma unroll
        for (int s=0;s<16;s++) acc[s]=0ull;
        for (int j=0;j<32;j++){
            u64t td = f2dup(Amat[i*33+j]*bet[j]);
            #pragma unroll
            for (int s=0;s<8;s++){
                ulonglong2 kv = *(ulonglong2*)&kc[j*WP + s*32 + mb];
                acc[2*s]   = ffma2(td, kv.x, acc[2*s]);
                acc[2*s+1] = ffma2(td, kv.y, acc[2*s+1]);
            }
        }
        #pragma unroll
        for (int s=0;s<8;s++){
            float2 p0 = f2unpack(acc[2*s]), p1 = f2unpack(acc[2*s+1]);
            float4 wv; wv.x = p0.x; wv.y = p0.y; wv.z = p1.x; wv.w = p1.y;
            size_t go = ((size_t)blk*32 + i)*DK + s*32 + mb;
            split_store4(wv, &g_Wh[go], &g_Wl[go]);
        }
    }
}

// ---------------- inter-chunk scan: tensor-core, 512 threads, SW-pipelined ---
// grid: 128 blocks = 16 (b,h) x 8 dv-slabs of 32 columns; 512 threads (16 warps)
#define SBP 40    // bf16 stride for S / ua limb tiles (80 B rows)
#define WQP 264   // bf16 stride for wq / kt limb tiles (528 B rows)

__global__ void __launch_bounds__(512,1) scan_kernel()
{
    extern __shared__ char sraw[];
    float* S32   = (float*)sraw;              // 256*36
    float* P32   = S32  + 256*36;             // 2 x 64*36 (partial K-halves)
    float* att32 = P32  + 2*64*36;            // 32*36
    float* T32   = att32+ 32*36;              // 32*36
    float* vb32  = T32  + 32*36;              // 32*36
    float* ua32  = vb32 + 32*36;              // 32*36
    __nv_bfloat16* S_hi  = (__nv_bfloat16*)(ua32 + 32*36);
    __nv_bfloat16* S_lo  = S_hi  + 256*SBP;
    __nv_bfloat16* wq_hi = S_lo  + 256*SBP;   // 64 rows (w:0-31, q:32-63)
    __nv_bfloat16* wq_lo = wq_hi + 64*WQP;
    __nv_bfloat16* kt_hi = wq_lo + 64*WQP;    // 32 rows
    __nv_bfloat16* kt_lo = kt_hi + 32*WQP;
    __nv_bfloat16* ua_hi = kt_lo + 32*WQP;    // 32 rows
    __nv_bfloat16* ua_lo = ua_hi + 32*SBP;

    const int tid  = threadIdx.x;
    const int lane = tid & 31, wid = tid >> 5;
    const int bh   = blockIdx.x >> 3;
    const int slab = blockIdx.x & 7;
    const int b = bh >> 2, h = bh & 3;
    const size_t ocol = (size_t)h*DK + slab*32;

    const uint32_t u_S_hi  = smem_u32(S_hi),  u_S_lo  = smem_u32(S_lo);
    const uint32_t u_wq_hi = smem_u32(wq_hi), u_wq_lo = smem_u32(wq_lo);
    const uint32_t u_kt_hi = smem_u32(kt_hi), u_kt_lo = smem_u32(kt_lo);
    const uint32_t u_ua_hi = smem_u32(ua_hi), u_ua_lo = smem_u32(ua_lo);

    // init S and its limbs
    for (int e=tid; e<256*36; e+=512) S32[e]=0.f;
    for (int e=tid; e<256*SBP; e+=512){
        ((uint16_t*)S_hi)[e] = 0; ((uint16_t*)S_lo)[e] = 0;
    }

    // scalar-stage geometry (512 threads, 2 cols each)
    const int i  = tid >> 4;          // row 0..31
    const int j2 = (tid & 15) << 1;   // col 0..30 step 2

    // stage-A geometry: 4 M-tiles x 2 N-tiles x 2 K-halves
    const int wmA = wid & 3;
    const int wnA = (wid >> 2) & 1;
    const int khA = wid >> 3;                     // 0 or 1
    const int aArow = wmA*16 + (lane & 15);
    const int aAcb  = ((lane >> 4) & 1) << 3;
    const int bArow = (lane & 15);
    const int bAcb  = wnA*16 + (((lane >> 4) & 1) << 3);
    // stage-B geometry: 16 warps x 16 rows
    const int aBrow = (lane & 7) + (((lane >> 4) & 1) << 3);
    const int aBcb  = ((lane >> 3) & 1) << 3;
    const int bBrow = (lane & 15);
    const int cr = lane >> 2, cc = (lane & 3) << 1;

    // prefetch geometry
    const int pr  = tid >> 5;          // limb row iter0 (0..15)
    const int pcx = (tid & 31) << 3;   // bf16 col base
    const int prr = tid >> 3;          // att/T/vb row (tid<256)
    const int pc4 = (tid & 7) << 2;

    // ---- prologue: direct full load of chunk 0
    {
        int blk = bh*NCHUNK;
        int rowbase = b*LL;
        for (int e=tid; e<1024; e+=512){
            int r = e >> 5; int cx = (e & 31) << 3;
            size_t gw = ((size_t)blk*32 + r)*DK + cx;
            size_t gq = (size_t)(rowbase+r)*DD + h*DK + cx;
            *(float4*)&wq_hi[r*WQP+cx]      = *(const float4*)&g_Wh[gw];
            *(float4*)&wq_lo[r*WQP+cx]      = *(const float4*)&g_Wl[gw];
            *(float4*)&wq_hi[(32+r)*WQP+cx] = *(const float4*)&g_Qh[gq];
            *(float4*)&wq_lo[(32+r)*WQP+cx] = *(const float4*)&g_Ql[gq];
            *(float4*)&kt_hi[r*WQP+cx]      = *(const float4*)&g_Kh[gq];
            *(float4*)&kt_lo[r*WQP+cx]      = *(const float4*)&g_Kl[gq];
        }
        if (tid < 256){
            *(float4*)&att32[prr*SP+pc4] = *(const float4*)&g_At[(size_t)blk*1024 + prr*32 + pc4];
            *(float4*)&T32 [prr*SP+pc4]  = *(const float4*)&g_T [(size_t)blk*1024 + prr*32 + pc4];
            float be = g_beta[(rowbase+prr)*HH + h];
            float4 vv = *(const float4*)&g_V[(size_t)(rowbase+prr)*DD + ocol + pc4];
            vv.x*=be; vv.y*=be; vv.z*=be; vv.w*=be;
            *(float4*)&vb32[prr*SP+pc4] = vv;
        }
    }
    __syncthreads();

    float4 pW0h, pW0l, pQ0h, pQ0l, pK0h, pK0l, pK1h, pK1l;
    float4 pAtt, pT, pVb;

    for (int c=0; c<NCHUNK; c++){
        int rowbase = b*LL + c*CHK;

        // ---- R1: store prefetched kt + att/T/vb for this chunk (c>=1)
        if (c > 0){
            *(float4*)&kt_hi[pr*WQP+pcx]      = pK0h;
            *(float4*)&kt_lo[pr*WQP+pcx]      = pK0l;
            *(float4*)&kt_hi[(pr+16)*WQP+pcx] = pK1h;
            *(float4*)&kt_lo[(pr+16)*WQP+pcx] = pK1l;
            if (tid < 256){
                *(float4*)&att32[prr*SP+pc4] = pAtt;
                *(float4*)&T32 [prr*SP+pc4]  = pT;
                *(float4*)&vb32[prr*SP+pc4]  = pVb;
            }
        }

        // ---- stage A: P_kh = [w|q] @ S_kh  (each warp: 8 k16-steps)
        {
            float acc[2][4];
            #pragma unroll
            for (int n8=0;n8<2;n8++)
                #pragma unroll
                for (int u=0;u<4;u++) acc[n8][u]=0.f;
            #pragma unroll 4
            for (int k16=0;k16<8;k16++){
                int kg = khA*8 + k16;
                uint32_t ah[4], al[4], bh_[4], bl_[4];
                uint32_t aofs = (uint32_t)(aArow*WQP + kg*16 + aAcb)*2;
                LDSM_X4(ah[0],ah[1],ah[2],ah[3], u_wq_hi + aofs);
                LDSM_X4(al[0],al[1],al[2],al[3], u_wq_lo + aofs);
                uint32_t bofs = (uint32_t)((kg*16 + bArow)*SBP + bAcb)*2;
                LDSM_X4_T(bh_[0],bh_[1],bh_[2],bh_[3], u_S_hi + bofs);
                LDSM_X4_T(bl_[0],bl_[1],bl_[2],bl_[3], u_S_lo + bofs);
                MMABF16(acc[0], ah, bh_[0], bh_[1]);
                MMABF16(acc[1], ah, bh_[2], bh_[3]);
                MMABF16(acc[0], ah, bl_[0], bl_[1]);
                MMABF16(acc[1], ah, bl_[2], bl_[3]);
                MMABF16(acc[0], al, bh_[0], bh_[1]);
                MMABF16(acc[1], al, bh_[2], bh_[3]);
            }
            float* Pp = P32 + khA*64*36;
            #pragma unroll
            for (int n8=0;n8<2;n8++){
                int col = wnA*16 + n8*8 + cc;
                Pp[(wmA*16+cr  )*SP + col  ] = acc[n8][0];
                Pp[(wmA*16+cr  )*SP + col+1] = acc[n8][1];
                Pp[(wmA*16+cr+8)*SP + col  ] = acc[n8][2];
                Pp[(wmA*16+cr+8)*SP + col+1] = acc[n8][3];
            }
        }
        __syncthreads();   // sync2

        // ---- R2: issue prefetch LDGs for chunk c+1
        if (c+1 < NCHUNK){
            int blkN = bh*NCHUNK + c + 1;
            int rbN  = b*LL + (c+1)*CHK;
            size_t gw  = ((size_t)blkN*32 + pr)*DK + pcx;
            size_t gq  = (size_t)(rbN + pr)*DD + h*DK + pcx;
            size_t gq1 = (size_t)(rbN + pr + 16)*DD + h*DK + pcx;
            pW0h = *(const float4*)&g_Wh[gw];
            pW0l = *(const float4*)&g_Wl[gw];
            pQ0h = *(const float4*)&g_Qh[gq];
            pQ0l = *(const float4*)&g_Ql[gq];
            pK0h = *(const float4*)&g_Kh[gq];
            pK0l = *(const float4*)&g_Kl[gq];
            pK1h = *(const float4*)&g_Kh[gq1];
            pK1l = *(const float4*)&g_Kl[gq1];
            if (tid < 256){
                pAtt = *(const float4*)&g_At[(size_t)blkN*1024 + prr*32 + pc4];
                pT   = *(const float4*)&g_T [(size_t)blkN*1024 + prr*32 + pc4];
                float be = g_beta[(rbN+prr)*HH + h];
                float4 vv = *(const float4*)&g_V[(size_t)(rbN+prr)*DD + ocol + pc4];
                vv.x*=be; vv.y*=be; vv.z*=be; vv.w*=be;
                pVb = vv;
            }
        }

        // ---- scalar: u = T@vb ; ua = u - (P0+P1)_w ; ua limbs (2 cols/thread)
        {
            u64t ui = 0ull;
            #pragma unroll
            for (int m=0;m<32;m++){
                u64t td = f2dup(T32[i*SP+m]);
                u64t vv = *(u64t*)&vb32[m*SP+j2];
                ui = ffma2(td, vv, ui);
            }
            float2 uu = f2unpack(ui);
            float2 pa = *(float2*)&P32[i*SP+j2];
            float2 pb = *(float2*)&P32[64*36 + i*SP+j2];
            float2 uav;
            uav.x = uu.x - pa.x - pb.x;
            uav.y = uu.y - pa.y - pb.y;
            *(float2*)&ua32[i*SP+j2] = uav;
            split_store2(uav, &ua_hi[i*SBP+j2], &ua_lo[i*SBP+j2]);
        }
        __syncthreads();   // sync3

        // ---- R3: issue wq-iter1 direct prefetch for c+1
        float4 dW1h, dW1l, dQ1h, dQ1l;
        if (c+1 < NCHUNK){
            int blkN = bh*NCHUNK + c + 1;
            int rbN  = b*LL + (c+1)*CHK;
            size_t gw1 = ((size_t)blkN*32 + pr + 16)*DK + pcx;
            size_t gq1 = (size_t)(rbN + pr + 16)*DD + h*DK + pcx;
            dW1h = *(const float4*)&g_Wh[gw1];
            dW1l = *(const float4*)&g_Wl[gw1];
            dQ1h = *(const float4*)&g_Qh[gq1];
            dQ1l = *(const float4*)&g_Ql[gq1];
        }

        // ---- scalar: o = (P0+P1)_q + att @ ua  -> global (2 cols/thread)
        {
            float2 qa = *(float2*)&P32[(32+i)*SP+j2];
            float2 qb = *(float2*)&P32[64*36 + (32+i)*SP+j2];
            u64t aO = f2pack(qa.x + qb.x, qa.y + qb.y);
            #pragma unroll
            for (int m=0;m<32;m++){
                u64t ad = f2dup(att32[i*SP+m]);
                u64t uv = *(u64t*)&ua32[m*SP+j2];
                aO = ffma2(ad, uv, aO);
            }
            float2 ov = f2unpack(aO);
            *(float2*)&g_Od[(size_t)(rowbase+i)*DD + ocol + j2] = ov;
        }

        // ---- stage B: dS = k^T @ ua  (16 warps x 16 rows, N=32, K=32)
        {
            float acc[4][4];
            #pragma unroll
            for (int n8=0;n8<4;n8++)
                #pragma unroll
                for (int u=0;u<4;u++) acc[n8][u]=0.f;
            const int D0 = wid*16;
            #pragma unroll
            for (int kk=0;kk<2;kk++){
                uint32_t bh0[4], bl0[4], bh1[4], bl1[4];
                uint32_t bofs0 = (uint32_t)((kk*16 + bBrow)*SBP + (((lane>>4)&1)<<3))*2;
                uint32_t bofs1 = bofs0 + 16*2;
                LDSM_X4_T(bh0[0],bh0[1],bh0[2],bh0[3], u_ua_hi + bofs0);
                LDSM_X4_T(bl0[0],bl0[1],bl0[2],bl0[3], u_ua_lo + bofs0);
                LDSM_X4_T(bh1[0],bh1[1],bh1[2],bh1[3], u_ua_hi + bofs1);
                LDSM_X4_T(bl1[0],bl1[1],bl1[2],bl1[3], u_ua_lo + bofs1);
                uint32_t ah[4], al[4];
                uint32_t aofs = (uint32_t)((kk*16 + aBrow)*WQP + D0 + aBcb)*2;
                LDSM_X4_T(ah[0],ah[1],ah[2],ah[3], u_kt_hi + aofs);
                LDSM_X4_T(al[0],al[1],al[2],al[3], u_kt_lo + aofs);
                MMABF16(acc[0], ah, bh0[0], bh0[1]);
                MMABF16(acc[1], ah, bh0[2], bh0[3]);
                MMABF16(acc[2], ah, bh1[0], bh1[1]);
                MMABF16(acc[3], ah, bh1[2], bh1[3]);
                MMABF16(acc[0], ah, bl0[0], bl0[1]);
                MMABF16(acc[1], ah, bl0[2], bl0[3]);
                MMABF16(acc[2], ah, bl1[0], bl1[1]);
                MMABF16(acc[3], ah, bl1[2], bl1[3]);
                MMABF16(acc[0], al, bh0[0], bh0[1]);
                MMABF16(acc[1], al, bh0[2], bh0[3]);
                MMABF16(acc[2], al, bh1[0], bh1[1]);
                MMABF16(acc[3], al, bh1[2], bh1[3]);
            }
            int r0 = D0 + cr;
            #pragma unroll
            for (int n8=0;n8<4;n8++){
                int col = n8*8 + cc;
                S32[(r0  )*SP + col  ] += acc[n8][0];
                S32[(r0  )*SP + col+1] += acc[n8][1];
                S32[(r0+8)*SP + col  ] += acc[n8][2];
                S32[(r0+8)*SP + col+1] += acc[n8][3];
            }
        }

        // ---- store prefetched wq tiles for c+1 (wq dead since sync2)
        if (c+1 < NCHUNK){
            *(float4*)&wq_hi[pr*WQP+pcx]         = pW0h;
            *(float4*)&wq_lo[pr*WQP+pcx]         = pW0l;
            *(float4*)&wq_hi[(32+pr)*WQP+pcx]    = pQ0h;
            *(float4*)&wq_lo[(32+pr)*WQP+pcx]    = pQ0l;
            *(float4*)&wq_hi[(pr+16)*WQP+pcx]    = dW1h;
            *(float4*)&wq_lo[(pr+16)*WQP+pcx]    = dW1l;
            *(float4*)&wq_hi[(48+pr)*WQP+pcx]    = dQ1h;
            *(float4*)&wq_lo[(48+pr)*WQP+pcx]    = dQ1l;
        }

        __syncwarp();
        // ---- refresh S limbs (warp w owns rows w*16..w*16+15; thread: half-row)
        {
            int r  = tid >> 1;
            int cb = (tid & 1) << 4;
            #pragma unroll
            for (int c4=0;c4<16;c4+=4){
                float4 sv = *(float4*)&S32[r*SP + cb + c4];
                split_store4(sv, &S_hi[r*SBP+cb+c4], &S_lo[r*SBP+cb+c4]);
            }
        }
        __syncthreads();   // sync4
    }
}

// ---------------- EMA phase 1: segmented local scan --------------------------
__global__ void __launch_bounds__(256) ema_local_kernel()
{
    extern __shared__ float esm[];
    float* cbuf = esm;             // ESEG*256
    float* gbuf = cbuf + ESEG*256; // ESEG
    float* Ps   = gbuf + ESEG;     // ESEG

    int bh = blockIdx.x, seg = blockIdx.y;
    int b = bh >> 2, h = bh & 3;
    int tid = threadIdx.x;
    int rowbase = b*LL + seg*ESEG;
    size_t hcol = (size_t)h*DK;

    if (tid < ESEG) gbuf[tid] = g_gamma[(rowbase+tid)*HH + h];
    __syncthreads();

    for (int e = tid; e < ESEG*64; e += 256){
        int r = e >> 6, c4 = (e & 63) << 2;
        float om = 1.f - gbuf[r];
        float4 vv = *(const float4*)&g_V[(size_t)(rowbase+r)*DD + hcol + c4];
        vv.x*=om; vv.y*=om; vv.z*=om; vv.w*=om;
        *(float4*)&cbuf[r*256 + c4] = vv;
    }
    if (tid < ESEG){
        int lane = tid & 31;
        float p = gbuf[tid];
        #pragma unroll
        for (int off=1; off<32; off<<=1){
            float o = __shfl_up_sync(0xffffffffu, p, off);
            if (lane >= off) p *= o;
        }
        Ps[tid] = p;
    }
    __syncthreads();
    if (tid < ESEG){
        int wmy = tid >> 5;
        float pre = 1.f;
        for (int wq = 0; wq < wmy; wq++) pre *= Ps[wq*32+31];
        g_P[bh*LL + seg*ESEG + tid] = pre * Ps[tid];
    }

    float s = 0.f;
    #pragma unroll 8
    for (int t = 0; t < ESEG; t++){
        s = fmaf(gbuf[t], s, cbuf[t*256 + tid]);
        cbuf[t*256 + tid] = s;
    }
    __syncthreads();

    for (int e = tid; e < ESEG*64; e += 256){
        int r = e >> 6, c4 = (e & 63) << 2;
        *(float4*)&g_Oe[(size_t)(rowbase+r)*DD + hcol + c4] = *(float4*)&cbuf[r*256 + c4];
    }
}

// ---------------- EMA phase 2: carry across segments -------------------------
__global__ void __launch_bounds__(256) ema_carry_kernel()
{
    int bh = blockIdx.x;
    int b = bh >> 2, h = bh & 3;
    int dv = threadIdx.x;
    float s = 0.f;
    #pragma unroll
    for (int seg = 0; seg < NSEG; seg++){
        g_C[(bh*NSEG + seg)*DK + dv] = s;
        int rend = b*LL + seg*ESEG + (ESEG-1);
        float P  = g_P[bh*LL + seg*ESEG + (ESEG-1)];
        float ye = g_Oe[(size_t)rend*DD + h*DK + dv];
        s = fmaf(P, s, ye);
    }
}

// ---------------- mix combine + RMS norm + fp16 split (fused, + ema carry) ---
__global__ void __launch_bounds__(256) combine_rms_kernel(const float* __restrict__ rmsw)
{
    int wid = threadIdx.x >> 5, lane = threadIdx.x & 31;
    int g = blockIdx.x*8 + wid;
    int row = g >> 2, h = g & 3;
    int b = row >> 11, t = row & (LL-1);
    int bh = b*4 + h, seg = t >> 7;
    float m = g_mixg[row*4+h];
    size_t base = (size_t)row*DD + h*DK;

    float P = g_P[bh*LL + t];
    const float* cav = &g_C[(bh*NSEG + seg)*DK];
    float4 c0 = *(const float4*)&cav[lane*4];
    float4 c1 = *(const float4*)&cav[128 + lane*4];

    float4 d0 = *(float4*)&g_Od[base + lane*4];
    float4 d1 = *(float4*)&g_Od[base + 128 + lane*4];
    float4 e0 = *(float4*)&g_Oe[base + lane*4];
    float4 e1 = *(float4*)&g_Oe[base + 128 + lane*4];
    e0.x += P*c0.x; e0.y += P*c0.y; e0.z += P*c0.z; e0.w += P*c0.w;
    e1.x += P*c1.x; e1.y += P*c1.y; e1.z += P*c1.z; e1.w += P*c1.w;

    float4 o0, o1;
    float om = 1.f - m;
    o0.x = om*d0.x + m*e0.x; o0.y = om*d0.y + m*e0.y;
    o0.z = om*d0.z + m*e0.z; o0.w = om*d0.w + m*e0.w;
    o1.x = om*d1.x + m*e1.x; o1.y = om*d1.y + m*e1.y;
    o1.z = om*d1.z + m*e1.z; o1.w = om*d1.w + m*e1.w;
    float s = o0.x*o0.x+o0.y*o0.y+o0.z*o0.z+o0.w*o0.w
            + o1.x*o1.x+o1.y*o1.y+o1.z*o1.z+o1.w*o1.w;
    #pragma unroll
    for (int off=16; off; off>>=1) s += __shfl_xor_sync(0xffffffffu, s, off);
    float sc = rsqrtf(s*(1.f/256.f) + 1e-5f);
    float4 r0 = *(const float4*)&rmsw[lane*4];
    float4 r1 = *(const float4*)&rmsw[128 + lane*4];
    o0.x *= sc*r0.x; o0.y *= sc*r0.y; o0.z *= sc*r0.z; o0.w *= sc*r0.w;
    o1.x *= sc*r1.x; o1.y *= sc*r1.y; o1.z *= sc*r1.z; o1.w *= sc*r1.w;

    __half h4[4], l4[4];
    float v[4];
    v[0]=o0.x; v[1]=o0.y; v[2]=o0.z; v[3]=o0.w;
    #pragma unroll
    for (int u=0;u<4;u++){
        h4[u]=__float2half_rn(v[u]);
        l4[u]=__float2half_rn(v[u]-__half2float(h4[u]));
    }
    *(u64t*)&g_Op_hi[base + lane*4] = *(u64t*)h4;
    *(u64t*)&g_Op_lo[base + lane*4] = *(u64t*)l4;
    v[0]=o1.x; v[1]=o1.y; v[2]=o1.z; v[3]=o1.w;
    #pragma unroll
    for (int u=0;u<4;u++){
        h4[u]=__float2half_rn(v[u]);
        l4[u]=__float2half_rn(v[u]-__half2float(h4[u]));
    }
    *(u64t*)&g_Op_hi[base + 128 + lane*4] = *(u64t*)h4;
    *(u64t*)&g_Op_lo[base + 128 + lane*4] = *(u64t*)l4;
}

// ---------------- host driver -----------------------------------------------
extern "C" void kernel_launch(void* const* d_in, const int* in_sizes, int n_in,
                              void* d_out, int out_size)
{
    const float* hs      = (const float*)d_in[0];
    const float* Wq      = (const float*)d_in[1];
    const float* Wk      = (const float*)d_in[2];
    const float* Wv      = (const float*)d_in[3];
    const float* convq   = (const float*)d_in[4];
    const float* convk   = (const float*)d_in[5];
    const float* convv   = (const float*)d_in[6];
    const float* Wb      = (const float*)d_in[7];
    const float* Wdec    = (const float*)d_in[8];
    const float* Wmix    = (const float*)d_in[9];
    const float* convmix = (const float*)d_in[10];
    const float* mixbias = (const float*)d_in[11];
    const float* rmsw    = (const float*)d_in[12];
    const float* Wo      = (const float*)d_in[13];

    void *pQL,*pKL,*pVL;
    cudaGetSymbolAddress(&pQL, g_QL);
    cudaGetSymbolAddress(&pKL, g_KL);
    cudaGetSymbolAddress(&pVL, g_VL);

    void *p_hs_hi,*p_hs_lo,*p_Op_hi,*p_Op_lo,*p_WT_h,*p_WoT_h;
    cudaGetSymbolAddress(&p_hs_hi, g_hs_hi);  cudaGetSymbolAddress(&p_hs_lo, g_hs_lo);
    cudaGetSymbolAddress(&p_Op_hi, g_Op_hi);  cudaGetSymbolAddress(&p_Op_lo, g_Op_lo);
    cudaGetSymbolAddress(&p_WT_h, g_WT_h);    cudaGetSymbolAddress(&p_WoT_h, g_WoT_h);

    int smem_chunk = (2*32*WP + 32*33 + 64) * 4;
    int smem_scan  = (256*36 + 2*64*36 + 4*32*36)*4
                   + (2*256*SBP + 2*64*WQP + 2*32*WQP + 2*32*SBP)*2;  // 221184
    int smem_gemm  = NSTG*STGB;
    int smem_ema   = (ESEG*256 + 2*ESEG) * 4;
    cudaFuncSetAttribute(chunk_kernel, cudaFuncAttributeMaxDynamicSharedMemorySize, smem_chunk);
    cudaFuncSetAttribute(scan_kernel,  cudaFuncAttributeMaxDynamicSharedMemorySize, smem_scan);
    cudaFuncSetAttribute(gemm_f16s,    cudaFuncAttributeMaxDynamicSharedMemorySize, smem_gemm);
    cudaFuncSetAttribute(ema_local_kernel, cudaFuncAttributeMaxDynamicSharedMemorySize, smem_ema);

    // 1: merged prep (split + weight transposes + small projections)
    prep_kernel<<<13312,256>>>(hs, Wq, Wk, Wv, Wo,
        (__half*)p_hs_hi, (__half*)p_hs_lo,
        (__half*)p_WT_h, (__half*)p_WoT_h,
        Wb, Wdec, Wmix);

    // 2: merged QKV GEMM (1536 CTAs)
    gemm_f16s<<<dim3(24,64),256,smem_gemm>>>(
        (__half*)p_hs_hi,(__half*)p_hs_lo,(__half*)p_WT_h,
        (float*)pQL, (float*)pKL, (float*)pVL, DD);

    // 3: conv(q,k,v) + mix path
    conv4_kernel<<<dim3(NT*DD/4/256,4),256>>>(convq, convk, convv, convmix, mixbias);

    // 4: l2norm (+limb emission)   <- ncu capture slot
    l2norm_kernel<<<NT*HH/8,256>>>();
    // 5: per-chunk precompute
    chunk_kernel<<<NBH*NCHUNK,256,smem_chunk>>>();
    // 6: sequential scan
    scan_kernel<<<NBH*8,512,smem_scan>>>();

    ema_local_kernel<<<dim3(NBH,NSEG),256,smem_ema>>>();
    ema_carry_kernel<<<NBH,DK>>>();

    combine_rms_kernel<<<NT*HH/8,256>>>(rmsw);

    gemm_f16s<<<dim3(8,64),256,smem_gemm>>>(
        (__half*)p_Op_hi,(__half*)p_Op_lo,(__half*)p_WoT_h,
        (float*)d_out, (float*)d_out, (float*)d_out, DD);
}

// round 17
// speedup vs baseline: 3.6503x; 1.0020x over previous
#include <cuda_runtime.h>
#include <cuda_bf16.h>
#include <cuda_fp16.h>
#include <math.h>
#include <stdint.h>

// Problem constants
#define BB 4
#define LL 2048
#define DD 1024
#define HH 4
#define DK 256
#define NT (BB*LL)       // 8192 tokens
#define NCHUNK 64        // chunks per sequence
#define CHK 32           // chunk length
#define NBH 16           // B*H
#define ESEG 128         // ema segment length
#define NSEG (LL/ESEG)   // 16

typedef unsigned long long u64t;

// ---------------- scratch (device globals; no allocation allowed) -------------
__device__ float g_QL[NT*DD];
__device__ float g_KL[NT*DD];
__device__ float g_VL[NT*DD];
__device__ float g_Q[NT*DD];
__device__ float g_K[NT*DD];
__device__ float g_V[NT*DD];
__device__ float g_beta[NT*HH];
__device__ float g_gamma[NT*HH];
__device__ float g_mixlin[NT*HH];
__device__ float g_mixg[NT*HH];
__device__ float g_T[NBH*NCHUNK*CHK*CHK];    // triangular inverse T
__device__ float g_At[NBH*NCHUNK*CHK*CHK];   // attn_i = tril(q@k^T)
__device__ float g_Od[NT*DD];                // delta-rule output
__device__ float g_Oe[NT*DD];                // ema LOCAL output (y_t)
__device__ float g_P[NBH*LL];                // in-segment prefix products of gamma
__device__ float g_C[NBH*NSEG*DK];           // carry state at segment start

// bf16 limb arrays for the scan's tensor-core stages
__device__ __nv_bfloat16 g_Qh[NT*DD], g_Ql[NT*DD];
__device__ __nv_bfloat16 g_Kh[NT*DD], g_Kl[NT*DD];
__device__ __nv_bfloat16 g_Wh[NBH*NCHUNK*CHK*DK], g_Wl[NBH*NCHUNK*CHK*DK];

// fp16 limb buffers for tensor-core GEMMs (A: 2 limbs; B: single fp16)
__device__ __half g_hs_hi[NT*DD], g_hs_lo[NT*DD];
__device__ __half g_Op_hi[NT*DD], g_Op_lo[NT*DD];
__device__ __half g_WT_h[3*DD*DD];           // Wq|Wk|Wv transposed, fp16
__device__ __half g_WoT_h[DD*DD];            // Wo transposed, fp16

__device__ __forceinline__ float silu_f(float x){ return x / (1.f + expf(-x)); }
__device__ __forceinline__ float sigm_f(float x){ return 1.f / (1.f + expf(-x)); }

// ===================== f32x2 packed-math helpers =============================
__device__ __forceinline__ u64t f2dup(float x){
    u64t r; unsigned int xi = __float_as_uint(x);
    asm("mov.b64 %0, {%1,%1};" : "=l"(r) : "r"(xi));
    return r;
}
__device__ __forceinline__ u64t f2pack(float x, float y){
    u64t r;
    asm("mov.b64 %0, {%1,%2};" : "=l"(r) : "r"(__float_as_uint(x)), "r"(__float_as_uint(y)));
    return r;
}
__device__ __forceinline__ u64t ffma2(u64t a, u64t b, u64t c){
    u64t d; asm("fma.rn.f32x2 %0, %1, %2, %3;" : "=l"(d) : "l"(a), "l"(b), "l"(c));
    return d;
}
__device__ __forceinline__ float2 f2unpack(u64t p){
    unsigned int lo, hi;
    asm("mov.b64 {%0,%1}, %2;" : "=r"(lo), "=r"(hi) : "l"(p));
    return make_float2(__uint_as_float(lo), __uint_as_float(hi));
}

// ===================== PTX helpers (mma.sync / ldmatrix / cp.async) ==========
__device__ __forceinline__ uint32_t smem_u32(const void* p){
    uint32_t a;
    asm("{ .reg .u64 t; cvta.to.shared.u64 t, %1; cvt.u32.u64 %0, t; }" : "=r"(a) : "l"(p));
    return a;
}
__device__ __forceinline__ void cp_async16(uint32_t dst, const void* src){
    asm volatile("cp.async.cg.shared.global [%0], [%1], 16;" :: "r"(dst), "l"(src) : "memory");
}
__device__ __forceinline__ void cp_commit(){ asm volatile("cp.async.commit_group;" ::: "memory"); }

#define LDSM_X4(r0,r1,r2,r3, addr) \
    asm volatile("ldmatrix.sync.aligned.m8n8.x4.shared.b16 {%0,%1,%2,%3}, [%4];" \
        : "=r"(r0),"=r"(r1),"=r"(r2),"=r"(r3) : "r"(addr))

#define LDSM_X4_T(r0,r1,r2,r3, addr) \
    asm volatile("ldmatrix.sync.aligned.m8n8.x4.trans.shared.b16 {%0,%1,%2,%3}, [%4];" \
        : "=r"(r0),"=r"(r1),"=r"(r2),"=r"(r3) : "r"(addr))

#define MMAF16(d, a, b0, b1) \
    asm volatile("mma.sync.aligned.m16n8k16.row.col.f32.f16.f16.f32 " \
        "{%0,%1,%2,%3}, {%4,%5,%6,%7}, {%8,%9}, {%0,%1,%2,%3};" \
        : "+f"((d)[0]),"+f"((d)[1]),"+f"((d)[2]),"+f"((d)[3]) \
        : "r"((a)[0]),"r"((a)[1]),"r"((a)[2]),"r"((a)[3]), "r"(b0),"r"(b1))

#define MMABF16(d, a, b0, b1) \
    asm volatile("mma.sync.aligned.m16n8k16.row.col.f32.bf16.bf16.f32 " \
        "{%0,%1,%2,%3}, {%4,%5,%6,%7}, {%8,%9}, {%0,%1,%2,%3};" \
        : "+f"((d)[0]),"+f"((d)[1]),"+f"((d)[2]),"+f"((d)[3]) \
        : "r"((a)[0]),"r"((a)[1]),"r"((a)[2]),"r"((a)[3]), "r"(b0),"r"(b1))

// bf16 hi/lo split-store of a float4 (4B-aligned destinations)
__device__ __forceinline__ void split_store4(float4 v, __nv_bfloat16* ph, __nv_bfloat16* pl){
    __nv_bfloat162 h01, h23, l01, l23;
    h01.x = __float2bfloat16(v.x); h01.y = __float2bfloat16(v.y);
    h23.x = __float2bfloat16(v.z); h23.y = __float2bfloat16(v.w);
    l01.x = __float2bfloat16(v.x - __bfloat162float(h01.x));
    l01.y = __float2bfloat16(v.y - __bfloat162float(h01.y));
    l23.x = __float2bfloat16(v.z - __bfloat162float(h23.x));
    l23.y = __float2bfloat16(v.w - __bfloat162float(h23.y));
    *(__nv_bfloat162*)(ph)   = h01; *(__nv_bfloat162*)(ph+2) = h23;
    *(__nv_bfloat162*)(pl)   = l01; *(__nv_bfloat162*)(pl+2) = l23;
}
__device__ __forceinline__ void split_store2(float2 v, __nv_bfloat16* ph, __nv_bfloat16* pl){
    __nv_bfloat162 h01, l01;
    h01.x = __float2bfloat16(v.x); h01.y = __float2bfloat16(v.y);
    l01.x = __float2bfloat16(v.x - __bfloat162float(h01.x));
    l01.y = __float2bfloat16(v.y - __bfloat162float(h01.y));
    *(__nv_bfloat162*)(ph) = h01;
    *(__nv_bfloat162*)(pl) = l01;
}

// ===================== merged prep: split + wsplitT + smallproj ==============
// grid: [0,8192) split ; [8192,12288) wsplit ; [12288,13312) smallproj
__global__ void __launch_bounds__(256) prep_kernel(
    const float* __restrict__ hs,
    const float* __restrict__ W0, const float* __restrict__ W1,
    const float* __restrict__ W2, const float* __restrict__ W3,
    __half* __restrict__ hs_hi, __half* __restrict__ hs_lo,
    __half* __restrict__ bigh, __half* __restrict__ woh,
    const float* __restrict__ Wb, const float* __restrict__ Wdec,
    const float* __restrict__ Wmix)
{
    __shared__ float t[32][33];
    int bid = blockIdx.x;
    if (bid < 8192){
        // split hs -> fp16 limbs
        int i4 = bid*256 + threadIdx.x;
        float4 v = *(const float4*)&hs[(size_t)i4*4];
        __half hh[4], l[4];
        float a[4] = {v.x, v.y, v.z, v.w};
        #pragma unroll
        for (int u=0;u<4;u++){
            hh[u] = __float2half_rn(a[u]);
            l[u] = __float2half_rn(a[u] - __half2float(hh[u]));
        }
        *(u64t*)&hs_hi[(size_t)i4*4] = *(u64t*)hh;
        *(u64t*)&hs_lo[(size_t)i4*4] = *(u64t*)l;
    } else if (bid < 12288){
        // weight transpose to fp16
        int r = bid - 8192;
        int z  = r >> 10;
        int k0 = ((r >> 5) & 31) * 32;
        int n0 = (r & 31) * 32;
        const float* W; __half* hiT;
        if      (z==0){ W=W0; hiT=bigh; }
        else if (z==1){ W=W1; hiT=bigh+DD*DD; }
        else if (z==2){ W=W2; hiT=bigh+2*DD*DD; }
        else          { W=W3; hiT=woh; }
        int tx = threadIdx.x & 31, ty = threadIdx.x >> 5;
        for (int i = ty; i < 32; i += 8)
            t[i][tx] = W[(size_t)(k0+i)*DD + n0+tx];
        __syncthreads();
        for (int i = ty; i < 32; i += 8)
            hiT[(size_t)(n0+i)*DD + k0+tx] = __float2half_rn(t[tx][i]);
    } else {
        // small projections: warp per row
        int wid = threadIdx.x >> 5, lane = threadIdx.x & 31;
        int row = (bid - 12288)*8 + wid;
        const float* xr = hs + (size_t)row*DD;
        float a[12];
        #pragma unroll
        for (int j=0;j<12;j++) a[j]=0.f;
        for (int c=lane; c<DD; c+=32){
            float hv = xr[c];
            float4 wb = *(const float4*)&Wb[c*4];
            float4 wd = *(const float4*)&Wdec[c*4];
            float4 wm = *(const float4*)&Wmix[c*4];
            a[0]+=hv*wb.x; a[1]+=hv*wb.y; a[2]+=hv*wb.z; a[3]+=hv*wb.w;
            a[4]+=hv*wd.x; a[5]+=hv*wd.y; a[6]+=hv*wd.z; a[7]+=hv*wd.w;
            a[8]+=hv*wm.x; a[9]+=hv*wm.y; a[10]+=hv*wm.z; a[11]+=hv*wm.w;
        }
        #pragma unroll
        for (int off=16; off; off>>=1){
            #pragma unroll
            for (int j=0;j<12;j++) a[j] += __shfl_down_sync(0xffffffffu, a[j], off);
        }
        if (lane == 0){
            #pragma unroll
            for (int j=0;j<4;j++){
                g_beta  [row*4+j] = sigm_f(a[j]);
                g_gamma [row*4+j] = sigm_f(a[4+j]);
                g_mixlin[row*4+j] = a[8+j];
            }
        }
    }
}

// ===================== mma.sync fp16 2-limb GEMM =============================
#define GRS 40            // smem row stride in fp16 elements (80 bytes)
#define MATB (128*GRS*2)  // 10240 bytes per matrix tile
#define STGB (3*MATB)     // 30720 per stage (Ahi, Alo, B)
#define NSTG 3

__global__ void __launch_bounds__(256,2) gemm_f16s(
    const __half* __restrict__ Ahi, const __half* __restrict__ Alo,
    const __half* __restrict__ BT,
    float* C0, float* C1, float* C2, int K)
{
    extern __shared__ char smem[];
    const uint32_t sbase = smem_u32(smem);
    const int tid  = threadIdx.x;
    const int lane = tid & 31, wid = tid >> 5;
    const int wm = wid & 3, wn = wid >> 2;          // 4x2 warp grid
    const int row0 = blockIdx.y*128;
    const int bcol = blockIdx.x*128;                // into B (up to 3072 wide)
    const int seg  = blockIdx.x >> 3;
    const int col0 = (blockIdx.x & 7)*128;          // into C
    float* C = (seg==0) ? C0 : (seg==1 ? C1 : C2);

    const __half* g0 = Ahi + (size_t)row0*K;
    const __half* g1 = Alo + (size_t)row0*K;
    const __half* g2 = BT  + (size_t)bcol*K;

    float acc[2][8][4];
    #pragma unroll
    for (int i=0;i<2;i++)
        #pragma unroll
        for (int j=0;j<8;j++)
            #pragma unroll
            for (int u=0;u<4;u++) acc[i][j][u]=0.f;

    auto fill = [&](int kb){
        uint32_t sb = sbase + (kb%NSTG)*STGB;
        #pragma unroll
        for (int t=0;t<2;t++){
            int ci = tid + t*256;
            int r = ci >> 2, c = ci & 3;
            uint32_t dst = sb + r*(GRS*2) + c*16;
            size_t go = (size_t)r*K + (size_t)kb*32 + c*8;
            cp_async16(dst + 0*MATB, g0 + go);
            cp_async16(dst + 1*MATB, g1 + go);
            cp_async16(dst + 2*MATB, g2 + go);
        }
        cp_commit();
    };

    const int nkb = K/32;
    fill(0);
    fill(1);

    const int a_r  = lane & 15;
    const int a_ko = ((lane >> 4) & 1) << 3;
    const int b_n  = (lane & 7) + (((lane >> 4) & 1) << 3);
    const int b_ko = ((lane >> 3) & 1) << 3;

    for (int kb = 0; kb < nkb; kb++){
        if (kb+1 < nkb) asm volatile("cp.async.wait_group 1;" ::: "memory");
        else            asm volatile("cp.async.wait_group 0;" ::: "memory");
        __syncthreads();

        uint32_t sb = sbase + (kb%NSTG)*STGB;
        #pragma unroll
        for (int ks=0; ks<2; ks++){
            const int k16 = ks*16;
            uint32_t ah[2][4], al[2][4];
            #pragma unroll
            for (int mt=0; mt<2; mt++){
                uint32_t ad = sb + (wm*32 + mt*16 + a_r)*(GRS*2) + (k16 + a_ko)*2;
                LDSM_X4(ah[mt][0],ah[mt][1],ah[mt][2],ah[mt][3], ad + 0*MATB);
                LDSM_X4(al[mt][0],al[mt][1],al[mt][2],al[mt][3], ad + 1*MATB);
            }
            #pragma unroll
            for (int n4=0; n4<4; n4++){
                uint32_t bd = sb + 2*MATB + (wn*64 + n4*16 + b_n)*(GRS*2) + (k16 + b_ko)*2;
                uint32_t bh[4];
                LDSM_X4(bh[0],bh[1],bh[2],bh[3], bd);
                #pragma unroll
                for (int mt=0; mt<2; mt++){
                    MMAF16(acc[mt][n4*2  ], ah[mt], bh[0], bh[1]);
                    MMAF16(acc[mt][n4*2+1], ah[mt], bh[2], bh[3]);
                    MMAF16(acc[mt][n4*2  ], al[mt], bh[0], bh[1]);
                    MMAF16(acc[mt][n4*2+1], al[mt], bh[2], bh[3]);
                }
            }
        }
        if (kb+2 < nkb) fill(kb+2);
    }

    float* Cg = C + (size_t)(row0 + wm*32)*DD + col0 + wn*64;
    const int cr = lane >> 2, cc = (lane & 3) << 1;
    #pragma unroll
    for (int mt=0; mt<2; mt++)
        #pragma unroll
        for (int nt=0; nt<8; nt++){
            float2 v0; v0.x = acc[mt][nt][0]; v0.y = acc[mt][nt][1];
            *(float2*)&Cg[(size_t)(mt*16+cr)*DD + nt*8+cc] = v0;
            float2 v1; v1.x = acc[mt][nt][2]; v1.y = acc[mt][nt][3];
            *(float2*)&Cg[(size_t)(mt*16+cr+8)*DD + nt*8+cc] = v1;
        }
}

// ---------------- fused conv+silu(+silu)+l2norm+limbs (Q,K), V conv, mixconv -
// grid: [0,4096) Q-norm ; [4096,8192) K-norm ; [8192,16384) V conv ;
//       [16384,16512) mixconv
__global__ void __launch_bounds__(256) convnorm_kernel(
    const float* __restrict__ convq, const float* __restrict__ convk,
    const float* __restrict__ convv, const float* __restrict__ convmix,
    const float* __restrict__ mixbias)
{
    int bid = blockIdx.x;
    if (bid < 8192){
        // warp per (token, head): conv -> silu -> silu -> l2norm -> write + limbs
        int isK = (bid >= 4096) ? 1 : 0;
        int g = (bid & 4095)*8 + (threadIdx.x >> 5);
        int lane = threadIdx.x & 31;
        int row = g >> 2, h = g & 3;
        const float* X  = isK ? g_KL : g_QL;
        const float* Wc = isK ? convk : convq;
        float* Y        = isK ? g_K : g_Q;
        __nv_bfloat16* Yh = isK ? g_Kh : g_Qh;
        __nv_bfloat16* Yl = isK ? g_Kl : g_Ql;
        int t = row & (LL-1);
        size_t base = (size_t)row*DD + h*DK;
        int c0 = h*DK + lane*4;
        float4 a0 = make_float4(0.f,0.f,0.f,0.f);
        float4 a1 = make_float4(0.f,0.f,0.f,0.f);
        #pragma unroll
        for (int k=0;k<4;k++){
            int ts = t-3+k;
            if (ts>=0){
                const float* xr = X + (size_t)(row + (ts-t))*DD;
                float4 x0 = *(const float4*)&xr[c0];
                float4 x1 = *(const float4*)&xr[c0+128];
                a0.x += x0.x * Wc[(c0+0)*4+k];
                a0.y += x0.y * Wc[(c0+1)*4+k];
                a0.z += x0.z * Wc[(c0+2)*4+k];
                a0.w += x0.w * Wc[(c0+3)*4+k];
                a1.x += x1.x * Wc[(c0+128)*4+k];
                a1.y += x1.y * Wc[(c0+129)*4+k];
                a1.z += x1.z * Wc[(c0+130)*4+k];
                a1.w += x1.w * Wc[(c0+131)*4+k];
            }
        }
        a0.x = silu_f(silu_f(a0.x)); a0.y = silu_f(silu_f(a0.y));
        a0.z = silu_f(silu_f(a0.z)); a0.w = silu_f(silu_f(a0.w));
        a1.x = silu_f(silu_f(a1.x)); a1.y = silu_f(silu_f(a1.y));
        a1.z = silu_f(silu_f(a1.z)); a1.w = silu_f(silu_f(a1.w));
        float s = a0.x*a0.x+a0.y*a0.y+a0.z*a0.z+a0.w*a0.w
                + a1.x*a1.x+a1.y*a1.y+a1.z*a1.z+a1.w*a1.w;
        #pragma unroll
        for (int off=16; off; off>>=1) s += __shfl_xor_sync(0xffffffffu, s, off);
        float sc = rsqrtf(s + 1e-6f);
        a0.x*=sc; a0.y*=sc; a0.z*=sc; a0.w*=sc;
        a1.x*=sc; a1.y*=sc; a1.z*=sc; a1.w*=sc;
        *(float4*)&Y[base + lane*4] = a0;
        *(float4*)&Y[base + 128 + lane*4] = a1;
        split_store4(a0, &Yh[base + lane*4], &Yl[base + lane*4]);
        split_store4(a1, &Yh[base + 128 + lane*4], &Yl[base + 128 + lane*4]);
    } else if (bid < 16384){
        // V conv (single silu), elementwise float4
        int idx4 = (bid - 8192)*256 + threadIdx.x;
        int ch  = (idx4 & 255) << 2;
        int bt  = idx4 >> 8;
        int t   = bt & (LL-1);
        float4 acc = make_float4(0.f,0.f,0.f,0.f);
        #pragma unroll
        for (int k=0;k<4;k++){
            int ts = t-3+k;
            if (ts>=0){
                float4 xv = *(const float4*)&g_VL[(size_t)(bt + (ts-t))*DD + ch];
                acc.x += xv.x * convv[(ch+0)*4+k];
                acc.y += xv.y * convv[(ch+1)*4+k];
                acc.z += xv.z * convv[(ch+2)*4+k];
                acc.w += xv.w * convv[(ch+3)*4+k];
            }
        }
        float4 y;
        y.x = silu_f(acc.x); y.y = silu_f(acc.y);
        y.z = silu_f(acc.z); y.w = silu_f(acc.w);
        *(float4*)&g_V[(size_t)bt*DD + ch] = y;
    } else {
        int idx = (bid - 16384)*256 + threadIdx.x;
        if (idx < NT*HH){
            int hh = idx & 3;
            int bt = idx >> 2;
            int t = bt & (LL-1);
            float acc = 0.f;
            #pragma unroll
            for (int k=0;k<4;k++){
                int ts = t-3+k;
                if (ts>=0) acc += g_mixlin[idx + (ts-t)*HH] * convmix[hh*4+k];
            }
            float mi = silu_f(acc);
            g_mixg[idx] = sigm_f(mi + mixbias[hh]);
        }
    }
}

// ---------------- per-chunk: T (tri inverse), W limbs, Attn ------------------
#define WP 260   // float stride for 32x256 tiles
#define SP 36    // float stride for 32x32 / 256x32 tiles

__global__ void __launch_bounds__(256) chunk_kernel()
{
    extern __shared__ float sm[];
    float* kc     = sm;                 // 32*WP
    float* qc     = kc + 32*WP;         // 32*WP
    float* Amat   = qc + 32*WP;         // 32*33
    float* bet    = Amat + 32*33;       // 32
    float* rowtmp = bet + 32;           // 32

    int blk = blockIdx.x;               // bh*64 + c
    int bh = blk >> 6, c = blk & 63;
    int b = bh >> 2, h = bh & 3;
    int tid = threadIdx.x;
    int rowbase = b*LL + c*CHK;

    for (int e = tid; e < 2048; e += 256){
        int r = e >> 6; int c4 = (e & 63) << 2;
        *(float4*)&kc[r*WP+c4] = *(const float4*)&g_K[(size_t)(rowbase+r)*DD + h*DK + c4];
        *(float4*)&qc[r*WP+c4] = *(const float4*)&g_Q[(size_t)(rowbase+r)*DD + h*DK + c4];
    }
    if (tid < 32) bet[tid] = g_beta[(rowbase+tid)*HH + h];
    __syncthreads();

    // A = -tril(k_beta @ k^T, -1),  Attn = tril(q @ k^T, 0)   [f32x2, pair over m]
    {
        int i = tid >> 3, j0 = tid & 7;
        u64t da[4], dq[4];
        #pragma unroll
        for (int u=0;u<4;u++){ da[u]=0ull; dq[u]=0ull; }
        #pragma unroll 4
        for (int m=0;m<256;m+=4){
            ulonglong2 ki = *(ulonglong2*)&kc[i*WP+m];
            ulonglong2 qi = *(ulonglong2*)&qc[i*WP+m];
            #pragma unroll
            for (int u=0;u<4;u++){
                ulonglong2 kj = *(ulonglong2*)&kc[(j0+8*u)*WP+m];
                da[u] = ffma2(ki.x, kj.x, da[u]);
                da[u] = ffma2(ki.y, kj.y, da[u]);
                dq[u] = ffma2(qi.x, kj.x, dq[u]);
                dq[u] = ffma2(qi.y, kj.y, dq[u]);
            }
        }
        #pragma unroll
        for (int u=0;u<4;u++){
            int j = j0 + 8*u;
            float2 ta = f2unpack(da[u]);
            float2 tq = f2unpack(dq[u]);
            float av = ta.x + ta.y, qv = tq.x + tq.y;
            Amat[i*33+j] = (j < i) ? -bet[i]*av : 0.f;
            g_At[(size_t)blk*1024 + i*32 + j] = (j <= i) ? qv : 0.f;
        }
    }
    __syncthreads();

    // sequential forward-substitution (warp 0)
    if (tid < 32){
        int cx = tid;
        for (int ii=1; ii<32; ii++){
            rowtmp[cx] = Amat[ii*33+cx];
            __syncwarp();
            float acc = 0.f;
            if (cx < ii){
                acc = rowtmp[cx];
                for (int j=cx+1; j<ii; j++) acc += rowtmp[j]*Amat[j*33+cx];
            }
            __syncwarp();
            if (cx < ii) Amat[ii*33+cx] = acc;
            __syncwarp();
        }
        Amat[cx*33+cx] = 1.0f;   // T = A + I
    }
    __syncthreads();

    for (int e=tid; e<1024; e+=256)
        g_T[(size_t)blk*1024 + e] = Amat[(e>>5)*33 + (e&31)];

    // W = T @ (beta * k)   [f32x2, pair over dk] -> write bf16 limbs directly
    {
        int i = tid >> 3, mb = (tid & 7) << 2;
        u64t acc[16];
        #pragma unroll
        for (int s=0;s<16;s++) acc[s]=0ull;
        for (int j=0;j<32;j++){
            u64t td = f2dup(Amat[i*33+j]*bet[j]);
            #pragma unroll
            for (int s=0;s<8;s++){
                ulonglong2 kv = *(ulonglong2*)&kc[j*WP + s*32 + mb];
                acc[2*s]   = ffma2(td, kv.x, acc[2*s]);
                acc[2*s+1] = ffma2(td, kv.y, acc[2*s+1]);
            }
        }
        #pragma unroll
        for (int s=0;s<8;s++){
            float2 p0 = f2unpack(acc[2*s]), p1 = f2unpack(acc[2*s+1]);
            float4 wv; wv.x = p0.x; wv.y = p0.y; wv.z = p1.x; wv.w = p1.y;
            size_t go = ((size_t)blk*32 + i)*DK + s*32 + mb;
            split_store4(wv, &g_Wh[go], &g_Wl[go]);
        }
    }
}

// ---------------- inter-chunk scan: tensor-core, 512 threads, SW-pipelined ---
// grid: 128 blocks = 16 (b,h) x 8 dv-slabs of 32 columns; 512 threads (16 warps)
#define SBP 40    // bf16 stride for S / ua limb tiles (80 B rows)
#define WQP 264   // bf16 stride for wq / kt limb tiles (528 B rows)

__global__ void __launch_bounds__(512,1) scan_kernel()
{
    extern __shared__ char sraw[];
    float* S32   = (float*)sraw;              // 256*36
    float* P32   = S32  + 256*36;             // 2 x 64*36 (partial K-halves)
    float* att32 = P32  + 2*64*36;            // 32*36
    float* T32   = att32+ 32*36;              // 32*36
    float* vb32  = T32  + 32*36;              // 32*36
    float* ua32  = vb32 + 32*36;              // 32*36
    __nv_bfloat16* S_hi  = (__nv_bfloat16*)(ua32 + 32*36);
    __nv_bfloat16* S_lo  = S_hi  + 256*SBP;
    __nv_bfloat16* wq_hi = S_lo  + 256*SBP;   // 64 rows (w:0-31, q:32-63)
    __nv_bfloat16* wq_lo = wq_hi + 64*WQP;
    __nv_bfloat16* kt_hi = wq_lo + 64*WQP;    // 32 rows
    __nv_bfloat16* kt_lo = kt_hi + 32*WQP;
    __nv_bfloat16* ua_hi = kt_lo + 32*WQP;    // 32 rows
    __nv_bfloat16* ua_lo = ua_hi + 32*SBP;

    const int tid  = threadIdx.x;
    const int lane = tid & 31, wid = tid >> 5;
    const int bh   = blockIdx.x >> 3;
    const int slab = blockIdx.x & 7;
    const int b = bh >> 2, h = bh & 3;
    const size_t ocol = (size_t)h*DK + slab*32;

    const uint32_t u_S_hi  = smem_u32(S_hi),  u_S_lo  = smem_u32(S_lo);
    const uint32_t u_wq_hi = smem_u32(wq_hi), u_wq_lo = smem_u32(wq_lo);
    const uint32_t u_kt_hi = smem_u32(kt_hi), u_kt_lo = smem_u32(kt_lo);
    const uint32_t u_ua_hi = smem_u32(ua_hi), u_ua_lo = smem_u32(ua_lo);

    // init S and its limbs
    for (int e=tid; e<256*36; e+=512) S32[e]=0.f;
    for (int e=tid; e<256*SBP; e+=512){
        ((uint16_t*)S_hi)[e] = 0; ((uint16_t*)S_lo)[e] = 0;
    }

    // scalar-stage geometry (512 threads, 2 cols each)
    const int i  = tid >> 4;          // row 0..31
    const int j2 = (tid & 15) << 1;   // col 0..30 step 2

    // stage-A geometry: 4 M-tiles x 2 N-tiles x 2 K-halves
    const int wmA = wid & 3;
    const int wnA = (wid >> 2) & 1;
    const int khA = wid >> 3;                     // 0 or 1
    const int aArow = wmA*16 + (lane & 15);
    const int aAcb  = ((lane >> 4) & 1) << 3;
    const int bArow = (lane & 15);
    const int bAcb  = wnA*16 + (((lane >> 4) & 1) << 3);
    // stage-B geometry: 16 warps x 16 rows
    const int aBrow = (lane & 7) + (((lane >> 4) & 1) << 3);
    const int aBcb  = ((lane >> 3) & 1) << 3;
    const int bBrow = (lane & 15);
    const int cr = lane >> 2, cc = (lane & 3) << 1;

    // prefetch geometry
    const int pr  = tid >> 5;          // limb row iter0 (0..15)
    const int pcx = (tid & 31) << 3;   // bf16 col base
    const int prr = tid >> 3;          // att/T/vb row (tid<256)
    const int pc4 = (tid & 7) << 2;

    // ---- prologue: direct full load of chunk 0
    {
        int blk = bh*NCHUNK;
        int rowbase = b*LL;
        for (int e=tid; e<1024; e+=512){
            int r = e >> 5; int cx = (e & 31) << 3;
            size_t gw = ((size_t)blk*32 + r)*DK + cx;
            size_t gq = (size_t)(rowbase+r)*DD + h*DK + cx;
            *(float4*)&wq_hi[r*WQP+cx]      = *(const float4*)&g_Wh[gw];
            *(float4*)&wq_lo[r*WQP+cx]      = *(const float4*)&g_Wl[gw];
            *(float4*)&wq_hi[(32+r)*WQP+cx] = *(const float4*)&g_Qh[gq];
            *(float4*)&wq_lo[(32+r)*WQP+cx] = *(const float4*)&g_Ql[gq];
            *(float4*)&kt_hi[r*WQP+cx]      = *(const float4*)&g_Kh[gq];
            *(float4*)&kt_lo[r*WQP+cx]      = *(const float4*)&g_Kl[gq];
        }
        if (tid < 256){
            *(float4*)&att32[prr*SP+pc4] = *(const float4*)&g_At[(size_t)blk*1024 + prr*32 + pc4];
            *(float4*)&T32 [prr*SP+pc4]  = *(const float4*)&g_T [(size_t)blk*1024 + prr*32 + pc4];
            float be = g_beta[(rowbase+prr)*HH + h];
            float4 vv = *(const float4*)&g_V[(size_t)(rowbase+prr)*DD + ocol + pc4];
            vv.x*=be; vv.y*=be; vv.z*=be; vv.w*=be;
            *(float4*)&vb32[prr*SP+pc4] = vv;
        }
    }
    __syncthreads();

    float4 pW0h, pW0l, pQ0h, pQ0l, pK0h, pK0l, pK1h, pK1l;
    float4 pAtt, pT, pVb;

    for (int c=0; c<NCHUNK; c++){
        int rowbase = b*LL + c*CHK;

        // ---- R1: store prefetched kt + att/T/vb for this chunk (c>=1)
        if (c > 0){
            *(float4*)&kt_hi[pr*WQP+pcx]      = pK0h;
            *(float4*)&kt_lo[pr*WQP+pcx]      = pK0l;
            *(float4*)&kt_hi[(pr+16)*WQP+pcx] = pK1h;
            *(float4*)&kt_lo[(pr+16)*WQP+pcx] = pK1l;
            if (tid < 256){
                *(float4*)&att32[prr*SP+pc4] = pAtt;
                *(float4*)&T32 [prr*SP+pc4]  = pT;
                *(float4*)&vb32[prr*SP+pc4]  = pVb;
            }
        }

        // ---- stage A: P_kh = [w|q] @ S_kh  (each warp: 8 k16-steps)
        {
            float acc[2][4];
            #pragma unroll
            for (int n8=0;n8<2;n8++)
                #pragma unroll
                for (int u=0;u<4;u++) acc[n8][u]=0.f;
            #pragma unroll 4
            for (int k16=0;k16<8;k16++){
                int kg = khA*8 + k16;
                uint32_t ah[4], al[4], bh_[4], bl_[4];
                uint32_t aofs = (uint32_t)(aArow*WQP + kg*16 + aAcb)*2;
                LDSM_X4(ah[0],ah[1],ah[2],ah[3], u_wq_hi + aofs);
                LDSM_X4(al[0],al[1],al[2],al[3], u_wq_lo + aofs);
                uint32_t bofs = (uint32_t)((kg*16 + bArow)*SBP + bAcb)*2;
                LDSM_X4_T(bh_[0],bh_[1],bh_[2],bh_[3], u_S_hi + bofs);
                LDSM_X4_T(bl_[0],bl_[1],bl_[2],bl_[3], u_S_lo + bofs);
                MMABF16(acc[0], ah, bh_[0], bh_[1]);
                MMABF16(acc[1], ah, bh_[2], bh_[3]);
                MMABF16(acc[0], ah, bl_[0], bl_[1]);
                MMABF16(acc[1], ah, bl_[2], bl_[3]);
                MMABF16(acc[0], al, bh_[0], bh_[1]);
                MMABF16(acc[1], al, bh_[2], bh_[3]);
            }
            float* Pp = P32 + khA*64*36;
            #pragma unroll
            for (int n8=0;n8<2;n8++){
                int col = wnA*16 + n8*8 + cc;
                Pp[(wmA*16+cr  )*SP + col  ] = acc[n8][0];
                Pp[(wmA*16+cr  )*SP + col+1] = acc[n8][1];
                Pp[(wmA*16+cr+8)*SP + col  ] = acc[n8][2];
                Pp[(wmA*16+cr+8)*SP + col+1] = acc[n8][3];
            }
        }
        __syncthreads();   // sync2

        // ---- R2: issue prefetch LDGs for chunk c+1
        if (c+1 < NCHUNK){
            int blkN = bh*NCHUNK + c + 1;
            int rbN  = b*LL + (c+1)*CHK;
            size_t gw  = ((size_t)blkN*32 + pr)*DK + pcx;
            size_t gq  = (size_t)(rbN + pr)*DD + h*DK + pcx;
            size_t gq1 = (size_t)(rbN + pr + 16)*DD + h*DK + pcx;
            pW0h = *(const float4*)&g_Wh[gw];
            pW0l = *(const float4*)&g_Wl[gw];
            pQ0h = *(const float4*)&g_Qh[gq];
            pQ0l = *(const float4*)&g_Ql[gq];
            pK0h = *(const float4*)&g_Kh[gq];
            pK0l = *(const float4*)&g_Kl[gq];
            pK1h = *(const float4*)&g_Kh[gq1];
            pK1l = *(const float4*)&g_Kl[gq1];
            if (tid < 256){
                pAtt = *(const float4*)&g_At[(size_t)blkN*1024 + prr*32 + pc4];
                pT   = *(const float4*)&g_T [(size_t)blkN*1024 + prr*32 + pc4];
                float be = g_beta[(rbN+prr)*HH + h];
                float4 vv = *(const float4*)&g_V[(size_t)(rbN+prr)*DD + ocol + pc4];
                vv.x*=be; vv.y*=be; vv.z*=be; vv.w*=be;
                pVb = vv;
            }
        }

        // ---- scalar: u = T@vb ; ua = u - (P0+P1)_w ; ua limbs (2 cols/thread)
        {
            u64t ui = 0ull;
            #pragma unroll
            for (int m=0;m<32;m++){
                u64t td = f2dup(T32[i*SP+m]);
                u64t vv = *(u64t*)&vb32[m*SP+j2];
                ui = ffma2(td, vv, ui);
            }
            float2 uu = f2unpack(ui);
            float2 pa = *(float2*)&P32[i*SP+j2];
            float2 pb = *(float2*)&P32[64*36 + i*SP+j2];
            float2 uav;
            uav.x = uu.x - pa.x - pb.x;
            uav.y = uu.y - pa.y - pb.y;
            *(float2*)&ua32[i*SP+j2] = uav;
            split_store2(uav, &ua_hi[i*SBP+j2], &ua_lo[i*SBP+j2]);
        }
        __syncthreads();   // sync3

        // ---- R3: issue wq-iter1 direct prefetch for c+1
        float4 dW1h, dW1l, dQ1h, dQ1l;
        if (c+1 < NCHUNK){
            int blkN = bh*NCHUNK + c + 1;
            int rbN  = b*LL + (c+1)*CHK;
            size_t gw1 = ((size_t)blkN*32 + pr + 16)*DK + pcx;
            size_t gq1 = (size_t)(rbN + pr + 16)*DD + h*DK + pcx;
            dW1h = *(const float4*)&g_Wh[gw1];
            dW1l = *(const float4*)&g_Wl[gw1];
            dQ1h = *(const float4*)&g_Qh[gq1];
            dQ1l = *(const float4*)&g_Ql[gq1];
        }

        // ---- scalar: o = (P0+P1)_q + att @ ua  -> global (2 cols/thread)
        {
            float2 qa = *(float2*)&P32[(32+i)*SP+j2];
            float2 qb = *(float2*)&P32[64*36 + (32+i)*SP+j2];
            u64t aO = f2pack(qa.x + qb.x, qa.y + qb.y);
            #pragma unroll
            for (int m=0;m<32;m++){
                u64t ad = f2dup(att32[i*SP+m]);
                u64t uv = *(u64t*)&ua32[m*SP+j2];
                aO = ffma2(ad, uv, aO);
            }
            float2 ov = f2unpack(aO);
            *(float2*)&g_Od[(size_t)(rowbase+i)*DD + ocol + j2] = ov;
        }

        // ---- stage B: dS = k^T @ ua  (16 warps x 16 rows, N=32, K=32)
        {
            float acc[4][4];
            #pragma unroll
            for (int n8=0;n8<4;n8++)
                #pragma unroll
                for (int u=0;u<4;u++) acc[n8][u]=0.f;
            const int D0 = wid*16;
            #pragma unroll
            for (int kk=0;kk<2;kk++){
                uint32_t bh0[4], bl0[4], bh1[4], bl1[4];
                uint32_t bofs0 = (uint32_t)((kk*16 + bBrow)*SBP + (((lane>>4)&1)<<3))*2;
                uint32_t bofs1 = bofs0 + 16*2;
                LDSM_X4_T(bh0[0],bh0[1],bh0[2],bh0[3], u_ua_hi + bofs0);
                LDSM_X4_T(bl0[0],bl0[1],bl0[2],bl0[3], u_ua_lo + bofs0);
                LDSM_X4_T(bh1[0],bh1[1],bh1[2],bh1[3], u_ua_hi + bofs1);
                LDSM_X4_T(bl1[0],bl1[1],bl1[2],bl1[3], u_ua_lo + bofs1);
                uint32_t ah[4], al[4];
                uint32_t aofs = (uint32_t)((kk*16 + aBrow)*WQP + D0 + aBcb)*2;
                LDSM_X4_T(ah[0],ah[1],ah[2],ah[3], u_kt_hi + aofs);
                LDSM_X4_T(al[0],al[1],al[2],al[3], u_kt_lo + aofs);
                MMABF16(acc[0], ah, bh0[0], bh0[1]);
                MMABF16(acc[1], ah, bh0[2], bh0[3]);
                MMABF16(acc[2], ah, bh1[0], bh1[1]);
                MMABF16(acc[3], ah, bh1[2], bh1[3]);
                MMABF16(acc[0], ah, bl0[0], bl0[1]);
                MMABF16(acc[1], ah, bl0[2], bl0[3]);
                MMABF16(acc[2], ah, bl1[0], bl1[1]);
                MMABF16(acc[3], ah, bl1[2], bl1[3]);
                MMABF16(acc[0], al, bh0[0], bh0[1]);
                MMABF16(acc[1], al, bh0[2], bh0[3]);
                MMABF16(acc[2], al, bh1[0], bh1[1]);
                MMABF16(acc[3], al, bh1[2], bh1[3]);
            }
            int r0 = D0 + cr;
            #pragma unroll
            for (int n8=0;n8<4;n8++){
                int col = n8*8 + cc;
                S32[(r0  )*SP + col  ] += acc[n8][0];
                S32[(r0  )*SP + col+1] += acc[n8][1];
                S32[(r0+8)*SP + col  ] += acc[n8][2];
                S32[(r0+8)*SP + col+1] += acc[n8][3];
            }
        }

        // ---- store prefetched wq tiles for c+1 (wq dead since sync2)
        if (c+1 < NCHUNK){
            *(float4*)&wq_hi[pr*WQP+pcx]         = pW0h;
            *(float4*)&wq_lo[pr*WQP+pcx]         = pW0l;
            *(float4*)&wq_hi[(32+pr)*WQP+pcx]    = pQ0h;
            *(float4*)&wq_lo[(32+pr)*WQP+pcx]    = pQ0l;
            *(float4*)&wq_hi[(pr+16)*WQP+pcx]    = dW1h;
            *(float4*)&wq_lo[(pr+16)*WQP+pcx]    = dW1l;
            *(float4*)&wq_hi[(48+pr)*WQP+pcx]    = dQ1h;
            *(float4*)&wq_lo[(48+pr)*WQP+pcx]    = dQ1l;
        }

        __syncwarp();
        // ---- refresh S limbs (warp w owns rows w*16..w*16+15; thread: half-row)
        {
            int r  = tid >> 1;
            int cb = (tid & 1) << 4;
            #pragma unroll
            for (int c4=0;c4<16;c4+=4){
                float4 sv = *(float4*)&S32[r*SP + cb + c4];
                split_store4(sv, &S_hi[r*SBP+cb+c4], &S_lo[r*SBP+cb+c4]);
            }
        }
        __syncthreads();   // sync4
    }
}

// ---------------- EMA phase 1: segmented local scan --------------------------
__global__ void __launch_bounds__(256) ema_local_kernel()
{
    extern __shared__ float esm[];
    float* cbuf = esm;             // ESEG*256
    float* gbuf = cbuf + ESEG*256; // ESEG
    float* Ps   = gbuf + ESEG;     // ESEG

    int bh = blockIdx.x, seg = blockIdx.y;
    int b = bh >> 2, h = bh & 3;
    int tid = threadIdx.x;
    int rowbase = b*LL + seg*ESEG;
    size_t hcol = (size_t)h*DK;

    if (tid < ESEG) gbuf[tid] = g_gamma[(rowbase+tid)*HH + h];
    __syncthreads();

    for (int e = tid; e < ESEG*64; e += 256){
        int r = e >> 6, c4 = (e & 63) << 2;
        float om = 1.f - gbuf[r];
        float4 vv = *(const float4*)&g_V[(size_t)(rowbase+r)*DD + hcol + c4];
        vv.x*=om; vv.y*=om; vv.z*=om; vv.w*=om;
        *(float4*)&cbuf[r*256 + c4] = vv;
    }
    if (tid < ESEG){
        int lane = tid & 31;
        float p = gbuf[tid];
        #pragma unroll
        for (int off=1; off<32; off<<=1){
            float o = __shfl_up_sync(0xffffffffu, p, off);
            if (lane >= off) p *= o;
        }
        Ps[tid] = p;
    }
    __syncthreads();
    if (tid < ESEG){
        int wmy = tid >> 5;
        float pre = 1.f;
        for (int wq = 0; wq < wmy; wq++) pre *= Ps[wq*32+31];
        g_P[bh*LL + seg*ESEG + tid] = pre * Ps[tid];
    }

    float s = 0.f;
    #pragma unroll 8
    for (int t = 0; t < ESEG; t++){
        s = fmaf(gbuf[t], s, cbuf[t*256 + tid]);
        cbuf[t*256 + tid] = s;
    }
    __syncthreads();

    for (int e = tid; e < ESEG*64; e += 256){
        int r = e >> 6, c4 = (e & 63) << 2;
        *(float4*)&g_Oe[(size_t)(rowbase+r)*DD + hcol + c4] = *(float4*)&cbuf[r*256 + c4];
    }
}

// ---------------- EMA phase 2: carry across segments -------------------------
__global__ void __launch_bounds__(256) ema_carry_kernel()
{
    int bh = blockIdx.x;
    int b = bh >> 2, h = bh & 3;
    int dv = threadIdx.x;
    float s = 0.f;
    #pragma unroll
    for (int seg = 0; seg < NSEG; seg++){
        g_C[(bh*NSEG + seg)*DK + dv] = s;
        int rend = b*LL + seg*ESEG + (ESEG-1);
        float P  = g_P[bh*LL + seg*ESEG + (ESEG-1)];
        float ye = g_Oe[(size_t)rend*DD + h*DK + dv];
        s = fmaf(P, s, ye);
    }
}

// ---------------- mix combine + RMS norm + fp16 split (fused, + ema carry) ---
__global__ void __launch_bounds__(256) combine_rms_kernel(const float* __restrict__ rmsw)
{
    int wid = threadIdx.x >> 5, lane = threadIdx.x & 31;
    int g = blockIdx.x*8 + wid;
    int row = g >> 2, h = g & 3;
    int b = row >> 11, t = row & (LL-1);
    int bh = b*4 + h, seg = t >> 7;
    float m = g_mixg[row*4+h];
    size_t base = (size_t)row*DD + h*DK;

    float P = g_P[bh*LL + t];
    const float* cav = &g_C[(bh*NSEG + seg)*DK];
    float4 c0 = *(const float4*)&cav[lane*4];
    float4 c1 = *(const float4*)&cav[128 + lane*4];

    float4 d0 = *(float4*)&g_Od[base + lane*4];
    float4 d1 = *(float4*)&g_Od[base + 128 + lane*4];
    float4 e0 = *(float4*)&g_Oe[base + lane*4];
    float4 e1 = *(float4*)&g_Oe[base + 128 + lane*4];
    e0.x += P*c0.x; e0.y += P*c0.y; e0.z += P*c0.z; e0.w += P*c0.w;
    e1.x += P*c1.x; e1.y += P*c1.y; e1.z += P*c1.z; e1.w += P*c1.w;

    float4 o0, o1;
    float om = 1.f - m;
    o0.x = om*d0.x + m*e0.x; o0.y = om*d0.y + m*e0.y;
    o0.z = om*d0.z + m*e0.z; o0.w = om*d0.w + m*e0.w;
    o1.x = om*d1.x + m*e1.x; o1.y = om*d1.y + m*e1.y;
    o1.z = om*d1.z + m*e1.z; o1.w = om*d1.w + m*e1.w;
    float s = o0.x*o0.x+o0.y*o0.y+o0.z*o0.z+o0.w*o0.w
            + o1.x*o1.x+o1.y*o1.y+o1.z*o1.z+o1.w*o1.w;
    #pragma unroll
    for (int off=16; off; off>>=1) s += __shfl_xor_sync(0xffffffffu, s, off);
    float sc = rsqrtf(s*(1.f/256.f) + 1e-5f);
    float4 r0 = *(const float4*)&rmsw[lane*4];
    float4 r1 = *(const float4*)&rmsw[128 + lane*4];
    o0.x *= sc*r0.x; o0.y *= sc*r0.y; o0.z *= sc*r0.z; o0.w *= sc*r0.w;
    o1.x *= sc*r1.x; o1.y *= sc*r1.y; o1.z *= sc*r1.z; o1.w *= sc*r1.w;

    __half h4[4], l4[4];
    float v[4];
    v[0]=o0.x; v[1]=o0.y; v[2]=o0.z; v[3]=o0.w;
    #pragma unroll
    for (int u=0;u<4;u++){
        h4[u]=__float2half_rn(v[u]);
        l4[u]=__float2half_rn(v[u]-__half2float(h4[u]));
    }
    *(u64t*)&g_Op_hi[base + lane*4] = *(u64t*)h4;
    *(u64t*)&g_Op_lo[base + lane*4] = *(u64t*)l4;
    v[0]=o1.x; v[1]=o1.y; v[2]=o1.z; v[3]=o1.w;
    #pragma unroll
    for (int u=0;u<4;u++){
        h4[u]=__float2half_rn(v[u]);
        l4[u]=__float2half_rn(v[u]-__half2float(h4[u]));
    }
    *(u64t*)&g_Op_hi[base + 128 + lane*4] = *(u64t*)h4;
    *(u64t*)&g_Op_lo[base + 128 + lane*4] = *(u64t*)l4;
}

// ---------------- host driver -----------------------------------------------
extern "C" void kernel_launch(void* const* d_in, const int* in_sizes, int n_in,
                              void* d_out, int out_size)
{
    const float* hs      = (const float*)d_in[0];
    const float* Wq      = (const float*)d_in[1];
    const float* Wk      = (const float*)d_in[2];
    const float* Wv      = (const float*)d_in[3];
    const float* convq   = (const float*)d_in[4];
    const float* convk   = (const float*)d_in[5];
    const float* convv   = (const float*)d_in[6];
    const float* Wb      = (const float*)d_in[7];
    const float* Wdec    = (const float*)d_in[8];
    const float* Wmix    = (const float*)d_in[9];
    const float* convmix = (const float*)d_in[10];
    const float* mixbias = (const float*)d_in[11];
    const float* rmsw    = (const float*)d_in[12];
    const float* Wo      = (const float*)d_in[13];

    void *pQL,*pKL,*pVL;
    cudaGetSymbolAddress(&pQL, g_QL);
    cudaGetSymbolAddress(&pKL, g_KL);
    cudaGetSymbolAddress(&pVL, g_VL);

    void *p_hs_hi,*p_hs_lo,*p_Op_hi,*p_Op_lo,*p_WT_h,*p_WoT_h;
    cudaGetSymbolAddress(&p_hs_hi, g_hs_hi);  cudaGetSymbolAddress(&p_hs_lo, g_hs_lo);
    cudaGetSymbolAddress(&p_Op_hi, g_Op_hi);  cudaGetSymbolAddress(&p_Op_lo, g_Op_lo);
    cudaGetSymbolAddress(&p_WT_h, g_WT_h);    cudaGetSymbolAddress(&p_WoT_h, g_WoT_h);

    int smem_chunk = (2*32*WP + 32*33 + 64) * 4;
    int smem_scan  = (256*36 + 2*64*36 + 4*32*36)*4
                   + (2*256*SBP + 2*64*WQP + 2*32*WQP + 2*32*SBP)*2;  // 221184
    int smem_gemm  = NSTG*STGB;
    int smem_ema   = (ESEG*256 + 2*ESEG) * 4;
    cudaFuncSetAttribute(chunk_kernel, cudaFuncAttributeMaxDynamicSharedMemorySize, smem_chunk);
    cudaFuncSetAttribute(scan_kernel,  cudaFuncAttributeMaxDynamicSharedMemorySize, smem_scan);
    cudaFuncSetAttribute(gemm_f16s,    cudaFuncAttributeMaxDynamicSharedMemorySize, smem_gemm);
    cudaFuncSetAttribute(ema_local_kernel, cudaFuncAttributeMaxDynamicSharedMemorySize, smem_ema);

    // 1: merged prep (split + weight transposes + small projections)
    prep_kernel<<<13312,256>>>(hs, Wq, Wk, Wv, Wo,
        (__half*)p_hs_hi, (__half*)p_hs_lo,
        (__half*)p_WT_h, (__half*)p_WoT_h,
        Wb, Wdec, Wmix);

    // 2: merged QKV GEMM (1536 CTAs)
    gemm_f16s<<<dim3(24,64),256,smem_gemm>>>(
        (__half*)p_hs_hi,(__half*)p_hs_lo,(__half*)p_WT_h,
        (float*)pQL, (float*)pKL, (float*)pVL, DD);

    // 3: fused conv+silu^2+l2norm+limbs (Q,K) / conv+silu (V) / mixconv
    convnorm_kernel<<<16512,256>>>(convq, convk, convv, convmix, mixbias);

    // 4: per-chunk precompute   <- ncu capture slot
    chunk_kernel<<<NBH*NCHUNK,256,smem_chunk>>>();
    // 5: sequential scan
    scan_kernel<<<NBH*8,512,smem_scan>>>();

    ema_local_kernel<<<dim3(NBH,NSEG),256,smem_ema>>>();
    ema_carry_kernel<<<NBH,DK>>>();

    combine_rms_kernel<<<NT*HH/8,256>>>(rmsw);

    gemm_f16s<<<dim3(8,64),256,smem_gemm>>>(
        (__half*)p_Op_hi,(__half*)p_Op_lo,(__half*)p_WoT_h,
        (float*)d_out, (float*)d_out, (float*)d_out, DD);
}